// round 1
// baseline (speedup 1.0000x reference)
#include <cuda_runtime.h>
#include <math.h>

#define QLEN 1024
#define KLEN 2048
#define MEMLEN 1024
#define BSZ 4
#define NH 8
#define DH 64
#define DM 512
#define QKV (3*DM)

// ---------------- scratch (static device globals; no allocation) ------------
__device__ float g_qkv[(size_t)KLEN*BSZ*QKV];   // (jk, b, 1536)
__device__ float g_rk [(size_t)KLEN*DM];        // (jj, n*64+d)
__device__ float g_q  [(size_t)QLEN*BSZ*DM];    // (i, b, n, d)
__device__ float g_k  [(size_t)KLEN*BSZ*DM];    // (j, b, n, d)
__device__ float g_v  [(size_t)KLEN*BSZ*DM];    // (j, b, n, d)
__device__ float g_av [(size_t)QLEN*BSZ*DM];    // (i, b, n, d)
__device__ float g_ao [(size_t)QLEN*BSZ*DM];    // (i, b, 512)

// ---------------- SGEMM: C[M,N] = A[M,K] @ B[N,K]^T  (all row-major) --------
// BM=BN=128, BK=8, 256 threads, 8x8 micro-tile. M%128==0, N%128==0, K%8==0.
__global__ __launch_bounds__(256) void sgemm_tn(const float* __restrict__ A,
                                                const float* __restrict__ B,
                                                float* __restrict__ C,
                                                int M, int N, int K)
{
    __shared__ float As[8][128];
    __shared__ float Bs[8][128];
    int tid = threadIdx.x;
    int tx = tid & 15, ty = tid >> 4;
    int m0 = blockIdx.y * 128, n0 = blockIdx.x * 128;
    int lr = tid >> 1;          // 0..127 (row within tile)
    int lk = (tid & 1) * 4;     // 0 or 4 (k offset)
    const float* Ap = A + (size_t)(m0 + lr) * K + lk;
    const float* Bp = B + (size_t)(n0 + lr) * K + lk;

    float acc[8][8];
    #pragma unroll
    for (int i = 0; i < 8; i++)
        #pragma unroll
        for (int j = 0; j < 8; j++) acc[i][j] = 0.f;

    for (int k0 = 0; k0 < K; k0 += 8) {
        float4 av = *(const float4*)(Ap + k0);
        float4 bv = *(const float4*)(Bp + k0);
        As[lk+0][lr] = av.x; As[lk+1][lr] = av.y; As[lk+2][lr] = av.z; As[lk+3][lr] = av.w;
        Bs[lk+0][lr] = bv.x; Bs[lk+1][lr] = bv.y; Bs[lk+2][lr] = bv.z; Bs[lk+3][lr] = bv.w;
        __syncthreads();
        #pragma unroll
        for (int kk = 0; kk < 8; kk++) {
            float a[8], b[8];
            *(float4*)(a)     = *(const float4*)(&As[kk][ty*8]);
            *(float4*)(a + 4) = *(const float4*)(&As[kk][ty*8 + 4]);
            *(float4*)(b)     = *(const float4*)(&Bs[kk][tx*8]);
            *(float4*)(b + 4) = *(const float4*)(&Bs[kk][tx*8 + 4]);
            #pragma unroll
            for (int i = 0; i < 8; i++)
                #pragma unroll
                for (int j = 0; j < 8; j++) acc[i][j] += a[i] * b[j];
        }
        __syncthreads();
    }
    #pragma unroll
    for (int i = 0; i < 8; i++) {
        float* Cp = C + (size_t)(m0 + ty*8 + i) * N + n0 + tx*8;
        *(float4*)(Cp)     = make_float4(acc[i][0], acc[i][1], acc[i][2], acc[i][3]);
        *(float4*)(Cp + 4) = make_float4(acc[i][4], acc[i][5], acc[i][6], acc[i][7]);
    }
}

// ---------------- per-head conv1d(7), pad 3 ---------------------------------
// out[o,t] = bias[o] + sum_{ic,tap} w[o,ic,tap] * x[ic, t+tap-3]
// x read from g_qkv slice; out written (pos, b, n, d) layout.
__global__ __launch_bounds__(256) void k_conv(const float* __restrict__ cw,
                                              const float* __restrict__ cb,
                                              float* __restrict__ out,
                                              int len, int posoff, int chanoff)
{
    __shared__ float xs[64][71];   // [in_ch][t0-3 .. t0+66]
    __shared__ float ws[64][65];   // [out_ch][in_ch] for one tap
    int t0 = blockIdx.x * 64;
    int nb = blockIdx.y;
    int n = nb >> 2, b = nb & 3;
    int tid = threadIdx.x;

    for (int e = tid; e < 64*70; e += 256) {
        int ic = e / 70, u = e % 70;
        int pos = t0 + u - 3;
        float v = 0.f;
        if (pos >= 0 && pos < len)
            v = g_qkv[(size_t)(pos + posoff) * (BSZ*QKV) + b*QKV + chanoff + n*DH + ic];
        xs[ic][u] = v;
    }

    int o0 = (tid >> 4) * 4, tl0 = (tid & 15) * 4;
    float acc[4][4];
    #pragma unroll
    for (int a = 0; a < 4; a++)
        #pragma unroll
        for (int q = 0; q < 4; q++) acc[a][q] = 0.f;

    for (int tap = 0; tap < 7; tap++) {
        __syncthreads();
        for (int e = tid; e < 64*64; e += 256) {
            int o = e >> 6, ic = e & 63;
            ws[o][ic] = cw[(o*64 + ic)*7 + tap];
        }
        __syncthreads();
        #pragma unroll 4
        for (int ic = 0; ic < 64; ic++) {
            float x0 = xs[ic][tl0+tap],   x1 = xs[ic][tl0+tap+1];
            float x2 = xs[ic][tl0+tap+2], x3 = xs[ic][tl0+tap+3];
            #pragma unroll
            for (int a = 0; a < 4; a++) {
                float wv = ws[o0+a][ic];
                acc[a][0] += wv*x0; acc[a][1] += wv*x1;
                acc[a][2] += wv*x2; acc[a][3] += wv*x3;
            }
        }
    }
    #pragma unroll
    for (int a = 0; a < 4; a++) {
        float bias = cb[o0+a];
        #pragma unroll
        for (int q = 0; q < 4; q++) {
            int t = tl0 + q;
            out[(size_t)(t0+t)*(BSZ*DM) + b*DM + n*DH + o0 + a] = acc[a][q] + bias;
        }
    }
}

// ---------------- attention (online softmax, fused AC + shifted BD) ---------
// score[i,j] = ((q_i+rwb)·k_j + (q_i+rrb)·rk[j-i+QLEN-1]) * 1/8, masked j>i+MEMLEN
__global__ __launch_bounds__(256) void k_attn(const float* __restrict__ rwb,
                                              const float* __restrict__ rrb)
{
    extern __shared__ float sm[];
    float* qw = sm;               // 64 x 65
    float* qr = qw + 64*65;
    float* kt = qr + 64*65;
    float* vt = kt + 64*65;
    float* sc = vt + 64*65;
    float* rk = sc + 64*65;       // 127 x 65
    int i0 = blockIdx.x * 64;
    int bn = blockIdx.y;
    int b = bn >> 3, n = bn & 7;
    int tid = threadIdx.x;

    for (int e = tid; e < 64*64; e += 256) {
        int ii = e >> 6, d = e & 63;
        float qv = g_q[(size_t)(i0+ii)*(BSZ*DM) + b*DM + n*DH + d];
        qw[ii*65 + d] = qv + rwb[n*DH + d];
        qr[ii*65 + d] = qv + rrb[n*DH + d];
    }

    int r = tid >> 2, c = tid & 3;  // 4 threads per query row
    float m_i = -1e30f, l_i = 0.f;
    float acc[16];
    #pragma unroll
    for (int dd = 0; dd < 16; dd++) acc[dd] = 0.f;

    int ntiles = i0/64 + 17;  // covers j <= i0+63+MEMLEN
    for (int t = 0; t < ntiles; t++) {
        int j0 = t * 64;
        __syncthreads();
        for (int e = tid; e < 64*64; e += 256) {
            int jl = e >> 6, d = e & 63;
            size_t gi = (size_t)(j0+jl)*(BSZ*DM) + b*DM + n*DH + d;
            kt[jl*65 + d] = g_k[gi];
            vt[jl*65 + d] = g_v[gi];
        }
        int jjb = j0 - i0 + 960;   // = j0 - i0 + (QLEN-1) - 63, always >= 0
        for (int e = tid; e < 127*64; e += 256) {
            int l = e >> 6, d = e & 63;
            int jj = jjb + l;
            rk[l*65 + d] = (jj < KLEN) ? g_rk[(size_t)jj*DM + n*DH + d] : 0.f;
        }
        __syncthreads();

        float s[16];
        #pragma unroll
        for (int q16 = 0; q16 < 16; q16++) s[q16] = 0.f;
        for (int d0 = 0; d0 < 64; d0 += 16) {
            float qwv[16], qrv[16];
            #pragma unroll
            for (int dd = 0; dd < 16; dd++) {
                qwv[dd] = qw[r*65 + d0 + dd];
                qrv[dd] = qr[r*65 + d0 + dd];
            }
            #pragma unroll
            for (int q16 = 0; q16 < 16; q16++) {
                int jl = q16*4 + c;
                int rl = jl - r + 63;           // local rel index into rk window
                float a = s[q16];
                #pragma unroll
                for (int dd = 0; dd < 16; dd++)
                    a += qwv[dd]*kt[jl*65 + d0 + dd] + qrv[dd]*rk[rl*65 + d0 + dd];
                s[q16] = a;
            }
        }
        float mt = -1e30f;
        #pragma unroll
        for (int q16 = 0; q16 < 16; q16++) {
            int j = j0 + q16*4 + c;
            s[q16] = (j > i0 + r + MEMLEN) ? -1e30f : s[q16] * 0.125f;
            mt = fmaxf(mt, s[q16]);
        }
        mt = fmaxf(mt, __shfl_xor_sync(0xffffffffu, mt, 1));
        mt = fmaxf(mt, __shfl_xor_sync(0xffffffffu, mt, 2));
        float m_new = fmaxf(m_i, mt);
        float corr = __expf(m_i - m_new);
        float ps = 0.f;
        #pragma unroll
        for (int q16 = 0; q16 < 16; q16++) {
            float p = __expf(s[q16] - m_new);
            s[q16] = p; ps += p;
        }
        ps += __shfl_xor_sync(0xffffffffu, ps, 1);
        ps += __shfl_xor_sync(0xffffffffu, ps, 2);
        l_i = l_i * corr + ps;
        m_i = m_new;
        #pragma unroll
        for (int dd = 0; dd < 16; dd++) acc[dd] *= corr;
        #pragma unroll
        for (int q16 = 0; q16 < 16; q16++) sc[r*65 + q16*4 + c] = s[q16];
        __syncthreads();
        #pragma unroll 8
        for (int j = 0; j < 64; j++) {
            float pv = sc[r*65 + j];
            #pragma unroll
            for (int dd = 0; dd < 16; dd++)
                acc[dd] += pv * vt[j*65 + c*16 + dd];
        }
    }
    float inv = 1.f / l_i;
    #pragma unroll
    for (int dd = 0; dd < 16; dd++)
        g_av[(size_t)(i0+r)*(BSZ*DM) + b*DM + n*DH + c*16 + dd] = acc[dd] * inv;
}

// ---------------- residual + layernorm --------------------------------------
__global__ __launch_bounds__(256) void k_ln(const float* __restrict__ w,
                                            const float* __restrict__ g,
                                            const float* __restrict__ be,
                                            float* __restrict__ out)
{
    __shared__ float red[256];
    int row = blockIdx.x;
    int tid = threadIdx.x;
    const float* wr = w    + (size_t)row * DM;
    const float* ar = g_ao + (size_t)row * DM;
    float x0 = wr[tid]       + ar[tid];
    float x1 = wr[tid + 256] + ar[tid + 256];
    red[tid] = x0 + x1;
    __syncthreads();
    for (int s = 128; s > 0; s >>= 1) { if (tid < s) red[tid] += red[tid + s]; __syncthreads(); }
    float mu = red[0] * (1.f / DM);
    __syncthreads();
    float d0 = x0 - mu, d1 = x1 - mu;
    red[tid] = d0*d0 + d1*d1;
    __syncthreads();
    for (int s = 128; s > 0; s >>= 1) { if (tid < s) red[tid] += red[tid + s]; __syncthreads(); }
    float rs = rsqrtf(red[0] * (1.f / DM) + 1e-5f);
    out[(size_t)row*DM + tid]       = d0 * rs * g[tid]       + be[tid];
    out[(size_t)row*DM + tid + 256] = d1 * rs * g[tid + 256] + be[tid + 256];
}

// ---------------- launcher ---------------------------------------------------
extern "C" void kernel_launch(void* const* d_in, const int* in_sizes, int n_in,
                              void* d_out, int out_size)
{
    (void)in_sizes; (void)n_in; (void)out_size;
    const float* w    = (const float*)d_in[0];
    const float* r    = (const float*)d_in[1];
    const float* mems = (const float*)d_in[2];
    const float* rwb  = (const float*)d_in[3];
    const float* rrb  = (const float*)d_in[4];
    const float* qkvW = (const float*)d_in[5];
    const float* rW   = (const float*)d_in[6];
    const float* cqw  = (const float*)d_in[7];
    const float* cqb  = (const float*)d_in[8];
    const float* ckw  = (const float*)d_in[9];
    const float* ckb  = (const float*)d_in[10];
    const float* cvw  = (const float*)d_in[11];
    const float* cvb  = (const float*)d_in[12];
    const float* oW   = (const float*)d_in[13];
    const float* lng  = (const float*)d_in[14];
    const float* lnb  = (const float*)d_in[15];
    // d_in[16] = attn_mask: causal structure computed analytically, unused.
    float* out = (float*)d_out;

    float *p_qkv, *p_rk, *p_q, *p_k, *p_v, *p_av, *p_ao;
    cudaGetSymbolAddress((void**)&p_qkv, g_qkv);
    cudaGetSymbolAddress((void**)&p_rk,  g_rk);
    cudaGetSymbolAddress((void**)&p_q,   g_q);
    cudaGetSymbolAddress((void**)&p_k,   g_k);
    cudaGetSymbolAddress((void**)&p_v,   g_v);
    cudaGetSymbolAddress((void**)&p_av,  g_av);
    cudaGetSymbolAddress((void**)&p_ao,  g_ao);

    dim3 b256(256);

    // QKV projection: cat = [mems; w], split into two GEMMs (4096 rows each).
    sgemm_tn<<<dim3(QKV/128, (MEMLEN*BSZ)/128), b256>>>(mems, qkvW, p_qkv,
                                                        MEMLEN*BSZ, QKV, DM);
    sgemm_tn<<<dim3(QKV/128, (QLEN*BSZ)/128), b256>>>(w, qkvW,
                                                      p_qkv + (size_t)MEMLEN*BSZ*QKV,
                                                      QLEN*BSZ, QKV, DM);
    // r @ r_W^T
    sgemm_tn<<<dim3(DM/128, KLEN/128), b256>>>(r, rW, p_rk, KLEN, DM, DM);

    // per-head convs (q uses only the last QLEN rows of the q slice)
    k_conv<<<dim3(QLEN/64, NH*BSZ), b256>>>(cqw, cqb, p_q, QLEN, MEMLEN, 0);
    k_conv<<<dim3(KLEN/64, NH*BSZ), b256>>>(ckw, ckb, p_k, KLEN, 0, DM);
    k_conv<<<dim3(KLEN/64, NH*BSZ), b256>>>(cvw, cvb, p_v, KLEN, 0, 2*DM);

    // fused rel-pos attention
    int smbytes = (5*64*65 + 127*65) * 4;
    cudaFuncSetAttribute(k_attn, cudaFuncAttributeMaxDynamicSharedMemorySize, smbytes);
    k_attn<<<dim3(QLEN/64, BSZ*NH), b256, smbytes>>>(rwb, rrb);

    // output projection + residual layernorm
    sgemm_tn<<<dim3(DM/128, (QLEN*BSZ)/128), b256>>>(p_av, oW, p_ao, QLEN*BSZ, DM, DM);
    k_ln<<<QLEN*BSZ, b256>>>(w, lng, lnb, out);
}

// round 2
// speedup vs baseline: 1.7551x; 1.7551x over previous
#include <cuda_runtime.h>
#include <math.h>
#include <stdint.h>

#define QLEN 1024
#define KLEN 2048
#define MEMLEN 1024
#define BSZ 4
#define NH 8
#define DH 64
#define DM 512
#define QKV (3*DM)

// ---------------- scratch (static device globals; no allocation) ------------
__device__ float g_qkv[(size_t)KLEN*BSZ*QKV];   // (jk, b, 1536)
__device__ float g_rk [(size_t)KLEN*DM];        // (jj, n*64+d)
__device__ float g_q  [(size_t)QLEN*BSZ*DM];    // (i, b, n, d)
__device__ float g_k  [(size_t)KLEN*BSZ*DM];    // (j, b, n, d)
__device__ float g_v  [(size_t)KLEN*BSZ*DM];    // (j, b, n, d)
__device__ float g_av [(size_t)QLEN*BSZ*DM];    // (i, b, n, d)
__device__ float g_ao [(size_t)QLEN*BSZ*DM];    // (i, b, 512)

__device__ __forceinline__ uint32_t f2t(float x) {
    uint32_t u;
    asm("cvt.rna.tf32.f32 %0, %1;" : "=r"(u) : "f"(x));
    return u;
}

__device__ __forceinline__ void mma_tf32(float& c0, float& c1, float& c2, float& c3,
                                         uint32_t a0, uint32_t a1, uint32_t a2, uint32_t a3,
                                         uint32_t b0, uint32_t b1)
{
    asm volatile("mma.sync.aligned.m16n8k8.row.col.f32.tf32.tf32.f32 "
                 "{%0,%1,%2,%3},{%4,%5,%6,%7},{%8,%9},{%0,%1,%2,%3};\n"
                 : "+f"(c0), "+f"(c1), "+f"(c2), "+f"(c3)
                 : "r"(a0), "r"(a1), "r"(a2), "r"(a3), "r"(b0), "r"(b1));
}

// ---------------- TF32 tensor GEMM: C[M,N] = A[M,K] @ B[N,K]^T ---------------
// BM=BN=128, BK=16, 256 threads = 8 warps (4m x 2n), warp tile 32m x 64n.
__global__ __launch_bounds__(256) void mm_tf32(const float* __restrict__ A,
                                               const float* __restrict__ B,
                                               float* __restrict__ C,
                                               int M, int N, int K)
{
    __shared__ uint32_t As[16][132];
    __shared__ uint32_t Bs[16][132];
    const int tid = threadIdx.x;
    const int warp = tid >> 5, lane = tid & 31;
    const int wm = warp & 3, wn = warp >> 2;
    const int g = lane >> 2, tg = lane & 3;
    const int m0 = blockIdx.y * 128, n0 = blockIdx.x * 128;

    float c[2][8][4];
    #pragma unroll
    for (int mt = 0; mt < 2; mt++)
        #pragma unroll
        for (int nt = 0; nt < 8; nt++)
            #pragma unroll
            for (int q = 0; q < 4; q++) c[mt][nt][q] = 0.f;

    const int lr = tid >> 2;          // 0..63
    const int lc = (tid & 3) * 4;     // 0,4,8,12
    const float* Ap = A + (size_t)m0 * K;
    const float* Bp = B + (size_t)n0 * K;

    for (int k0 = 0; k0 < K; k0 += 16) {
        float4 a0 = *(const float4*)(Ap + (size_t)lr * K + k0 + lc);
        float4 a1 = *(const float4*)(Ap + (size_t)(lr + 64) * K + k0 + lc);
        float4 b0 = *(const float4*)(Bp + (size_t)lr * K + k0 + lc);
        float4 b1 = *(const float4*)(Bp + (size_t)(lr + 64) * K + k0 + lc);
        __syncthreads();
        As[lc+0][lr] = f2t(a0.x); As[lc+1][lr] = f2t(a0.y);
        As[lc+2][lr] = f2t(a0.z); As[lc+3][lr] = f2t(a0.w);
        As[lc+0][lr+64] = f2t(a1.x); As[lc+1][lr+64] = f2t(a1.y);
        As[lc+2][lr+64] = f2t(a1.z); As[lc+3][lr+64] = f2t(a1.w);
        Bs[lc+0][lr] = f2t(b0.x); Bs[lc+1][lr] = f2t(b0.y);
        Bs[lc+2][lr] = f2t(b0.z); Bs[lc+3][lr] = f2t(b0.w);
        Bs[lc+0][lr+64] = f2t(b1.x); Bs[lc+1][lr+64] = f2t(b1.y);
        Bs[lc+2][lr+64] = f2t(b1.z); Bs[lc+3][lr+64] = f2t(b1.w);
        __syncthreads();

        #pragma unroll
        for (int kk = 0; kk < 16; kk += 8) {
            uint32_t af[2][4], bf[8][2];
            #pragma unroll
            for (int mt = 0; mt < 2; mt++) {
                int mb = wm * 32 + mt * 16;
                af[mt][0] = As[kk + tg][mb + g];
                af[mt][1] = As[kk + tg][mb + g + 8];
                af[mt][2] = As[kk + tg + 4][mb + g];
                af[mt][3] = As[kk + tg + 4][mb + g + 8];
            }
            #pragma unroll
            for (int nt = 0; nt < 8; nt++) {
                int nb = wn * 64 + nt * 8;
                bf[nt][0] = Bs[kk + tg][nb + g];
                bf[nt][1] = Bs[kk + tg + 4][nb + g];
            }
            #pragma unroll
            for (int mt = 0; mt < 2; mt++)
                #pragma unroll
                for (int nt = 0; nt < 8; nt++)
                    mma_tf32(c[mt][nt][0], c[mt][nt][1], c[mt][nt][2], c[mt][nt][3],
                             af[mt][0], af[mt][1], af[mt][2], af[mt][3],
                             bf[nt][0], bf[nt][1]);
        }
    }

    #pragma unroll
    for (int mt = 0; mt < 2; mt++) {
        int row0 = m0 + wm * 32 + mt * 16 + g;
        #pragma unroll
        for (int nt = 0; nt < 8; nt++) {
            int col = n0 + wn * 64 + nt * 8 + tg * 2;
            *(float2*)&C[(size_t)row0 * N + col]       = make_float2(c[mt][nt][0], c[mt][nt][1]);
            *(float2*)&C[(size_t)(row0 + 8) * N + col] = make_float2(c[mt][nt][2], c[mt][nt][3]);
        }
    }
}

// ---------------- per-head conv1d(7), pad 3 ---------------------------------
__global__ __launch_bounds__(256) void k_conv(const float* __restrict__ cw,
                                              const float* __restrict__ cb,
                                              float* __restrict__ out,
                                              int len, int posoff, int chanoff)
{
    __shared__ float xs[64][71];
    __shared__ float ws[64][65];
    int t0 = blockIdx.x * 64;
    int nb = blockIdx.y;
    int n = nb >> 2, b = nb & 3;
    int tid = threadIdx.x;

    for (int e = tid; e < 64*70; e += 256) {
        int ic = e / 70, u = e % 70;
        int pos = t0 + u - 3;
        float v = 0.f;
        if (pos >= 0 && pos < len)
            v = g_qkv[(size_t)(pos + posoff) * (BSZ*QKV) + b*QKV + chanoff + n*DH + ic];
        xs[ic][u] = v;
    }

    int o0 = (tid >> 4) * 4, tl0 = (tid & 15) * 4;
    float acc[4][4];
    #pragma unroll
    for (int a = 0; a < 4; a++)
        #pragma unroll
        for (int q = 0; q < 4; q++) acc[a][q] = 0.f;

    for (int tap = 0; tap < 7; tap++) {
        __syncthreads();
        for (int e = tid; e < 64*64; e += 256) {
            int o = e >> 6, ic = e & 63;
            ws[o][ic] = cw[(o*64 + ic)*7 + tap];
        }
        __syncthreads();
        #pragma unroll 4
        for (int ic = 0; ic < 64; ic++) {
            float x0 = xs[ic][tl0+tap],   x1 = xs[ic][tl0+tap+1];
            float x2 = xs[ic][tl0+tap+2], x3 = xs[ic][tl0+tap+3];
            #pragma unroll
            for (int a = 0; a < 4; a++) {
                float wv = ws[o0+a][ic];
                acc[a][0] += wv*x0; acc[a][1] += wv*x1;
                acc[a][2] += wv*x2; acc[a][3] += wv*x3;
            }
        }
    }
    #pragma unroll
    for (int a = 0; a < 4; a++) {
        float bias = cb[o0+a];
        #pragma unroll
        for (int q = 0; q < 4; q++) {
            int t = tl0 + q;
            out[(size_t)(t0+t)*(BSZ*DM) + b*DM + n*DH + o0 + a] = acc[a][q] + bias;
        }
    }
}

// ---------------- attention v2: 4x4 register tile + rel-pos ring buffer ------
// score[i,j] = ((q_i+rwb)·k_j + (q_i+rrb)·rk[j-i+QLEN-1]) * 1/8, masked j>i+MEMLEN
__global__ __launch_bounds__(256) void k_attn2(const float* __restrict__ rwb,
                                               const float* __restrict__ rrb)
{
    extern __shared__ float sm[];
    float* qwT = sm;               // [d][i]  64 x 68
    float* qrT = qwT + 64*68;      // [d][i]
    float* ktT = qrT + 64*68;      // [d][j]
    float* vt  = ktT + 64*68;      // [j][d]
    float* scT = vt  + 64*68;      // [j][i]
    float* rkT = scT + 64*68;      // [d][slot]  64 x 136 (128-ring + 6 dup + pad)
    const int i0 = blockIdx.x * 64;
    const int bn = blockIdx.y;
    const int b = bn >> 3, n = bn & 7;
    const int tid = threadIdx.x;
    const int TI = tid >> 4, TJ = tid & 15;

    // load Q (+biases), transposed to [d][i]
    for (int e = tid; e < 64*16; e += 256) {
        int ii = e >> 4, d4 = (e & 15) * 4;
        float4 qv = *(const float4*)&g_q[(size_t)(i0+ii)*(BSZ*DM) + b*DM + n*DH + d4];
        float4 wv = *(const float4*)&rwb[n*DH + d4];
        float4 rv = *(const float4*)&rrb[n*DH + d4];
        qwT[(d4+0)*68 + ii] = qv.x + wv.x;
        qwT[(d4+1)*68 + ii] = qv.y + wv.y;
        qwT[(d4+2)*68 + ii] = qv.z + wv.z;
        qwT[(d4+3)*68 + ii] = qv.w + wv.w;
        qrT[(d4+0)*68 + ii] = qv.x + rv.x;
        qrT[(d4+1)*68 + ii] = qv.y + rv.y;
        qrT[(d4+2)*68 + ii] = qv.z + rv.z;
        qrT[(d4+3)*68 + ii] = qv.w + rv.w;
    }
    // initial rel-pos ring fill: jj in [jjb0, jjb0+128)
    const int jjb0 = 960 - i0;
    for (int e = tid; e < 128*16; e += 256) {
        int l = e >> 4, d4 = (e & 15) * 4;
        int jj = jjb0 + l;
        float4 v = make_float4(0.f, 0.f, 0.f, 0.f);
        if (jj < KLEN) v = *(const float4*)&g_rk[(size_t)jj*DM + n*DH + d4];
        int slot = jj & 127;
        rkT[(d4+0)*136 + slot] = v.x;
        rkT[(d4+1)*136 + slot] = v.y;
        rkT[(d4+2)*136 + slot] = v.z;
        rkT[(d4+3)*136 + slot] = v.w;
        if (slot < 6) {
            rkT[(d4+0)*136 + slot + 128] = v.x;
            rkT[(d4+1)*136 + slot + 128] = v.y;
            rkT[(d4+2)*136 + slot + 128] = v.z;
            rkT[(d4+3)*136 + slot + 128] = v.w;
        }
    }

    float m_i[4], l_i[4], acc[4][4];
    #pragma unroll
    for (int a = 0; a < 4; a++) {
        m_i[a] = -1e30f; l_i[a] = 0.f;
        #pragma unroll
        for (int q = 0; q < 4; q++) acc[a][q] = 0.f;
    }

    const int ntiles = i0/64 + 17;
    for (int t = 0; t < ntiles; t++) {
        const int j0 = t * 64;
        const int jjb = j0 - i0 + 960;
        __syncthreads();
        // fill K (transposed) and V tiles
        for (int e = tid; e < 64*16; e += 256) {
            int jl = e >> 4, d4 = (e & 15) * 4;
            size_t gi = (size_t)(j0+jl)*(BSZ*DM) + b*DM + n*DH + d4;
            float4 kv = *(const float4*)&g_k[gi];
            float4 vv = *(const float4*)&g_v[gi];
            ktT[(d4+0)*68 + jl] = kv.x;
            ktT[(d4+1)*68 + jl] = kv.y;
            ktT[(d4+2)*68 + jl] = kv.z;
            ktT[(d4+3)*68 + jl] = kv.w;
            *(float4*)&vt[jl*68 + d4] = vv;
        }
        if (t > 0) {
            // slide ring: new rows jj in [jjb+64, jjb+128)
            for (int e = tid; e < 64*16; e += 256) {
                int l = e >> 4, d4 = (e & 15) * 4;
                int jj = jjb + 64 + l;
                float4 v = make_float4(0.f, 0.f, 0.f, 0.f);
                if (jj < KLEN) v = *(const float4*)&g_rk[(size_t)jj*DM + n*DH + d4];
                int slot = jj & 127;
                rkT[(d4+0)*136 + slot] = v.x;
                rkT[(d4+1)*136 + slot] = v.y;
                rkT[(d4+2)*136 + slot] = v.z;
                rkT[(d4+3)*136 + slot] = v.w;
                if (slot < 6) {
                    rkT[(d4+0)*136 + slot + 128] = v.x;
                    rkT[(d4+1)*136 + slot + 128] = v.y;
                    rkT[(d4+2)*136 + slot + 128] = v.z;
                    rkT[(d4+3)*136 + slot + 128] = v.w;
                }
            }
        }
        __syncthreads();

        // scores: s[a][b] for i = i0+TI*4+a, j = j0+TJ*4+b
        float s[4][4];
        #pragma unroll
        for (int a = 0; a < 4; a++)
            #pragma unroll
            for (int bb = 0; bb < 4; bb++) s[a][bb] = 0.f;

        const int sb = (jjb + 60 + 4*(TJ - TI)) & 127;  // slot of min jj in micro-tile
        #pragma unroll 4
        for (int d = 0; d < 64; d++) {
            float4 qa = *(float4*)&qwT[d*68 + TI*4];
            float4 qb = *(float4*)&qrT[d*68 + TI*4];
            float4 kb = *(float4*)&ktT[d*68 + TJ*4];
            const float* rp = &rkT[d*136 + sb];
            float qwv[4] = {qa.x, qa.y, qa.z, qa.w};
            float qrv[4] = {qb.x, qb.y, qb.z, qb.w};
            float kv[4]  = {kb.x, kb.y, kb.z, kb.w};
            float rr[7];
            #pragma unroll
            for (int u = 0; u < 7; u++) rr[u] = rp[u];
            #pragma unroll
            for (int a = 0; a < 4; a++)
                #pragma unroll
                for (int bb = 0; bb < 4; bb++)
                    s[a][bb] += qwv[a]*kv[bb] + qrv[a]*rr[bb - a + 3];
        }

        // online softmax
        #pragma unroll
        for (int a = 0; a < 4; a++) {
            const int ig = i0 + TI*4 + a;
            float mx = -1e30f;
            #pragma unroll
            for (int bb = 0; bb < 4; bb++) {
                int jg = j0 + TJ*4 + bb;
                float v = (jg > ig + MEMLEN) ? -1e30f : s[a][bb] * 0.125f;
                s[a][bb] = v;
                mx = fmaxf(mx, v);
            }
            mx = fmaxf(mx, __shfl_xor_sync(0xffffffffu, mx, 1));
            mx = fmaxf(mx, __shfl_xor_sync(0xffffffffu, mx, 2));
            mx = fmaxf(mx, __shfl_xor_sync(0xffffffffu, mx, 4));
            mx = fmaxf(mx, __shfl_xor_sync(0xffffffffu, mx, 8));
            float mnew = fmaxf(m_i[a], mx);
            float corr = __expf(m_i[a] - mnew);
            m_i[a] = mnew;
            float ps = 0.f;
            #pragma unroll
            for (int bb = 0; bb < 4; bb++) {
                float p = __expf(s[a][bb] - mnew);
                s[a][bb] = p; ps += p;
            }
            ps += __shfl_xor_sync(0xffffffffu, ps, 1);
            ps += __shfl_xor_sync(0xffffffffu, ps, 2);
            ps += __shfl_xor_sync(0xffffffffu, ps, 4);
            ps += __shfl_xor_sync(0xffffffffu, ps, 8);
            l_i[a] = l_i[a] * corr + ps;
            #pragma unroll
            for (int q = 0; q < 4; q++) acc[a][q] *= corr;
        }
        #pragma unroll
        for (int a = 0; a < 4; a++)
            #pragma unroll
            for (int bb = 0; bb < 4; bb++)
                scT[(TJ*4+bb)*68 + TI*4 + a] = s[a][bb];
        __syncthreads();

        // PV: acc[a][q] += p[i_a, j] * v[j, d_q]
        #pragma unroll 4
        for (int j = 0; j < 64; j++) {
            float4 p4 = *(float4*)&scT[j*68 + TI*4];
            float4 v4 = *(float4*)&vt[j*68 + TJ*4];
            float pv[4] = {p4.x, p4.y, p4.z, p4.w};
            float vv[4] = {v4.x, v4.y, v4.z, v4.w};
            #pragma unroll
            for (int a = 0; a < 4; a++)
                #pragma unroll
                for (int q = 0; q < 4; q++) acc[a][q] += pv[a]*vv[q];
        }
    }

    #pragma unroll
    for (int a = 0; a < 4; a++) {
        float inv = 1.f / l_i[a];
        float4 o = make_float4(acc[a][0]*inv, acc[a][1]*inv, acc[a][2]*inv, acc[a][3]*inv);
        *(float4*)&g_av[(size_t)(i0+TI*4+a)*(BSZ*DM) + b*DM + n*DH + TJ*4] = o;
    }
}

// ---------------- residual + layernorm --------------------------------------
__global__ __launch_bounds__(256) void k_ln(const float* __restrict__ w,
                                            const float* __restrict__ g,
                                            const float* __restrict__ be,
                                            float* __restrict__ out)
{
    __shared__ float red[256];
    int row = blockIdx.x;
    int tid = threadIdx.x;
    const float* wr = w    + (size_t)row * DM;
    const float* ar = g_ao + (size_t)row * DM;
    float x0 = wr[tid]       + ar[tid];
    float x1 = wr[tid + 256] + ar[tid + 256];
    red[tid] = x0 + x1;
    __syncthreads();
    for (int s = 128; s > 0; s >>= 1) { if (tid < s) red[tid] += red[tid + s]; __syncthreads(); }
    float mu = red[0] * (1.f / DM);
    __syncthreads();
    float d0 = x0 - mu, d1 = x1 - mu;
    red[tid] = d0*d0 + d1*d1;
    __syncthreads();
    for (int s = 128; s > 0; s >>= 1) { if (tid < s) red[tid] += red[tid + s]; __syncthreads(); }
    float rs = rsqrtf(red[0] * (1.f / DM) + 1e-5f);
    out[(size_t)row*DM + tid]       = d0 * rs * g[tid]       + be[tid];
    out[(size_t)row*DM + tid + 256] = d1 * rs * g[tid + 256] + be[tid + 256];
}

// ---------------- launcher ---------------------------------------------------
extern "C" void kernel_launch(void* const* d_in, const int* in_sizes, int n_in,
                              void* d_out, int out_size)
{
    (void)in_sizes; (void)n_in; (void)out_size;
    const float* w    = (const float*)d_in[0];
    const float* r    = (const float*)d_in[1];
    const float* mems = (const float*)d_in[2];
    const float* rwb  = (const float*)d_in[3];
    const float* rrb  = (const float*)d_in[4];
    const float* qkvW = (const float*)d_in[5];
    const float* rW   = (const float*)d_in[6];
    const float* cqw  = (const float*)d_in[7];
    const float* cqb  = (const float*)d_in[8];
    const float* ckw  = (const float*)d_in[9];
    const float* ckb  = (const float*)d_in[10];
    const float* cvw  = (const float*)d_in[11];
    const float* cvb  = (const float*)d_in[12];
    const float* oW   = (const float*)d_in[13];
    const float* lng  = (const float*)d_in[14];
    const float* lnb  = (const float*)d_in[15];
    float* out = (float*)d_out;

    float *p_qkv, *p_rk, *p_q, *p_k, *p_v, *p_av, *p_ao;
    cudaGetSymbolAddress((void**)&p_qkv, g_qkv);
    cudaGetSymbolAddress((void**)&p_rk,  g_rk);
    cudaGetSymbolAddress((void**)&p_q,   g_q);
    cudaGetSymbolAddress((void**)&p_k,   g_k);
    cudaGetSymbolAddress((void**)&p_v,   g_v);
    cudaGetSymbolAddress((void**)&p_av,  g_av);
    cudaGetSymbolAddress((void**)&p_ao,  g_ao);

    dim3 b256(256);

    // QKV projection: cat = [mems; w] handled as two GEMMs into one buffer.
    mm_tf32<<<dim3(QKV/128, (MEMLEN*BSZ)/128), b256>>>(mems, qkvW, p_qkv,
                                                       MEMLEN*BSZ, QKV, DM);
    mm_tf32<<<dim3(QKV/128, (QLEN*BSZ)/128), b256>>>(w, qkvW,
                                                     p_qkv + (size_t)MEMLEN*BSZ*QKV,
                                                     QLEN*BSZ, QKV, DM);
    // r @ r_W^T
    mm_tf32<<<dim3(DM/128, KLEN/128), b256>>>(r, rW, p_rk, KLEN, DM, DM);

    // per-head convs (q uses only the last QLEN rows of the q slice)
    k_conv<<<dim3(QLEN/64, NH*BSZ), b256>>>(cqw, cqb, p_q, QLEN, MEMLEN, 0);
    k_conv<<<dim3(KLEN/64, NH*BSZ), b256>>>(ckw, ckb, p_k, KLEN, 0, DM);
    k_conv<<<dim3(KLEN/64, NH*BSZ), b256>>>(cvw, cvb, p_v, KLEN, 0, 2*DM);

    // fused rel-pos attention
    int smbytes = (5*64*68 + 64*136) * 4;
    cudaFuncSetAttribute(k_attn2, cudaFuncAttributeMaxDynamicSharedMemorySize, smbytes);
    k_attn2<<<dim3(QLEN/64, BSZ*NH), b256, smbytes>>>(rwb, rrb);

    // output projection + residual layernorm
    mm_tf32<<<dim3(DM/128, (QLEN*BSZ)/128), b256>>>(p_av, oW, p_ao, QLEN*BSZ, DM, DM);
    k_ln<<<QLEN*BSZ, b256>>>(w, lng, lnb, out);
}

// round 3
// speedup vs baseline: 2.7547x; 1.5696x over previous
#include <cuda_runtime.h>
#include <math.h>
#include <stdint.h>

#define QLEN 1024
#define KLEN 2048
#define MEMLEN 1024
#define BSZ 4
#define NH 8
#define DH 64
#define DM 512
#define QKV (3*DM)

// ---------------- scratch (static device globals; no allocation) ------------
__device__ float g_qkv[(size_t)KLEN*BSZ*QKV];   // (jk, b, 1536)
__device__ float g_rk [(size_t)KLEN*DM];        // (jj, n*64+d)
__device__ float g_q  [(size_t)QLEN*BSZ*DM];    // (i, b, n, d)
__device__ float g_k  [(size_t)KLEN*BSZ*DM];    // (j, b, n, d)
__device__ float g_v  [(size_t)KLEN*BSZ*DM];    // (j, b, n, d)
__device__ float g_av [(size_t)QLEN*BSZ*DM];    // (i, b, n, d)
__device__ float g_ao [(size_t)QLEN*BSZ*DM];    // (i, b, 512)
__device__ uint32_t g_wt[3*7*64*64];            // conv weights tf32 [c][tap][ic][oc]

__device__ __forceinline__ uint32_t f2t(float x) {
    uint32_t u;
    asm("cvt.rna.tf32.f32 %0, %1;" : "=r"(u) : "f"(x));
    return u;
}

__device__ __forceinline__ void mma_tf32(float& c0, float& c1, float& c2, float& c3,
                                         uint32_t a0, uint32_t a1, uint32_t a2, uint32_t a3,
                                         uint32_t b0, uint32_t b1)
{
    asm volatile("mma.sync.aligned.m16n8k8.row.col.f32.tf32.tf32.f32 "
                 "{%0,%1,%2,%3},{%4,%5,%6,%7},{%8,%9},{%0,%1,%2,%3};\n"
                 : "+f"(c0), "+f"(c1), "+f"(c2), "+f"(c3)
                 : "r"(a0), "r"(a1), "r"(a2), "r"(a3), "r"(b0), "r"(b1));
}

// 2^y via magic-round + deg-4 poly; no MUFU. y >= -100 handled, y <= ~+30 expected.
__device__ __forceinline__ float exp2_fast(float y) {
    y = fmaxf(y, -100.f);
    float z = __fadd_rn(y, 12582912.f);      // round-to-nearest int lands in mantissa
    float n = __fsub_rn(z, 12582912.f);
    float f = __fsub_rn(y, n);               // f in [-0.5, 0.5]
    float r = 0.0096181291f;
    r = fmaf(r, f, 0.055504109f);
    r = fmaf(r, f, 0.24022651f);
    r = fmaf(r, f, 0.69314718f);
    r = fmaf(r, f, 1.0f);
    int e = __float_as_int(z);               // = 0x4B400000 + n
    float s = __int_as_float((e - 1262485377) << 23);   // 2^n
    return r * s;
}

// ---------------- TF32 tensor GEMM: C[M,N] = A[M,K] @ B[N,K]^T ---------------
__global__ __launch_bounds__(256) void mm_tf32(const float* __restrict__ A,
                                               const float* __restrict__ B,
                                               float* __restrict__ C,
                                               int M, int N, int K)
{
    __shared__ uint32_t As[16][132];
    __shared__ uint32_t Bs[16][132];
    const int tid = threadIdx.x;
    const int warp = tid >> 5, lane = tid & 31;
    const int wm = warp & 3, wn = warp >> 2;
    const int g = lane >> 2, tg = lane & 3;
    const int m0 = blockIdx.y * 128, n0 = blockIdx.x * 128;

    float c[2][8][4];
    #pragma unroll
    for (int mt = 0; mt < 2; mt++)
        #pragma unroll
        for (int nt = 0; nt < 8; nt++)
            #pragma unroll
            for (int q = 0; q < 4; q++) c[mt][nt][q] = 0.f;

    const int lr = tid >> 2;
    const int lc = (tid & 3) * 4;
    const float* Ap = A + (size_t)m0 * K;
    const float* Bp = B + (size_t)n0 * K;

    for (int k0 = 0; k0 < K; k0 += 16) {
        float4 a0 = *(const float4*)(Ap + (size_t)lr * K + k0 + lc);
        float4 a1 = *(const float4*)(Ap + (size_t)(lr + 64) * K + k0 + lc);
        float4 b0 = *(const float4*)(Bp + (size_t)lr * K + k0 + lc);
        float4 b1 = *(const float4*)(Bp + (size_t)(lr + 64) * K + k0 + lc);
        __syncthreads();
        As[lc+0][lr] = f2t(a0.x); As[lc+1][lr] = f2t(a0.y);
        As[lc+2][lr] = f2t(a0.z); As[lc+3][lr] = f2t(a0.w);
        As[lc+0][lr+64] = f2t(a1.x); As[lc+1][lr+64] = f2t(a1.y);
        As[lc+2][lr+64] = f2t(a1.z); As[lc+3][lr+64] = f2t(a1.w);
        Bs[lc+0][lr] = f2t(b0.x); Bs[lc+1][lr] = f2t(b0.y);
        Bs[lc+2][lr] = f2t(b0.z); Bs[lc+3][lr] = f2t(b0.w);
        Bs[lc+0][lr+64] = f2t(b1.x); Bs[lc+1][lr+64] = f2t(b1.y);
        Bs[lc+2][lr+64] = f2t(b1.z); Bs[lc+3][lr+64] = f2t(b1.w);
        __syncthreads();

        #pragma unroll
        for (int kk = 0; kk < 16; kk += 8) {
            uint32_t af[2][4], bf[8][2];
            #pragma unroll
            for (int mt = 0; mt < 2; mt++) {
                int mb = wm * 32 + mt * 16;
                af[mt][0] = As[kk + tg][mb + g];
                af[mt][1] = As[kk + tg][mb + g + 8];
                af[mt][2] = As[kk + tg + 4][mb + g];
                af[mt][3] = As[kk + tg + 4][mb + g + 8];
            }
            #pragma unroll
            for (int nt = 0; nt < 8; nt++) {
                int nb = wn * 64 + nt * 8;
                bf[nt][0] = Bs[kk + tg][nb + g];
                bf[nt][1] = Bs[kk + tg + 4][nb + g];
            }
            #pragma unroll
            for (int mt = 0; mt < 2; mt++)
                #pragma unroll
                for (int nt = 0; nt < 8; nt++)
                    mma_tf32(c[mt][nt][0], c[mt][nt][1], c[mt][nt][2], c[mt][nt][3],
                             af[mt][0], af[mt][1], af[mt][2], af[mt][3],
                             bf[nt][0], bf[nt][1]);
        }
    }

    #pragma unroll
    for (int mt = 0; mt < 2; mt++) {
        int row0 = m0 + wm * 32 + mt * 16 + g;
        #pragma unroll
        for (int nt = 0; nt < 8; nt++) {
            int col = n0 + wn * 64 + nt * 8 + tg * 2;
            *(float2*)&C[(size_t)row0 * N + col]       = make_float2(c[mt][nt][0], c[mt][nt][1]);
            *(float2*)&C[(size_t)(row0 + 8) * N + col] = make_float2(c[mt][nt][2], c[mt][nt][3]);
        }
    }
}

// ---------------- weight prep: w[o][ic][tap] -> tf32 [c][tap][ic][oc] --------
__global__ void k_prepw(const float* __restrict__ cq,
                        const float* __restrict__ ck,
                        const float* __restrict__ cv)
{
    int idx = blockIdx.x;
    int c = idx / 7, tap = idx % 7;
    const float* src = (c == 0) ? cq : (c == 1) ? ck : cv;
    for (int e = threadIdx.x; e < 4096; e += 256) {
        int ic = e >> 6, oc = e & 63;
        g_wt[((c*7 + tap)*64 + ic)*64 + oc] = f2t(src[(oc*64 + ic)*7 + tap]);
    }
}

// ---------------- conv via MMA: 128 t-positions per block, 7 tap-GEMMs -------
__global__ __launch_bounds__(256) void k_conv2(const float* __restrict__ cb,
                                               const uint32_t* __restrict__ wt,
                                               float* __restrict__ out,
                                               int len, int posoff, int chanoff)
{
    extern __shared__ uint32_t cs[];
    uint32_t* xsT = cs;            // [ic=64][u=134 pad 136]
    uint32_t* ws  = cs + 64*136;   // [ic=64][oc pad 68]
    const int t0 = blockIdx.x * 128;
    const int nb = blockIdx.y;
    const int n = nb >> 2, b = nb & 3;
    const int tid = threadIdx.x;
    const int warp = tid >> 5, lane = tid & 31;
    const int wm = warp;           // 8 warps x 16 rows = 128 t
    const int g = lane >> 2, tg = lane & 3;

    // stage x window [t0-3, t0+130]
    for (int e = tid; e < 16*134; e += 256) {
        int u = e % 134, ic4 = (e / 134) * 4;
        int pos = t0 + u - 3;
        float4 v = make_float4(0.f, 0.f, 0.f, 0.f);
        if (pos >= 0 && pos < len)
            v = *(const float4*)&g_qkv[(size_t)(pos + posoff)*(BSZ*QKV) + b*QKV + chanoff + n*DH + ic4];
        xsT[(ic4+0)*136 + u] = f2t(v.x);
        xsT[(ic4+1)*136 + u] = f2t(v.y);
        xsT[(ic4+2)*136 + u] = f2t(v.z);
        xsT[(ic4+3)*136 + u] = f2t(v.w);
    }

    float acc[8][4];
    #pragma unroll
    for (int nf = 0; nf < 8; nf++)
        #pragma unroll
        for (int q = 0; q < 4; q++) acc[nf][q] = 0.f;

    for (int tap = 0; tap < 7; tap++) {
        __syncthreads();
        for (int e = tid; e < 1024; e += 256) {
            int ic = e >> 4, oc4 = (e & 15) * 4;
            *(uint4*)&ws[ic*68 + oc4] = *(const uint4*)&wt[(tap*64 + ic)*64 + oc4];
        }
        __syncthreads();
        #pragma unroll
        for (int k0 = 0; k0 < 64; k0 += 8) {
            uint32_t a0 = xsT[(k0+tg)*136   + wm*16 + g     + tap];
            uint32_t a1 = xsT[(k0+tg)*136   + wm*16 + g + 8 + tap];
            uint32_t a2 = xsT[(k0+tg+4)*136 + wm*16 + g     + tap];
            uint32_t a3 = xsT[(k0+tg+4)*136 + wm*16 + g + 8 + tap];
            #pragma unroll
            for (int nf = 0; nf < 8; nf++) {
                uint32_t b0 = ws[(k0+tg)*68   + nf*8 + g];
                uint32_t b1 = ws[(k0+tg+4)*68 + nf*8 + g];
                mma_tf32(acc[nf][0], acc[nf][1], acc[nf][2], acc[nf][3],
                         a0, a1, a2, a3, b0, b1);
            }
        }
    }

    #pragma unroll
    for (int nf = 0; nf < 8; nf++) {
        int oc = nf*8 + 2*tg;
        float bb0 = cb[oc], bb1 = cb[oc+1];
        int row = t0 + wm*16 + g;
        *(float2*)&out[(size_t)row*(BSZ*DM) + b*DM + n*DH + oc] =
            make_float2(acc[nf][0] + bb0, acc[nf][1] + bb1);
        *(float2*)&out[(size_t)(row+8)*(BSZ*DM) + b*DM + n*DH + oc] =
            make_float2(acc[nf][2] + bb0, acc[nf][3] + bb1);
    }
}

// ---------------- attention v3: full tensor-core, no-max softmax -------------
__global__ __launch_bounds__(256) void k_attn3(const float* __restrict__ rwb,
                                               const float* __restrict__ rrb)
{
    extern __shared__ uint32_t smu[];
    uint32_t* QW = smu;              // [d=64][i pad 68]  (k-major)
    uint32_t* QR = QW + 64*68;
    uint32_t* KS = QR + 64*68;       // [d][jl]
    uint32_t* VT = KS + 64*68;       // [jl][d]
    uint32_t* PR = VT + 64*68;       // [jl][il] scores(float) then probs(tf32)
    float*    PS = (float*)(PR + 64*68);      // [il][l pad 132]
    uint32_t* RW = (uint32_t*)(PS + 64*132);  // [d][slot pad 132]
    float* PRf = (float*)PR;

    const int i0 = (gridDim.x - 1 - blockIdx.x) * 64;   // heavy blocks first
    const int bn = blockIdx.y;
    const int b = bn >> 3, n = bn & 7;
    const int tid = threadIdx.x;
    const int warp = tid >> 5, lane = tid & 31;
    const int wm = warp & 3, wn = warp >> 2;
    const int g = lane >> 2, tg = lane & 3;
    const int TI = tid >> 4, TJ = tid & 15;

    // load Q (+biases) transposed
    for (int e = tid; e < 64*16; e += 256) {
        int ii = e >> 4, d4 = (e & 15) * 4;
        float4 qv = *(const float4*)&g_q[(size_t)(i0+ii)*(BSZ*DM) + b*DM + n*DH + d4];
        float4 wv = *(const float4*)&rwb[n*DH + d4];
        float4 rv = *(const float4*)&rrb[n*DH + d4];
        QW[(d4+0)*68 + ii] = f2t(qv.x + wv.x);
        QW[(d4+1)*68 + ii] = f2t(qv.y + wv.y);
        QW[(d4+2)*68 + ii] = f2t(qv.z + wv.z);
        QW[(d4+3)*68 + ii] = f2t(qv.w + wv.w);
        QR[(d4+0)*68 + ii] = f2t(qv.x + rv.x);
        QR[(d4+1)*68 + ii] = f2t(qv.y + rv.y);
        QR[(d4+2)*68 + ii] = f2t(qv.z + rv.z);
        QR[(d4+3)*68 + ii] = f2t(qv.w + rv.w);
    }
    // rel-pos ring init: jj in [jjb0, jjb0+127], always inside [0, 2048)
    const int jjb0 = 960 - i0;
    for (int e = tid; e < 128*16; e += 256) {
        int l = e >> 4, d4 = (e & 15) * 4;
        int jj = jjb0 + l;
        float4 v = *(const float4*)&g_rk[(size_t)jj*DM + n*DH + d4];
        int slot = jj & 127;
        RW[(d4+0)*132 + slot] = f2t(v.x);
        RW[(d4+1)*132 + slot] = f2t(v.y);
        RW[(d4+2)*132 + slot] = f2t(v.z);
        RW[(d4+3)*132 + slot] = f2t(v.w);
    }

    float oacc[4][4];
    float l_acc[4];
    #pragma unroll
    for (int a = 0; a < 4; a++) {
        l_acc[a] = 0.f;
        #pragma unroll
        for (int q = 0; q < 4; q++) oacc[a][q] = 0.f;
    }

    const int ntiles = i0/64 + 17;
    for (int t = 0; t < ntiles; t++) {
        const int j0 = t * 64;
        const int jjb = j0 - i0 + 960;
        __syncthreads();
        // stage K (transposed), V
        for (int e = tid; e < 64*16; e += 256) {
            int jl = e >> 4, d4 = (e & 15) * 4;
            size_t gi = (size_t)(j0+jl)*(BSZ*DM) + b*DM + n*DH + d4;
            float4 kv = *(const float4*)&g_k[gi];
            float4 vv = *(const float4*)&g_v[gi];
            KS[(d4+0)*68 + jl] = f2t(kv.x);
            KS[(d4+1)*68 + jl] = f2t(kv.y);
            KS[(d4+2)*68 + jl] = f2t(kv.z);
            KS[(d4+3)*68 + jl] = f2t(kv.w);
            uint4 vu = make_uint4(f2t(vv.x), f2t(vv.y), f2t(vv.z), f2t(vv.w));
            *(uint4*)&VT[jl*68 + d4] = vu;
        }
        if (t > 0) {
            // slide ring: new jj in [jjb+64, jjb+127]
            for (int e = tid; e < 64*16; e += 256) {
                int l = e >> 4, d4 = (e & 15) * 4;
                int jj = jjb + 64 + l;
                float4 v = make_float4(0.f, 0.f, 0.f, 0.f);
                if (jj < KLEN) v = *(const float4*)&g_rk[(size_t)jj*DM + n*DH + d4];
                int slot = jj & 127;
                RW[(d4+0)*132 + slot] = f2t(v.x);
                RW[(d4+1)*132 + slot] = f2t(v.y);
                RW[(d4+2)*132 + slot] = f2t(v.z);
                RW[(d4+3)*132 + slot] = f2t(v.w);
            }
        }
        __syncthreads();

        // ---- AC = Qw @ K^T  (64x64), warp tile 16x32 ----
        {
            float sc[4][4];
            #pragma unroll
            for (int nf = 0; nf < 4; nf++)
                #pragma unroll
                for (int q = 0; q < 4; q++) sc[nf][q] = 0.f;
            #pragma unroll
            for (int k0 = 0; k0 < 64; k0 += 8) {
                uint32_t a0 = QW[(k0+tg)*68   + wm*16 + g];
                uint32_t a1 = QW[(k0+tg)*68   + wm*16 + g + 8];
                uint32_t a2 = QW[(k0+tg+4)*68 + wm*16 + g];
                uint32_t a3 = QW[(k0+tg+4)*68 + wm*16 + g + 8];
                #pragma unroll
                for (int nf = 0; nf < 4; nf++) {
                    uint32_t b0 = KS[(k0+tg)*68   + wn*32 + nf*8 + g];
                    uint32_t b1 = KS[(k0+tg+4)*68 + wn*32 + nf*8 + g];
                    mma_tf32(sc[nf][0], sc[nf][1], sc[nf][2], sc[nf][3],
                             a0, a1, a2, a3, b0, b1);
                }
            }
            int il = wm*16 + g;
            #pragma unroll
            for (int nf = 0; nf < 4; nf++) {
                int jl = wn*32 + nf*8 + 2*tg;
                PRf[jl*68     + il]     = sc[nf][0];
                PRf[(jl+1)*68 + il]     = sc[nf][1];
                PRf[jl*68     + il + 8] = sc[nf][2];
                PRf[(jl+1)*68 + il + 8] = sc[nf][3];
            }
        }
        // ---- P = Qr @ RW^T  (64x128), warp tile 16x64 ----
        {
            float pc[8][4];
            #pragma unroll
            for (int nf = 0; nf < 8; nf++)
                #pragma unroll
                for (int q = 0; q < 4; q++) pc[nf][q] = 0.f;
            #pragma unroll
            for (int k0 = 0; k0 < 64; k0 += 8) {
                uint32_t a0 = QR[(k0+tg)*68   + wm*16 + g];
                uint32_t a1 = QR[(k0+tg)*68   + wm*16 + g + 8];
                uint32_t a2 = QR[(k0+tg+4)*68 + wm*16 + g];
                uint32_t a3 = QR[(k0+tg+4)*68 + wm*16 + g + 8];
                #pragma unroll
                for (int nf = 0; nf < 8; nf++) {
                    uint32_t b0 = RW[(k0+tg)*132   + wn*64 + nf*8 + g];
                    uint32_t b1 = RW[(k0+tg+4)*132 + wn*64 + nf*8 + g];
                    mma_tf32(pc[nf][0], pc[nf][1], pc[nf][2], pc[nf][3],
                             a0, a1, a2, a3, b0, b1);
                }
            }
            int il = wm*16 + g;
            #pragma unroll
            for (int nf = 0; nf < 8; nf++) {
                int l = wn*64 + nf*8 + 2*tg;
                *(float2*)&PS[il*132 + l]     = make_float2(pc[nf][0], pc[nf][1]);
                *(float2*)&PS[(il+8)*132 + l] = make_float2(pc[nf][2], pc[nf][3]);
            }
        }
        __syncthreads();

        // ---- softmax (no max-tracking; scores are small) ----
        const int jjb2 = jjb + 63;
        #pragma unroll
        for (int bb = 0; bb < 4; bb++) {
            int jl = TJ*4 + bb;
            int jg = j0 + jl;
            float4 sv = *(float4*)&PRf[jl*68 + TI*4];
            float sarr[4] = {sv.x, sv.y, sv.z, sv.w};
            uint32_t pv[4];
            #pragma unroll
            for (int a = 0; a < 4; a++) {
                int il = TI*4 + a;
                int ig = i0 + il;
                int slot = (jjb2 + jl - il) & 127;
                float sbd = PS[il*132 + slot];
                float p = 0.f;
                if (jg <= ig + MEMLEN) {
                    float y = (sarr[a] + sbd) * 0.18033688f;  // *0.125*log2(e)
                    p = exp2_fast(y);
                }
                l_acc[a] += p;
                pv[a] = f2t(p);
            }
            *(uint4*)&PR[jl*68 + TI*4] = make_uint4(pv[0], pv[1], pv[2], pv[3]);
        }
        __syncthreads();

        // ---- O += P @ V  (64x64), warp tile 16x32, accumulators persistent ----
        #pragma unroll
        for (int k0 = 0; k0 < 64; k0 += 8) {
            uint32_t a0 = PR[(k0+tg)*68   + wm*16 + g];
            uint32_t a1 = PR[(k0+tg)*68   + wm*16 + g + 8];
            uint32_t a2 = PR[(k0+tg+4)*68 + wm*16 + g];
            uint32_t a3 = PR[(k0+tg+4)*68 + wm*16 + g + 8];
            #pragma unroll
            for (int nf = 0; nf < 4; nf++) {
                uint32_t b0 = VT[(k0+tg)*68   + wn*32 + nf*8 + g];
                uint32_t b1 = VT[(k0+tg+4)*68 + wn*32 + nf*8 + g];
                mma_tf32(oacc[nf][0], oacc[nf][1], oacc[nf][2], oacc[nf][3],
                         a0, a1, a2, a3, b0, b1);
            }
        }
    }

    // reduce l over TJ lanes (within warp), write 1/l
    #pragma unroll
    for (int a = 0; a < 4; a++) {
        float l = l_acc[a];
        l += __shfl_xor_sync(0xffffffffu, l, 1);
        l += __shfl_xor_sync(0xffffffffu, l, 2);
        l += __shfl_xor_sync(0xffffffffu, l, 4);
        l += __shfl_xor_sync(0xffffffffu, l, 8);
        if (TJ == 0) PS[TI*4 + a] = 1.f / l;
    }
    __syncthreads();

    {
        int il = wm*16 + g;
        float inv0 = PS[il], inv1 = PS[il + 8];
        #pragma unroll
        for (int nf = 0; nf < 4; nf++) {
            int d = wn*32 + nf*8 + 2*tg;
            *(float2*)&g_av[(size_t)(i0+il)*(BSZ*DM) + b*DM + n*DH + d] =
                make_float2(oacc[nf][0]*inv0, oacc[nf][1]*inv0);
            *(float2*)&g_av[(size_t)(i0+il+8)*(BSZ*DM) + b*DM + n*DH + d] =
                make_float2(oacc[nf][2]*inv1, oacc[nf][3]*inv1);
        }
    }
}

// ---------------- residual + layernorm --------------------------------------
__global__ __launch_bounds__(256) void k_ln(const float* __restrict__ w,
                                            const float* __restrict__ g,
                                            const float* __restrict__ be,
                                            float* __restrict__ out)
{
    __shared__ float red[256];
    int row = blockIdx.x;
    int tid = threadIdx.x;
    const float* wr = w    + (size_t)row * DM;
    const float* ar = g_ao + (size_t)row * DM;
    float x0 = wr[tid]       + ar[tid];
    float x1 = wr[tid + 256] + ar[tid + 256];
    red[tid] = x0 + x1;
    __syncthreads();
    for (int s = 128; s > 0; s >>= 1) { if (tid < s) red[tid] += red[tid + s]; __syncthreads(); }
    float mu = red[0] * (1.f / DM);
    __syncthreads();
    float d0 = x0 - mu, d1 = x1 - mu;
    red[tid] = d0*d0 + d1*d1;
    __syncthreads();
    for (int s = 128; s > 0; s >>= 1) { if (tid < s) red[tid] += red[tid + s]; __syncthreads(); }
    float rs = rsqrtf(red[0] * (1.f / DM) + 1e-5f);
    out[(size_t)row*DM + tid]       = d0 * rs * g[tid]       + be[tid];
    out[(size_t)row*DM + tid + 256] = d1 * rs * g[tid + 256] + be[tid + 256];
}

// ---------------- launcher ---------------------------------------------------
extern "C" void kernel_launch(void* const* d_in, const int* in_sizes, int n_in,
                              void* d_out, int out_size)
{
    (void)in_sizes; (void)n_in; (void)out_size;
    const float* w    = (const float*)d_in[0];
    const float* r    = (const float*)d_in[1];
    const float* mems = (const float*)d_in[2];
    const float* rwb  = (const float*)d_in[3];
    const float* rrb  = (const float*)d_in[4];
    const float* qkvW = (const float*)d_in[5];
    const float* rW   = (const float*)d_in[6];
    const float* cqw  = (const float*)d_in[7];
    const float* cqb  = (const float*)d_in[8];
    const float* ckw  = (const float*)d_in[9];
    const float* ckb  = (const float*)d_in[10];
    const float* cvw  = (const float*)d_in[11];
    const float* cvb  = (const float*)d_in[12];
    const float* oW   = (const float*)d_in[13];
    const float* lng  = (const float*)d_in[14];
    const float* lnb  = (const float*)d_in[15];
    float* out = (float*)d_out;

    float *p_qkv, *p_rk, *p_q, *p_k, *p_v, *p_av, *p_ao;
    uint32_t* p_wt;
    cudaGetSymbolAddress((void**)&p_qkv, g_qkv);
    cudaGetSymbolAddress((void**)&p_rk,  g_rk);
    cudaGetSymbolAddress((void**)&p_q,   g_q);
    cudaGetSymbolAddress((void**)&p_k,   g_k);
    cudaGetSymbolAddress((void**)&p_v,   g_v);
    cudaGetSymbolAddress((void**)&p_av,  g_av);
    cudaGetSymbolAddress((void**)&p_ao,  g_ao);
    cudaGetSymbolAddress((void**)&p_wt,  g_wt);

    dim3 b256(256);

    // conv weight prep (tiny)
    k_prepw<<<21, b256>>>(cqw, ckw, cvw);

    // QKV projection: cat = [mems; w] as two GEMMs
    mm_tf32<<<dim3(QKV/128, (MEMLEN*BSZ)/128), b256>>>(mems, qkvW, p_qkv,
                                                       MEMLEN*BSZ, QKV, DM);
    mm_tf32<<<dim3(QKV/128, (QLEN*BSZ)/128), b256>>>(w, qkvW,
                                                     p_qkv + (size_t)MEMLEN*BSZ*QKV,
                                                     QLEN*BSZ, QKV, DM);
    mm_tf32<<<dim3(DM/128, KLEN/128), b256>>>(r, rW, p_rk, KLEN, DM, DM);

    // convs via MMA
    int csm = (64*136 + 64*68) * 4;
    cudaFuncSetAttribute(k_conv2, cudaFuncAttributeMaxDynamicSharedMemorySize, csm);
    k_conv2<<<dim3(QLEN/128, NH*BSZ), b256, csm>>>(cqb, p_wt,           p_q, QLEN, MEMLEN, 0);
    k_conv2<<<dim3(KLEN/128, NH*BSZ), b256, csm>>>(ckb, p_wt + 7*4096,  p_k, KLEN, 0, DM);
    k_conv2<<<dim3(KLEN/128, NH*BSZ), b256, csm>>>(cvb, p_wt + 14*4096, p_v, KLEN, 0, 2*DM);

    // fused rel-pos attention (tensor core)
    int asm_ = (5*64*68 + 2*64*132) * 4;
    cudaFuncSetAttribute(k_attn3, cudaFuncAttributeMaxDynamicSharedMemorySize, asm_);
    k_attn3<<<dim3(QLEN/64, BSZ*NH), b256, asm_>>>(rwb, rrb);

    // output projection + residual layernorm
    mm_tf32<<<dim3(DM/128, (QLEN*BSZ)/128), b256>>>(p_av, oW, p_ao, QLEN*BSZ, DM, DM);
    k_ln<<<QLEN*BSZ, b256>>>(w, lng, lnb, out);
}

// round 4
// speedup vs baseline: 3.0582x; 1.1102x over previous
#include <cuda_runtime.h>
#include <math.h>
#include <stdint.h>

#define QLEN 1024
#define KLEN 2048
#define MEMLEN 1024
#define BSZ 4
#define NH 8
#define DH 64
#define DM 512
#define QKV (3*DM)

// ---------------- scratch (static device globals; no allocation) ------------
__device__ float g_qkv[(size_t)KLEN*BSZ*QKV];   // (jk, b, 1536)
__device__ float g_rk [(size_t)KLEN*DM];        // (jj, n*64+d)
__device__ float g_q  [(size_t)QLEN*BSZ*DM];    // (i, b, n, d)
__device__ float g_k  [(size_t)KLEN*BSZ*DM];    // (j, b, n, d)
__device__ float g_v  [(size_t)KLEN*BSZ*DM];    // (j, b, n, d)
__device__ float g_av [(size_t)QLEN*BSZ*DM];    // (i, b, n, d)
__device__ float g_ao [(size_t)QLEN*BSZ*DM];    // (i, b, 512)
__device__ uint32_t g_wt[3*7*64*64];            // conv weights tf32 [c][tap][ic][oc]

__device__ __forceinline__ uint32_t f2t(float x) {
    uint32_t u;
    asm("cvt.rna.tf32.f32 %0, %1;" : "=r"(u) : "f"(x));
    return u;
}
__device__ __forceinline__ uint32_t fbits(float x) { return __float_as_uint(x); }

__device__ __forceinline__ void mma_tf32(float& c0, float& c1, float& c2, float& c3,
                                         uint32_t a0, uint32_t a1, uint32_t a2, uint32_t a3,
                                         uint32_t b0, uint32_t b1)
{
    asm volatile("mma.sync.aligned.m16n8k8.row.col.f32.tf32.tf32.f32 "
                 "{%0,%1,%2,%3},{%4,%5,%6,%7},{%8,%9},{%0,%1,%2,%3};\n"
                 : "+f"(c0), "+f"(c1), "+f"(c2), "+f"(c3)
                 : "r"(a0), "r"(a1), "r"(a2), "r"(a3), "r"(b0), "r"(b1));
}

// 2^y via magic-round + deg-4 poly; no MUFU.
__device__ __forceinline__ float exp2_fast(float y) {
    y = fmaxf(y, -100.f);
    float z = __fadd_rn(y, 12582912.f);
    float n = __fsub_rn(z, 12582912.f);
    float f = __fsub_rn(y, n);
    float r = 0.0096181291f;
    r = fmaf(r, f, 0.055504109f);
    r = fmaf(r, f, 0.24022651f);
    r = fmaf(r, f, 0.69314718f);
    r = fmaf(r, f, 1.0f);
    int e = __float_as_int(z);
    float s = __int_as_float((e - 1262485377) << 23);
    return r * s;
}

// ---------------- TF32 tensor GEMM, double-buffered, 1 sync/iter -------------
__global__ __launch_bounds__(256, 2) void mm_tf32(const float* __restrict__ A,
                                                  const float* __restrict__ B,
                                                  float* __restrict__ C,
                                                  int M, int N, int K)
{
    __shared__ uint32_t As[2][16][132];
    __shared__ uint32_t Bs[2][16][132];
    const int tid = threadIdx.x;
    const int warp = tid >> 5, lane = tid & 31;
    const int wm = warp & 3, wn = warp >> 2;
    const int g = lane >> 2, tg = lane & 3;
    const int m0 = blockIdx.y * 128, n0 = blockIdx.x * 128;

    float c[2][8][4];
    #pragma unroll
    for (int mt = 0; mt < 2; mt++)
        #pragma unroll
        for (int nt = 0; nt < 8; nt++)
            #pragma unroll
            for (int q = 0; q < 4; q++) c[mt][nt][q] = 0.f;

    const int lr = tid >> 2;
    const int lc = (tid & 3) * 4;
    const float* Ap = A + (size_t)m0 * K;
    const float* Bp = B + (size_t)n0 * K;

    float4 ra0 = *(const float4*)(Ap + (size_t)lr * K + lc);
    float4 ra1 = *(const float4*)(Ap + (size_t)(lr + 64) * K + lc);
    float4 rb0 = *(const float4*)(Bp + (size_t)lr * K + lc);
    float4 rb1 = *(const float4*)(Bp + (size_t)(lr + 64) * K + lc);
    As[0][lc+0][lr] = fbits(ra0.x); As[0][lc+1][lr] = fbits(ra0.y);
    As[0][lc+2][lr] = fbits(ra0.z); As[0][lc+3][lr] = fbits(ra0.w);
    As[0][lc+0][lr+64] = fbits(ra1.x); As[0][lc+1][lr+64] = fbits(ra1.y);
    As[0][lc+2][lr+64] = fbits(ra1.z); As[0][lc+3][lr+64] = fbits(ra1.w);
    Bs[0][lc+0][lr] = fbits(rb0.x); Bs[0][lc+1][lr] = fbits(rb0.y);
    Bs[0][lc+2][lr] = fbits(rb0.z); Bs[0][lc+3][lr] = fbits(rb0.w);
    Bs[0][lc+0][lr+64] = fbits(rb1.x); Bs[0][lc+1][lr+64] = fbits(rb1.y);
    Bs[0][lc+2][lr+64] = fbits(rb1.z); Bs[0][lc+3][lr+64] = fbits(rb1.w);

    int buf = 0;
    for (int k0 = 0; k0 < K; k0 += 16) {
        const bool more = (k0 + 16) < K;
        if (more) {
            ra0 = *(const float4*)(Ap + (size_t)lr * K + k0 + 16 + lc);
            ra1 = *(const float4*)(Ap + (size_t)(lr + 64) * K + k0 + 16 + lc);
            rb0 = *(const float4*)(Bp + (size_t)lr * K + k0 + 16 + lc);
            rb1 = *(const float4*)(Bp + (size_t)(lr + 64) * K + k0 + 16 + lc);
        }
        __syncthreads();
        #pragma unroll
        for (int kk = 0; kk < 16; kk += 8) {
            uint32_t af[2][4], bf[8][2];
            #pragma unroll
            for (int mt = 0; mt < 2; mt++) {
                int mb = wm * 32 + mt * 16;
                af[mt][0] = As[buf][kk + tg][mb + g];
                af[mt][1] = As[buf][kk + tg][mb + g + 8];
                af[mt][2] = As[buf][kk + tg + 4][mb + g];
                af[mt][3] = As[buf][kk + tg + 4][mb + g + 8];
            }
            #pragma unroll
            for (int nt = 0; nt < 8; nt++) {
                int nb = wn * 64 + nt * 8;
                bf[nt][0] = Bs[buf][kk + tg][nb + g];
                bf[nt][1] = Bs[buf][kk + tg + 4][nb + g];
            }
            #pragma unroll
            for (int mt = 0; mt < 2; mt++)
                #pragma unroll
                for (int nt = 0; nt < 8; nt++)
                    mma_tf32(c[mt][nt][0], c[mt][nt][1], c[mt][nt][2], c[mt][nt][3],
                             af[mt][0], af[mt][1], af[mt][2], af[mt][3],
                             bf[nt][0], bf[nt][1]);
        }
        if (more) {
            int nb = buf ^ 1;
            As[nb][lc+0][lr] = fbits(ra0.x); As[nb][lc+1][lr] = fbits(ra0.y);
            As[nb][lc+2][lr] = fbits(ra0.z); As[nb][lc+3][lr] = fbits(ra0.w);
            As[nb][lc+0][lr+64] = fbits(ra1.x); As[nb][lc+1][lr+64] = fbits(ra1.y);
            As[nb][lc+2][lr+64] = fbits(ra1.z); As[nb][lc+3][lr+64] = fbits(ra1.w);
            Bs[nb][lc+0][lr] = fbits(rb0.x); Bs[nb][lc+1][lr] = fbits(rb0.y);
            Bs[nb][lc+2][lr] = fbits(rb0.z); Bs[nb][lc+3][lr] = fbits(rb0.w);
            Bs[nb][lc+0][lr+64] = fbits(rb1.x); Bs[nb][lc+1][lr+64] = fbits(rb1.y);
            Bs[nb][lc+2][lr+64] = fbits(rb1.z); Bs[nb][lc+3][lr+64] = fbits(rb1.w);
        }
        buf ^= 1;
    }

    #pragma unroll
    for (int mt = 0; mt < 2; mt++) {
        int row0 = m0 + wm * 32 + mt * 16 + g;
        #pragma unroll
        for (int nt = 0; nt < 8; nt++) {
            int col = n0 + wn * 64 + nt * 8 + tg * 2;
            *(float2*)&C[(size_t)row0 * N + col]       = make_float2(c[mt][nt][0], c[mt][nt][1]);
            *(float2*)&C[(size_t)(row0 + 8) * N + col] = make_float2(c[mt][nt][2], c[mt][nt][3]);
        }
    }
}

// ---------------- weight prep ------------------------------------------------
__global__ void k_prepw(const float* __restrict__ cq,
                        const float* __restrict__ ck,
                        const float* __restrict__ cv)
{
    int idx = blockIdx.x;
    int c = idx / 7, tap = idx % 7;
    const float* src = (c == 0) ? cq : (c == 1) ? ck : cv;
    for (int e = threadIdx.x; e < 4096; e += 256) {
        int ic = e >> 6, oc = e & 63;
        g_wt[((c*7 + tap)*64 + ic)*64 + oc] = f2t(src[(oc*64 + ic)*7 + tap]);
    }
}

// ---------------- conv via MMA ----------------------------------------------
__global__ __launch_bounds__(256) void k_conv2(const float* __restrict__ cb,
                                               const uint32_t* __restrict__ wt,
                                               float* __restrict__ out,
                                               int len, int posoff, int chanoff)
{
    extern __shared__ uint32_t cs[];
    uint32_t* xsT = cs;            // [ic=64][u pad 136]
    uint32_t* ws  = cs + 64*136;   // [ic=64][oc pad 68]
    const int t0 = blockIdx.x * 128;
    const int nb = blockIdx.y;
    const int n = nb >> 2, b = nb & 3;
    const int tid = threadIdx.x;
    const int warp = tid >> 5, lane = tid & 31;
    const int wm = warp;
    const int g = lane >> 2, tg = lane & 3;

    for (int e = tid; e < 16*134; e += 256) {
        int u = e % 134, ic4 = (e / 134) * 4;
        int pos = t0 + u - 3;
        float4 v = make_float4(0.f, 0.f, 0.f, 0.f);
        if (pos >= 0 && pos < len)
            v = *(const float4*)&g_qkv[(size_t)(pos + posoff)*(BSZ*QKV) + b*QKV + chanoff + n*DH + ic4];
        xsT[(ic4+0)*136 + u] = fbits(v.x);
        xsT[(ic4+1)*136 + u] = fbits(v.y);
        xsT[(ic4+2)*136 + u] = fbits(v.z);
        xsT[(ic4+3)*136 + u] = fbits(v.w);
    }

    float acc[8][4];
    #pragma unroll
    for (int nf = 0; nf < 8; nf++)
        #pragma unroll
        for (int q = 0; q < 4; q++) acc[nf][q] = 0.f;

    for (int tap = 0; tap < 7; tap++) {
        __syncthreads();
        for (int e = tid; e < 1024; e += 256) {
            int ic = e >> 4, oc4 = (e & 15) * 4;
            *(uint4*)&ws[ic*68 + oc4] = *(const uint4*)&wt[(tap*64 + ic)*64 + oc4];
        }
        __syncthreads();
        #pragma unroll
        for (int k0 = 0; k0 < 64; k0 += 8) {
            uint32_t a0 = xsT[(k0+tg)*136   + wm*16 + g     + tap];
            uint32_t a1 = xsT[(k0+tg)*136   + wm*16 + g + 8 + tap];
            uint32_t a2 = xsT[(k0+tg+4)*136 + wm*16 + g     + tap];
            uint32_t a3 = xsT[(k0+tg+4)*136 + wm*16 + g + 8 + tap];
            #pragma unroll
            for (int nf = 0; nf < 8; nf++) {
                uint32_t b0 = ws[(k0+tg)*68   + nf*8 + g];
                uint32_t b1 = ws[(k0+tg+4)*68 + nf*8 + g];
                mma_tf32(acc[nf][0], acc[nf][1], acc[nf][2], acc[nf][3],
                         a0, a1, a2, a3, b0, b1);
            }
        }
    }

    #pragma unroll
    for (int nf = 0; nf < 8; nf++) {
        int oc = nf*8 + 2*tg;
        float bb0 = cb[oc], bb1 = cb[oc+1];
        int row = t0 + wm*16 + g;
        *(float2*)&out[(size_t)row*(BSZ*DM) + b*DM + n*DH + oc] =
            make_float2(acc[nf][0] + bb0, acc[nf][1] + bb1);
        *(float2*)&out[(size_t)(row+8)*(BSZ*DM) + b*DM + n*DH + oc] =
            make_float2(acc[nf][2] + bb0, acc[nf][3] + bb1);
    }
}

// ---------------- attention v4: BD ring (64-wide BD per tile) ----------------
__global__ __launch_bounds__(256) void k_attn4(const float* __restrict__ rwb,
                                               const float* __restrict__ rrb)
{
    extern __shared__ uint32_t smu[];
    uint32_t* QW = smu;              // [d=64][i pad 68]
    uint32_t* QR = QW + 64*68;
    uint32_t* KS = QR + 64*68;       // [d][jl]
    uint32_t* VT = KS + 64*68;       // [jl][d]
    uint32_t* PR = VT + 64*68;       // AC scores (float), then probs (bits)
    uint32_t* RW = PR + 64*68;       // [d][c] staged rk chunk
    float*   BDR = (float*)(RW + 64*68);   // [il][slot pad 132] persistent ring
    float* PRf = (float*)PR;

    const int i0 = (gridDim.x - 1 - blockIdx.x) * 64;
    const int bn = blockIdx.y;
    const int b = bn >> 3, n = bn & 7;
    const int tid = threadIdx.x;
    const int warp = tid >> 5, lane = tid & 31;
    const int wm = warp & 3, wn = warp >> 2;
    const int g = lane >> 2, tg = lane & 3;
    const int TI = tid >> 4, TJ = tid & 15;

    for (int e = tid; e < 64*16; e += 256) {
        int ii = e >> 4, d4 = (e & 15) * 4;
        float4 qv = *(const float4*)&g_q[(size_t)(i0+ii)*(BSZ*DM) + b*DM + n*DH + d4];
        float4 wv = *(const float4*)&rwb[n*DH + d4];
        float4 rv = *(const float4*)&rrb[n*DH + d4];
        QW[(d4+0)*68 + ii] = fbits(qv.x + wv.x);
        QW[(d4+1)*68 + ii] = fbits(qv.y + wv.y);
        QW[(d4+2)*68 + ii] = fbits(qv.z + wv.z);
        QW[(d4+3)*68 + ii] = fbits(qv.w + wv.w);
        QR[(d4+0)*68 + ii] = fbits(qv.x + rv.x);
        QR[(d4+1)*68 + ii] = fbits(qv.y + rv.y);
        QR[(d4+2)*68 + ii] = fbits(qv.z + rv.z);
        QR[(d4+3)*68 + ii] = fbits(qv.w + rv.w);
    }

    float oacc[4][4];
    float l_acc[4];
    #pragma unroll
    for (int a = 0; a < 4; a++) {
        l_acc[a] = 0.f;
        #pragma unroll
        for (int q = 0; q < 4; q++) oacc[a][q] = 0.f;
    }

    const int jjb0 = 960 - i0;
    const int ntiles = i0/64 + 17;
    for (int t = 0; t < ntiles; t++) {
        const int j0 = t * 64;
        const int jjb = j0 - i0 + 960;
        __syncthreads();
        // stage K (transposed), V
        for (int e = tid; e < 64*16; e += 256) {
            int jl = e >> 4, d4 = (e & 15) * 4;
            size_t gi = (size_t)(j0+jl)*(BSZ*DM) + b*DM + n*DH + d4;
            float4 kv = *(const float4*)&g_k[gi];
            float4 vv = *(const float4*)&g_v[gi];
            KS[(d4+0)*68 + jl] = fbits(kv.x);
            KS[(d4+1)*68 + jl] = fbits(kv.y);
            KS[(d4+2)*68 + jl] = fbits(kv.z);
            KS[(d4+3)*68 + jl] = fbits(kv.w);
            uint4 vu = make_uint4(fbits(vv.x), fbits(vv.y), fbits(vv.z), fbits(vv.w));
            *(uint4*)&VT[jl*68 + d4] = vu;
        }
        // stage rk chunk
        int cbase = (t == 0) ? jjb0 : (jjb + 64);
        for (int e = tid; e < 64*16; e += 256) {
            int l = e >> 4, d4 = (e & 15) * 4;
            int jj = cbase + l;
            float4 v = make_float4(0.f, 0.f, 0.f, 0.f);
            if (jj < KLEN) v = *(const float4*)&g_rk[(size_t)jj*DM + n*DH + d4];
            RW[(d4+0)*68 + l] = fbits(v.x);
            RW[(d4+1)*68 + l] = fbits(v.y);
            RW[(d4+2)*68 + l] = fbits(v.z);
            RW[(d4+3)*68 + l] = fbits(v.w);
        }
        __syncthreads();

        // ---- AC = Qw @ K^T (64x64) ----
        {
            float sc[4][4];
            #pragma unroll
            for (int nf = 0; nf < 4; nf++)
                #pragma unroll
                for (int q = 0; q < 4; q++) sc[nf][q] = 0.f;
            #pragma unroll
            for (int k0 = 0; k0 < 64; k0 += 8) {
                uint32_t a0 = QW[(k0+tg)*68   + wm*16 + g];
                uint32_t a1 = QW[(k0+tg)*68   + wm*16 + g + 8];
                uint32_t a2 = QW[(k0+tg+4)*68 + wm*16 + g];
                uint32_t a3 = QW[(k0+tg+4)*68 + wm*16 + g + 8];
                #pragma unroll
                for (int nf = 0; nf < 4; nf++) {
                    uint32_t b0 = KS[(k0+tg)*68   + wn*32 + nf*8 + g];
                    uint32_t b1 = KS[(k0+tg+4)*68 + wn*32 + nf*8 + g];
                    mma_tf32(sc[nf][0], sc[nf][1], sc[nf][2], sc[nf][3],
                             a0, a1, a2, a3, b0, b1);
                }
            }
            int il = wm*16 + g;
            #pragma unroll
            for (int nf = 0; nf < 4; nf++) {
                int jl = wn*32 + nf*8 + 2*tg;
                PRf[jl*68     + il]     = sc[nf][0];
                PRf[(jl+1)*68 + il]     = sc[nf][1];
                PRf[jl*68     + il + 8] = sc[nf][2];
                PRf[(jl+1)*68 + il + 8] = sc[nf][3];
            }
        }
        // ---- BD chunk(s) = Qr @ RW^T (64x64) -> BDR ring ----
        const int nch = (t == 0) ? 2 : 1;
        for (int ch = 0; ch < nch; ch++) {
            if (ch == 1) {
                // stage second chunk at t==0
                __syncthreads();
                cbase = jjb0 + 64;
                for (int e = tid; e < 64*16; e += 256) {
                    int l = e >> 4, d4 = (e & 15) * 4;
                    int jj = cbase + l;
                    float4 v = make_float4(0.f, 0.f, 0.f, 0.f);
                    if (jj < KLEN) v = *(const float4*)&g_rk[(size_t)jj*DM + n*DH + d4];
                    RW[(d4+0)*68 + l] = fbits(v.x);
                    RW[(d4+1)*68 + l] = fbits(v.y);
                    RW[(d4+2)*68 + l] = fbits(v.z);
                    RW[(d4+3)*68 + l] = fbits(v.w);
                }
                __syncthreads();
            }
            const int s0 = cbase & 127;
            float pc[4][4];
            #pragma unroll
            for (int nf = 0; nf < 4; nf++)
                #pragma unroll
                for (int q = 0; q < 4; q++) pc[nf][q] = 0.f;
            #pragma unroll
            for (int k0 = 0; k0 < 64; k0 += 8) {
                uint32_t a0 = QR[(k0+tg)*68   + wm*16 + g];
                uint32_t a1 = QR[(k0+tg)*68   + wm*16 + g + 8];
                uint32_t a2 = QR[(k0+tg+4)*68 + wm*16 + g];
                uint32_t a3 = QR[(k0+tg+4)*68 + wm*16 + g + 8];
                #pragma unroll
                for (int nf = 0; nf < 4; nf++) {
                    uint32_t b0 = RW[(k0+tg)*68   + wn*32 + nf*8 + g];
                    uint32_t b1 = RW[(k0+tg+4)*68 + wn*32 + nf*8 + g];
                    mma_tf32(pc[nf][0], pc[nf][1], pc[nf][2], pc[nf][3],
                             a0, a1, a2, a3, b0, b1);
                }
            }
            int il = wm*16 + g;
            #pragma unroll
            for (int nf = 0; nf < 4; nf++) {
                int cc = s0 + wn*32 + nf*8 + 2*tg;
                BDR[il*132 + cc]         = pc[nf][0];
                BDR[il*132 + cc + 1]     = pc[nf][1];
                BDR[(il+8)*132 + cc]     = pc[nf][2];
                BDR[(il+8)*132 + cc + 1] = pc[nf][3];
            }
        }
        __syncthreads();

        // ---- softmax ----
        const int jjb2 = jjb + 63;
        #pragma unroll
        for (int bb = 0; bb < 4; bb++) {
            int jl = TJ*4 + bb;
            int jg = j0 + jl;
            float4 sv = *(float4*)&PRf[jl*68 + TI*4];
            float sarr[4] = {sv.x, sv.y, sv.z, sv.w};
            uint32_t pv[4];
            #pragma unroll
            for (int a = 0; a < 4; a++) {
                int il = TI*4 + a;
                int ig = i0 + il;
                int slot = (jjb2 + jl - il) & 127;
                float sbd = BDR[il*132 + slot];
                float p = 0.f;
                if (jg <= ig + MEMLEN) {
                    float y = (sarr[a] + sbd) * 0.18033688f;   // *0.125*log2(e)
                    p = exp2_fast(y);
                }
                l_acc[a] += p;
                pv[a] = fbits(p);
            }
            *(uint4*)&PR[jl*68 + TI*4] = make_uint4(pv[0], pv[1], pv[2], pv[3]);
        }
        __syncthreads();

        // ---- O += P @ V ----
        #pragma unroll
        for (int k0 = 0; k0 < 64; k0 += 8) {
            uint32_t a0 = PR[(k0+tg)*68   + wm*16 + g];
            uint32_t a1 = PR[(k0+tg)*68   + wm*16 + g + 8];
            uint32_t a2 = PR[(k0+tg+4)*68 + wm*16 + g];
            uint32_t a3 = PR[(k0+tg+4)*68 + wm*16 + g + 8];
            #pragma unroll
            for (int nf = 0; nf < 4; nf++) {
                uint32_t b0 = VT[(k0+tg)*68   + wn*32 + nf*8 + g];
                uint32_t b1 = VT[(k0+tg+4)*68 + wn*32 + nf*8 + g];
                mma_tf32(oacc[nf][0], oacc[nf][1], oacc[nf][2], oacc[nf][3],
                         a0, a1, a2, a3, b0, b1);
            }
        }
    }

    __syncthreads();
    #pragma unroll
    for (int a = 0; a < 4; a++) {
        float l = l_acc[a];
        l += __shfl_xor_sync(0xffffffffu, l, 1);
        l += __shfl_xor_sync(0xffffffffu, l, 2);
        l += __shfl_xor_sync(0xffffffffu, l, 4);
        l += __shfl_xor_sync(0xffffffffu, l, 8);
        if (TJ == 0) BDR[TI*4 + a] = 1.f / l;
    }
    __syncthreads();

    {
        int il = wm*16 + g;
        float inv0 = BDR[il], inv1 = BDR[il + 8];
        #pragma unroll
        for (int nf = 0; nf < 4; nf++) {
            int d = wn*32 + nf*8 + 2*tg;
            *(float2*)&g_av[(size_t)(i0+il)*(BSZ*DM) + b*DM + n*DH + d] =
                make_float2(oacc[nf][0]*inv0, oacc[nf][1]*inv0);
            *(float2*)&g_av[(size_t)(i0+il+8)*(BSZ*DM) + b*DM + n*DH + d] =
                make_float2(oacc[nf][2]*inv1, oacc[nf][3]*inv1);
        }
    }
}

// ---------------- residual + layernorm --------------------------------------
__global__ __launch_bounds__(256) void k_ln(const float* __restrict__ w,
                                            const float* __restrict__ g,
                                            const float* __restrict__ be,
                                            float* __restrict__ out)
{
    __shared__ float red[256];
    int row = blockIdx.x;
    int tid = threadIdx.x;
    const float* wr = w    + (size_t)row * DM;
    const float* ar = g_ao + (size_t)row * DM;
    float x0 = wr[tid]       + ar[tid];
    float x1 = wr[tid + 256] + ar[tid + 256];
    red[tid] = x0 + x1;
    __syncthreads();
    for (int s = 128; s > 0; s >>= 1) { if (tid < s) red[tid] += red[tid + s]; __syncthreads(); }
    float mu = red[0] * (1.f / DM);
    __syncthreads();
    float d0 = x0 - mu, d1 = x1 - mu;
    red[tid] = d0*d0 + d1*d1;
    __syncthreads();
    for (int s = 128; s > 0; s >>= 1) { if (tid < s) red[tid] += red[tid + s]; __syncthreads(); }
    float rs = rsqrtf(red[0] * (1.f / DM) + 1e-5f);
    out[(size_t)row*DM + tid]       = d0 * rs * g[tid]       + be[tid];
    out[(size_t)row*DM + tid + 256] = d1 * rs * g[tid + 256] + be[tid + 256];
}

// ---------------- launcher ---------------------------------------------------
extern "C" void kernel_launch(void* const* d_in, const int* in_sizes, int n_in,
                              void* d_out, int out_size)
{
    (void)in_sizes; (void)n_in; (void)out_size;
    const float* w    = (const float*)d_in[0];
    const float* r    = (const float*)d_in[1];
    const float* mems = (const float*)d_in[2];
    const float* rwb  = (const float*)d_in[3];
    const float* rrb  = (const float*)d_in[4];
    const float* qkvW = (const float*)d_in[5];
    const float* rW   = (const float*)d_in[6];
    const float* cqw  = (const float*)d_in[7];
    const float* cqb  = (const float*)d_in[8];
    const float* ckw  = (const float*)d_in[9];
    const float* ckb  = (const float*)d_in[10];
    const float* cvw  = (const float*)d_in[11];
    const float* cvb  = (const float*)d_in[12];
    const float* oW   = (const float*)d_in[13];
    const float* lng  = (const float*)d_in[14];
    const float* lnb  = (const float*)d_in[15];
    float* out = (float*)d_out;

    float *p_qkv, *p_rk, *p_q, *p_k, *p_v, *p_av, *p_ao;
    uint32_t* p_wt;
    cudaGetSymbolAddress((void**)&p_qkv, g_qkv);
    cudaGetSymbolAddress((void**)&p_rk,  g_rk);
    cudaGetSymbolAddress((void**)&p_q,   g_q);
    cudaGetSymbolAddress((void**)&p_k,   g_k);
    cudaGetSymbolAddress((void**)&p_v,   g_v);
    cudaGetSymbolAddress((void**)&p_av,  g_av);
    cudaGetSymbolAddress((void**)&p_ao,  g_ao);
    cudaGetSymbolAddress((void**)&p_wt,  g_wt);

    dim3 b256(256);

    k_prepw<<<21, b256>>>(cqw, ckw, cvw);

    mm_tf32<<<dim3(QKV/128, (MEMLEN*BSZ)/128), b256>>>(mems, qkvW, p_qkv,
                                                       MEMLEN*BSZ, QKV, DM);
    mm_tf32<<<dim3(QKV/128, (QLEN*BSZ)/128), b256>>>(w, qkvW,
                                                     p_qkv + (size_t)MEMLEN*BSZ*QKV,
                                                     QLEN*BSZ, QKV, DM);
    mm_tf32<<<dim3(DM/128, KLEN/128), b256>>>(r, rW, p_rk, KLEN, DM, DM);

    int csm = (64*136 + 64*68) * 4;
    cudaFuncSetAttribute(k_conv2, cudaFuncAttributeMaxDynamicSharedMemorySize, csm);
    k_conv2<<<dim3(QLEN/128, NH*BSZ), b256, csm>>>(cqb, p_wt,           p_q, QLEN, MEMLEN, 0);
    k_conv2<<<dim3(KLEN/128, NH*BSZ), b256, csm>>>(ckb, p_wt + 7*4096,  p_k, KLEN, 0, DM);
    k_conv2<<<dim3(KLEN/128, NH*BSZ), b256, csm>>>(cvb, p_wt + 14*4096, p_v, KLEN, 0, 2*DM);

    int asm_ = (6*64*68 + 64*132) * 4;
    cudaFuncSetAttribute(k_attn4, cudaFuncAttributeMaxDynamicSharedMemorySize, asm_);
    k_attn4<<<dim3(QLEN/64, BSZ*NH), b256, asm_>>>(rwb, rrb);

    mm_tf32<<<dim3(DM/128, (QLEN*BSZ)/128), b256>>>(p_av, oW, p_ao, QLEN*BSZ, DM, DM);
    k_ln<<<QLEN*BSZ, b256>>>(w, lng, lnb, out);
}

// round 5
// speedup vs baseline: 5.4713x; 1.7891x over previous
#include <cuda_runtime.h>
#include <cuda_bf16.h>
#include <math.h>
#include <stdint.h>

#define QLEN 1024
#define KLEN 2048
#define MEMLEN 1024
#define BSZ 4
#define NH 8
#define DH 64
#define DM 512
#define QKV (3*DM)

// ---------------- scratch (static device globals; no allocation) ------------
__device__ float    g_qkv[(size_t)KLEN*BSZ*QKV]; // fp32 (jk, b, 1536)
__device__ float    g_rk [(size_t)KLEN*DM];      // fp32 (jj, n*64+d)
__device__ uint32_t g_q  [(size_t)QLEN*BSZ*DM/2]; // bf16 pairs (i, b, n, d)
__device__ uint32_t g_k  [(size_t)KLEN*BSZ*DM/2]; // bf16 pairs
__device__ uint32_t g_v  [(size_t)KLEN*BSZ*DM/2]; // bf16 pairs
__device__ float    g_av [(size_t)QLEN*BSZ*DM];  // fp32
__device__ float    g_ao [(size_t)QLEN*BSZ*DM];  // fp32
__device__ uint32_t g_wt[3*7*64*32];             // conv weights bf16 [c][tap][oc][ic/2]

__device__ __forceinline__ uint32_t pk(float x, float y) {
    __nv_bfloat162 t = __floats2bfloat162_rn(x, y);
    return *(uint32_t*)&t;
}
__device__ __forceinline__ float bl(uint32_t w) {   // low half -> float
    __nv_bfloat16 h = *(__nv_bfloat16*)&w;
    return __bfloat162float(h);
}
__device__ __forceinline__ float bh(uint32_t w) {   // high half -> float
    uint16_t u = (uint16_t)(w >> 16);
    __nv_bfloat16 h = *(__nv_bfloat16*)&u;
    return __bfloat162float(h);
}

__device__ __forceinline__ void mma_bf16(float& c0, float& c1, float& c2, float& c3,
                                         uint32_t a0, uint32_t a1, uint32_t a2, uint32_t a3,
                                         uint32_t b0, uint32_t b1)
{
    asm volatile("mma.sync.aligned.m16n8k16.row.col.f32.bf16.bf16.f32 "
                 "{%0,%1,%2,%3},{%4,%5,%6,%7},{%8,%9},{%0,%1,%2,%3};\n"
                 : "+f"(c0), "+f"(c1), "+f"(c2), "+f"(c3)
                 : "r"(a0), "r"(a1), "r"(a2), "r"(a3), "r"(b0), "r"(b1));
}

// 2^y via magic-round + deg-4 poly; no MUFU.
__device__ __forceinline__ float exp2_fast(float y) {
    y = fmaxf(y, -100.f);
    float z = __fadd_rn(y, 12582912.f);
    float n = __fsub_rn(z, 12582912.f);
    float f = __fsub_rn(y, n);
    float r = 0.0096181291f;
    r = fmaf(r, f, 0.055504109f);
    r = fmaf(r, f, 0.24022651f);
    r = fmaf(r, f, 0.69314718f);
    r = fmaf(r, f, 1.0f);
    int e = __float_as_int(z);
    float s = __int_as_float((e - 1262485377) << 23);
    return r * s;
}

// ---------------- BF16 tensor GEMM: C[M,N] = A[M,K] @ B[N,K]^T ---------------
// BK=16, double-buffered, 256 thr, warp tile 32m x 64n. A split at row M1.
#define GSW 12   // smem row stride in words (8 data + 4 pad)
__global__ __launch_bounds__(256, 2) void mm_bf16(const float* __restrict__ A0,
                                                  const float* __restrict__ A1,
                                                  int M1,
                                                  const float* __restrict__ B,
                                                  float* __restrict__ C,
                                                  int N, int K)
{
    __shared__ uint32_t As[2][128*GSW];
    __shared__ uint32_t Bs[2][128*GSW];
    const int tid = threadIdx.x;
    const int warp = tid >> 5, lane = tid & 31;
    const int wm = warp & 3, wn = warp >> 2;
    const int g = lane >> 2, tg = lane & 3;
    const int m0 = blockIdx.y * 128, n0 = blockIdx.x * 128;

    const float* Abase = (m0 < M1) ? (A0 + (size_t)m0 * K)
                                   : (A1 + (size_t)(m0 - M1) * K);

    float c[2][8][4];
    #pragma unroll
    for (int mt = 0; mt < 2; mt++)
        #pragma unroll
        for (int nt = 0; nt < 8; nt++)
            #pragma unroll
            for (int q = 0; q < 4; q++) c[mt][nt][q] = 0.f;

    const int lr = tid >> 1;        // row 0..127
    const int lh = tid & 1;         // k half (8 floats each)
    const float* Ap = Abase + (size_t)lr * K + lh * 8;
    const float* Bp = B + (size_t)(n0 + lr) * K + lh * 8;

    float4 ra0 = *(const float4*)(Ap);
    float4 ra1 = *(const float4*)(Ap + 4);
    float4 rb0 = *(const float4*)(Bp);
    float4 rb1 = *(const float4*)(Bp + 4);
    {
        uint32_t* ad = &As[0][lr*GSW + lh*4];
        ad[0] = pk(ra0.x, ra0.y); ad[1] = pk(ra0.z, ra0.w);
        ad[2] = pk(ra1.x, ra1.y); ad[3] = pk(ra1.z, ra1.w);
        uint32_t* bd = &Bs[0][lr*GSW + lh*4];
        bd[0] = pk(rb0.x, rb0.y); bd[1] = pk(rb0.z, rb0.w);
        bd[2] = pk(rb1.x, rb1.y); bd[3] = pk(rb1.z, rb1.w);
    }

    int buf = 0;
    for (int k0 = 0; k0 < K; k0 += 16) {
        const bool more = (k0 + 16) < K;
        if (more) {
            ra0 = *(const float4*)(Ap + k0 + 16);
            ra1 = *(const float4*)(Ap + k0 + 20);
            rb0 = *(const float4*)(Bp + k0 + 16);
            rb1 = *(const float4*)(Bp + k0 + 20);
        }
        __syncthreads();
        {
            uint32_t af[2][4], bf[8][2];
            #pragma unroll
            for (int mt = 0; mt < 2; mt++) {
                int mb = wm * 32 + mt * 16;
                af[mt][0] = As[buf][(mb + g)*GSW + tg];
                af[mt][1] = As[buf][(mb + g + 8)*GSW + tg];
                af[mt][2] = As[buf][(mb + g)*GSW + tg + 4];
                af[mt][3] = As[buf][(mb + g + 8)*GSW + tg + 4];
            }
            #pragma unroll
            for (int nt = 0; nt < 8; nt++) {
                int nb = wn * 64 + nt * 8;
                bf[nt][0] = Bs[buf][(nb + g)*GSW + tg];
                bf[nt][1] = Bs[buf][(nb + g)*GSW + tg + 4];
            }
            #pragma unroll
            for (int mt = 0; mt < 2; mt++)
                #pragma unroll
                for (int nt = 0; nt < 8; nt++)
                    mma_bf16(c[mt][nt][0], c[mt][nt][1], c[mt][nt][2], c[mt][nt][3],
                             af[mt][0], af[mt][1], af[mt][2], af[mt][3],
                             bf[nt][0], bf[nt][1]);
        }
        if (more) {
            int nb = buf ^ 1;
            uint32_t* ad = &As[nb][lr*GSW + lh*4];
            ad[0] = pk(ra0.x, ra0.y); ad[1] = pk(ra0.z, ra0.w);
            ad[2] = pk(ra1.x, ra1.y); ad[3] = pk(ra1.z, ra1.w);
            uint32_t* bd = &Bs[nb][lr*GSW + lh*4];
            bd[0] = pk(rb0.x, rb0.y); bd[1] = pk(rb0.z, rb0.w);
            bd[2] = pk(rb1.x, rb1.y); bd[3] = pk(rb1.z, rb1.w);
        }
        buf ^= 1;
    }

    #pragma unroll
    for (int mt = 0; mt < 2; mt++) {
        int row0 = m0 + wm * 32 + mt * 16 + g;
        #pragma unroll
        for (int nt = 0; nt < 8; nt++) {
            int col = n0 + wn * 64 + nt * 8 + tg * 2;
            *(float2*)&C[(size_t)row0 * N + col]       = make_float2(c[mt][nt][0], c[mt][nt][1]);
            *(float2*)&C[(size_t)(row0 + 8) * N + col] = make_float2(c[mt][nt][2], c[mt][nt][3]);
        }
    }
}

// ---------------- weight prep: w[oc][ic][tap] -> bf16 [c][tap][oc][ic/2] -----
__global__ void k_prepw(const float* __restrict__ cq,
                        const float* __restrict__ ck,
                        const float* __restrict__ cv)
{
    int idx = blockIdx.x;
    int c = idx / 7, tap = idx % 7;
    const float* src = (c == 0) ? cq : (c == 1) ? ck : cv;
    for (int e = threadIdx.x; e < 2048; e += 256) {
        int oc = e >> 5, icw = e & 31;
        float w0 = src[(oc*64 + 2*icw    )*7 + tap];
        float w1 = src[(oc*64 + 2*icw + 1)*7 + tap];
        g_wt[((c*7 + tap)*64 + oc)*32 + icw] = pk(w0, w1);
    }
}

// ---------------- fused conv (q/k/v) via bf16 MMA ----------------------------
// blockIdx.x: [0,8) q, [8,24) k, [24,40) v. 128 t per block, 8 warps x 16 rows.
#define CSW 36   // row stride in words (32 data + 4 pad)
__global__ __launch_bounds__(256) void k_conv3(const float* __restrict__ cqb,
                                               const float* __restrict__ ckb,
                                               const float* __restrict__ cvb)
{
    extern __shared__ uint32_t cs[];
    uint32_t* xs = cs;             // [u=0..133][CSW]
    uint32_t* ws = cs + 134*CSW;   // [tap][oc=64][CSW]
    const int bx = blockIdx.x;
    int c, t0, len, posoff, chanoff;
    const float* cb;
    uint32_t* outp;
    if (bx < 8)       { c = 0; t0 = bx*128;      len = QLEN; posoff = MEMLEN; chanoff = 0;    cb = cqb; outp = g_q; }
    else if (bx < 24) { c = 1; t0 = (bx-8)*128;  len = KLEN; posoff = 0;      chanoff = DM;   cb = ckb; outp = g_k; }
    else              { c = 2; t0 = (bx-24)*128; len = KLEN; posoff = 0;      chanoff = 2*DM; cb = cvb; outp = g_v; }
    const int nb = blockIdx.y;
    const int n = nb >> 2, b = nb & 3;
    const int tid = threadIdx.x;
    const int warp = tid >> 5, lane = tid & 31;
    const int wm = warp;
    const int g = lane >> 2, tg = lane & 3;

    // stage x window [t0-3, t0+130], rows [u][ic/2 words], bf16 pack
    for (int e = tid; e < 134*16; e += 256) {
        int u = e >> 4, i4 = (e & 15);           // ic = i4*4
        int pos = t0 + u - 3;
        float4 v = make_float4(0.f, 0.f, 0.f, 0.f);
        if (pos >= 0 && pos < len)
            v = *(const float4*)&g_qkv[(size_t)(pos + posoff)*(BSZ*QKV) + b*QKV + chanoff + n*DH + i4*4];
        xs[u*CSW + i4*2]     = pk(v.x, v.y);
        xs[u*CSW + i4*2 + 1] = pk(v.z, v.w);
    }
    // stage all 7 tap-weight matrices [tap][oc][icw]
    {
        const uint32_t* src = g_wt + c*7*64*32;
        for (int e = tid; e < 3584; e += 256) {
            int s4 = e * 4;
            int to = s4 >> 5, icw = s4 & 31;
            *(uint4*)&ws[to*CSW + icw] = *(const uint4*)&src[s4];
        }
    }
    __syncthreads();

    float acc[8][4];
    #pragma unroll
    for (int nf = 0; nf < 8; nf++)
        #pragma unroll
        for (int q = 0; q < 4; q++) acc[nf][q] = 0.f;

    #pragma unroll
    for (int tap = 0; tap < 7; tap++) {
        #pragma unroll
        for (int k0 = 0; k0 < 4; k0++) {          // k = ic, 16 per step
            int kw = k0 * 8;
            uint32_t a0 = xs[(wm*16 + g     + tap)*CSW + kw + tg];
            uint32_t a1 = xs[(wm*16 + g + 8 + tap)*CSW + kw + tg];
            uint32_t a2 = xs[(wm*16 + g     + tap)*CSW + kw + tg + 4];
            uint32_t a3 = xs[(wm*16 + g + 8 + tap)*CSW + kw + tg + 4];
            #pragma unroll
            for (int nf = 0; nf < 8; nf++) {
                uint32_t b0 = ws[(tap*64 + nf*8 + g)*CSW + kw + tg];
                uint32_t b1 = ws[(tap*64 + nf*8 + g)*CSW + kw + tg + 4];
                mma_bf16(acc[nf][0], acc[nf][1], acc[nf][2], acc[nf][3],
                         a0, a1, a2, a3, b0, b1);
            }
        }
    }

    #pragma unroll
    for (int nf = 0; nf < 8; nf++) {
        int oc = nf*8 + 2*tg;
        float2 bb = *(const float2*)&cb[oc];
        int row = t0 + wm*16 + g;
        size_t w0 = ((size_t)row*(BSZ*DM) + b*DM)/2 + n*32 + nf*4 + tg;
        size_t w1 = ((size_t)(row+8)*(BSZ*DM) + b*DM)/2 + n*32 + nf*4 + tg;
        outp[w0] = pk(acc[nf][0] + bb.x, acc[nf][1] + bb.y);
        outp[w1] = pk(acc[nf][2] + bb.x, acc[nf][3] + bb.y);
    }
}

// ---------------- attention v5: bf16 MMA, BD ring, no-max softmax ------------
#define ASW 36
__global__ __launch_bounds__(256) void k_attn5(const float* __restrict__ rwb,
                                               const float* __restrict__ rrb)
{
    extern __shared__ uint32_t smu[];
    uint32_t* QWs = smu;                 // [i][d/2]   bf16
    uint32_t* QRs = QWs + 64*ASW;
    uint32_t* KS  = QRs + 64*ASW;        // [j][d/2]
    uint32_t* VT  = KS  + 64*ASW;        // [d][j/2]
    uint32_t* Ps  = VT  + 64*ASW;        // [i][j/2]   probs bf16
    uint32_t* RW  = Ps  + 64*ASW;        // [cc][d/2]  staged rel chunk
    float*    SC  = (float*)(RW + 64*ASW);     // [i][j pad 68] AC fp32
    float*    BDR = SC + 64*68;                // [i][slot pad 132] ring fp32

    const int i0 = (gridDim.x - 1 - blockIdx.x) * 64;
    const int bn = blockIdx.y;
    const int b = bn >> 3, n = bn & 7;
    const int tid = threadIdx.x;
    const int warp = tid >> 5, lane = tid & 31;
    const int wm = warp & 3, wn = warp >> 2;
    const int g = lane >> 2, tg = lane & 3;
    const int TI = tid >> 4, TJ = tid & 15;

    // Q (+biases): unpack bf16, add fp32 bias, repack
    for (int e = tid; e < 64*16; e += 256) {
        int ii = e >> 4, d4 = (e & 15) * 4;
        size_t wi = ((size_t)(i0+ii)*(BSZ*DM) + b*DM + n*DH + d4) / 2;
        uint2 qv = *(const uint2*)&g_q[wi];
        float q0 = bl(qv.x), q1 = bh(qv.x), q2 = bl(qv.y), q3 = bh(qv.y);
        float4 wv = *(const float4*)&rwb[n*DH + d4];
        float4 rv = *(const float4*)&rrb[n*DH + d4];
        QWs[ii*ASW + d4/2]     = pk(q0 + wv.x, q1 + wv.y);
        QWs[ii*ASW + d4/2 + 1] = pk(q2 + wv.z, q3 + wv.w);
        QRs[ii*ASW + d4/2]     = pk(q0 + rv.x, q1 + rv.y);
        QRs[ii*ASW + d4/2 + 1] = pk(q2 + rv.z, q3 + rv.w);
    }

    float oacc[4][4];
    float l_acc[4];
    #pragma unroll
    for (int a = 0; a < 4; a++) {
        l_acc[a] = 0.f;
        #pragma unroll
        for (int q = 0; q < 4; q++) oacc[a][q] = 0.f;
    }

    const int jjb0 = 960 - i0;
    const int ntiles = i0/64 + 17;
    for (int t = 0; t < ntiles; t++) {
        const int j0 = t * 64;
        const int jjb = j0 - i0 + 960;
        __syncthreads();
        // K: straight word copy
        for (int e = tid; e < 64*16; e += 256) {
            int jl = e >> 4, w2 = (e & 15) * 2;
            size_t wi = ((size_t)(j0+jl)*(BSZ*DM) + b*DM + n*DH) / 2 + w2;
            *(uint2*)&KS[jl*ASW + w2] = *(const uint2*)&g_k[wi];
        }
        // V: transpose to [d][j/2] via half splicing
        for (int e = tid; e < 32*16; e += 256) {
            int jp = e >> 4, d4 = (e & 15) * 4;
            size_t wa = ((size_t)(j0+2*jp  )*(BSZ*DM) + b*DM + n*DH + d4) / 2;
            size_t wb = ((size_t)(j0+2*jp+1)*(BSZ*DM) + b*DM + n*DH + d4) / 2;
            uint2 va = *(const uint2*)&g_v[wa];
            uint2 vb = *(const uint2*)&g_v[wb];
            VT[(d4+0)*ASW + jp] = (va.x & 0xffffu) | (vb.x << 16);
            VT[(d4+1)*ASW + jp] = (va.x >> 16)     | (vb.x & 0xffff0000u);
            VT[(d4+2)*ASW + jp] = (va.y & 0xffffu) | (vb.y << 16);
            VT[(d4+3)*ASW + jp] = (va.y >> 16)     | (vb.y & 0xffff0000u);
        }
        // rel chunk [cbase, cbase+64) from fp32 g_rk, packed
        int cbase = (t == 0) ? jjb0 : (jjb + 64);
        for (int e = tid; e < 64*16; e += 256) {
            int l = e >> 4, d4 = (e & 15) * 4;
            int jj = cbase + l;
            float4 v = make_float4(0.f, 0.f, 0.f, 0.f);
            if (jj < KLEN) v = *(const float4*)&g_rk[(size_t)jj*DM + n*DH + d4];
            RW[l*ASW + d4/2]     = pk(v.x, v.y);
            RW[l*ASW + d4/2 + 1] = pk(v.z, v.w);
        }
        __syncthreads();

        // ---- AC = Qw @ K^T (64x64) -> SC fp32 ----
        {
            float sc[4][4];
            #pragma unroll
            for (int nf = 0; nf < 4; nf++)
                #pragma unroll
                for (int q = 0; q < 4; q++) sc[nf][q] = 0.f;
            #pragma unroll
            for (int k0 = 0; k0 < 4; k0++) {
                int kw = k0 * 8;
                uint32_t a0 = QWs[(wm*16 + g)*ASW + kw + tg];
                uint32_t a1 = QWs[(wm*16 + g + 8)*ASW + kw + tg];
                uint32_t a2 = QWs[(wm*16 + g)*ASW + kw + tg + 4];
                uint32_t a3 = QWs[(wm*16 + g + 8)*ASW + kw + tg + 4];
                #pragma unroll
                for (int nf = 0; nf < 4; nf++) {
                    uint32_t b0 = KS[(wn*32 + nf*8 + g)*ASW + kw + tg];
                    uint32_t b1 = KS[(wn*32 + nf*8 + g)*ASW + kw + tg + 4];
                    mma_bf16(sc[nf][0], sc[nf][1], sc[nf][2], sc[nf][3],
                             a0, a1, a2, a3, b0, b1);
                }
            }
            int il = wm*16 + g;
            #pragma unroll
            for (int nf = 0; nf < 4; nf++) {
                int jl = wn*32 + nf*8 + 2*tg;
                *(float2*)&SC[il*68 + jl]     = make_float2(sc[nf][0], sc[nf][1]);
                *(float2*)&SC[(il+8)*68 + jl] = make_float2(sc[nf][2], sc[nf][3]);
            }
        }
        // ---- BD chunk(s) = Qr @ RW^T (64x64) -> BDR ring ----
        const int nch = (t == 0) ? 2 : 1;
        for (int ch = 0; ch < nch; ch++) {
            if (ch == 1) {
                __syncthreads();
                cbase = jjb0 + 64;
                for (int e = tid; e < 64*16; e += 256) {
                    int l = e >> 4, d4 = (e & 15) * 4;
                    int jj = cbase + l;
                    float4 v = make_float4(0.f, 0.f, 0.f, 0.f);
                    if (jj < KLEN) v = *(const float4*)&g_rk[(size_t)jj*DM + n*DH + d4];
                    RW[l*ASW + d4/2]     = pk(v.x, v.y);
                    RW[l*ASW + d4/2 + 1] = pk(v.z, v.w);
                }
                __syncthreads();
            }
            const int s0 = cbase & 127;
            float pc[4][4];
            #pragma unroll
            for (int nf = 0; nf < 4; nf++)
                #pragma unroll
                for (int q = 0; q < 4; q++) pc[nf][q] = 0.f;
            #pragma unroll
            for (int k0 = 0; k0 < 4; k0++) {
                int kw = k0 * 8;
                uint32_t a0 = QRs[(wm*16 + g)*ASW + kw + tg];
                uint32_t a1 = QRs[(wm*16 + g + 8)*ASW + kw + tg];
                uint32_t a2 = QRs[(wm*16 + g)*ASW + kw + tg + 4];
                uint32_t a3 = QRs[(wm*16 + g + 8)*ASW + kw + tg + 4];
                #pragma unroll
                for (int nf = 0; nf < 4; nf++) {
                    uint32_t b0 = RW[(wn*32 + nf*8 + g)*ASW + kw + tg];
                    uint32_t b1 = RW[(wn*32 + nf*8 + g)*ASW + kw + tg + 4];
                    mma_bf16(pc[nf][0], pc[nf][1], pc[nf][2], pc[nf][3],
                             a0, a1, a2, a3, b0, b1);
                }
            }
            int il = wm*16 + g;
            #pragma unroll
            for (int nf = 0; nf < 4; nf++) {
                int cc = s0 + wn*32 + nf*8 + 2*tg;
                *(float2*)&BDR[il*132 + cc]     = make_float2(pc[nf][0], pc[nf][1]);
                *(float2*)&BDR[(il+8)*132 + cc] = make_float2(pc[nf][2], pc[nf][3]);
            }
        }
        __syncthreads();

        // ---- softmax ----
        const int jjb2 = jjb + 63;
        #pragma unroll
        for (int a = 0; a < 4; a++) {
            const int il = TI*4 + a;
            const int ig = i0 + il;
            float4 sv = *(float4*)&SC[il*68 + TJ*4];
            float sarr[4] = {sv.x, sv.y, sv.z, sv.w};
            float p[4];
            #pragma unroll
            for (int bb = 0; bb < 4; bb++) {
                int jl = TJ*4 + bb;
                int jg = j0 + jl;
                int slot = (jjb2 + jl - il) & 127;
                float sbd = BDR[il*132 + slot];
                float pe = 0.f;
                if (jg <= ig + MEMLEN) {
                    float y = (sarr[bb] + sbd) * 0.18033688f;  // *0.125*log2(e)
                    pe = exp2_fast(y);
                }
                p[bb] = pe;
                l_acc[a] += pe;
            }
            Ps[il*ASW + TJ*2]     = pk(p[0], p[1]);
            Ps[il*ASW + TJ*2 + 1] = pk(p[2], p[3]);
        }
        __syncthreads();

        // ---- O += P @ V ----
        #pragma unroll
        for (int k0 = 0; k0 < 4; k0++) {
            int kw = k0 * 8;
            uint32_t a0 = Ps[(wm*16 + g)*ASW + kw + tg];
            uint32_t a1 = Ps[(wm*16 + g + 8)*ASW + kw + tg];
            uint32_t a2 = Ps[(wm*16 + g)*ASW + kw + tg + 4];
            uint32_t a3 = Ps[(wm*16 + g + 8)*ASW + kw + tg + 4];
            #pragma unroll
            for (int nf = 0; nf < 4; nf++) {
                uint32_t b0 = VT[(wn*32 + nf*8 + g)*ASW + kw + tg];
                uint32_t b1 = VT[(wn*32 + nf*8 + g)*ASW + kw + tg + 4];
                mma_bf16(oacc[nf][0], oacc[nf][1], oacc[nf][2], oacc[nf][3],
                         a0, a1, a2, a3, b0, b1);
            }
        }
    }

    __syncthreads();
    #pragma unroll
    for (int a = 0; a < 4; a++) {
        float l = l_acc[a];
        l += __shfl_xor_sync(0xffffffffu, l, 1);
        l += __shfl_xor_sync(0xffffffffu, l, 2);
        l += __shfl_xor_sync(0xffffffffu, l, 4);
        l += __shfl_xor_sync(0xffffffffu, l, 8);
        if (TJ == 0) BDR[TI*4 + a] = 1.f / l;
    }
    __syncthreads();

    {
        int il = wm*16 + g;
        float inv0 = BDR[il], inv1 = BDR[il + 8];
        #pragma unroll
        for (int nf = 0; nf < 4; nf++) {
            int d = wn*32 + nf*8 + 2*tg;
            *(float2*)&g_av[(size_t)(i0+il)*(BSZ*DM) + b*DM + n*DH + d] =
                make_float2(oacc[nf][0]*inv0, oacc[nf][1]*inv0);
            *(float2*)&g_av[(size_t)(i0+il+8)*(BSZ*DM) + b*DM + n*DH + d] =
                make_float2(oacc[nf][2]*inv1, oacc[nf][3]*inv1);
        }
    }
}

// ---------------- residual + layernorm --------------------------------------
__global__ __launch_bounds__(256) void k_ln(const float* __restrict__ w,
                                            const float* __restrict__ g,
                                            const float* __restrict__ be,
                                            float* __restrict__ out)
{
    __shared__ float red[256];
    int row = blockIdx.x;
    int tid = threadIdx.x;
    const float* wr = w    + (size_t)row * DM;
    const float* ar = g_ao + (size_t)row * DM;
    float x0 = wr[tid]       + ar[tid];
    float x1 = wr[tid + 256] + ar[tid + 256];
    red[tid] = x0 + x1;
    __syncthreads();
    for (int s = 128; s > 0; s >>= 1) { if (tid < s) red[tid] += red[tid + s]; __syncthreads(); }
    float mu = red[0] * (1.f / DM);
    __syncthreads();
    float d0 = x0 - mu, d1 = x1 - mu;
    red[tid] = d0*d0 + d1*d1;
    __syncthreads();
    for (int s = 128; s > 0; s >>= 1) { if (tid < s) red[tid] += red[tid + s]; __syncthreads(); }
    float rs = rsqrtf(red[0] * (1.f / DM) + 1e-5f);
    out[(size_t)row*DM + tid]       = d0 * rs * g[tid]       + be[tid];
    out[(size_t)row*DM + tid + 256] = d1 * rs * g[tid + 256] + be[tid + 256];
}

// ---------------- launcher ---------------------------------------------------
extern "C" void kernel_launch(void* const* d_in, const int* in_sizes, int n_in,
                              void* d_out, int out_size)
{
    (void)in_sizes; (void)n_in; (void)out_size;
    const float* w    = (const float*)d_in[0];
    const float* r    = (const float*)d_in[1];
    const float* mems = (const float*)d_in[2];
    const float* rwb  = (const float*)d_in[3];
    const float* rrb  = (const float*)d_in[4];
    const float* qkvW = (const float*)d_in[5];
    const float* rW   = (const float*)d_in[6];
    const float* cqw  = (const float*)d_in[7];
    const float* cqb  = (const float*)d_in[8];
    const float* ckw  = (const float*)d_in[9];
    const float* ckb  = (const float*)d_in[10];
    const float* cvw  = (const float*)d_in[11];
    const float* cvb  = (const float*)d_in[12];
    const float* oW   = (const float*)d_in[13];
    const float* lng  = (const float*)d_in[14];
    const float* lnb  = (const float*)d_in[15];
    float* out = (float*)d_out;

    float *p_qkv, *p_rk, *p_av, *p_ao;
    cudaGetSymbolAddress((void**)&p_qkv, g_qkv);
    cudaGetSymbolAddress((void**)&p_rk,  g_rk);
    cudaGetSymbolAddress((void**)&p_av,  g_av);
    cudaGetSymbolAddress((void**)&p_ao,  g_ao);

    dim3 b256(256);

    k_prepw<<<21, b256>>>(cqw, ckw, cvw);

    // QKV projection fused over [mems; w] (8192 rows, split at 4096)
    mm_bf16<<<dim3(QKV/128, (KLEN*BSZ)/128), b256>>>(mems, w, MEMLEN*BSZ,
                                                     qkvW, p_qkv, QKV, DM);
    // r @ r_W^T
    mm_bf16<<<dim3(DM/128, KLEN/128), b256>>>(r, r, 1<<30, rW, p_rk, DM, DM);

    // fused convs (q: 8 blocks, k: 16, v: 16 along x)
    int csm = (134*CSW + 7*64*CSW) * 4;
    cudaFuncSetAttribute(k_conv3, cudaFuncAttributeMaxDynamicSharedMemorySize, csm);
    k_conv3<<<dim3(40, NH*BSZ), b256, csm>>>(cqb, ckb, cvb);

    // attention
    int asm_ = (6*64*ASW + 64*68 + 64*132) * 4;
    cudaFuncSetAttribute(k_attn5, cudaFuncAttributeMaxDynamicSharedMemorySize, asm_);
    k_attn5<<<dim3(QLEN/64, BSZ*NH), b256, asm_>>>(rwb, rrb);

    // output projection + residual layernorm
    mm_bf16<<<dim3(DM/128, (QLEN*BSZ)/128), b256>>>(p_av, p_av, 1<<30, oW, p_ao,
                                                    DM, DM);
    k_ln<<<QLEN*BSZ, b256>>>(w, lng, lnb, out);
}

// round 6
// speedup vs baseline: 6.2181x; 1.1365x over previous
#include <cuda_runtime.h>
#include <cuda_bf16.h>
#include <math.h>
#include <stdint.h>

#define QLEN 1024
#define KLEN 2048
#define MEMLEN 1024
#define BSZ 4
#define NH 8
#define DH 64
#define DM 512
#define QKV (3*DM)

// ---------------- scratch (static device globals; no allocation) ------------
__device__ uint32_t g_qkvh[(size_t)KLEN*BSZ*QKV/2]; // bf16 pairs (jk, b, 1536)
__device__ uint32_t g_rkh [(size_t)KLEN*DM/2];      // bf16 pairs (jj, n*64+d)
__device__ uint32_t g_q  [(size_t)QLEN*BSZ*DM/2];   // bf16 pairs (i, b, n, d)
__device__ uint32_t g_k  [(size_t)KLEN*BSZ*DM/2];   // bf16 pairs
__device__ uint32_t g_v  [(size_t)KLEN*BSZ*DM/2];   // bf16 pairs
__device__ float    g_av [(size_t)QLEN*BSZ*DM];     // fp32
__device__ float    g_ao [(size_t)QLEN*BSZ*DM];     // fp32
__device__ uint32_t g_wt[3*7*64*32];                // conv weights bf16 [c][tap][oc][ic/2]

__device__ __forceinline__ uint32_t pk(float x, float y) {
    __nv_bfloat162 t = __floats2bfloat162_rn(x, y);
    return *(uint32_t*)&t;
}
__device__ __forceinline__ float bl(uint32_t w) {
    __nv_bfloat16 h = *(__nv_bfloat16*)&w;
    return __bfloat162float(h);
}
__device__ __forceinline__ float bh(uint32_t w) {
    uint16_t u = (uint16_t)(w >> 16);
    __nv_bfloat16 h = *(__nv_bfloat16*)&u;
    return __bfloat162float(h);
}

__device__ __forceinline__ void mma_bf16(float& c0, float& c1, float& c2, float& c3,
                                         uint32_t a0, uint32_t a1, uint32_t a2, uint32_t a3,
                                         uint32_t b0, uint32_t b1)
{
    asm volatile("mma.sync.aligned.m16n8k16.row.col.f32.bf16.bf16.f32 "
                 "{%0,%1,%2,%3},{%4,%5,%6,%7},{%8,%9},{%0,%1,%2,%3};\n"
                 : "+f"(c0), "+f"(c1), "+f"(c2), "+f"(c3)
                 : "r"(a0), "r"(a1), "r"(a2), "r"(a3), "r"(b0), "r"(b1));
}

__device__ __forceinline__ void ldsm4(uint32_t& r0, uint32_t& r1, uint32_t& r2, uint32_t& r3,
                                      uint32_t addr)
{
    asm volatile("ldmatrix.sync.aligned.m8n8.x4.shared.b16 {%0,%1,%2,%3}, [%4];"
                 : "=r"(r0), "=r"(r1), "=r"(r2), "=r"(r3) : "r"(addr));
}

// 2^y via magic-round + deg-4 poly; no MUFU.
__device__ __forceinline__ float exp2_fast(float y) {
    y = fmaxf(y, -100.f);
    float z = __fadd_rn(y, 12582912.f);
    float n = __fsub_rn(z, 12582912.f);
    float f = __fsub_rn(y, n);
    float r = 0.0096181291f;
    r = fmaf(r, f, 0.055504109f);
    r = fmaf(r, f, 0.24022651f);
    r = fmaf(r, f, 0.69314718f);
    r = fmaf(r, f, 1.0f);
    int e = __float_as_int(z);
    float s = __int_as_float((e - 1262485377) << 23);
    return r * s;
}

// ---------------- BF16 tensor GEMM: C[M,N] = A[M,K] @ B[N,K]^T ---------------
#define GSW 12
__global__ __launch_bounds__(256, 2) void mm_bf16(const float* __restrict__ A0,
                                                  const float* __restrict__ A1,
                                                  int M1,
                                                  const float* __restrict__ B,
                                                  void* __restrict__ Cout,
                                                  int N, int K, int pack)
{
    __shared__ uint32_t As[2][128*GSW];
    __shared__ uint32_t Bs[2][128*GSW];
    const int tid = threadIdx.x;
    const int warp = tid >> 5, lane = tid & 31;
    const int wm = warp & 3, wn = warp >> 2;
    const int g = lane >> 2, tg = lane & 3;
    const int m0 = blockIdx.y * 128, n0 = blockIdx.x * 128;

    const float* Abase = (m0 < M1) ? (A0 + (size_t)m0 * K)
                                   : (A1 + (size_t)(m0 - M1) * K);

    float c[2][8][4];
    #pragma unroll
    for (int mt = 0; mt < 2; mt++)
        #pragma unroll
        for (int nt = 0; nt < 8; nt++)
            #pragma unroll
            for (int q = 0; q < 4; q++) c[mt][nt][q] = 0.f;

    const int lr = tid >> 1;
    const int lh = tid & 1;
    const float* Ap = Abase + (size_t)lr * K + lh * 8;
    const float* Bp = B + (size_t)(n0 + lr) * K + lh * 8;

    float4 ra0 = *(const float4*)(Ap);
    float4 ra1 = *(const float4*)(Ap + 4);
    float4 rb0 = *(const float4*)(Bp);
    float4 rb1 = *(const float4*)(Bp + 4);
    {
        uint32_t* ad = &As[0][lr*GSW + lh*4];
        ad[0] = pk(ra0.x, ra0.y); ad[1] = pk(ra0.z, ra0.w);
        ad[2] = pk(ra1.x, ra1.y); ad[3] = pk(ra1.z, ra1.w);
        uint32_t* bd = &Bs[0][lr*GSW + lh*4];
        bd[0] = pk(rb0.x, rb0.y); bd[1] = pk(rb0.z, rb0.w);
        bd[2] = pk(rb1.x, rb1.y); bd[3] = pk(rb1.z, rb1.w);
    }

    int buf = 0;
    for (int k0 = 0; k0 < K; k0 += 16) {
        const bool more = (k0 + 16) < K;
        if (more) {
            ra0 = *(const float4*)(Ap + k0 + 16);
            ra1 = *(const float4*)(Ap + k0 + 20);
            rb0 = *(const float4*)(Bp + k0 + 16);
            rb1 = *(const float4*)(Bp + k0 + 20);
        }
        __syncthreads();
        {
            uint32_t af[2][4], bf[8][2];
            #pragma unroll
            for (int mt = 0; mt < 2; mt++) {
                int mb = wm * 32 + mt * 16;
                af[mt][0] = As[buf][(mb + g)*GSW + tg];
                af[mt][1] = As[buf][(mb + g + 8)*GSW + tg];
                af[mt][2] = As[buf][(mb + g)*GSW + tg + 4];
                af[mt][3] = As[buf][(mb + g + 8)*GSW + tg + 4];
            }
            #pragma unroll
            for (int nt = 0; nt < 8; nt++) {
                int nb = wn * 64 + nt * 8;
                bf[nt][0] = Bs[buf][(nb + g)*GSW + tg];
                bf[nt][1] = Bs[buf][(nb + g)*GSW + tg + 4];
            }
            #pragma unroll
            for (int mt = 0; mt < 2; mt++)
                #pragma unroll
                for (int nt = 0; nt < 8; nt++)
                    mma_bf16(c[mt][nt][0], c[mt][nt][1], c[mt][nt][2], c[mt][nt][3],
                             af[mt][0], af[mt][1], af[mt][2], af[mt][3],
                             bf[nt][0], bf[nt][1]);
        }
        if (more) {
            int nb = buf ^ 1;
            uint32_t* ad = &As[nb][lr*GSW + lh*4];
            ad[0] = pk(ra0.x, ra0.y); ad[1] = pk(ra0.z, ra0.w);
            ad[2] = pk(ra1.x, ra1.y); ad[3] = pk(ra1.z, ra1.w);
            uint32_t* bd = &Bs[nb][lr*GSW + lh*4];
            bd[0] = pk(rb0.x, rb0.y); bd[1] = pk(rb0.z, rb0.w);
            bd[2] = pk(rb1.x, rb1.y); bd[3] = pk(rb1.z, rb1.w);
        }
        buf ^= 1;
    }

    #pragma unroll
    for (int mt = 0; mt < 2; mt++) {
        int row0 = m0 + wm * 32 + mt * 16 + g;
        #pragma unroll
        for (int nt = 0; nt < 8; nt++) {
            int col = n0 + wn * 64 + nt * 8 + tg * 2;
            if (pack) {
                uint32_t* Cp = (uint32_t*)Cout;
                Cp[((size_t)row0 * N + col)/2]       = pk(c[mt][nt][0], c[mt][nt][1]);
                Cp[((size_t)(row0 + 8) * N + col)/2] = pk(c[mt][nt][2], c[mt][nt][3]);
            } else {
                float* C = (float*)Cout;
                *(float2*)&C[(size_t)row0 * N + col]       = make_float2(c[mt][nt][0], c[mt][nt][1]);
                *(float2*)&C[(size_t)(row0 + 8) * N + col] = make_float2(c[mt][nt][2], c[mt][nt][3]);
            }
        }
    }
}

// ---------------- weight prep: w[oc][ic][tap] -> bf16 [c][tap][oc][ic/2] -----
__global__ void k_prepw(const float* __restrict__ cq,
                        const float* __restrict__ ck,
                        const float* __restrict__ cv)
{
    int idx = blockIdx.x;
    int c = idx / 7, tap = idx % 7;
    const float* src = (c == 0) ? cq : (c == 1) ? ck : cv;
    for (int e = threadIdx.x; e < 2048; e += 256) {
        int oc = e >> 5, icw = e & 31;
        float w0 = src[(oc*64 + 2*icw    )*7 + tap];
        float w1 = src[(oc*64 + 2*icw + 1)*7 + tap];
        g_wt[((c*7 + tap)*64 + oc)*32 + icw] = pk(w0, w1);
    }
}

// ---------------- fused conv (q/k/v) via bf16 MMA, bf16 input ----------------
#define CSW 36
__global__ __launch_bounds__(256) void k_conv3(const float* __restrict__ cqb,
                                               const float* __restrict__ ckb,
                                               const float* __restrict__ cvb)
{
    extern __shared__ uint32_t cs[];
    uint32_t* xs = cs;             // [u=0..133][CSW]
    uint32_t* ws = cs + 134*CSW;   // [tap][oc=64][CSW]
    const int bx = blockIdx.x;
    int c, t0, len, posoff, chanoff;
    const float* cb;
    uint32_t* outp;
    if (bx < 8)       { c = 0; t0 = bx*128;      len = QLEN; posoff = MEMLEN; chanoff = 0;    cb = cqb; outp = g_q; }
    else if (bx < 24) { c = 1; t0 = (bx-8)*128;  len = KLEN; posoff = 0;      chanoff = DM;   cb = ckb; outp = g_k; }
    else              { c = 2; t0 = (bx-24)*128; len = KLEN; posoff = 0;      chanoff = 2*DM; cb = cvb; outp = g_v; }
    const int nb = blockIdx.y;
    const int n = nb >> 2, b = nb & 3;
    const int tid = threadIdx.x;
    const int warp = tid >> 5, lane = tid & 31;
    const int wm = warp;
    const int g = lane >> 2, tg = lane & 3;

    // stage x window [t0-3, t0+130]: straight uint4 copies of bf16 pairs
    for (int e = tid; e < 134*8; e += 256) {
        int u = e >> 3, w4 = (e & 7) * 4;
        int pos = t0 + u - 3;
        uint4 v = make_uint4(0u, 0u, 0u, 0u);
        if (pos >= 0 && pos < len)
            v = *(const uint4*)&g_qkvh[((size_t)(pos + posoff)*(BSZ*QKV) + b*QKV + chanoff + n*DH)/2 + w4];
        *(uint4*)&xs[u*CSW + w4] = v;
    }
    // stage all 7 tap-weight matrices
    {
        const uint32_t* src = g_wt + c*7*64*32;
        for (int e = tid; e < 3584; e += 256) {
            int s4 = e * 4;
            int to = s4 >> 5, icw = s4 & 31;
            *(uint4*)&ws[to*CSW + icw] = *(const uint4*)&src[s4];
        }
    }
    __syncthreads();

    float acc[8][4];
    #pragma unroll
    for (int nf = 0; nf < 8; nf++)
        #pragma unroll
        for (int q = 0; q < 4; q++) acc[nf][q] = 0.f;

    #pragma unroll
    for (int tap = 0; tap < 7; tap++) {
        #pragma unroll
        for (int k0 = 0; k0 < 4; k0++) {
            int kw = k0 * 8;
            uint32_t a0 = xs[(wm*16 + g     + tap)*CSW + kw + tg];
            uint32_t a1 = xs[(wm*16 + g + 8 + tap)*CSW + kw + tg];
            uint32_t a2 = xs[(wm*16 + g     + tap)*CSW + kw + tg + 4];
            uint32_t a3 = xs[(wm*16 + g + 8 + tap)*CSW + kw + tg + 4];
            #pragma unroll
            for (int nf = 0; nf < 8; nf++) {
                uint32_t b0 = ws[(tap*64 + nf*8 + g)*CSW + kw + tg];
                uint32_t b1 = ws[(tap*64 + nf*8 + g)*CSW + kw + tg + 4];
                mma_bf16(acc[nf][0], acc[nf][1], acc[nf][2], acc[nf][3],
                         a0, a1, a2, a3, b0, b1);
            }
        }
    }

    #pragma unroll
    for (int nf = 0; nf < 8; nf++) {
        int oc = nf*8 + 2*tg;
        float2 bb = *(const float2*)&cb[oc];
        int row = t0 + wm*16 + g;
        size_t w0 = ((size_t)row*(BSZ*DM) + b*DM)/2 + n*32 + nf*4 + tg;
        size_t w1 = ((size_t)(row+8)*(BSZ*DM) + b*DM)/2 + n*32 + nf*4 + tg;
        outp[w0] = pk(acc[nf][0] + bb.x, acc[nf][1] + bb.y);
        outp[w1] = pk(acc[nf][2] + bb.x, acc[nf][3] + bb.y);
    }
}

// ---------------- attention v6: ldmatrix fragments, BD ring ------------------
#define ASW 36
#define OFF_QW 0
#define OFF_QR (64*ASW*4)
#define OFF_KS (2*64*ASW*4)
#define OFF_VT (3*64*ASW*4)
#define OFF_PS (4*64*ASW*4)
#define OFF_RW (5*64*ASW*4)
__global__ __launch_bounds__(256) void k_attn6(const float* __restrict__ rwb,
                                               const float* __restrict__ rrb)
{
    extern __shared__ uint32_t smu[];
    uint32_t* QWs = smu;                 // [i][d/2]
    uint32_t* QRs = QWs + 64*ASW;
    uint32_t* KS  = QRs + 64*ASW;        // [j][d/2]
    uint32_t* VT  = KS  + 64*ASW;        // [d][j/2]
    uint32_t* Ps  = VT  + 64*ASW;        // [i][j/2]
    uint32_t* RW  = Ps  + 64*ASW;        // [cc][d/2]
    float*    SC  = (float*)(RW + 64*ASW);     // [i][j pad 68]
    float*    BDR = SC + 64*68;                // [i][slot pad 132]

    const int i0 = (gridDim.x - 1 - blockIdx.x) * 64;
    const int bn = blockIdx.y;
    const int b = bn >> 3, n = bn & 7;
    const int tid = threadIdx.x;
    const int warp = tid >> 5, lane = tid & 31;
    const int wm = warp & 3, wn = warp >> 2;
    const int g = lane >> 2, tg = lane & 3;
    const int TI = tid >> 4, TJ = tid & 15;

    const uint32_t smb = (uint32_t)__cvta_generic_to_shared(smu);
    // A-fragment lane address pattern (rows wm*16.., 16B column halves)
    const uint32_t aoff = ((wm*16 + (lane & 15))*ASW + (lane >> 4)*4)*4;
    // B-fragment lane address pattern (covers two 8-row n-blocks via x4)
    const int quad = lane >> 3;
    const uint32_t boff = ((((quad & 2)*4) + (lane & 7))*ASW + (quad & 1)*4)*4
                          + (uint32_t)(wn*32)*ASW*4;

    // Q (+biases)
    for (int e = tid; e < 64*16; e += 256) {
        int ii = e >> 4, d4 = (e & 15) * 4;
        size_t wi = ((size_t)(i0+ii)*(BSZ*DM) + b*DM + n*DH + d4) / 2;
        uint2 qv = *(const uint2*)&g_q[wi];
        float q0 = bl(qv.x), q1 = bh(qv.x), q2 = bl(qv.y), q3 = bh(qv.y);
        float4 wv = *(const float4*)&rwb[n*DH + d4];
        float4 rv = *(const float4*)&rrb[n*DH + d4];
        QWs[ii*ASW + d4/2]     = pk(q0 + wv.x, q1 + wv.y);
        QWs[ii*ASW + d4/2 + 1] = pk(q2 + wv.z, q3 + wv.w);
        QRs[ii*ASW + d4/2]     = pk(q0 + rv.x, q1 + rv.y);
        QRs[ii*ASW + d4/2 + 1] = pk(q2 + rv.z, q3 + rv.w);
    }

    float oacc[4][4];
    float l_acc[4];
    #pragma unroll
    for (int a = 0; a < 4; a++) {
        l_acc[a] = 0.f;
        #pragma unroll
        for (int q = 0; q < 4; q++) oacc[a][q] = 0.f;
    }

    const int jjb0 = 960 - i0;
    const int ntiles = i0/64 + 17;
    for (int t = 0; t < ntiles; t++) {
        const int j0 = t * 64;
        const int jjb = j0 - i0 + 960;
        __syncthreads();
        // K: straight uint4 copy
        for (int e = tid; e < 64*8; e += 256) {
            int jl = e >> 3, w4 = (e & 7) * 4;
            size_t wi = ((size_t)(j0+jl)*(BSZ*DM) + b*DM + n*DH)/2 + w4;
            *(uint4*)&KS[jl*ASW + w4] = *(const uint4*)&g_k[wi];
        }
        // V: transpose to [d][j/2] via half splicing
        for (int e = tid; e < 32*16; e += 256) {
            int jp = e >> 4, d4 = (e & 15) * 4;
            size_t wa = ((size_t)(j0+2*jp  )*(BSZ*DM) + b*DM + n*DH + d4) / 2;
            size_t wb = ((size_t)(j0+2*jp+1)*(BSZ*DM) + b*DM + n*DH + d4) / 2;
            uint2 va = *(const uint2*)&g_v[wa];
            uint2 vb = *(const uint2*)&g_v[wb];
            VT[(d4+0)*ASW + jp] = (va.x & 0xffffu) | (vb.x << 16);
            VT[(d4+1)*ASW + jp] = (va.x >> 16)     | (vb.x & 0xffff0000u);
            VT[(d4+2)*ASW + jp] = (va.y & 0xffffu) | (vb.y << 16);
            VT[(d4+3)*ASW + jp] = (va.y >> 16)     | (vb.y & 0xffff0000u);
        }
        // rel chunk: straight uint4 copy from bf16 g_rkh
        int cbase = (t == 0) ? jjb0 : (jjb + 64);
        for (int e = tid; e < 64*8; e += 256) {
            int l = e >> 3, w4 = (e & 7) * 4;
            int jj = cbase + l;
            uint4 v = make_uint4(0u, 0u, 0u, 0u);
            if (jj < KLEN) v = *(const uint4*)&g_rkh[((size_t)jj*DM + n*DH)/2 + w4];
            *(uint4*)&RW[l*ASW + w4] = v;
        }
        __syncthreads();

        // ---- AC = Qw @ K^T (64x64) -> SC fp32 ----
        {
            float sc[4][4];
            #pragma unroll
            for (int nf = 0; nf < 4; nf++)
                #pragma unroll
                for (int q = 0; q < 4; q++) sc[nf][q] = 0.f;
            #pragma unroll
            for (int k0 = 0; k0 < 4; k0++) {
                uint32_t a0, a1, a2, a3, p0, p1, p2, p3, q0, q1, q2, q3;
                ldsm4(a0, a1, a2, a3, smb + OFF_QW + aoff + k0*32);
                ldsm4(p0, p1, p2, p3, smb + OFF_KS + boff + k0*32);
                ldsm4(q0, q1, q2, q3, smb + OFF_KS + boff + 16*ASW*4 + k0*32);
                mma_bf16(sc[0][0], sc[0][1], sc[0][2], sc[0][3], a0, a1, a2, a3, p0, p1);
                mma_bf16(sc[1][0], sc[1][1], sc[1][2], sc[1][3], a0, a1, a2, a3, p2, p3);
                mma_bf16(sc[2][0], sc[2][1], sc[2][2], sc[2][3], a0, a1, a2, a3, q0, q1);
                mma_bf16(sc[3][0], sc[3][1], sc[3][2], sc[3][3], a0, a1, a2, a3, q2, q3);
            }
            int il = wm*16 + g;
            #pragma unroll
            for (int nf = 0; nf < 4; nf++) {
                int jl = wn*32 + nf*8 + 2*tg;
                *(float2*)&SC[il*68 + jl]     = make_float2(sc[nf][0], sc[nf][1]);
                *(float2*)&SC[(il+8)*68 + jl] = make_float2(sc[nf][2], sc[nf][3]);
            }
        }
        // ---- BD chunk(s) = Qr @ RW^T (64x64) -> BDR ring ----
        const int nch = (t == 0) ? 2 : 1;
        for (int ch = 0; ch < nch; ch++) {
            if (ch == 1) {
                __syncthreads();
                cbase = jjb0 + 64;
                for (int e = tid; e < 64*8; e += 256) {
                    int l = e >> 3, w4 = (e & 7) * 4;
                    int jj = cbase + l;
                    uint4 v = make_uint4(0u, 0u, 0u, 0u);
                    if (jj < KLEN) v = *(const uint4*)&g_rkh[((size_t)jj*DM + n*DH)/2 + w4];
                    *(uint4*)&RW[l*ASW + w4] = v;
                }
                __syncthreads();
            }
            const int s0 = cbase & 127;
            float pc[4][4];
            #pragma unroll
            for (int nf = 0; nf < 4; nf++)
                #pragma unroll
                for (int q = 0; q < 4; q++) pc[nf][q] = 0.f;
            #pragma unroll
            for (int k0 = 0; k0 < 4; k0++) {
                uint32_t a0, a1, a2, a3, p0, p1, p2, p3, q0, q1, q2, q3;
                ldsm4(a0, a1, a2, a3, smb + OFF_QR + aoff + k0*32);
                ldsm4(p0, p1, p2, p3, smb + OFF_RW + boff + k0*32);
                ldsm4(q0, q1, q2, q3, smb + OFF_RW + boff + 16*ASW*4 + k0*32);
                mma_bf16(pc[0][0], pc[0][1], pc[0][2], pc[0][3], a0, a1, a2, a3, p0, p1);
                mma_bf16(pc[1][0], pc[1][1], pc[1][2], pc[1][3], a0, a1, a2, a3, p2, p3);
                mma_bf16(pc[2][0], pc[2][1], pc[2][2], pc[2][3], a0, a1, a2, a3, q0, q1);
                mma_bf16(pc[3][0], pc[3][1], pc[3][2], pc[3][3], a0, a1, a2, a3, q2, q3);
            }
            int il = wm*16 + g;
            #pragma unroll
            for (int nf = 0; nf < 4; nf++) {
                int cc = s0 + wn*32 + nf*8 + 2*tg;
                *(float2*)&BDR[il*132 + cc]     = make_float2(pc[nf][0], pc[nf][1]);
                *(float2*)&BDR[(il+8)*132 + cc] = make_float2(pc[nf][2], pc[nf][3]);
            }
        }
        __syncthreads();

        // ---- softmax ----
        const int jjb2 = jjb + 63;
        #pragma unroll
        for (int a = 0; a < 4; a++) {
            const int il = TI*4 + a;
            const int ig = i0 + il;
            float4 sv = *(float4*)&SC[il*68 + TJ*4];
            float sarr[4] = {sv.x, sv.y, sv.z, sv.w};
            float p[4];
            #pragma unroll
            for (int bb = 0; bb < 4; bb++) {
                int jl = TJ*4 + bb;
                int jg = j0 + jl;
                int slot = (jjb2 + jl - il) & 127;
                float sbd = BDR[il*132 + slot];
                float pe = 0.f;
                if (jg <= ig + MEMLEN) {
                    float y = (sarr[bb] + sbd) * 0.18033688f;
                    pe = exp2_fast(y);
                }
                p[bb] = pe;
                l_acc[a] += pe;
            }
            Ps[il*ASW + TJ*2]     = pk(p[0], p[1]);
            Ps[il*ASW + TJ*2 + 1] = pk(p[2], p[3]);
        }
        __syncthreads();

        // ---- O += P @ V ----
        #pragma unroll
        for (int k0 = 0; k0 < 4; k0++) {
            uint32_t a0, a1, a2, a3, p0, p1, p2, p3, q0, q1, q2, q3;
            ldsm4(a0, a1, a2, a3, smb + OFF_PS + aoff + k0*32);
            ldsm4(p0, p1, p2, p3, smb + OFF_VT + boff + k0*32);
            ldsm4(q0, q1, q2, q3, smb + OFF_VT + boff + 16*ASW*4 + k0*32);
            mma_bf16(oacc[0][0], oacc[0][1], oacc[0][2], oacc[0][3], a0, a1, a2, a3, p0, p1);
            mma_bf16(oacc[1][0], oacc[1][1], oacc[1][2], oacc[1][3], a0, a1, a2, a3, p2, p3);
            mma_bf16(oacc[2][0], oacc[2][1], oacc[2][2], oacc[2][3], a0, a1, a2, a3, q0, q1);
            mma_bf16(oacc[3][0], oacc[3][1], oacc[3][2], oacc[3][3], a0, a1, a2, a3, q2, q3);
        }
    }

    __syncthreads();
    #pragma unroll
    for (int a = 0; a < 4; a++) {
        float l = l_acc[a];
        l += __shfl_xor_sync(0xffffffffu, l, 1);
        l += __shfl_xor_sync(0xffffffffu, l, 2);
        l += __shfl_xor_sync(0xffffffffu, l, 4);
        l += __shfl_xor_sync(0xffffffffu, l, 8);
        if (TJ == 0) BDR[TI*4 + a] = 1.f / l;
    }
    __syncthreads();

    {
        int il = wm*16 + g;
        float inv0 = BDR[il], inv1 = BDR[il + 8];
        #pragma unroll
        for (int nf = 0; nf < 4; nf++) {
            int d = wn*32 + nf*8 + 2*tg;
            *(float2*)&g_av[(size_t)(i0+il)*(BSZ*DM) + b*DM + n*DH + d] =
                make_float2(oacc[nf][0]*inv0, oacc[nf][1]*inv0);
            *(float2*)&g_av[(size_t)(i0+il+8)*(BSZ*DM) + b*DM + n*DH + d] =
                make_float2(oacc[nf][2]*inv1, oacc[nf][3]*inv1);
        }
    }
}

// ---------------- residual + layernorm --------------------------------------
__global__ __launch_bounds__(256) void k_ln(const float* __restrict__ w,
                                            const float* __restrict__ g,
                                            const float* __restrict__ be,
                                            float* __restrict__ out)
{
    __shared__ float red[256];
    int row = blockIdx.x;
    int tid = threadIdx.x;
    const float* wr = w    + (size_t)row * DM;
    const float* ar = g_ao + (size_t)row * DM;
    float x0 = wr[tid]       + ar[tid];
    float x1 = wr[tid + 256] + ar[tid + 256];
    red[tid] = x0 + x1;
    __syncthreads();
    for (int s = 128; s > 0; s >>= 1) { if (tid < s) red[tid] += red[tid + s]; __syncthreads(); }
    float mu = red[0] * (1.f / DM);
    __syncthreads();
    float d0 = x0 - mu, d1 = x1 - mu;
    red[tid] = d0*d0 + d1*d1;
    __syncthreads();
    for (int s = 128; s > 0; s >>= 1) { if (tid < s) red[tid] += red[tid + s]; __syncthreads(); }
    float rs = rsqrtf(red[0] * (1.f / DM) + 1e-5f);
    out[(size_t)row*DM + tid]       = d0 * rs * g[tid]       + be[tid];
    out[(size_t)row*DM + tid + 256] = d1 * rs * g[tid + 256] + be[tid + 256];
}

// ---------------- launcher ---------------------------------------------------
extern "C" void kernel_launch(void* const* d_in, const int* in_sizes, int n_in,
                              void* d_out, int out_size)
{
    (void)in_sizes; (void)n_in; (void)out_size;
    const float* w    = (const float*)d_in[0];
    const float* r    = (const float*)d_in[1];
    const float* mems = (const float*)d_in[2];
    const float* rwb  = (const float*)d_in[3];
    const float* rrb  = (const float*)d_in[4];
    const float* qkvW = (const float*)d_in[5];
    const float* rW   = (const float*)d_in[6];
    const float* cqw  = (const float*)d_in[7];
    const float* cqb  = (const float*)d_in[8];
    const float* ckw  = (const float*)d_in[9];
    const float* ckb  = (const float*)d_in[10];
    const float* cvw  = (const float*)d_in[11];
    const float* cvb  = (const float*)d_in[12];
    const float* oW   = (const float*)d_in[13];
    const float* lng  = (const float*)d_in[14];
    const float* lnb  = (const float*)d_in[15];
    float* out = (float*)d_out;

    void *p_qkvh, *p_rkh;
    float *p_av, *p_ao;
    cudaGetSymbolAddress(&p_qkvh, g_qkvh);
    cudaGetSymbolAddress(&p_rkh,  g_rkh);
    cudaGetSymbolAddress((void**)&p_av,  g_av);
    cudaGetSymbolAddress((void**)&p_ao,  g_ao);

    dim3 b256(256);

    k_prepw<<<21, b256>>>(cqw, ckw, cvw);

    // QKV projection fused over [mems; w], packed bf16 output
    mm_bf16<<<dim3(QKV/128, (KLEN*BSZ)/128), b256>>>(mems, w, MEMLEN*BSZ,
                                                     qkvW, p_qkvh, QKV, DM, 1);
    // r @ r_W^T, packed bf16 output
    mm_bf16<<<dim3(DM/128, KLEN/128), b256>>>(r, r, 1<<30, rW, p_rkh, DM, DM, 1);

    // fused convs
    int csm = (134*CSW + 7*64*CSW) * 4;
    cudaFuncSetAttribute(k_conv3, cudaFuncAttributeMaxDynamicSharedMemorySize, csm);
    k_conv3<<<dim3(40, NH*BSZ), b256, csm>>>(cqb, ckb, cvb);

    // attention
    int asm_ = (6*64*ASW + 64*68 + 64*132) * 4;
    cudaFuncSetAttribute(k_attn6, cudaFuncAttributeMaxDynamicSharedMemorySize, asm_);
    k_attn6<<<dim3(QLEN/64, BSZ*NH), b256, asm_>>>(rwb, rrb);

    // output projection (fp32 out) + residual layernorm
    mm_bf16<<<dim3(DM/128, (QLEN*BSZ)/128), b256>>>(p_av, p_av, 1<<30, oW, p_ao,
                                                    DM, DM, 0);
    k_ln<<<QLEN*BSZ, b256>>>(w, lng, lnb, out);
}

// round 7
// speedup vs baseline: 6.6422x; 1.0682x over previous
#include <cuda_runtime.h>
#include <cuda_bf16.h>
#include <math.h>
#include <stdint.h>

#define QLEN 1024
#define KLEN 2048
#define MEMLEN 1024
#define BSZ 4
#define NH 8
#define DH 64
#define DM 512
#define QKV (3*DM)

__device__ uint32_t g_qkvh[(size_t)KLEN*BSZ*QKV/2];
__device__ uint32_t g_rkh [(size_t)KLEN*DM/2];
__device__ uint32_t g_q  [(size_t)QLEN*BSZ*DM/2];
__device__ uint32_t g_k  [(size_t)KLEN*BSZ*DM/2];
__device__ uint32_t g_v  [(size_t)KLEN*BSZ*DM/2];
__device__ float    g_av [(size_t)QLEN*BSZ*DM];
__device__ float    g_ao [(size_t)QLEN*BSZ*DM];
__device__ uint32_t g_wt[3*7*64*32];

__device__ __forceinline__ uint32_t pk(float x, float y) {
    __nv_bfloat162 t = __floats2bfloat162_rn(x, y);
    return *(uint32_t*)&t;
}
__device__ __forceinline__ float bl(uint32_t w) {
    __nv_bfloat16 h = *(__nv_bfloat16*)&w;
    return __bfloat162float(h);
}
__device__ __forceinline__ float bh(uint32_t w) {
    uint16_t u = (uint16_t)(w >> 16);
    __nv_bfloat16 h = *(__nv_bfloat16*)&u;
    return __bfloat162float(h);
}

__device__ __forceinline__ void mma_bf16(float& c0, float& c1, float& c2, float& c3,
                                         uint32_t a0, uint32_t a1, uint32_t a2, uint32_t a3,
                                         uint32_t b0, uint32_t b1)
{
    asm volatile("mma.sync.aligned.m16n8k16.row.col.f32.bf16.bf16.f32 "
                 "{%0,%1,%2,%3},{%4,%5,%6,%7},{%8,%9},{%0,%1,%2,%3};\n"
                 : "+f"(c0), "+f"(c1), "+f"(c2), "+f"(c3)
                 : "r"(a0), "r"(a1), "r"(a2), "r"(a3), "r"(b0), "r"(b1));
}

__device__ __forceinline__ void ldsm4(uint32_t& r0, uint32_t& r1, uint32_t& r2, uint32_t& r3,
                                      uint32_t addr)
{
    asm volatile("ldmatrix.sync.aligned.m8n8.x4.shared.b16 {%0,%1,%2,%3}, [%4];"
                 : "=r"(r0), "=r"(r1), "=r"(r2), "=r"(r3) : "r"(addr));
}

__device__ __forceinline__ float exp2_fast(float y) {
    y = fmaxf(y, -100.f);
    float z = __fadd_rn(y, 12582912.f);
    float n = __fsub_rn(z, 12582912.f);
    float f = __fsub_rn(y, n);
    float r = 0.0096181291f;
    r = fmaf(r, f, 0.055504109f);
    r = fmaf(r, f, 0.24022651f);
    r = fmaf(r, f, 0.69314718f);
    r = fmaf(r, f, 1.0f);
    int e = __float_as_int(z);
    float s = __int_as_float((e - 1262485377) << 23);
    return r * s;
}

// ---------------- BF16 tensor GEMM -------------------------------------------
#define GSW 12
__global__ __launch_bounds__(256, 2) void mm_bf16(const float* __restrict__ A0,
                                                  const float* __restrict__ A1,
                                                  int M1,
                                                  const float* __restrict__ B,
                                                  void* __restrict__ Cout,
                                                  int N, int K, int pack)
{
    __shared__ uint32_t As[2][128*GSW];
    __shared__ uint32_t Bs[2][128*GSW];
    const int tid = threadIdx.x;
    const int warp = tid >> 5, lane = tid & 31;
    const int wm = warp & 3, wn = warp >> 2;
    const int g = lane >> 2, tg = lane & 3;
    const int m0 = blockIdx.y * 128, n0 = blockIdx.x * 128;

    const float* Abase = (m0 < M1) ? (A0 + (size_t)m0 * K)
                                   : (A1 + (size_t)(m0 - M1) * K);

    float c[2][8][4];
    #pragma unroll
    for (int mt = 0; mt < 2; mt++)
        #pragma unroll
        for (int nt = 0; nt < 8; nt++)
            #pragma unroll
            for (int q = 0; q < 4; q++) c[mt][nt][q] = 0.f;

    const int lr = tid >> 1;
    const int lh = tid & 1;
    const float* Ap = Abase + (size_t)lr * K + lh * 8;
    const float* Bp = B + (size_t)(n0 + lr) * K + lh * 8;

    float4 ra0 = *(const float4*)(Ap);
    float4 ra1 = *(const float4*)(Ap + 4);
    float4 rb0 = *(const float4*)(Bp);
    float4 rb1 = *(const float4*)(Bp + 4);
    {
        uint32_t* ad = &As[0][lr*GSW + lh*4];
        ad[0] = pk(ra0.x, ra0.y); ad[1] = pk(ra0.z, ra0.w);
        ad[2] = pk(ra1.x, ra1.y); ad[3] = pk(ra1.z, ra1.w);
        uint32_t* bd = &Bs[0][lr*GSW + lh*4];
        bd[0] = pk(rb0.x, rb0.y); bd[1] = pk(rb0.z, rb0.w);
        bd[2] = pk(rb1.x, rb1.y); bd[3] = pk(rb1.z, rb1.w);
    }

    int buf = 0;
    for (int k0 = 0; k0 < K; k0 += 16) {
        const bool more = (k0 + 16) < K;
        if (more) {
            ra0 = *(const float4*)(Ap + k0 + 16);
            ra1 = *(const float4*)(Ap + k0 + 20);
            rb0 = *(const float4*)(Bp + k0 + 16);
            rb1 = *(const float4*)(Bp + k0 + 20);
        }
        __syncthreads();
        {
            uint32_t af[2][4], bf[8][2];
            #pragma unroll
            for (int mt = 0; mt < 2; mt++) {
                int mb = wm * 32 + mt * 16;
                af[mt][0] = As[buf][(mb + g)*GSW + tg];
                af[mt][1] = As[buf][(mb + g + 8)*GSW + tg];
                af[mt][2] = As[buf][(mb + g)*GSW + tg + 4];
                af[mt][3] = As[buf][(mb + g + 8)*GSW + tg + 4];
            }
            #pragma unroll
            for (int nt = 0; nt < 8; nt++) {
                int nb = wn * 64 + nt * 8;
                bf[nt][0] = Bs[buf][(nb + g)*GSW + tg];
                bf[nt][1] = Bs[buf][(nb + g)*GSW + tg + 4];
            }
            #pragma unroll
            for (int mt = 0; mt < 2; mt++)
                #pragma unroll
                for (int nt = 0; nt < 8; nt++)
                    mma_bf16(c[mt][nt][0], c[mt][nt][1], c[mt][nt][2], c[mt][nt][3],
                             af[mt][0], af[mt][1], af[mt][2], af[mt][3],
                             bf[nt][0], bf[nt][1]);
        }
        if (more) {
            int nb = buf ^ 1;
            uint32_t* ad = &As[nb][lr*GSW + lh*4];
            ad[0] = pk(ra0.x, ra0.y); ad[1] = pk(ra0.z, ra0.w);
            ad[2] = pk(ra1.x, ra1.y); ad[3] = pk(ra1.z, ra1.w);
            uint32_t* bd = &Bs[nb][lr*GSW + lh*4];
            bd[0] = pk(rb0.x, rb0.y); bd[1] = pk(rb0.z, rb0.w);
            bd[2] = pk(rb1.x, rb1.y); bd[3] = pk(rb1.z, rb1.w);
        }
        buf ^= 1;
    }

    #pragma unroll
    for (int mt = 0; mt < 2; mt++) {
        int row0 = m0 + wm * 32 + mt * 16 + g;
        #pragma unroll
        for (int nt = 0; nt < 8; nt++) {
            int col = n0 + wn * 64 + nt * 8 + tg * 2;
            if (pack) {
                uint32_t* Cp = (uint32_t*)Cout;
                Cp[((size_t)row0 * N + col)/2]       = pk(c[mt][nt][0], c[mt][nt][1]);
                Cp[((size_t)(row0 + 8) * N + col)/2] = pk(c[mt][nt][2], c[mt][nt][3]);
            } else {
                float* C = (float*)Cout;
                *(float2*)&C[(size_t)row0 * N + col]       = make_float2(c[mt][nt][0], c[mt][nt][1]);
                *(float2*)&C[(size_t)(row0 + 8) * N + col] = make_float2(c[mt][nt][2], c[mt][nt][3]);
            }
        }
    }
}

// ---------------- weight prep ------------------------------------------------
__global__ void k_prepw(const float* __restrict__ cq,
                        const float* __restrict__ ck,
                        const float* __restrict__ cv)
{
    int idx = blockIdx.x;
    int c = idx / 7, tap = idx % 7;
    const float* src = (c == 0) ? cq : (c == 1) ? ck : cv;
    for (int e = threadIdx.x; e < 2048; e += 256) {
        int oc = e >> 5, icw = e & 31;
        float w0 = src[(oc*64 + 2*icw    )*7 + tap];
        float w1 = src[(oc*64 + 2*icw + 1)*7 + tap];
        g_wt[((c*7 + tap)*64 + oc)*32 + icw] = pk(w0, w1);
    }
}

// ---------------- fused conv via bf16 MMA + ldmatrix -------------------------
#define CSW 36
#define OFF_WS (134*CSW*4)
__global__ __launch_bounds__(256, 2) void k_conv4(const float* __restrict__ cqb,
                                                  const float* __restrict__ ckb,
                                                  const float* __restrict__ cvb)
{
    extern __shared__ uint32_t cs[];
    uint32_t* xs = cs;
    uint32_t* ws = cs + 134*CSW;
    const int bx = blockIdx.x;
    int c, t0, len, posoff, chanoff;
    const float* cb;
    uint32_t* outp;
    if (bx < 8)       { c = 0; t0 = bx*128;      len = QLEN; posoff = MEMLEN; chanoff = 0;    cb = cqb; outp = g_q; }
    else if (bx < 24) { c = 1; t0 = (bx-8)*128;  len = KLEN; posoff = 0;      chanoff = DM;   cb = ckb; outp = g_k; }
    else              { c = 2; t0 = (bx-24)*128; len = KLEN; posoff = 0;      chanoff = 2*DM; cb = cvb; outp = g_v; }
    const int nb = blockIdx.y;
    const int n = nb >> 2, b = nb & 3;
    const int tid = threadIdx.x;
    const int warp = tid >> 5, lane = tid & 31;
    const int wm = warp;
    const int g = lane >> 2, tg = lane & 3;
    const int quad = lane >> 3;
    const uint32_t smbC = (uint32_t)__cvta_generic_to_shared(cs);

    for (int e = tid; e < 134*8; e += 256) {
        int u = e >> 3, w4 = (e & 7) * 4;
        int pos = t0 + u - 3;
        uint4 v = make_uint4(0u, 0u, 0u, 0u);
        if (pos >= 0 && pos < len)
            v = *(const uint4*)&g_qkvh[((size_t)(pos + posoff)*(BSZ*QKV) + b*QKV + chanoff + n*DH)/2 + w4];
        *(uint4*)&xs[u*CSW + w4] = v;
    }
    {
        const uint32_t* src = g_wt + c*7*64*32;
        for (int e = tid; e < 3584; e += 256) {
            int s4 = e * 4;
            int to = s4 >> 5, icw = s4 & 31;
            *(uint4*)&ws[to*CSW + icw] = *(const uint4*)&src[s4];
        }
    }
    __syncthreads();

    float acc[8][4];
    #pragma unroll
    for (int nf = 0; nf < 8; nf++)
        #pragma unroll
        for (int q = 0; q < 4; q++) acc[nf][q] = 0.f;

    const uint32_t bpat = (uint32_t)((((quad & 2)*4) + (lane & 7))*CSW + (quad & 1)*4)*4;

    #pragma unroll
    for (int tap = 0; tap < 7; tap++) {
        const uint32_t apat = (uint32_t)((wm*16 + (lane & 15) + tap)*CSW + (lane >> 4)*4)*4;
        #pragma unroll
        for (int k0 = 0; k0 < 4; k0++) {
            uint32_t a0, a1, a2, a3;
            ldsm4(a0, a1, a2, a3, smbC + apat + k0*32);
            #pragma unroll
            for (int nf2 = 0; nf2 < 4; nf2++) {
                uint32_t b0, b1, b2, b3;
                ldsm4(b0, b1, b2, b3,
                      smbC + OFF_WS + bpat + (uint32_t)((tap*64 + nf2*16)*CSW)*4 + k0*32);
                mma_bf16(acc[nf2*2][0], acc[nf2*2][1], acc[nf2*2][2], acc[nf2*2][3],
                         a0, a1, a2, a3, b0, b1);
                mma_bf16(acc[nf2*2+1][0], acc[nf2*2+1][1], acc[nf2*2+1][2], acc[nf2*2+1][3],
                         a0, a1, a2, a3, b2, b3);
            }
        }
    }

    #pragma unroll
    for (int nf = 0; nf < 8; nf++) {
        int oc = nf*8 + 2*tg;
        float2 bb = *(const float2*)&cb[oc];
        int row = t0 + wm*16 + g;
        size_t w0 = ((size_t)row*(BSZ*DM) + b*DM)/2 + n*32 + nf*4 + tg;
        size_t w1 = ((size_t)(row+8)*(BSZ*DM) + b*DM)/2 + n*32 + nf*4 + tg;
        outp[w0] = pk(acc[nf][0] + bb.x, acc[nf][1] + bb.y);
        outp[w1] = pk(acc[nf][2] + bb.x, acc[nf][3] + bb.y);
    }
}

// ---------------- attention v7: register softmax + direct P->PV --------------
#define ASW 36
#define OFF_QW 0
#define OFF_QR (64*ASW*4)
#define OFF_KS (2*64*ASW*4)
#define OFF_VT (3*64*ASW*4)
#define OFF_RW (4*64*ASW*4)
__global__ __launch_bounds__(256, 2) void k_attn7(const float* __restrict__ rwb,
                                                  const float* __restrict__ rrb)
{
    extern __shared__ uint32_t smu[];
    uint32_t* QWs = smu;
    uint32_t* QRs = QWs + 64*ASW;
    uint32_t* KS  = QRs + 64*ASW;
    uint32_t* VT  = KS  + 64*ASW;
    uint32_t* RW  = VT  + 64*ASW;
    float*    BDR = (float*)(RW + 64*ASW);

    const int i0 = (gridDim.x - 1 - blockIdx.x) * 64;
    const int bn = blockIdx.y;
    const int b = bn >> 3, n = bn & 7;
    const int tid = threadIdx.x;
    const int warp = tid >> 5, lane = tid & 31;
    const int wm = warp & 3, wn = warp >> 2;
    const int g = lane >> 2, tg = lane & 3;
    const int quad = lane >> 3;

    const uint32_t smb = (uint32_t)__cvta_generic_to_shared(smu);
    const uint32_t aoff = (uint32_t)((wm*16 + (lane & 15))*ASW + (lane >> 4)*4)*4;
    const uint32_t bpat = (uint32_t)((((quad & 2)*4) + (lane & 7))*ASW + (quad & 1)*4)*4;
    const uint32_t boff = bpat + (uint32_t)(wn*32)*ASW*4;

    for (int e = tid; e < 64*16; e += 256) {
        int ii = e >> 4, d4 = (e & 15) * 4;
        size_t wi = ((size_t)(i0+ii)*(BSZ*DM) + b*DM + n*DH + d4) / 2;
        uint2 qv = *(const uint2*)&g_q[wi];
        float q0 = bl(qv.x), q1 = bh(qv.x), q2 = bl(qv.y), q3 = bh(qv.y);
        float4 wv = *(const float4*)&rwb[n*DH + d4];
        float4 rv = *(const float4*)&rrb[n*DH + d4];
        QWs[ii*ASW + d4/2]     = pk(q0 + wv.x, q1 + wv.y);
        QWs[ii*ASW + d4/2 + 1] = pk(q2 + wv.z, q3 + wv.w);
        QRs[ii*ASW + d4/2]     = pk(q0 + rv.x, q1 + rv.y);
        QRs[ii*ASW + d4/2 + 1] = pk(q2 + rv.z, q3 + rv.w);
    }

    float oacc[8][4];
    #pragma unroll
    for (int nf = 0; nf < 8; nf++)
        #pragma unroll
        for (int q = 0; q < 4; q++) oacc[nf][q] = 0.f;
    float l0 = 0.f, l1 = 0.f;

    const int il0 = wm*16 + g;
    const int il1 = il0 + 8;
    const int jjb0 = 960 - i0;
    const int ntiles = i0/64 + 17;
    for (int t = 0; t < ntiles; t++) {
        const int j0 = t * 64;
        const int jjb = j0 - i0 + 960;
        __syncthreads();
        for (int e = tid; e < 64*8; e += 256) {
            int jl = e >> 3, w4 = (e & 7) * 4;
            size_t wi = ((size_t)(j0+jl)*(BSZ*DM) + b*DM + n*DH)/2 + w4;
            *(uint4*)&KS[jl*ASW + w4] = *(const uint4*)&g_k[wi];
        }
        for (int e = tid; e < 32*16; e += 256) {
            int jp = e >> 4, d4 = (e & 15) * 4;
            size_t wa = ((size_t)(j0+2*jp  )*(BSZ*DM) + b*DM + n*DH + d4) / 2;
            size_t wb = ((size_t)(j0+2*jp+1)*(BSZ*DM) + b*DM + n*DH + d4) / 2;
            uint2 va = *(const uint2*)&g_v[wa];
            uint2 vb = *(const uint2*)&g_v[wb];
            VT[(d4+0)*ASW + jp] = (va.x & 0xffffu) | (vb.x << 16);
            VT[(d4+1)*ASW + jp] = (va.x >> 16)     | (vb.x & 0xffff0000u);
            VT[(d4+2)*ASW + jp] = (va.y & 0xffffu) | (vb.y << 16);
            VT[(d4+3)*ASW + jp] = (va.y >> 16)     | (vb.y & 0xffff0000u);
        }
        int cbase = (t == 0) ? jjb0 : (jjb + 64);
        for (int e = tid; e < 64*8; e += 256) {
            int l = e >> 3, w4 = (e & 7) * 4;
            int jj = cbase + l;
            uint4 v = make_uint4(0u, 0u, 0u, 0u);
            if (jj < KLEN) v = *(const uint4*)&g_rkh[((size_t)jj*DM + n*DH)/2 + w4];
            *(uint4*)&RW[l*ASW + w4] = v;
        }
        __syncthreads();

        // AC -> registers
        float sc[4][4];
        #pragma unroll
        for (int nf = 0; nf < 4; nf++)
            #pragma unroll
            for (int q = 0; q < 4; q++) sc[nf][q] = 0.f;
        #pragma unroll
        for (int k0 = 0; k0 < 4; k0++) {
            uint32_t a0, a1, a2, a3, p0, p1, p2, p3, q0, q1, q2, q3;
            ldsm4(a0, a1, a2, a3, smb + OFF_QW + aoff + k0*32);
            ldsm4(p0, p1, p2, p3, smb + OFF_KS + boff + k0*32);
            ldsm4(q0, q1, q2, q3, smb + OFF_KS + boff + 16*ASW*4 + k0*32);
            mma_bf16(sc[0][0], sc[0][1], sc[0][2], sc[0][3], a0, a1, a2, a3, p0, p1);
            mma_bf16(sc[1][0], sc[1][1], sc[1][2], sc[1][3], a0, a1, a2, a3, p2, p3);
            mma_bf16(sc[2][0], sc[2][1], sc[2][2], sc[2][3], a0, a1, a2, a3, q0, q1);
            mma_bf16(sc[3][0], sc[3][1], sc[3][2], sc[3][3], a0, a1, a2, a3, q2, q3);
        }
        // BD -> BDR ring
        const int nch = (t == 0) ? 2 : 1;
        for (int ch = 0; ch < nch; ch++) {
            if (ch == 1) {
                __syncthreads();
                cbase = jjb0 + 64;
                for (int e = tid; e < 64*8; e += 256) {
                    int l = e >> 3, w4 = (e & 7) * 4;
                    int jj = cbase + l;
                    uint4 v = make_uint4(0u, 0u, 0u, 0u);
                    if (jj < KLEN) v = *(const uint4*)&g_rkh[((size_t)jj*DM + n*DH)/2 + w4];
                    *(uint4*)&RW[l*ASW + w4] = v;
                }
                __syncthreads();
            }
            const int s0 = cbase & 127;
            float pc[4][4];
            #pragma unroll
            for (int nf = 0; nf < 4; nf++)
                #pragma unroll
                for (int q = 0; q < 4; q++) pc[nf][q] = 0.f;
            #pragma unroll
            for (int k0 = 0; k0 < 4; k0++) {
                uint32_t a0, a1, a2, a3, p0, p1, p2, p3, q0, q1, q2, q3;
                ldsm4(a0, a1, a2, a3, smb + OFF_QR + aoff + k0*32);
                ldsm4(p0, p1, p2, p3, smb + OFF_RW + boff + k0*32);
                ldsm4(q0, q1, q2, q3, smb + OFF_RW + boff + 16*ASW*4 + k0*32);
                mma_bf16(pc[0][0], pc[0][1], pc[0][2], pc[0][3], a0, a1, a2, a3, p0, p1);
                mma_bf16(pc[1][0], pc[1][1], pc[1][2], pc[1][3], a0, a1, a2, a3, p2, p3);
                mma_bf16(pc[2][0], pc[2][1], pc[2][2], pc[2][3], a0, a1, a2, a3, q0, q1);
                mma_bf16(pc[3][0], pc[3][1], pc[3][2], pc[3][3], a0, a1, a2, a3, q2, q3);
            }
            #pragma unroll
            for (int nf = 0; nf < 4; nf++) {
                int cc = s0 + wn*32 + nf*8 + 2*tg;
                *(float2*)&BDR[il0*132 + cc] = make_float2(pc[nf][0], pc[nf][1]);
                *(float2*)&BDR[il1*132 + cc] = make_float2(pc[nf][2], pc[nf][3]);
            }
        }
        __syncthreads();

        // softmax in registers
        const int jjb2 = jjb + 63;
        uint32_t a_lo[4], a_hi[4];
        #pragma unroll
        for (int nf = 0; nf < 4; nf++) {
            int jl = wn*32 + nf*8 + 2*tg;
            int jg = j0 + jl;
            int s00 = (jjb2 + jl - il0) & 127;
            int s01 = (jjb2 + jl + 1 - il0) & 127;
            int s10 = (jjb2 + jl - il1) & 127;
            int s11 = (jjb2 + jl + 1 - il1) & 127;
            float p00 = 0.f, p01 = 0.f, p10 = 0.f, p11 = 0.f;
            if (jg <= i0 + il0 + MEMLEN)
                p00 = exp2_fast((sc[nf][0] + BDR[il0*132 + s00]) * 0.18033688f);
            if (jg + 1 <= i0 + il0 + MEMLEN)
                p01 = exp2_fast((sc[nf][1] + BDR[il0*132 + s01]) * 0.18033688f);
            if (jg <= i0 + il1 + MEMLEN)
                p10 = exp2_fast((sc[nf][2] + BDR[il1*132 + s10]) * 0.18033688f);
            if (jg + 1 <= i0 + il1 + MEMLEN)
                p11 = exp2_fast((sc[nf][3] + BDR[il1*132 + s11]) * 0.18033688f);
            l0 += p00 + p01;
            l1 += p10 + p11;
            a_lo[nf] = pk(p00, p01);
            a_hi[nf] = pk(p10, p11);
        }

        // PV with A from registers
        #pragma unroll
        for (int k0 = 0; k0 < 2; k0++) {
            uint32_t a0 = a_lo[2*k0], a1 = a_hi[2*k0];
            uint32_t a2 = a_lo[2*k0+1], a3 = a_hi[2*k0+1];
            uint32_t koffs = (uint32_t)(wn*16 + k0*8)*4;
            #pragma unroll
            for (int dd = 0; dd < 4; dd++) {
                uint32_t b0, b1, b2, b3;
                ldsm4(b0, b1, b2, b3, smb + OFF_VT + bpat + (uint32_t)(dd*16*ASW)*4 + koffs);
                mma_bf16(oacc[dd*2][0], oacc[dd*2][1], oacc[dd*2][2], oacc[dd*2][3],
                         a0, a1, a2, a3, b0, b1);
                mma_bf16(oacc[dd*2+1][0], oacc[dd*2+1][1], oacc[dd*2+1][2], oacc[dd*2+1][3],
                         a0, a1, a2, a3, b2, b3);
            }
        }
    }

    // merge wn halves
    __syncthreads();
    l0 += __shfl_xor_sync(0xffffffffu, l0, 1);
    l0 += __shfl_xor_sync(0xffffffffu, l0, 2);
    l1 += __shfl_xor_sync(0xffffffffu, l1, 1);
    l1 += __shfl_xor_sync(0xffffffffu, l1, 2);
    float* obuf = BDR;
    float* lbuf = BDR + 4*16*68;
    if (wn == 1) {
        #pragma unroll
        for (int nf = 0; nf < 8; nf++) {
            int d = nf*8 + 2*tg;
            *(float2*)&obuf[il0*68 + d] = make_float2(oacc[nf][0], oacc[nf][1]);
            *(float2*)&obuf[il1*68 + d] = make_float2(oacc[nf][2], oacc[nf][3]);
        }
        if (tg == 0) { lbuf[il0] = l0; lbuf[il1] = l1; }
    }
    __syncthreads();
    if (wn == 0) {
        float inv0 = 1.f / (l0 + lbuf[il0]);
        float inv1 = 1.f / (l1 + lbuf[il1]);
        #pragma unroll
        for (int nf = 0; nf < 8; nf++) {
            int d = nf*8 + 2*tg;
            float2 o0 = *(float2*)&obuf[il0*68 + d];
            float2 o1 = *(float2*)&obuf[il1*68 + d];
            *(float2*)&g_av[(size_t)(i0+il0)*(BSZ*DM) + b*DM + n*DH + d] =
                make_float2((oacc[nf][0]+o0.x)*inv0, (oacc[nf][1]+o0.y)*inv0);
            *(float2*)&g_av[(size_t)(i0+il1)*(BSZ*DM) + b*DM + n*DH + d] =
                make_float2((oacc[nf][2]+o1.x)*inv1, (oacc[nf][3]+o1.y)*inv1);
        }
    }
}

// ---------------- residual + layernorm --------------------------------------
__global__ __launch_bounds__(256) void k_ln(const float* __restrict__ w,
                                            const float* __restrict__ g,
                                            const float* __restrict__ be,
                                            float* __restrict__ out)
{
    __shared__ float red[256];
    int row = blockIdx.x;
    int tid = threadIdx.x;
    const float* wr = w    + (size_t)row * DM;
    const float* ar = g_ao + (size_t)row * DM;
    float x0 = wr[tid]       + ar[tid];
    float x1 = wr[tid + 256] + ar[tid + 256];
    red[tid] = x0 + x1;
    __syncthreads();
    for (int s = 128; s > 0; s >>= 1) { if (tid < s) red[tid] += red[tid + s]; __syncthreads(); }
    float mu = red[0] * (1.f / DM);
    __syncthreads();
    float d0 = x0 - mu, d1 = x1 - mu;
    red[tid] = d0*d0 + d1*d1;
    __syncthreads();
    for (int s = 128; s > 0; s >>= 1) { if (tid < s) red[tid] += red[tid + s]; __syncthreads(); }
    float rs = rsqrtf(red[0] * (1.f / DM) + 1e-5f);
    out[(size_t)row*DM + tid]       = d0 * rs * g[tid]       + be[tid];
    out[(size_t)row*DM + tid + 256] = d1 * rs * g[tid + 256] + be[tid + 256];
}

// ---------------- launcher ---------------------------------------------------
extern "C" void kernel_launch(void* const* d_in, const int* in_sizes, int n_in,
                              void* d_out, int out_size)
{
    (void)in_sizes; (void)n_in; (void)out_size;
    const float* w    = (const float*)d_in[0];
    const float* r    = (const float*)d_in[1];
    const float* mems = (const float*)d_in[2];
    const float* rwb  = (const float*)d_in[3];
    const float* rrb  = (const float*)d_in[4];
    const float* qkvW = (const float*)d_in[5];
    const float* rW   = (const float*)d_in[6];
    const float* cqw  = (const float*)d_in[7];
    const float* cqb  = (const float*)d_in[8];
    const float* ckw  = (const float*)d_in[9];
    const float* ckb  = (const float*)d_in[10];
    const float* cvw  = (const float*)d_in[11];
    const float* cvb  = (const float*)d_in[12];
    const float* oW   = (const float*)d_in[13];
    const float* lng  = (const float*)d_in[14];
    const float* lnb  = (const float*)d_in[15];
    float* out = (float*)d_out;

    void *p_qkvh, *p_rkh;
    float *p_av, *p_ao;
    cudaGetSymbolAddress(&p_qkvh, g_qkvh);
    cudaGetSymbolAddress(&p_rkh,  g_rkh);
    cudaGetSymbolAddress((void**)&p_av,  g_av);
    cudaGetSymbolAddress((void**)&p_ao,  g_ao);

    dim3 b256(256);

    k_prepw<<<21, b256>>>(cqw, ckw, cvw);

    mm_bf16<<<dim3(QKV/128, (KLEN*BSZ)/128), b256>>>(mems, w, MEMLEN*BSZ,
                                                     qkvW, p_qkvh, QKV, DM, 1);
    mm_bf16<<<dim3(DM/128, KLEN/128), b256>>>(r, r, 1<<30, rW, p_rkh, DM, DM, 1);

    int csm = (134*CSW + 7*64*CSW) * 4;
    cudaFuncSetAttribute(k_conv4, cudaFuncAttributeMaxDynamicSharedMemorySize, csm);
    k_conv4<<<dim3(40, NH*BSZ), b256, csm>>>(cqb, ckb, cvb);

    int asm_ = (5*64*ASW + 64*132) * 4;
    cudaFuncSetAttribute(k_attn7, cudaFuncAttributeMaxDynamicSharedMemorySize, asm_);
    k_attn7<<<dim3(QLEN/64, BSZ*NH), b256, asm_>>>(rwb, rrb);

    mm_bf16<<<dim3(DM/128, (QLEN*BSZ)/128), b256>>>(p_av, p_av, 1<<30, oW, p_ao,
                                                    DM, DM, 0);
    k_ln<<<QLEN*BSZ, b256>>>(w, lng, lnb, out);
}

// round 8
// speedup vs baseline: 7.7423x; 1.1656x over previous
#include <cuda_runtime.h>
#include <cuda_bf16.h>
#include <math.h>
#include <stdint.h>

#define QLEN 1024
#define KLEN 2048
#define MEMLEN 1024
#define BSZ 4
#define NH 8
#define DH 64
#define DM 512
#define QKV (3*DM)

__device__ uint32_t g_qkvh[(size_t)KLEN*BSZ*QKV/2];
__device__ uint32_t g_rkh [(size_t)KLEN*DM/2];
__device__ uint32_t g_q  [(size_t)QLEN*BSZ*DM/2];
__device__ uint32_t g_k  [(size_t)KLEN*BSZ*DM/2];
__device__ uint32_t g_v  [(size_t)KLEN*BSZ*DM/2];
__device__ float    g_av [(size_t)QLEN*BSZ*DM];
__device__ float    g_ao [(size_t)QLEN*BSZ*DM];
__device__ uint32_t g_wt[3*7*64*32];

__device__ __forceinline__ uint32_t pk(float x, float y) {
    __nv_bfloat162 t = __floats2bfloat162_rn(x, y);
    return *(uint32_t*)&t;
}
__device__ __forceinline__ float bl(uint32_t w) {
    __nv_bfloat16 h = *(__nv_bfloat16*)&w;
    return __bfloat162float(h);
}
__device__ __forceinline__ float bh(uint32_t w) {
    uint16_t u = (uint16_t)(w >> 16);
    __nv_bfloat16 h = *(__nv_bfloat16*)&u;
    return __bfloat162float(h);
}

__device__ __forceinline__ void mma_bf16(float& c0, float& c1, float& c2, float& c3,
                                         uint32_t a0, uint32_t a1, uint32_t a2, uint32_t a3,
                                         uint32_t b0, uint32_t b1)
{
    asm volatile("mma.sync.aligned.m16n8k16.row.col.f32.bf16.bf16.f32 "
                 "{%0,%1,%2,%3},{%4,%5,%6,%7},{%8,%9},{%0,%1,%2,%3};\n"
                 : "+f"(c0), "+f"(c1), "+f"(c2), "+f"(c3)
                 : "r"(a0), "r"(a1), "r"(a2), "r"(a3), "r"(b0), "r"(b1));
}

__device__ __forceinline__ void ldsm4(uint32_t& r0, uint32_t& r1, uint32_t& r2, uint32_t& r3,
                                      uint32_t addr)
{
    asm volatile("ldmatrix.sync.aligned.m8n8.x4.shared.b16 {%0,%1,%2,%3}, [%4];"
                 : "=r"(r0), "=r"(r1), "=r"(r2), "=r"(r3) : "r"(addr));
}
__device__ __forceinline__ void ldsm4t(uint32_t& r0, uint32_t& r1, uint32_t& r2, uint32_t& r3,
                                       uint32_t addr)
{
    asm volatile("ldmatrix.sync.aligned.m8n8.x4.trans.shared.b16 {%0,%1,%2,%3}, [%4];"
                 : "=r"(r0), "=r"(r1), "=r"(r2), "=r"(r3) : "r"(addr));
}

__device__ __forceinline__ void cpa16(uint32_t saddr, const void* gaddr) {
    asm volatile("cp.async.cg.shared.global [%0], [%1], 16;" :: "r"(saddr), "l"(gaddr));
}
__device__ __forceinline__ void cpa16z(uint32_t saddr, const void* gaddr, int ok) {
    int sz = ok ? 16 : 0;
    asm volatile("cp.async.cg.shared.global [%0], [%1], 16, %2;"
                 :: "r"(saddr), "l"(gaddr), "r"(sz));
}
#define CP_COMMIT() asm volatile("cp.async.commit_group;")
#define CP_WAIT0()  asm volatile("cp.async.wait_group 0;")

__device__ __forceinline__ float exp2_fast(float y) {
    y = fmaxf(y, -100.f);
    float z = __fadd_rn(y, 12582912.f);
    float n = __fsub_rn(z, 12582912.f);
    float f = __fsub_rn(y, n);
    float r = 0.0096181291f;
    r = fmaf(r, f, 0.055504109f);
    r = fmaf(r, f, 0.24022651f);
    r = fmaf(r, f, 0.69314718f);
    r = fmaf(r, f, 1.0f);
    int e = __float_as_int(z);
    float s = __int_as_float((e - 1262485377) << 23);
    return r * s;
}

// ---------------- BF16 tensor GEMM -------------------------------------------
#define GSW 12
__global__ __launch_bounds__(256, 2) void mm_bf16(const float* __restrict__ A0,
                                                  const float* __restrict__ A1,
                                                  int M1,
                                                  const float* __restrict__ B,
                                                  void* __restrict__ Cout,
                                                  int N, int K, int pack)
{
    __shared__ uint32_t As[2][128*GSW];
    __shared__ uint32_t Bs[2][128*GSW];
    const int tid = threadIdx.x;
    const int warp = tid >> 5, lane = tid & 31;
    const int wm = warp & 3, wn = warp >> 2;
    const int g = lane >> 2, tg = lane & 3;
    const int m0 = blockIdx.y * 128, n0 = blockIdx.x * 128;

    const float* Abase = (m0 < M1) ? (A0 + (size_t)m0 * K)
                                   : (A1 + (size_t)(m0 - M1) * K);

    float c[2][8][4];
    #pragma unroll
    for (int mt = 0; mt < 2; mt++)
        #pragma unroll
        for (int nt = 0; nt < 8; nt++)
            #pragma unroll
            for (int q = 0; q < 4; q++) c[mt][nt][q] = 0.f;

    const int lr = tid >> 1;
    const int lh = tid & 1;
    const float* Ap = Abase + (size_t)lr * K + lh * 8;
    const float* Bp = B + (size_t)(n0 + lr) * K + lh * 8;

    float4 ra0 = *(const float4*)(Ap);
    float4 ra1 = *(const float4*)(Ap + 4);
    float4 rb0 = *(const float4*)(Bp);
    float4 rb1 = *(const float4*)(Bp + 4);
    {
        uint32_t* ad = &As[0][lr*GSW + lh*4];
        ad[0] = pk(ra0.x, ra0.y); ad[1] = pk(ra0.z, ra0.w);
        ad[2] = pk(ra1.x, ra1.y); ad[3] = pk(ra1.z, ra1.w);
        uint32_t* bd = &Bs[0][lr*GSW + lh*4];
        bd[0] = pk(rb0.x, rb0.y); bd[1] = pk(rb0.z, rb0.w);
        bd[2] = pk(rb1.x, rb1.y); bd[3] = pk(rb1.z, rb1.w);
    }

    int buf = 0;
    for (int k0 = 0; k0 < K; k0 += 16) {
        const bool more = (k0 + 16) < K;
        if (more) {
            ra0 = *(const float4*)(Ap + k0 + 16);
            ra1 = *(const float4*)(Ap + k0 + 20);
            rb0 = *(const float4*)(Bp + k0 + 16);
            rb1 = *(const float4*)(Bp + k0 + 20);
        }
        __syncthreads();
        {
            uint32_t af[2][4], bf[8][2];
            #pragma unroll
            for (int mt = 0; mt < 2; mt++) {
                int mb = wm * 32 + mt * 16;
                af[mt][0] = As[buf][(mb + g)*GSW + tg];
                af[mt][1] = As[buf][(mb + g + 8)*GSW + tg];
                af[mt][2] = As[buf][(mb + g)*GSW + tg + 4];
                af[mt][3] = As[buf][(mb + g + 8)*GSW + tg + 4];
            }
            #pragma unroll
            for (int nt = 0; nt < 8; nt++) {
                int nb = wn * 64 + nt * 8;
                bf[nt][0] = Bs[buf][(nb + g)*GSW + tg];
                bf[nt][1] = Bs[buf][(nb + g)*GSW + tg + 4];
            }
            #pragma unroll
            for (int mt = 0; mt < 2; mt++)
                #pragma unroll
                for (int nt = 0; nt < 8; nt++)
                    mma_bf16(c[mt][nt][0], c[mt][nt][1], c[mt][nt][2], c[mt][nt][3],
                             af[mt][0], af[mt][1], af[mt][2], af[mt][3],
                             bf[nt][0], bf[nt][1]);
        }
        if (more) {
            int nb = buf ^ 1;
            uint32_t* ad = &As[nb][lr*GSW + lh*4];
            ad[0] = pk(ra0.x, ra0.y); ad[1] = pk(ra0.z, ra0.w);
            ad[2] = pk(ra1.x, ra1.y); ad[3] = pk(ra1.z, ra1.w);
            uint32_t* bd = &Bs[nb][lr*GSW + lh*4];
            bd[0] = pk(rb0.x, rb0.y); bd[1] = pk(rb0.z, rb0.w);
            bd[2] = pk(rb1.x, rb1.y); bd[3] = pk(rb1.z, rb1.w);
        }
        buf ^= 1;
    }

    #pragma unroll
    for (int mt = 0; mt < 2; mt++) {
        int row0 = m0 + wm * 32 + mt * 16 + g;
        #pragma unroll
        for (int nt = 0; nt < 8; nt++) {
            int col = n0 + wn * 64 + nt * 8 + tg * 2;
            if (pack) {
                uint32_t* Cp = (uint32_t*)Cout;
                Cp[((size_t)row0 * N + col)/2]       = pk(c[mt][nt][0], c[mt][nt][1]);
                Cp[((size_t)(row0 + 8) * N + col)/2] = pk(c[mt][nt][2], c[mt][nt][3]);
            } else {
                float* C = (float*)Cout;
                *(float2*)&C[(size_t)row0 * N + col]       = make_float2(c[mt][nt][0], c[mt][nt][1]);
                *(float2*)&C[(size_t)(row0 + 8) * N + col] = make_float2(c[mt][nt][2], c[mt][nt][3]);
            }
        }
    }
}

// ---------------- weight prep ------------------------------------------------
__global__ void k_prepw(const float* __restrict__ cq,
                        const float* __restrict__ ck,
                        const float* __restrict__ cv)
{
    int idx = blockIdx.x;
    int c = idx / 7, tap = idx % 7;
    const float* src = (c == 0) ? cq : (c == 1) ? ck : cv;
    for (int e = threadIdx.x; e < 2048; e += 256) {
        int oc = e >> 5, icw = e & 31;
        float w0 = src[(oc*64 + 2*icw    )*7 + tap];
        float w1 = src[(oc*64 + 2*icw + 1)*7 + tap];
        g_wt[((c*7 + tap)*64 + oc)*32 + icw] = pk(w0, w1);
    }
}

// ---------------- fused conv via bf16 MMA + ldmatrix + cp.async --------------
#define CSW 36
#define OFF_WS (134*CSW*4)
__global__ __launch_bounds__(256, 2) void k_conv5(const float* __restrict__ cqb,
                                                  const float* __restrict__ ckb,
                                                  const float* __restrict__ cvb)
{
    extern __shared__ uint32_t cs[];
    const int bx = blockIdx.x;
    int c, t0, len, posoff, chanoff;
    const float* cb;
    uint32_t* outp;
    if (bx < 8)       { c = 0; t0 = bx*128;      len = QLEN; posoff = MEMLEN; chanoff = 0;    cb = cqb; outp = g_q; }
    else if (bx < 24) { c = 1; t0 = (bx-8)*128;  len = KLEN; posoff = 0;      chanoff = DM;   cb = ckb; outp = g_k; }
    else              { c = 2; t0 = (bx-24)*128; len = KLEN; posoff = 0;      chanoff = 2*DM; cb = cvb; outp = g_v; }
    const int nb = blockIdx.y;
    const int n = nb >> 2, b = nb & 3;
    const int tid = threadIdx.x;
    const int warp = tid >> 5, lane = tid & 31;
    const int wm = warp;
    const int g = lane >> 2, tg = lane & 3;
    const int quad = lane >> 3;
    const uint32_t smbC = (uint32_t)__cvta_generic_to_shared(cs);

    // x window via cp.async (zero-filled out-of-range)
    for (int e = tid; e < 134*8; e += 256) {
        int u = e >> 3, w4 = (e & 7) * 4;
        int pos = t0 + u - 3;
        int ok = (pos >= 0 && pos < len);
        int pc = ok ? pos : 0;
        cpa16z(smbC + (uint32_t)(u*CSW + w4)*4,
               &g_qkvh[((size_t)(pc + posoff)*(BSZ*QKV) + b*QKV + chanoff + n*DH)/2 + w4], ok);
    }
    // all 7 tap-weight matrices via cp.async
    {
        const uint32_t* src = g_wt + c*7*64*32;
        for (int e = tid; e < 3584; e += 256) {
            int s4 = e * 4;
            int to = s4 >> 5, icw = s4 & 31;
            cpa16(smbC + OFF_WS + (uint32_t)(to*CSW + icw)*4, &src[s4]);
        }
    }
    CP_COMMIT();
    CP_WAIT0();
    __syncthreads();

    float acc[8][4];
    #pragma unroll
    for (int nf = 0; nf < 8; nf++)
        #pragma unroll
        for (int q = 0; q < 4; q++) acc[nf][q] = 0.f;

    const uint32_t bpat = (uint32_t)((((quad & 2)*4) + (lane & 7))*CSW + (quad & 1)*4)*4;

    #pragma unroll
    for (int tap = 0; tap < 7; tap++) {
        const uint32_t apat = (uint32_t)((wm*16 + (lane & 15) + tap)*CSW + (lane >> 4)*4)*4;
        #pragma unroll
        for (int k0 = 0; k0 < 4; k0++) {
            uint32_t a0, a1, a2, a3;
            ldsm4(a0, a1, a2, a3, smbC + apat + k0*32);
            #pragma unroll
            for (int nf2 = 0; nf2 < 4; nf2++) {
                uint32_t b0, b1, b2, b3;
                ldsm4(b0, b1, b2, b3,
                      smbC + OFF_WS + bpat + (uint32_t)((tap*64 + nf2*16)*CSW)*4 + k0*32);
                mma_bf16(acc[nf2*2][0], acc[nf2*2][1], acc[nf2*2][2], acc[nf2*2][3],
                         a0, a1, a2, a3, b0, b1);
                mma_bf16(acc[nf2*2+1][0], acc[nf2*2+1][1], acc[nf2*2+1][2], acc[nf2*2+1][3],
                         a0, a1, a2, a3, b2, b3);
            }
        }
    }

    #pragma unroll
    for (int nf = 0; nf < 8; nf++) {
        int oc = nf*8 + 2*tg;
        float2 bb = *(const float2*)&cb[oc];
        int row = t0 + wm*16 + g;
        size_t w0 = ((size_t)row*(BSZ*DM) + b*DM)/2 + n*32 + nf*4 + tg;
        size_t w1 = ((size_t)(row+8)*(BSZ*DM) + b*DM)/2 + n*32 + nf*4 + tg;
        outp[w0] = pk(acc[nf][0] + bb.x, acc[nf][1] + bb.y);
        outp[w1] = pk(acc[nf][2] + bb.x, acc[nf][3] + bb.y);
    }
}

// ---------------- attention v8: cp.async pipelined, ldmatrix.trans PV --------
#define ASW 36
#define W_QW 0
#define W_QR 2304
#define W_K0 4608
#define W_K1 6912
#define W_V0 9216
#define W_V1 11520
#define W_R0 13824
#define W_R1 16128
#define W_BDR 18432
__global__ __launch_bounds__(256, 1) void k_attn8(const float* __restrict__ rwb,
                                                  const float* __restrict__ rrb)
{
    extern __shared__ uint32_t smu[];
    float* BDR = (float*)(smu + W_BDR);

    const int i0 = (gridDim.x - 1 - blockIdx.x) * 64;
    const int bn = blockIdx.y;
    const int b = bn >> 3, n = bn & 7;
    const int tid = threadIdx.x;
    const int warp = tid >> 5, lane = tid & 31;
    const int wm = warp & 3, wn = warp >> 2;
    const int g = lane >> 2, tg = lane & 3;
    const int quad = lane >> 3;

    const uint32_t smb = (uint32_t)__cvta_generic_to_shared(smu);
    const uint32_t aoff  = (uint32_t)((wm*16 + (lane & 15))*ASW + (lane >> 4)*4)*4;
    const uint32_t bpat  = (uint32_t)((((quad & 2)*4) + (lane & 7))*ASW + (quad & 1)*4)*4;
    const uint32_t boff  = bpat + (uint32_t)(wn*32)*ASW*4;
    const uint32_t tvpat = (uint32_t)(((quad & 1)*8 + (lane & 7))*ASW + (quad >> 1)*4)*4;

    const int il0 = wm*16 + g;
    const int il1 = il0 + 8;
    const int jjb0 = 960 - i0;
    const int ntiles = i0/64 + 17;

    // ---- staging helpers ----
    auto stage_kv = [&](int buf, int j0c) {
        const uint32_t kb = smb + (uint32_t)(buf ? W_K1 : W_K0)*4;
        const uint32_t vb = smb + (uint32_t)(buf ? W_V1 : W_V0)*4;
        #pragma unroll
        for (int e0 = 0; e0 < 2; e0++) {
            int e = tid + e0*256;
            int jl = e >> 3, w4 = (e & 7) * 4;
            size_t wi = ((size_t)(j0c + jl)*(BSZ*DM) + b*DM + n*DH)/2 + w4;
            uint32_t so = (uint32_t)(jl*ASW + w4)*4;
            cpa16(kb + so, &g_k[wi]);
            cpa16(vb + so, &g_v[wi]);
        }
    };
    auto stage_rw = [&](int buf, int cb2) {
        const uint32_t rb = smb + (uint32_t)(buf ? W_R1 : W_R0)*4;
        #pragma unroll
        for (int e0 = 0; e0 < 2; e0++) {
            int e = tid + e0*256;
            int l = e >> 3, w4 = (e & 7) * 4;
            int jj = cb2 + l;
            int ok = (jj < KLEN);
            int jc = ok ? jj : (KLEN - 1);
            cpa16z(rb + (uint32_t)(l*ASW + w4)*4,
                   &g_rkh[((size_t)jc*DM + n*DH)/2 + w4], ok);
        }
    };
    auto bd_pass = [&](int rbuf, int cb2) {
        const uint32_t rwo = smb + (uint32_t)(rbuf ? W_R1 : W_R0)*4;
        const int s0 = cb2 & 127;
        float pc[4][4];
        #pragma unroll
        for (int nf = 0; nf < 4; nf++)
            #pragma unroll
            for (int q = 0; q < 4; q++) pc[nf][q] = 0.f;
        #pragma unroll
        for (int k0 = 0; k0 < 4; k0++) {
            uint32_t a0, a1, a2, a3, p0, p1, p2, p3, q0, q1, q2, q3;
            ldsm4(a0, a1, a2, a3, smb + W_QR*4 + aoff + k0*32);
            ldsm4(p0, p1, p2, p3, rwo + boff + k0*32);
            ldsm4(q0, q1, q2, q3, rwo + boff + 16*ASW*4 + k0*32);
            mma_bf16(pc[0][0], pc[0][1], pc[0][2], pc[0][3], a0, a1, a2, a3, p0, p1);
            mma_bf16(pc[1][0], pc[1][1], pc[1][2], pc[1][3], a0, a1, a2, a3, p2, p3);
            mma_bf16(pc[2][0], pc[2][1], pc[2][2], pc[2][3], a0, a1, a2, a3, q0, q1);
            mma_bf16(pc[3][0], pc[3][1], pc[3][2], pc[3][3], a0, a1, a2, a3, q2, q3);
        }
        #pragma unroll
        for (int nf = 0; nf < 4; nf++) {
            int cc = s0 + wn*32 + nf*8 + 2*tg;
            *(float2*)&BDR[il0*132 + cc] = make_float2(pc[nf][0], pc[nf][1]);
            *(float2*)&BDR[il1*132 + cc] = make_float2(pc[nf][2], pc[nf][3]);
        }
    };

    // ---- preamble: prefetch tile 0 + both initial rel chunks ----
    stage_kv(0, 0);
    stage_rw(0, jjb0);
    stage_rw(1, jjb0 + 64);
    CP_COMMIT();

    // Q (+biases) staged via normal LDG/STS, overlapping the cp.asyncs
    for (int e = tid; e < 64*16; e += 256) {
        int ii = e >> 4, d4 = (e & 15) * 4;
        size_t wi = ((size_t)(i0+ii)*(BSZ*DM) + b*DM + n*DH + d4) / 2;
        uint2 qv = *(const uint2*)&g_q[wi];
        float q0 = bl(qv.x), q1 = bh(qv.x), q2 = bl(qv.y), q3 = bh(qv.y);
        float4 wv = *(const float4*)&rwb[n*DH + d4];
        float4 rv = *(const float4*)&rrb[n*DH + d4];
        smu[W_QW + ii*ASW + d4/2]     = pk(q0 + wv.x, q1 + wv.y);
        smu[W_QW + ii*ASW + d4/2 + 1] = pk(q2 + wv.z, q3 + wv.w);
        smu[W_QR + ii*ASW + d4/2]     = pk(q0 + rv.x, q1 + rv.y);
        smu[W_QR + ii*ASW + d4/2 + 1] = pk(q2 + rv.z, q3 + rv.w);
    }
    CP_WAIT0();
    __syncthreads();

    // BD for chunk c0 (visible to tile0 softmax via tile0's mid-sync)
    bd_pass(0, jjb0);

    float oacc[8][4];
    #pragma unroll
    for (int nf = 0; nf < 8; nf++)
        #pragma unroll
        for (int q = 0; q < 4; q++) oacc[nf][q] = 0.f;
    float l0 = 0.f, l1 = 0.f;

    for (int t = 0; t < ntiles; t++) {
        const int kvb = t & 1;
        const int j0 = t * 64;
        const int jjb = j0 - i0 + 960;

        // prefetch next tile (K/V) and rel chunk c_{t+2}
        if (t + 1 < ntiles) stage_kv(kvb ^ 1, j0 + 64);
        stage_rw(kvb, jjb0 + 64*(t + 2));
        CP_COMMIT();

        // ---- AC from KS[kvb] -> registers ----
        const uint32_t kso = smb + (uint32_t)(kvb ? W_K1 : W_K0)*4;
        float sc[4][4];
        #pragma unroll
        for (int nf = 0; nf < 4; nf++)
            #pragma unroll
            for (int q = 0; q < 4; q++) sc[nf][q] = 0.f;
        #pragma unroll
        for (int k0 = 0; k0 < 4; k0++) {
            uint32_t a0, a1, a2, a3, p0, p1, p2, p3, q0, q1, q2, q3;
            ldsm4(a0, a1, a2, a3, smb + W_QW*4 + aoff + k0*32);
            ldsm4(p0, p1, p2, p3, kso + boff + k0*32);
            ldsm4(q0, q1, q2, q3, kso + boff + 16*ASW*4 + k0*32);
            mma_bf16(sc[0][0], sc[0][1], sc[0][2], sc[0][3], a0, a1, a2, a3, p0, p1);
            mma_bf16(sc[1][0], sc[1][1], sc[1][2], sc[1][3], a0, a1, a2, a3, p2, p3);
            mma_bf16(sc[2][0], sc[2][1], sc[2][2], sc[2][3], a0, a1, a2, a3, q0, q1);
            mma_bf16(sc[3][0], sc[3][1], sc[3][2], sc[3][3], a0, a1, a2, a3, q2, q3);
        }

        // ---- BD chunk c_{t+1} from RW[(t+1)&1] -> ring ----
        bd_pass(kvb ^ 1, jjb0 + 64*(t + 1));
        __syncthreads();

        // ---- softmax in registers ----
        const int jjb2 = jjb + 63;
        uint32_t a_lo[4], a_hi[4];
        #pragma unroll
        for (int nf = 0; nf < 4; nf++) {
            int jl = wn*32 + nf*8 + 2*tg;
            int jg = j0 + jl;
            int s00 = (jjb2 + jl - il0) & 127;
            int s01 = (jjb2 + jl + 1 - il0) & 127;
            int s10 = (jjb2 + jl - il1) & 127;
            int s11 = (jjb2 + jl + 1 - il1) & 127;
            float p00 = 0.f, p01 = 0.f, p10 = 0.f, p11 = 0.f;
            if (jg <= i0 + il0 + MEMLEN)
                p00 = exp2_fast((sc[nf][0] + BDR[il0*132 + s00]) * 0.18033688f);
            if (jg + 1 <= i0 + il0 + MEMLEN)
                p01 = exp2_fast((sc[nf][1] + BDR[il0*132 + s01]) * 0.18033688f);
            if (jg <= i0 + il1 + MEMLEN)
                p10 = exp2_fast((sc[nf][2] + BDR[il1*132 + s10]) * 0.18033688f);
            if (jg + 1 <= i0 + il1 + MEMLEN)
                p11 = exp2_fast((sc[nf][3] + BDR[il1*132 + s11]) * 0.18033688f);
            l0 += p00 + p01;
            l1 += p10 + p11;
            a_lo[nf] = pk(p00, p01);
            a_hi[nf] = pk(p10, p11);
        }

        // ---- PV from VS[kvb] via ldmatrix.trans ----
        const uint32_t vso = smb + (uint32_t)(kvb ? W_V1 : W_V0)*4;
        #pragma unroll
        for (int k0 = 0; k0 < 2; k0++) {
            uint32_t a0 = a_lo[2*k0], a1 = a_hi[2*k0];
            uint32_t a2 = a_lo[2*k0+1], a3 = a_hi[2*k0+1];
            uint32_t jbase = (uint32_t)((wn*32 + k0*16)*ASW)*4;
            #pragma unroll
            for (int dd = 0; dd < 4; dd++) {
                uint32_t b0, b1, b2, b3;
                ldsm4t(b0, b1, b2, b3, vso + tvpat + jbase + (uint32_t)(dd*8)*4);
                mma_bf16(oacc[dd*2][0], oacc[dd*2][1], oacc[dd*2][2], oacc[dd*2][3],
                         a0, a1, a2, a3, b0, b1);
                mma_bf16(oacc[dd*2+1][0], oacc[dd*2+1][1], oacc[dd*2+1][2], oacc[dd*2+1][3],
                         a0, a1, a2, a3, b2, b3);
            }
        }

        CP_WAIT0();
        __syncthreads();
    }

    // ---- merge wn halves ----
    l0 += __shfl_xor_sync(0xffffffffu, l0, 1);
    l0 += __shfl_xor_sync(0xffffffffu, l0, 2);
    l1 += __shfl_xor_sync(0xffffffffu, l1, 1);
    l1 += __shfl_xor_sync(0xffffffffu, l1, 2);
    float* obuf = BDR;
    float* lbuf = BDR + 4*16*68;
    if (wn == 1) {
        #pragma unroll
        for (int nf = 0; nf < 8; nf++) {
            int d = nf*8 + 2*tg;
            *(float2*)&obuf[il0*68 + d] = make_float2(oacc[nf][0], oacc[nf][1]);
            *(float2*)&obuf[il1*68 + d] = make_float2(oacc[nf][2], oacc[nf][3]);
        }
        if (tg == 0) { lbuf[il0] = l0; lbuf[il1] = l1; }
    }
    __syncthreads();
    if (wn == 0) {
        float inv0 = 1.f / (l0 + lbuf[il0]);
        float inv1 = 1.f / (l1 + lbuf[il1]);
        #pragma unroll
        for (int nf = 0; nf < 8; nf++) {
            int d = nf*8 + 2*tg;
            float2 o0 = *(float2*)&obuf[il0*68 + d];
            float2 o1 = *(float2*)&obuf[il1*68 + d];
            *(float2*)&g_av[(size_t)(i0+il0)*(BSZ*DM) + b*DM + n*DH + d] =
                make_float2((oacc[nf][0]+o0.x)*inv0, (oacc[nf][1]+o0.y)*inv0);
            *(float2*)&g_av[(size_t)(i0+il1)*(BSZ*DM) + b*DM + n*DH + d] =
                make_float2((oacc[nf][2]+o1.x)*inv1, (oacc[nf][3]+o1.y)*inv1);
        }
    }
}

// ---------------- residual + layernorm: warp per row -------------------------
__global__ __launch_bounds__(256) void k_ln2(const float* __restrict__ w,
                                             const float* __restrict__ g,
                                             const float* __restrict__ be,
                                             float* __restrict__ out)
{
    int row = blockIdx.x * 8 + (threadIdx.x >> 5);
    int lane = threadIdx.x & 31;
    const float* wr = w    + (size_t)row * DM;
    const float* ar = g_ao + (size_t)row * DM;

    float4 x[4];
    float s = 0.f;
    #pragma unroll
    for (int c = 0; c < 4; c++) {
        int idx = c*128 + lane*4;
        float4 a = *(const float4*)&wr[idx];
        float4 o = *(const float4*)&ar[idx];
        x[c] = make_float4(a.x+o.x, a.y+o.y, a.z+o.z, a.w+o.w);
        s += x[c].x + x[c].y + x[c].z + x[c].w;
    }
    #pragma unroll
    for (int m = 16; m > 0; m >>= 1) s += __shfl_xor_sync(0xffffffffu, s, m);
    float mu = s * (1.f / DM);
    float v = 0.f;
    #pragma unroll
    for (int c = 0; c < 4; c++) {
        float dx = x[c].x - mu, dy = x[c].y - mu, dz = x[c].z - mu, dw = x[c].w - mu;
        x[c] = make_float4(dx, dy, dz, dw);
        v += dx*dx + dy*dy + dz*dz + dw*dw;
    }
    #pragma unroll
    for (int m = 16; m > 0; m >>= 1) v += __shfl_xor_sync(0xffffffffu, v, m);
    float rs = rsqrtf(v * (1.f / DM) + 1e-5f);
    #pragma unroll
    for (int c = 0; c < 4; c++) {
        int idx = c*128 + lane*4;
        float4 gg = *(const float4*)&g[idx];
        float4 bb = *(const float4*)&be[idx];
        float4 r = make_float4(x[c].x*rs*gg.x + bb.x, x[c].y*rs*gg.y + bb.y,
                               x[c].z*rs*gg.z + bb.z, x[c].w*rs*gg.w + bb.w);
        *(float4*)&out[(size_t)row*DM + idx] = r;
    }
}

// ---------------- launcher ---------------------------------------------------
extern "C" void kernel_launch(void* const* d_in, const int* in_sizes, int n_in,
                              void* d_out, int out_size)
{
    (void)in_sizes; (void)n_in; (void)out_size;
    const float* w    = (const float*)d_in[0];
    const float* r    = (const float*)d_in[1];
    const float* mems = (const float*)d_in[2];
    const float* rwb  = (const float*)d_in[3];
    const float* rrb  = (const float*)d_in[4];
    const float* qkvW = (const float*)d_in[5];
    const float* rW   = (const float*)d_in[6];
    const float* cqw  = (const float*)d_in[7];
    const float* cqb  = (const float*)d_in[8];
    const float* ckw  = (const float*)d_in[9];
    const float* ckb  = (const float*)d_in[10];
    const float* cvw  = (const float*)d_in[11];
    const float* cvb  = (const float*)d_in[12];
    const float* oW   = (const float*)d_in[13];
    const float* lng  = (const float*)d_in[14];
    const float* lnb  = (const float*)d_in[15];
    float* out = (float*)d_out;

    void *p_qkvh, *p_rkh;
    float *p_av, *p_ao;
    cudaGetSymbolAddress(&p_qkvh, g_qkvh);
    cudaGetSymbolAddress(&p_rkh,  g_rkh);
    cudaGetSymbolAddress((void**)&p_av,  g_av);
    cudaGetSymbolAddress((void**)&p_ao,  g_ao);

    dim3 b256(256);

    k_prepw<<<21, b256>>>(cqw, ckw, cvw);

    mm_bf16<<<dim3(QKV/128, (KLEN*BSZ)/128), b256>>>(mems, w, MEMLEN*BSZ,
                                                     qkvW, p_qkvh, QKV, DM, 1);
    mm_bf16<<<dim3(DM/128, KLEN/128), b256>>>(r, r, 1<<30, rW, p_rkh, DM, DM, 1);

    int csm = (134*CSW + 7*64*CSW) * 4;
    cudaFuncSetAttribute(k_conv5, cudaFuncAttributeMaxDynamicSharedMemorySize, csm);
    k_conv5<<<dim3(40, NH*BSZ), b256, csm>>>(cqb, ckb, cvb);

    int asm_ = (W_BDR + 64*132) * 4;
    cudaFuncSetAttribute(k_attn8, cudaFuncAttributeMaxDynamicSharedMemorySize, asm_);
    k_attn8<<<dim3(QLEN/64, BSZ*NH), b256, asm_>>>(rwb, rrb);

    mm_bf16<<<dim3(DM/128, (QLEN*BSZ)/128), b256>>>(p_av, p_av, 1<<30, oW, p_ao,
                                                    DM, DM, 0);
    k_ln2<<<(QLEN*BSZ)/8, b256>>>(w, lng, lnb, out);
}

// round 10
// speedup vs baseline: 8.3503x; 1.0785x over previous
#include <cuda_runtime.h>
#include <cuda_bf16.h>
#include <math.h>
#include <stdint.h>

#define QLEN 1024
#define KLEN 2048
#define MEMLEN 1024
#define BSZ 4
#define NH 8
#define DH 64
#define DM 512
#define QKV (3*DM)

__device__ uint32_t g_qkvh[(size_t)KLEN*BSZ*QKV/2]; // bf16 pairs (jk, b, 1536)
__device__ uint32_t g_rkh [(size_t)KLEN*DM/2];      // bf16 pairs (jj, n*64+d)
__device__ uint32_t g_q  [(size_t)QLEN*BSZ*DM/2];
__device__ uint32_t g_k  [(size_t)KLEN*BSZ*DM/2];
__device__ uint32_t g_v  [(size_t)KLEN*BSZ*DM/2];
__device__ uint32_t g_avh[(size_t)QLEN*BSZ*DM/2];   // attention out, bf16
__device__ float    g_ao [(size_t)QLEN*BSZ*DM];
__device__ uint32_t g_wt[3*7*64*32];
// bf16 copies of GEMM operands
__device__ uint32_t g_xh [(size_t)KLEN*BSZ*DM/2];   // [mems; w]
__device__ uint32_t g_wh [(size_t)QKV*DM/2];        // qkvW
__device__ uint32_t g_rh [(size_t)KLEN*DM/2];       // r
__device__ uint32_t g_rWh[(size_t)DM*DM/2];         // rW
__device__ uint32_t g_oWh[(size_t)DM*DM/2];         // oW

__device__ __forceinline__ uint32_t pk(float x, float y) {
    __nv_bfloat162 t = __floats2bfloat162_rn(x, y);
    return *(uint32_t*)&t;
}
__device__ __forceinline__ float bl(uint32_t w) {
    __nv_bfloat16 h = *(__nv_bfloat16*)&w;
    return __bfloat162float(h);
}
__device__ __forceinline__ float bh(uint32_t w) {
    uint16_t u = (uint16_t)(w >> 16);
    __nv_bfloat16 h = *(__nv_bfloat16*)&u;
    return __bfloat162float(h);
}

__device__ __forceinline__ void mma_bf16(float& c0, float& c1, float& c2, float& c3,
                                         uint32_t a0, uint32_t a1, uint32_t a2, uint32_t a3,
                                         uint32_t b0, uint32_t b1)
{
    asm volatile("mma.sync.aligned.m16n8k16.row.col.f32.bf16.bf16.f32 "
                 "{%0,%1,%2,%3},{%4,%5,%6,%7},{%8,%9},{%0,%1,%2,%3};\n"
                 : "+f"(c0), "+f"(c1), "+f"(c2), "+f"(c3)
                 : "r"(a0), "r"(a1), "r"(a2), "r"(a3), "r"(b0), "r"(b1));
}

__device__ __forceinline__ void ldsm4(uint32_t& r0, uint32_t& r1, uint32_t& r2, uint32_t& r3,
                                      uint32_t addr)
{
    asm volatile("ldmatrix.sync.aligned.m8n8.x4.shared.b16 {%0,%1,%2,%3}, [%4];"
                 : "=r"(r0), "=r"(r1), "=r"(r2), "=r"(r3) : "r"(addr));
}
__device__ __forceinline__ void ldsm4t(uint32_t& r0, uint32_t& r1, uint32_t& r2, uint32_t& r3,
                                       uint32_t addr)
{
    asm volatile("ldmatrix.sync.aligned.m8n8.x4.trans.shared.b16 {%0,%1,%2,%3}, [%4];"
                 : "=r"(r0), "=r"(r1), "=r"(r2), "=r"(r3) : "r"(addr));
}

__device__ __forceinline__ void cpa16(uint32_t saddr, const void* gaddr) {
    asm volatile("cp.async.cg.shared.global [%0], [%1], 16;" :: "r"(saddr), "l"(gaddr));
}
__device__ __forceinline__ void cpa16z(uint32_t saddr, const void* gaddr, int ok) {
    int sz = ok ? 16 : 0;
    asm volatile("cp.async.cg.shared.global [%0], [%1], 16, %2;"
                 :: "r"(saddr), "l"(gaddr), "r"(sz));
}
#define CP_COMMIT() asm volatile("cp.async.commit_group;")
#define CP_WAIT0()  asm volatile("cp.async.wait_group 0;")

__device__ __forceinline__ float exp2_fast(float y) {
    y = fmaxf(y, -100.f);
    float z = __fadd_rn(y, 12582912.f);
    float n = __fsub_rn(z, 12582912.f);
    float f = __fsub_rn(y, n);
    float r = 0.0096181291f;
    r = fmaf(r, f, 0.055504109f);
    r = fmaf(r, f, 0.24022651f);
    r = fmaf(r, f, 0.69314718f);
    r = fmaf(r, f, 1.0f);
    int e = __float_as_int(z);
    float s = __int_as_float((e - 1262485377) << 23);
    return r * s;
}

// ---------------- fp32 -> bf16-pair convert ----------------------------------
__global__ void k_cvt(const float* __restrict__ src, uint32_t* __restrict__ dst, int nw)
{
    int idx = blockIdx.x * blockDim.x + threadIdx.x;
    int stride = gridDim.x * blockDim.x;
    for (int i = idx; i < nw; i += stride) {
        float2 v = *(const float2*)&src[2*i];
        dst[i] = pk(v.x, v.y);
    }
}

// ---------------- BF16 GEMM (round-8 structure, bf16-word inputs) ------------
// C[M,N] = A[M,K] @ B[N,K]^T. A/B are bf16-pair word pointers, Kw = K/2.
#define GSW 12
__global__ __launch_bounds__(256, 2) void mm_h(const uint32_t* __restrict__ A0,
                                               const uint32_t* __restrict__ A1,
                                               int M1,
                                               const uint32_t* __restrict__ B,
                                               void* __restrict__ Cout,
                                               int N, int K, int pack)
{
    __shared__ uint32_t As[2][128*GSW];
    __shared__ uint32_t Bs[2][128*GSW];
    const int tid = threadIdx.x;
    const int warp = tid >> 5, lane = tid & 31;
    const int wm = warp & 3, wn = warp >> 2;
    const int g = lane >> 2, tg = lane & 3;
    const int m0 = blockIdx.y * 128, n0 = blockIdx.x * 128;
    const int Kw = K / 2;

    const uint32_t* Abase = (m0 < M1) ? (A0 + (size_t)m0 * Kw)
                                      : (A1 + (size_t)(m0 - M1) * Kw);

    float c[2][8][4];
    #pragma unroll
    for (int mt = 0; mt < 2; mt++)
        #pragma unroll
        for (int nt = 0; nt < 8; nt++)
            #pragma unroll
            for (int q = 0; q < 4; q++) c[mt][nt][q] = 0.f;

    const int lr = tid >> 1;        // row 0..127
    const int lh = tid & 1;         // 4-word half of the 8-word (BK=16) chunk
    const uint32_t* Ap = Abase + (size_t)lr * Kw + lh * 4;
    const uint32_t* Bp = B + (size_t)(n0 + lr) * Kw + lh * 4;

    uint4 ra = *(const uint4*)(Ap);
    uint4 rb = *(const uint4*)(Bp);
    *(uint4*)&As[0][lr*GSW + lh*4] = ra;
    *(uint4*)&Bs[0][lr*GSW + lh*4] = rb;

    int buf = 0;
    for (int kw = 0; kw < Kw; kw += 8) {
        const bool more = (kw + 8) < Kw;
        if (more) {
            ra = *(const uint4*)(Ap + kw + 8);
            rb = *(const uint4*)(Bp + kw + 8);
        }
        __syncthreads();
        {
            uint32_t af[2][4], bf[8][2];
            #pragma unroll
            for (int mt = 0; mt < 2; mt++) {
                int mb = wm * 32 + mt * 16;
                af[mt][0] = As[buf][(mb + g)*GSW + tg];
                af[mt][1] = As[buf][(mb + g + 8)*GSW + tg];
                af[mt][2] = As[buf][(mb + g)*GSW + tg + 4];
                af[mt][3] = As[buf][(mb + g + 8)*GSW + tg + 4];
            }
            #pragma unroll
            for (int nt = 0; nt < 8; nt++) {
                int nb = wn * 64 + nt * 8;
                bf[nt][0] = Bs[buf][(nb + g)*GSW + tg];
                bf[nt][1] = Bs[buf][(nb + g)*GSW + tg + 4];
            }
            #pragma unroll
            for (int mt = 0; mt < 2; mt++)
                #pragma unroll
                for (int nt = 0; nt < 8; nt++)
                    mma_bf16(c[mt][nt][0], c[mt][nt][1], c[mt][nt][2], c[mt][nt][3],
                             af[mt][0], af[mt][1], af[mt][2], af[mt][3],
                             bf[nt][0], bf[nt][1]);
        }
        if (more) {
            int nb = buf ^ 1;
            *(uint4*)&As[nb][lr*GSW + lh*4] = ra;
            *(uint4*)&Bs[nb][lr*GSW + lh*4] = rb;
        }
        buf ^= 1;
    }

    #pragma unroll
    for (int mt = 0; mt < 2; mt++) {
        int row0 = m0 + wm * 32 + mt * 16 + g;
        #pragma unroll
        for (int nt = 0; nt < 8; nt++) {
            int col = n0 + wn * 64 + nt * 8 + tg * 2;
            if (pack) {
                uint32_t* Cp = (uint32_t*)Cout;
                Cp[((size_t)row0 * N + col)/2]       = pk(c[mt][nt][0], c[mt][nt][1]);
                Cp[((size_t)(row0 + 8) * N + col)/2] = pk(c[mt][nt][2], c[mt][nt][3]);
            } else {
                float* C = (float*)Cout;
                *(float2*)&C[(size_t)row0 * N + col]       = make_float2(c[mt][nt][0], c[mt][nt][1]);
                *(float2*)&C[(size_t)(row0 + 8) * N + col] = make_float2(c[mt][nt][2], c[mt][nt][3]);
            }
        }
    }
}

// ---------------- weight prep ------------------------------------------------
__global__ void k_prepw(const float* __restrict__ cq,
                        const float* __restrict__ ck,
                        const float* __restrict__ cv)
{
    int idx = blockIdx.x;
    int c = idx / 7, tap = idx % 7;
    const float* src = (c == 0) ? cq : (c == 1) ? ck : cv;
    for (int e = threadIdx.x; e < 2048; e += 256) {
        int oc = e >> 5, icw = e & 31;
        float w0 = src[(oc*64 + 2*icw    )*7 + tap];
        float w1 = src[(oc*64 + 2*icw + 1)*7 + tap];
        g_wt[((c*7 + tap)*64 + oc)*32 + icw] = pk(w0, w1);
    }
}

// ---------------- fused conv via bf16 MMA + ldmatrix + cp.async --------------
#define CSW 36
#define OFF_WS (134*CSW*4)
__global__ __launch_bounds__(256, 2) void k_conv5(const float* __restrict__ cqb,
                                                  const float* __restrict__ ckb,
                                                  const float* __restrict__ cvb)
{
    extern __shared__ uint32_t cs[];
    const int bx = blockIdx.x;
    int c, t0, len, posoff, chanoff;
    const float* cb;
    uint32_t* outp;
    if (bx < 8)       { c = 0; t0 = bx*128;      len = QLEN; posoff = MEMLEN; chanoff = 0;    cb = cqb; outp = g_q; }
    else if (bx < 24) { c = 1; t0 = (bx-8)*128;  len = KLEN; posoff = 0;      chanoff = DM;   cb = ckb; outp = g_k; }
    else              { c = 2; t0 = (bx-24)*128; len = KLEN; posoff = 0;      chanoff = 2*DM; cb = cvb; outp = g_v; }
    const int nb = blockIdx.y;
    const int n = nb >> 2, b = nb & 3;
    const int tid = threadIdx.x;
    const int warp = tid >> 5, lane = tid & 31;
    const int wm = warp;
    const int g = lane >> 2, tg = lane & 3;
    const int quad = lane >> 3;
    const uint32_t smbC = (uint32_t)__cvta_generic_to_shared(cs);

    for (int e = tid; e < 134*8; e += 256) {
        int u = e >> 3, w4 = (e & 7) * 4;
        int pos = t0 + u - 3;
        int ok = (pos >= 0 && pos < len);
        int pc = ok ? pos : 0;
        cpa16z(smbC + (uint32_t)(u*CSW + w4)*4,
               &g_qkvh[((size_t)(pc + posoff)*(BSZ*QKV) + b*QKV + chanoff + n*DH)/2 + w4], ok);
    }
    {
        const uint32_t* src = g_wt + c*7*64*32;
        for (int e = tid; e < 3584; e += 256) {
            int s4 = e * 4;
            int to = s4 >> 5, icw = s4 & 31;
            cpa16(smbC + OFF_WS + (uint32_t)(to*CSW + icw)*4, &src[s4]);
        }
    }
    CP_COMMIT();
    CP_WAIT0();
    __syncthreads();

    float acc[8][4];
    #pragma unroll
    for (int nf = 0; nf < 8; nf++)
        #pragma unroll
        for (int q = 0; q < 4; q++) acc[nf][q] = 0.f;

    const uint32_t bpat = (uint32_t)((((quad & 2)*4) + (lane & 7))*CSW + (quad & 1)*4)*4;

    #pragma unroll
    for (int tap = 0; tap < 7; tap++) {
        const uint32_t apat = (uint32_t)((wm*16 + (lane & 15) + tap)*CSW + (lane >> 4)*4)*4;
        #pragma unroll
        for (int k0 = 0; k0 < 4; k0++) {
            uint32_t a0, a1, a2, a3;
            ldsm4(a0, a1, a2, a3, smbC + apat + k0*32);
            #pragma unroll
            for (int nf2 = 0; nf2 < 4; nf2++) {
                uint32_t b0, b1, b2, b3;
                ldsm4(b0, b1, b2, b3,
                      smbC + OFF_WS + bpat + (uint32_t)((tap*64 + nf2*16)*CSW)*4 + k0*32);
                mma_bf16(acc[nf2*2][0], acc[nf2*2][1], acc[nf2*2][2], acc[nf2*2][3],
                         a0, a1, a2, a3, b0, b1);
                mma_bf16(acc[nf2*2+1][0], acc[nf2*2+1][1], acc[nf2*2+1][2], acc[nf2*2+1][3],
                         a0, a1, a2, a3, b2, b3);
            }
        }
    }

    #pragma unroll
    for (int nf = 0; nf < 8; nf++) {
        int oc = nf*8 + 2*tg;
        float2 bb = *(const float2*)&cb[oc];
        int row = t0 + wm*16 + g;
        size_t w0 = ((size_t)row*(BSZ*DM) + b*DM)/2 + n*32 + nf*4 + tg;
        size_t w1 = ((size_t)(row+8)*(BSZ*DM) + b*DM)/2 + n*32 + nf*4 + tg;
        outp[w0] = pk(acc[nf][0] + bb.x, acc[nf][1] + bb.y);
        outp[w1] = pk(acc[nf][2] + bb.x, acc[nf][3] + bb.y);
    }
}

// ---------------- attention v8: cp.async pipelined, ldmatrix.trans PV --------
#define ASW 36
#define W_QW 0
#define W_QR 2304
#define W_K0 4608
#define W_K1 6912
#define W_V0 9216
#define W_V1 11520
#define W_R0 13824
#define W_R1 16128
#define W_BDR 18432
__global__ __launch_bounds__(256, 1) void k_attn8(const float* __restrict__ rwb,
                                                  const float* __restrict__ rrb)
{
    extern __shared__ uint32_t smu[];
    float* BDR = (float*)(smu + W_BDR);

    const int i0 = (gridDim.x - 1 - blockIdx.x) * 64;
    const int bn = blockIdx.y;
    const int b = bn >> 3, n = bn & 7;
    const int tid = threadIdx.x;
    const int warp = tid >> 5, lane = tid & 31;
    const int wm = warp & 3, wn = warp >> 2;
    const int g = lane >> 2, tg = lane & 3;
    const int quad = lane >> 3;

    const uint32_t smb = (uint32_t)__cvta_generic_to_shared(smu);
    const uint32_t aoff  = (uint32_t)((wm*16 + (lane & 15))*ASW + (lane >> 4)*4)*4;
    const uint32_t bpat  = (uint32_t)((((quad & 2)*4) + (lane & 7))*ASW + (quad & 1)*4)*4;
    const uint32_t boff  = bpat + (uint32_t)(wn*32)*ASW*4;
    const uint32_t tvpat = (uint32_t)(((quad & 1)*8 + (lane & 7))*ASW + (quad >> 1)*4)*4;

    const int il0 = wm*16 + g;
    const int il1 = il0 + 8;
    const int jjb0 = 960 - i0;
    const int ntiles = i0/64 + 17;

    auto stage_kv = [&](int buf, int j0c) {
        const uint32_t kb = smb + (uint32_t)(buf ? W_K1 : W_K0)*4;
        const uint32_t vb = smb + (uint32_t)(buf ? W_V1 : W_V0)*4;
        #pragma unroll
        for (int e0 = 0; e0 < 2; e0++) {
            int e = tid + e0*256;
            int jl = e >> 3, w4 = (e & 7) * 4;
            size_t wi = ((size_t)(j0c + jl)*(BSZ*DM) + b*DM + n*DH)/2 + w4;
            uint32_t so = (uint32_t)(jl*ASW + w4)*4;
            cpa16(kb + so, &g_k[wi]);
            cpa16(vb + so, &g_v[wi]);
        }
    };
    auto stage_rw = [&](int buf, int cb2) {
        const uint32_t rb = smb + (uint32_t)(buf ? W_R1 : W_R0)*4;
        #pragma unroll
        for (int e0 = 0; e0 < 2; e0++) {
            int e = tid + e0*256;
            int l = e >> 3, w4 = (e & 7) * 4;
            int jj = cb2 + l;
            int ok = (jj < KLEN);
            int jc = ok ? jj : (KLEN - 1);
            cpa16z(rb + (uint32_t)(l*ASW + w4)*4,
                   &g_rkh[((size_t)jc*DM + n*DH)/2 + w4], ok);
        }
    };
    auto bd_pass = [&](int rbuf, int cb2) {
        const uint32_t rwo = smb + (uint32_t)(rbuf ? W_R1 : W_R0)*4;
        const int s0 = cb2 & 127;
        float pc[4][4];
        #pragma unroll
        for (int nf = 0; nf < 4; nf++)
            #pragma unroll
            for (int q = 0; q < 4; q++) pc[nf][q] = 0.f;
        #pragma unroll
        for (int k0 = 0; k0 < 4; k0++) {
            uint32_t a0, a1, a2, a3, p0, p1, p2, p3, q0, q1, q2, q3;
            ldsm4(a0, a1, a2, a3, smb + W_QR*4 + aoff + k0*32);
            ldsm4(p0, p1, p2, p3, rwo + boff + k0*32);
            ldsm4(q0, q1, q2, q3, rwo + boff + 16*ASW*4 + k0*32);
            mma_bf16(pc[0][0], pc[0][1], pc[0][2], pc[0][3], a0, a1, a2, a3, p0, p1);
            mma_bf16(pc[1][0], pc[1][1], pc[1][2], pc[1][3], a0, a1, a2, a3, p2, p3);
            mma_bf16(pc[2][0], pc[2][1], pc[2][2], pc[2][3], a0, a1, a2, a3, q0, q1);
            mma_bf16(pc[3][0], pc[3][1], pc[3][2], pc[3][3], a0, a1, a2, a3, q2, q3);
        }
        #pragma unroll
        for (int nf = 0; nf < 4; nf++) {
            int cc = s0 + wn*32 + nf*8 + 2*tg;
            *(float2*)&BDR[il0*132 + cc] = make_float2(pc[nf][0], pc[nf][1]);
            *(float2*)&BDR[il1*132 + cc] = make_float2(pc[nf][2], pc[nf][3]);
        }
    };

    stage_kv(0, 0);
    stage_rw(0, jjb0);
    stage_rw(1, jjb0 + 64);
    CP_COMMIT();

    for (int e = tid; e < 64*16; e += 256) {
        int ii = e >> 4, d4 = (e & 15) * 4;
        size_t wi = ((size_t)(i0+ii)*(BSZ*DM) + b*DM + n*DH + d4) / 2;
        uint2 qv = *(const uint2*)&g_q[wi];
        float q0 = bl(qv.x), q1 = bh(qv.x), q2 = bl(qv.y), q3 = bh(qv.y);
        float4 wv = *(const float4*)&rwb[n*DH + d4];
        float4 rv = *(const float4*)&rrb[n*DH + d4];
        smu[W_QW + ii*ASW + d4/2]     = pk(q0 + wv.x, q1 + wv.y);
        smu[W_QW + ii*ASW + d4/2 + 1] = pk(q2 + wv.z, q3 + wv.w);
        smu[W_QR + ii*ASW + d4/2]     = pk(q0 + rv.x, q1 + rv.y);
        smu[W_QR + ii*ASW + d4/2 + 1] = pk(q2 + rv.z, q3 + rv.w);
    }
    CP_WAIT0();
    __syncthreads();

    bd_pass(0, jjb0);

    float oacc[8][4];
    #pragma unroll
    for (int nf = 0; nf < 8; nf++)
        #pragma unroll
        for (int q = 0; q < 4; q++) oacc[nf][q] = 0.f;
    float l0 = 0.f, l1 = 0.f;

    for (int t = 0; t < ntiles; t++) {
        const int kvb = t & 1;
        const int j0 = t * 64;
        const int jjb = j0 - i0 + 960;

        if (t + 1 < ntiles) stage_kv(kvb ^ 1, j0 + 64);
        stage_rw(kvb, jjb0 + 64*(t + 2));
        CP_COMMIT();

        const uint32_t kso = smb + (uint32_t)(kvb ? W_K1 : W_K0)*4;
        float sc[4][4];
        #pragma unroll
        for (int nf = 0; nf < 4; nf++)
            #pragma unroll
            for (int q = 0; q < 4; q++) sc[nf][q] = 0.f;
        #pragma unroll
        for (int k0 = 0; k0 < 4; k0++) {
            uint32_t a0, a1, a2, a3, p0, p1, p2, p3, q0, q1, q2, q3;
            ldsm4(a0, a1, a2, a3, smb + W_QW*4 + aoff + k0*32);
            ldsm4(p0, p1, p2, p3, kso + boff + k0*32);
            ldsm4(q0, q1, q2, q3, kso + boff + 16*ASW*4 + k0*32);
            mma_bf16(sc[0][0], sc[0][1], sc[0][2], sc[0][3], a0, a1, a2, a3, p0, p1);
            mma_bf16(sc[1][0], sc[1][1], sc[1][2], sc[1][3], a0, a1, a2, a3, p2, p3);
            mma_bf16(sc[2][0], sc[2][1], sc[2][2], sc[2][3], a0, a1, a2, a3, q0, q1);
            mma_bf16(sc[3][0], sc[3][1], sc[3][2], sc[3][3], a0, a1, a2, a3, q2, q3);
        }

        bd_pass(kvb ^ 1, jjb0 + 64*(t + 1));
        __syncthreads();

        const int jjb2 = jjb + 63;
        uint32_t a_lo[4], a_hi[4];
        #pragma unroll
        for (int nf = 0; nf < 4; nf++) {
            int jl = wn*32 + nf*8 + 2*tg;
            int jg = j0 + jl;
            int s00 = (jjb2 + jl - il0) & 127;
            int s01 = (jjb2 + jl + 1 - il0) & 127;
            int s10 = (jjb2 + jl - il1) & 127;
            int s11 = (jjb2 + jl + 1 - il1) & 127;
            float p00 = 0.f, p01 = 0.f, p10 = 0.f, p11 = 0.f;
            if (jg <= i0 + il0 + MEMLEN)
                p00 = exp2_fast((sc[nf][0] + BDR[il0*132 + s00]) * 0.18033688f);
            if (jg + 1 <= i0 + il0 + MEMLEN)
                p01 = exp2_fast((sc[nf][1] + BDR[il0*132 + s01]) * 0.18033688f);
            if (jg <= i0 + il1 + MEMLEN)
                p10 = exp2_fast((sc[nf][2] + BDR[il1*132 + s10]) * 0.18033688f);
            if (jg + 1 <= i0 + il1 + MEMLEN)
                p11 = exp2_fast((sc[nf][3] + BDR[il1*132 + s11]) * 0.18033688f);
            l0 += p00 + p01;
            l1 += p10 + p11;
            a_lo[nf] = pk(p00, p01);
            a_hi[nf] = pk(p10, p11);
        }

        const uint32_t vso = smb + (uint32_t)(kvb ? W_V1 : W_V0)*4;
        #pragma unroll
        for (int k0 = 0; k0 < 2; k0++) {
            uint32_t a0 = a_lo[2*k0], a1 = a_hi[2*k0];
            uint32_t a2 = a_lo[2*k0+1], a3 = a_hi[2*k0+1];
            uint32_t jbase = (uint32_t)((wn*32 + k0*16)*ASW)*4;
            #pragma unroll
            for (int dd = 0; dd < 4; dd++) {
                uint32_t b0, b1, b2, b3;
                ldsm4t(b0, b1, b2, b3, vso + tvpat + jbase + (uint32_t)(dd*8)*4);
                mma_bf16(oacc[dd*2][0], oacc[dd*2][1], oacc[dd*2][2], oacc[dd*2][3],
                         a0, a1, a2, a3, b0, b1);
                mma_bf16(oacc[dd*2+1][0], oacc[dd*2+1][1], oacc[dd*2+1][2], oacc[dd*2+1][3],
                         a0, a1, a2, a3, b2, b3);
            }
        }

        CP_WAIT0();
        __syncthreads();
    }

    l0 += __shfl_xor_sync(0xffffffffu, l0, 1);
    l0 += __shfl_xor_sync(0xffffffffu, l0, 2);
    l1 += __shfl_xor_sync(0xffffffffu, l1, 1);
    l1 += __shfl_xor_sync(0xffffffffu, l1, 2);
    float* obuf = BDR;
    float* lbuf = BDR + 4*16*68;
    if (wn == 1) {
        #pragma unroll
        for (int nf = 0; nf < 8; nf++) {
            int d = nf*8 + 2*tg;
            *(float2*)&obuf[il0*68 + d] = make_float2(oacc[nf][0], oacc[nf][1]);
            *(float2*)&obuf[il1*68 + d] = make_float2(oacc[nf][2], oacc[nf][3]);
        }
        if (tg == 0) { lbuf[il0] = l0; lbuf[il1] = l1; }
    }
    __syncthreads();
    if (wn == 0) {
        float inv0 = 1.f / (l0 + lbuf[il0]);
        float inv1 = 1.f / (l1 + lbuf[il1]);
        #pragma unroll
        for (int nf = 0; nf < 8; nf++) {
            int d = nf*8 + 2*tg;
            float2 o0 = *(float2*)&obuf[il0*68 + d];
            float2 o1 = *(float2*)&obuf[il1*68 + d];
            g_avh[((size_t)(i0+il0)*(BSZ*DM) + b*DM + n*DH + d)/2] =
                pk((oacc[nf][0]+o0.x)*inv0, (oacc[nf][1]+o0.y)*inv0);
            g_avh[((size_t)(i0+il1)*(BSZ*DM) + b*DM + n*DH + d)/2] =
                pk((oacc[nf][2]+o1.x)*inv1, (oacc[nf][3]+o1.y)*inv1);
        }
    }
}

// ---------------- residual + layernorm: warp per row -------------------------
__global__ __launch_bounds__(256) void k_ln2(const float* __restrict__ w,
                                             const float* __restrict__ g,
                                             const float* __restrict__ be,
                                             float* __restrict__ out)
{
    int row = blockIdx.x * 8 + (threadIdx.x >> 5);
    int lane = threadIdx.x & 31;
    const float* wr = w    + (size_t)row * DM;
    const float* ar = g_ao + (size_t)row * DM;

    float4 x[4];
    float s = 0.f;
    #pragma unroll
    for (int c = 0; c < 4; c++) {
        int idx = c*128 + lane*4;
        float4 a = *(const float4*)&wr[idx];
        float4 o = *(const float4*)&ar[idx];
        x[c] = make_float4(a.x+o.x, a.y+o.y, a.z+o.z, a.w+o.w);
        s += x[c].x + x[c].y + x[c].z + x[c].w;
    }
    #pragma unroll
    for (int m = 16; m > 0; m >>= 1) s += __shfl_xor_sync(0xffffffffu, s, m);
    float mu = s * (1.f / DM);
    float v = 0.f;
    #pragma unroll
    for (int c = 0; c < 4; c++) {
        float dx = x[c].x - mu, dy = x[c].y - mu, dz = x[c].z - mu, dw = x[c].w - mu;
        x[c] = make_float4(dx, dy, dz, dw);
        v += dx*dx + dy*dy + dz*dz + dw*dw;
    }
    #pragma unroll
    for (int m = 16; m > 0; m >>= 1) v += __shfl_xor_sync(0xffffffffu, v, m);
    float rs = rsqrtf(v * (1.f / DM) + 1e-5f);
    #pragma unroll
    for (int c = 0; c < 4; c++) {
        int idx = c*128 + lane*4;
        float4 gg = *(const float4*)&g[idx];
        float4 bb = *(const float4*)&be[idx];
        float4 r = make_float4(x[c].x*rs*gg.x + bb.x, x[c].y*rs*gg.y + bb.y,
                               x[c].z*rs*gg.z + bb.z, x[c].w*rs*gg.w + bb.w);
        *(float4*)&out[(size_t)row*DM + idx] = r;
    }
}

// ---------------- launcher ---------------------------------------------------
extern "C" void kernel_launch(void* const* d_in, const int* in_sizes, int n_in,
                              void* d_out, int out_size)
{
    (void)in_sizes; (void)n_in; (void)out_size;
    const float* w    = (const float*)d_in[0];
    const float* r    = (const float*)d_in[1];
    const float* mems = (const float*)d_in[2];
    const float* rwb  = (const float*)d_in[3];
    const float* rrb  = (const float*)d_in[4];
    const float* qkvW = (const float*)d_in[5];
    const float* rW   = (const float*)d_in[6];
    const float* cqw  = (const float*)d_in[7];
    const float* cqb  = (const float*)d_in[8];
    const float* ckw  = (const float*)d_in[9];
    const float* ckb  = (const float*)d_in[10];
    const float* cvw  = (const float*)d_in[11];
    const float* cvb  = (const float*)d_in[12];
    const float* oW   = (const float*)d_in[13];
    const float* lng  = (const float*)d_in[14];
    const float* lnb  = (const float*)d_in[15];
    float* out = (float*)d_out;

    uint32_t *p_qkvh, *p_rkh, *p_xh, *p_wh, *p_rh, *p_rWh, *p_oWh, *p_avh;
    float *p_ao;
    cudaGetSymbolAddress((void**)&p_qkvh, g_qkvh);
    cudaGetSymbolAddress((void**)&p_rkh,  g_rkh);
    cudaGetSymbolAddress((void**)&p_xh,   g_xh);
    cudaGetSymbolAddress((void**)&p_wh,   g_wh);
    cudaGetSymbolAddress((void**)&p_rh,   g_rh);
    cudaGetSymbolAddress((void**)&p_rWh,  g_rWh);
    cudaGetSymbolAddress((void**)&p_oWh,  g_oWh);
    cudaGetSymbolAddress((void**)&p_avh,  g_avh);
    cudaGetSymbolAddress((void**)&p_ao,   g_ao);

    dim3 b256(256);

    // fp32 -> bf16 conversions + conv weight prep
    k_cvt<<<1024, b256>>>(mems, p_xh,                           MEMLEN*BSZ*DM/2);
    k_cvt<<<1024, b256>>>(w,    p_xh + (size_t)MEMLEN*BSZ*DM/2, QLEN*BSZ*DM/2);
    k_cvt<<<512,  b256>>>(qkvW, p_wh,  QKV*DM/2);
    k_cvt<<<512,  b256>>>(r,    p_rh,  KLEN*DM/2);
    k_cvt<<<256,  b256>>>(rW,   p_rWh, DM*DM/2);
    k_cvt<<<256,  b256>>>(oW,   p_oWh, DM*DM/2);
    k_prepw<<<21, b256>>>(cqw, ckw, cvw);

    // QKV projection over [mems; w] (bf16 in, bf16 out)
    mm_h<<<dim3(QKV/128, (KLEN*BSZ)/128), b256>>>(p_xh, p_xh, 1<<30,
                                                  p_wh, p_qkvh, QKV, DM, 1);
    // r @ r_W^T
    mm_h<<<dim3(DM/128, KLEN/128), b256>>>(p_rh, p_rh, 1<<30, p_rWh, p_rkh, DM, DM, 1);

    // fused convs
    int csm = (134*CSW + 7*64*CSW) * 4;
    cudaFuncSetAttribute(k_conv5, cudaFuncAttributeMaxDynamicSharedMemorySize, csm);
    k_conv5<<<dim3(40, NH*BSZ), b256, csm>>>(cqb, ckb, cvb);

    // attention
    int asm_ = (W_BDR + 64*132) * 4;
    cudaFuncSetAttribute(k_attn8, cudaFuncAttributeMaxDynamicSharedMemorySize, asm_);
    k_attn8<<<dim3(QLEN/64, BSZ*NH), b256, asm_>>>(rwb, rrb);

    // output projection (bf16 A, fp32 out) + residual layernorm
    mm_h<<<dim3(DM/128, (QLEN*BSZ)/128), b256>>>(p_avh, p_avh, 1<<30,
                                                 p_oWh, p_ao, DM, DM, 0);
    k_ln2<<<(QLEN*BSZ)/8, b256>>>(w, lng, lnb, out);
}

// round 11
// speedup vs baseline: 10.3578x; 1.2404x over previous
#include <cuda_runtime.h>
#include <cuda_bf16.h>
#include <math.h>
#include <stdint.h>

#define QLEN 1024
#define KLEN 2048
#define MEMLEN 1024
#define BSZ 4
#define NH 8
#define DH 64
#define DM 512
#define QKV (3*DM)

__device__ uint32_t g_qkvh[(size_t)KLEN*BSZ*QKV/2]; // bf16 pairs (jk, b, 1536)
__device__ uint32_t g_rkh [(size_t)KLEN*DM/2];      // bf16 pairs (jj, n*64+d)
__device__ uint32_t g_q  [(size_t)QLEN*BSZ*DM/2];
__device__ uint32_t g_k  [(size_t)KLEN*BSZ*DM/2];
__device__ uint32_t g_v  [(size_t)KLEN*BSZ*DM/2];
__device__ uint32_t g_avh[(size_t)QLEN*BSZ*DM/2];   // attention out, bf16
__device__ float    g_ao [(size_t)QLEN*BSZ*DM];
__device__ uint32_t g_wt[3*7*64*32];
// bf16 copies of GEMM operands
__device__ uint32_t g_xh [(size_t)KLEN*BSZ*DM/2];   // [mems; w]
__device__ uint32_t g_wh [(size_t)QKV*DM/2];        // qkvW
__device__ uint32_t g_rh [(size_t)KLEN*DM/2];       // r
__device__ uint32_t g_rWh[(size_t)DM*DM/2];         // rW
__device__ uint32_t g_oWh[(size_t)DM*DM/2];         // oW

__device__ __forceinline__ uint32_t pk(float x, float y) {
    __nv_bfloat162 t = __floats2bfloat162_rn(x, y);
    return *(uint32_t*)&t;
}
__device__ __forceinline__ float bl(uint32_t w) {
    __nv_bfloat16 h = *(__nv_bfloat16*)&w;
    return __bfloat162float(h);
}
__device__ __forceinline__ float bh(uint32_t w) {
    uint16_t u = (uint16_t)(w >> 16);
    __nv_bfloat16 h = *(__nv_bfloat16*)&u;
    return __bfloat162float(h);
}

__device__ __forceinline__ void mma_bf16(float& c0, float& c1, float& c2, float& c3,
                                         uint32_t a0, uint32_t a1, uint32_t a2, uint32_t a3,
                                         uint32_t b0, uint32_t b1)
{
    asm volatile("mma.sync.aligned.m16n8k16.row.col.f32.bf16.bf16.f32 "
                 "{%0,%1,%2,%3},{%4,%5,%6,%7},{%8,%9},{%0,%1,%2,%3};\n"
                 : "+f"(c0), "+f"(c1), "+f"(c2), "+f"(c3)
                 : "r"(a0), "r"(a1), "r"(a2), "r"(a3), "r"(b0), "r"(b1));
}

__device__ __forceinline__ void ldsm4(uint32_t& r0, uint32_t& r1, uint32_t& r2, uint32_t& r3,
                                      uint32_t addr)
{
    asm volatile("ldmatrix.sync.aligned.m8n8.x4.shared.b16 {%0,%1,%2,%3}, [%4];"
                 : "=r"(r0), "=r"(r1), "=r"(r2), "=r"(r3) : "r"(addr));
}
__device__ __forceinline__ void ldsm4t(uint32_t& r0, uint32_t& r1, uint32_t& r2, uint32_t& r3,
                                       uint32_t addr)
{
    asm volatile("ldmatrix.sync.aligned.m8n8.x4.trans.shared.b16 {%0,%1,%2,%3}, [%4];"
                 : "=r"(r0), "=r"(r1), "=r"(r2), "=r"(r3) : "r"(addr));
}

__device__ __forceinline__ void cpa16(uint32_t saddr, const void* gaddr) {
    asm volatile("cp.async.cg.shared.global [%0], [%1], 16;" :: "r"(saddr), "l"(gaddr));
}
__device__ __forceinline__ void cpa16z(uint32_t saddr, const void* gaddr, int ok) {
    int sz = ok ? 16 : 0;
    asm volatile("cp.async.cg.shared.global [%0], [%1], 16, %2;"
                 :: "r"(saddr), "l"(gaddr), "r"(sz));
}
#define CP_COMMIT() asm volatile("cp.async.commit_group;")
#define CP_WAIT0()  asm volatile("cp.async.wait_group 0;")

__device__ __forceinline__ float exp2_fast(float y) {
    y = fmaxf(y, -100.f);
    float z = __fadd_rn(y, 12582912.f);
    float n = __fsub_rn(z, 12582912.f);
    float f = __fsub_rn(y, n);
    float r = 0.0096181291f;
    r = fmaf(r, f, 0.055504109f);
    r = fmaf(r, f, 0.24022651f);
    r = fmaf(r, f, 0.69314718f);
    r = fmaf(r, f, 1.0f);
    int e = __float_as_int(z);
    float s = __int_as_float((e - 1262485377) << 23);
    return r * s;
}

// ---------------- fused fp32 -> bf16-pair convert (6 segments) ---------------
#define CVT_N0 (MEMLEN*BSZ*DM/2)
#define CVT_N1 (QLEN*BSZ*DM/2)
#define CVT_N2 (QKV*DM/2)
#define CVT_N3 (KLEN*DM/2)
#define CVT_N4 (DM*DM/2)
#define CVT_C0 (CVT_N0)
#define CVT_C1 (CVT_C0 + CVT_N1)
#define CVT_C2 (CVT_C1 + CVT_N2)
#define CVT_C3 (CVT_C2 + CVT_N3)
#define CVT_C4 (CVT_C3 + CVT_N4)
#define CVT_TOT (CVT_C4 + CVT_N4)
__global__ void k_cvt6(const float* __restrict__ mems, const float* __restrict__ w,
                       const float* __restrict__ qkvW, const float* __restrict__ r,
                       const float* __restrict__ rW,   const float* __restrict__ oW)
{
    int idx = blockIdx.x * blockDim.x + threadIdx.x;
    int stride = gridDim.x * blockDim.x;
    for (int i = idx; i < CVT_TOT; i += stride) {
        const float* s;
        uint32_t* d;
        int off;
        if (i < CVT_C0)      { s = mems; d = g_xh;            off = i; }
        else if (i < CVT_C1) { s = w;    d = g_xh + CVT_C0;   off = i - CVT_C0; }
        else if (i < CVT_C2) { s = qkvW; d = g_wh;            off = i - CVT_C1; }
        else if (i < CVT_C3) { s = r;    d = g_rh;            off = i - CVT_C2; }
        else if (i < CVT_C4) { s = rW;   d = g_rWh;           off = i - CVT_C3; }
        else                 { s = oW;   d = g_oWh;           off = i - CVT_C4; }
        float2 v = *(const float2*)&s[2*off];
        d[off] = pk(v.x, v.y);
    }
}

// ---------------- BF16 GEMM: cp.async staged + ldmatrix fragment feeds -------
// C[M,N] = A[M,K] @ B[N,K]^T. A/B bf16-pair word pointers, Kw = K/2.
#define GSW 12
__global__ __launch_bounds__(256, 2) void mm_h(const uint32_t* __restrict__ A0,
                                               const uint32_t* __restrict__ A1,
                                               int M1,
                                               const uint32_t* __restrict__ B,
                                               void* __restrict__ Cout,
                                               int N, int K, int pack)
{
    __shared__ uint32_t As[2][128*GSW];
    __shared__ uint32_t Bs[2][128*GSW];
    const int tid = threadIdx.x;
    const int warp = tid >> 5, lane = tid & 31;
    const int wm = warp & 3, wn = warp >> 2;
    const int g = lane >> 2, tg = lane & 3;
    const int quad = lane >> 3;
    const int m0 = blockIdx.y * 128, n0 = blockIdx.x * 128;
    const int Kw = K / 2;

    const uint32_t* Abase = (m0 < M1) ? (A0 + (size_t)m0 * Kw)
                                      : (A1 + (size_t)(m0 - M1) * Kw);
    const uint32_t* Bbase = B + (size_t)n0 * Kw;

    const uint32_t smA = (uint32_t)__cvta_generic_to_shared(As);
    const uint32_t smB = (uint32_t)__cvta_generic_to_shared(Bs);
    const uint32_t apat = (uint32_t)((lane & 15)*GSW + (lane >> 4)*4)*4;
    const uint32_t bpat = (uint32_t)((((quad & 2)*4) + (lane & 7))*GSW + (quad & 1)*4)*4;

    float c[2][8][4];
    #pragma unroll
    for (int mt = 0; mt < 2; mt++)
        #pragma unroll
        for (int nt = 0; nt < 8; nt++)
            #pragma unroll
            for (int q = 0; q < 4; q++) c[mt][nt][q] = 0.f;

    const int lr = tid >> 1;        // row 0..127
    const int lh = tid & 1;         // 4-word half of the BK=16 chunk
    const uint32_t* Ap = Abase + (size_t)lr * Kw + lh * 4;
    const uint32_t* Bp = Bbase + (size_t)lr * Kw + lh * 4;

    auto stage = [&](int bf2, int kw) {
        uint32_t so = (uint32_t)(bf2*128*GSW + lr*GSW + lh*4)*4;
        cpa16(smA + so, Ap + kw);
        cpa16(smB + so, Bp + kw);
    };

    stage(0, 0);
    CP_COMMIT();
    CP_WAIT0();
    __syncthreads();

    int buf = 0;
    for (int kw = 0; kw < Kw; kw += 8) {
        const bool more = (kw + 8) < Kw;
        if (more) {
            stage(buf ^ 1, kw + 8);
            CP_COMMIT();
        }
        {
            const uint32_t abase = smA + (uint32_t)(buf*128*GSW)*4;
            const uint32_t bbase = smB + (uint32_t)(buf*128*GSW)*4;
            uint32_t af[2][4], bf[8][2];
            #pragma unroll
            for (int mt = 0; mt < 2; mt++)
                ldsm4(af[mt][0], af[mt][1], af[mt][2], af[mt][3],
                      abase + (uint32_t)((wm*32 + mt*16)*GSW)*4 + apat);
            #pragma unroll
            for (int nt2 = 0; nt2 < 4; nt2++) {
                uint32_t b0, b1, b2, b3;
                ldsm4(b0, b1, b2, b3,
                      bbase + (uint32_t)((wn*64 + nt2*16)*GSW)*4 + bpat);
                bf[nt2*2][0] = b0;   bf[nt2*2][1] = b1;
                bf[nt2*2+1][0] = b2; bf[nt2*2+1][1] = b3;
            }
            #pragma unroll
            for (int mt = 0; mt < 2; mt++)
                #pragma unroll
                for (int nt = 0; nt < 8; nt++)
                    mma_bf16(c[mt][nt][0], c[mt][nt][1], c[mt][nt][2], c[mt][nt][3],
                             af[mt][0], af[mt][1], af[mt][2], af[mt][3],
                             bf[nt][0], bf[nt][1]);
        }
        if (more) CP_WAIT0();
        __syncthreads();
        buf ^= 1;
    }

    #pragma unroll
    for (int mt = 0; mt < 2; mt++) {
        int row0 = m0 + wm * 32 + mt * 16 + g;
        #pragma unroll
        for (int nt = 0; nt < 8; nt++) {
            int col = n0 + wn * 64 + nt * 8 + tg * 2;
            if (pack) {
                uint32_t* Cp = (uint32_t*)Cout;
                Cp[((size_t)row0 * N + col)/2]       = pk(c[mt][nt][0], c[mt][nt][1]);
                Cp[((size_t)(row0 + 8) * N + col)/2] = pk(c[mt][nt][2], c[mt][nt][3]);
            } else {
                float* C = (float*)Cout;
                *(float2*)&C[(size_t)row0 * N + col]       = make_float2(c[mt][nt][0], c[mt][nt][1]);
                *(float2*)&C[(size_t)(row0 + 8) * N + col] = make_float2(c[mt][nt][2], c[mt][nt][3]);
            }
        }
    }
}

// ---------------- weight prep ------------------------------------------------
__global__ void k_prepw(const float* __restrict__ cq,
                        const float* __restrict__ ck,
                        const float* __restrict__ cv)
{
    int idx = blockIdx.x;
    int c = idx / 7, tap = idx % 7;
    const float* src = (c == 0) ? cq : (c == 1) ? ck : cv;
    for (int e = threadIdx.x; e < 2048; e += 256) {
        int oc = e >> 5, icw = e & 31;
        float w0 = src[(oc*64 + 2*icw    )*7 + tap];
        float w1 = src[(oc*64 + 2*icw + 1)*7 + tap];
        g_wt[((c*7 + tap)*64 + oc)*32 + icw] = pk(w0, w1);
    }
}

// ---------------- fused conv via bf16 MMA + ldmatrix + cp.async --------------
#define CSW 36
#define OFF_WS (134*CSW*4)
__global__ __launch_bounds__(256, 2) void k_conv5(const float* __restrict__ cqb,
                                                  const float* __restrict__ ckb,
                                                  const float* __restrict__ cvb)
{
    extern __shared__ uint32_t cs[];
    const int bx = blockIdx.x;
    int c, t0, len, posoff, chanoff;
    const float* cb;
    uint32_t* outp;
    if (bx < 8)       { c = 0; t0 = bx*128;      len = QLEN; posoff = MEMLEN; chanoff = 0;    cb = cqb; outp = g_q; }
    else if (bx < 24) { c = 1; t0 = (bx-8)*128;  len = KLEN; posoff = 0;      chanoff = DM;   cb = ckb; outp = g_k; }
    else              { c = 2; t0 = (bx-24)*128; len = KLEN; posoff = 0;      chanoff = 2*DM; cb = cvb; outp = g_v; }
    const int nb = blockIdx.y;
    const int n = nb >> 2, b = nb & 3;
    const int tid = threadIdx.x;
    const int warp = tid >> 5, lane = tid & 31;
    const int wm = warp;
    const int g = lane >> 2, tg = lane & 3;
    const int quad = lane >> 3;
    const uint32_t smbC = (uint32_t)__cvta_generic_to_shared(cs);

    for (int e = tid; e < 134*8; e += 256) {
        int u = e >> 3, w4 = (e & 7) * 4;
        int pos = t0 + u - 3;
        int ok = (pos >= 0 && pos < len);
        int pc = ok ? pos : 0;
        cpa16z(smbC + (uint32_t)(u*CSW + w4)*4,
               &g_qkvh[((size_t)(pc + posoff)*(BSZ*QKV) + b*QKV + chanoff + n*DH)/2 + w4], ok);
    }
    {
        const uint32_t* src = g_wt + c*7*64*32;
        for (int e = tid; e < 3584; e += 256) {
            int s4 = e * 4;
            int to = s4 >> 5, icw = s4 & 31;
            cpa16(smbC + OFF_WS + (uint32_t)(to*CSW + icw)*4, &src[s4]);
        }
    }
    CP_COMMIT();
    CP_WAIT0();
    __syncthreads();

    float acc[8][4];
    #pragma unroll
    for (int nf = 0; nf < 8; nf++)
        #pragma unroll
        for (int q = 0; q < 4; q++) acc[nf][q] = 0.f;

    const uint32_t bpat = (uint32_t)((((quad & 2)*4) + (lane & 7))*CSW + (quad & 1)*4)*4;

    #pragma unroll
    for (int tap = 0; tap < 7; tap++) {
        const uint32_t apat = (uint32_t)((wm*16 + (lane & 15) + tap)*CSW + (lane >> 4)*4)*4;
        #pragma unroll
        for (int k0 = 0; k0 < 4; k0++) {
            uint32_t a0, a1, a2, a3;
            ldsm4(a0, a1, a2, a3, smbC + apat + k0*32);
            #pragma unroll
            for (int nf2 = 0; nf2 < 4; nf2++) {
                uint32_t b0, b1, b2, b3;
                ldsm4(b0, b1, b2, b3,
                      smbC + OFF_WS + bpat + (uint32_t)((tap*64 + nf2*16)*CSW)*4 + k0*32);
                mma_bf16(acc[nf2*2][0], acc[nf2*2][1], acc[nf2*2][2], acc[nf2*2][3],
                         a0, a1, a2, a3, b0, b1);
                mma_bf16(acc[nf2*2+1][0], acc[nf2*2+1][1], acc[nf2*2+1][2], acc[nf2*2+1][3],
                         a0, a1, a2, a3, b2, b3);
            }
        }
    }

    #pragma unroll
    for (int nf = 0; nf < 8; nf++) {
        int oc = nf*8 + 2*tg;
        float2 bb = *(const float2*)&cb[oc];
        int row = t0 + wm*16 + g;
        size_t w0 = ((size_t)row*(BSZ*DM) + b*DM)/2 + n*32 + nf*4 + tg;
        size_t w1 = ((size_t)(row+8)*(BSZ*DM) + b*DM)/2 + n*32 + nf*4 + tg;
        outp[w0] = pk(acc[nf][0] + bb.x, acc[nf][1] + bb.y);
        outp[w1] = pk(acc[nf][2] + bb.x, acc[nf][3] + bb.y);
    }
}

// ---------------- attention v8: cp.async pipelined, ldmatrix.trans PV --------
#define ASW 36
#define W_QW 0
#define W_QR 2304
#define W_K0 4608
#define W_K1 6912
#define W_V0 9216
#define W_V1 11520
#define W_R0 13824
#define W_R1 16128
#define W_BDR 18432
__global__ __launch_bounds__(256, 2) void k_attn8(const float* __restrict__ rwb,
                                                  const float* __restrict__ rrb)
{
    extern __shared__ uint32_t smu[];
    float* BDR = (float*)(smu + W_BDR);

    const int i0 = (gridDim.x - 1 - blockIdx.x) * 64;
    const int bn = blockIdx.y;
    const int b = bn >> 3, n = bn & 7;
    const int tid = threadIdx.x;
    const int warp = tid >> 5, lane = tid & 31;
    const int wm = warp & 3, wn = warp >> 2;
    const int g = lane >> 2, tg = lane & 3;
    const int quad = lane >> 3;

    const uint32_t smb = (uint32_t)__cvta_generic_to_shared(smu);
    const uint32_t aoff  = (uint32_t)((wm*16 + (lane & 15))*ASW + (lane >> 4)*4)*4;
    const uint32_t bpat  = (uint32_t)((((quad & 2)*4) + (lane & 7))*ASW + (quad & 1)*4)*4;
    const uint32_t boff  = bpat + (uint32_t)(wn*32)*ASW*4;
    const uint32_t tvpat = (uint32_t)(((quad & 1)*8 + (lane & 7))*ASW + (quad >> 1)*4)*4;

    const int il0 = wm*16 + g;
    const int il1 = il0 + 8;
    const int jjb0 = 960 - i0;
    const int ntiles = i0/64 + 17;

    auto stage_kv = [&](int buf, int j0c) {
        const uint32_t kb = smb + (uint32_t)(buf ? W_K1 : W_K0)*4;
        const uint32_t vb = smb + (uint32_t)(buf ? W_V1 : W_V0)*4;
        #pragma unroll
        for (int e0 = 0; e0 < 2; e0++) {
            int e = tid + e0*256;
            int jl = e >> 3, w4 = (e & 7) * 4;
            size_t wi = ((size_t)(j0c + jl)*(BSZ*DM) + b*DM + n*DH)/2 + w4;
            uint32_t so = (uint32_t)(jl*ASW + w4)*4;
            cpa16(kb + so, &g_k[wi]);
            cpa16(vb + so, &g_v[wi]);
        }
    };
    auto stage_rw = [&](int buf, int cb2) {
        const uint32_t rb = smb + (uint32_t)(buf ? W_R1 : W_R0)*4;
        #pragma unroll
        for (int e0 = 0; e0 < 2; e0++) {
            int e = tid + e0*256;
            int l = e >> 3, w4 = (e & 7) * 4;
            int jj = cb2 + l;
            int ok = (jj < KLEN);
            int jc = ok ? jj : (KLEN - 1);
            cpa16z(rb + (uint32_t)(l*ASW + w4)*4,
                   &g_rkh[((size_t)jc*DM + n*DH)/2 + w4], ok);
        }
    };
    auto bd_pass = [&](int rbuf, int cb2) {
        const uint32_t rwo = smb + (uint32_t)(rbuf ? W_R1 : W_R0)*4;
        const int s0 = cb2 & 127;
        float pc[4][4];
        #pragma unroll
        for (int nf = 0; nf < 4; nf++)
            #pragma unroll
            for (int q = 0; q < 4; q++) pc[nf][q] = 0.f;
        #pragma unroll
        for (int k0 = 0; k0 < 4; k0++) {
            uint32_t a0, a1, a2, a3, p0, p1, p2, p3, q0, q1, q2, q3;
            ldsm4(a0, a1, a2, a3, smb + W_QR*4 + aoff + k0*32);
            ldsm4(p0, p1, p2, p3, rwo + boff + k0*32);
            ldsm4(q0, q1, q2, q3, rwo + boff + 16*ASW*4 + k0*32);
            mma_bf16(pc[0][0], pc[0][1], pc[0][2], pc[0][3], a0, a1, a2, a3, p0, p1);
            mma_bf16(pc[1][0], pc[1][1], pc[1][2], pc[1][3], a0, a1, a2, a3, p2, p3);
            mma_bf16(pc[2][0], pc[2][1], pc[2][2], pc[2][3], a0, a1, a2, a3, q0, q1);
            mma_bf16(pc[3][0], pc[3][1], pc[3][2], pc[3][3], a0, a1, a2, a3, q2, q3);
        }
        #pragma unroll
        for (int nf = 0; nf < 4; nf++) {
            int cc = s0 + wn*32 + nf*8 + 2*tg;
            *(float2*)&BDR[il0*132 + cc] = make_float2(pc[nf][0], pc[nf][1]);
            *(float2*)&BDR[il1*132 + cc] = make_float2(pc[nf][2], pc[nf][3]);
        }
    };

    stage_kv(0, 0);
    stage_rw(0, jjb0);
    stage_rw(1, jjb0 + 64);
    CP_COMMIT();

    for (int e = tid; e < 64*16; e += 256) {
        int ii = e >> 4, d4 = (e & 15) * 4;
        size_t wi = ((size_t)(i0+ii)*(BSZ*DM) + b*DM + n*DH + d4) / 2;
        uint2 qv = *(const uint2*)&g_q[wi];
        float q0 = bl(qv.x), q1 = bh(qv.x), q2 = bl(qv.y), q3 = bh(qv.y);
        float4 wv = *(const float4*)&rwb[n*DH + d4];
        float4 rv = *(const float4*)&rrb[n*DH + d4];
        smu[W_QW + ii*ASW + d4/2]     = pk(q0 + wv.x, q1 + wv.y);
        smu[W_QW + ii*ASW + d4/2 + 1] = pk(q2 + wv.z, q3 + wv.w);
        smu[W_QR + ii*ASW + d4/2]     = pk(q0 + rv.x, q1 + rv.y);
        smu[W_QR + ii*ASW + d4/2 + 1] = pk(q2 + rv.z, q3 + rv.w);
    }
    CP_WAIT0();
    __syncthreads();

    bd_pass(0, jjb0);

    float oacc[8][4];
    #pragma unroll
    for (int nf = 0; nf < 8; nf++)
        #pragma unroll
        for (int q = 0; q < 4; q++) oacc[nf][q] = 0.f;
    float l0 = 0.f, l1 = 0.f;

    for (int t = 0; t < ntiles; t++) {
        const int kvb = t & 1;
        const int j0 = t * 64;
        const int jjb = j0 - i0 + 960;

        if (t + 1 < ntiles) stage_kv(kvb ^ 1, j0 + 64);
        stage_rw(kvb, jjb0 + 64*(t + 2));
        CP_COMMIT();

        const uint32_t kso = smb + (uint32_t)(kvb ? W_K1 : W_K0)*4;
        float sc[4][4];
        #pragma unroll
        for (int nf = 0; nf < 4; nf++)
            #pragma unroll
            for (int q = 0; q < 4; q++) sc[nf][q] = 0.f;
        #pragma unroll
        for (int k0 = 0; k0 < 4; k0++) {
            uint32_t a0, a1, a2, a3, p0, p1, p2, p3, q0, q1, q2, q3;
            ldsm4(a0, a1, a2, a3, smb + W_QW*4 + aoff + k0*32);
            ldsm4(p0, p1, p2, p3, kso + boff + k0*32);
            ldsm4(q0, q1, q2, q3, kso + boff + 16*ASW*4 + k0*32);
            mma_bf16(sc[0][0], sc[0][1], sc[0][2], sc[0][3], a0, a1, a2, a3, p0, p1);
            mma_bf16(sc[1][0], sc[1][1], sc[1][2], sc[1][3], a0, a1, a2, a3, p2, p3);
            mma_bf16(sc[2][0], sc[2][1], sc[2][2], sc[2][3], a0, a1, a2, a3, q0, q1);
            mma_bf16(sc[3][0], sc[3][1], sc[3][2], sc[3][3], a0, a1, a2, a3, q2, q3);
        }

        bd_pass(kvb ^ 1, jjb0 + 64*(t + 1));
        __syncthreads();

        const int jjb2 = jjb + 63;
        uint32_t a_lo[4], a_hi[4];
        #pragma unroll
        for (int nf = 0; nf < 4; nf++) {
            int jl = wn*32 + nf*8 + 2*tg;
            int jg = j0 + jl;
            int s00 = (jjb2 + jl - il0) & 127;
            int s01 = (jjb2 + jl + 1 - il0) & 127;
            int s10 = (jjb2 + jl - il1) & 127;
            int s11 = (jjb2 + jl + 1 - il1) & 127;
            float p00 = 0.f, p01 = 0.f, p10 = 0.f, p11 = 0.f;
            if (jg <= i0 + il0 + MEMLEN)
                p00 = exp2_fast((sc[nf][0] + BDR[il0*132 + s00]) * 0.18033688f);
            if (jg + 1 <= i0 + il0 + MEMLEN)
                p01 = exp2_fast((sc[nf][1] + BDR[il0*132 + s01]) * 0.18033688f);
            if (jg <= i0 + il1 + MEMLEN)
                p10 = exp2_fast((sc[nf][2] + BDR[il1*132 + s10]) * 0.18033688f);
            if (jg + 1 <= i0 + il1 + MEMLEN)
                p11 = exp2_fast((sc[nf][3] + BDR[il1*132 + s11]) * 0.18033688f);
            l0 += p00 + p01;
            l1 += p10 + p11;
            a_lo[nf] = pk(p00, p01);
            a_hi[nf] = pk(p10, p11);
        }

        const uint32_t vso = smb + (uint32_t)(kvb ? W_V1 : W_V0)*4;
        #pragma unroll
        for (int k0 = 0; k0 < 2; k0++) {
            uint32_t a0 = a_lo[2*k0], a1 = a_hi[2*k0];
            uint32_t a2 = a_lo[2*k0+1], a3 = a_hi[2*k0+1];
            uint32_t jbase = (uint32_t)((wn*32 + k0*16)*ASW)*4;
            #pragma unroll
            for (int dd = 0; dd < 4; dd++) {
                uint32_t b0, b1, b2, b3;
                ldsm4t(b0, b1, b2, b3, vso + tvpat + jbase + (uint32_t)(dd*8)*4);
                mma_bf16(oacc[dd*2][0], oacc[dd*2][1], oacc[dd*2][2], oacc[dd*2][3],
                         a0, a1, a2, a3, b0, b1);
                mma_bf16(oacc[dd*2+1][0], oacc[dd*2+1][1], oacc[dd*2+1][2], oacc[dd*2+1][3],
                         a0, a1, a2, a3, b2, b3);
            }
        }

        CP_WAIT0();
        __syncthreads();
    }

    l0 += __shfl_xor_sync(0xffffffffu, l0, 1);
    l0 += __shfl_xor_sync(0xffffffffu, l0, 2);
    l1 += __shfl_xor_sync(0xffffffffu, l1, 1);
    l1 += __shfl_xor_sync(0xffffffffu, l1, 2);
    float* obuf = BDR;
    float* lbuf = BDR + 4*16*68;
    if (wn == 1) {
        #pragma unroll
        for (int nf = 0; nf < 8; nf++) {
            int d = nf*8 + 2*tg;
            *(float2*)&obuf[il0*68 + d] = make_float2(oacc[nf][0], oacc[nf][1]);
            *(float2*)&obuf[il1*68 + d] = make_float2(oacc[nf][2], oacc[nf][3]);
        }
        if (tg == 0) { lbuf[il0] = l0; lbuf[il1] = l1; }
    }
    __syncthreads();
    if (wn == 0) {
        float inv0 = 1.f / (l0 + lbuf[il0]);
        float inv1 = 1.f / (l1 + lbuf[il1]);
        #pragma unroll
        for (int nf = 0; nf < 8; nf++) {
            int d = nf*8 + 2*tg;
            float2 o0 = *(float2*)&obuf[il0*68 + d];
            float2 o1 = *(float2*)&obuf[il1*68 + d];
            g_avh[((size_t)(i0+il0)*(BSZ*DM) + b*DM + n*DH + d)/2] =
                pk((oacc[nf][0]+o0.x)*inv0, (oacc[nf][1]+o0.y)*inv0);
            g_avh[((size_t)(i0+il1)*(BSZ*DM) + b*DM + n*DH + d)/2] =
                pk((oacc[nf][2]+o1.x)*inv1, (oacc[nf][3]+o1.y)*inv1);
        }
    }
}

// ---------------- residual + layernorm: warp per row -------------------------
__global__ __launch_bounds__(256) void k_ln2(const float* __restrict__ w,
                                             const float* __restrict__ g,
                                             const float* __restrict__ be,
                                             float* __restrict__ out)
{
    int row = blockIdx.x * 8 + (threadIdx.x >> 5);
    int lane = threadIdx.x & 31;
    const float* wr = w    + (size_t)row * DM;
    const float* ar = g_ao + (size_t)row * DM;

    float4 x[4];
    float s = 0.f;
    #pragma unroll
    for (int c = 0; c < 4; c++) {
        int idx = c*128 + lane*4;
        float4 a = *(const float4*)&wr[idx];
        float4 o = *(const float4*)&ar[idx];
        x[c] = make_float4(a.x+o.x, a.y+o.y, a.z+o.z, a.w+o.w);
        s += x[c].x + x[c].y + x[c].z + x[c].w;
    }
    #pragma unroll
    for (int m = 16; m > 0; m >>= 1) s += __shfl_xor_sync(0xffffffffu, s, m);
    float mu = s * (1.f / DM);
    float v = 0.f;
    #pragma unroll
    for (int c = 0; c < 4; c++) {
        float dx = x[c].x - mu, dy = x[c].y - mu, dz = x[c].z - mu, dw = x[c].w - mu;
        x[c] = make_float4(dx, dy, dz, dw);
        v += dx*dx + dy*dy + dz*dz + dw*dw;
    }
    #pragma unroll
    for (int m = 16; m > 0; m >>= 1) v += __shfl_xor_sync(0xffffffffu, v, m);
    float rs = rsqrtf(v * (1.f / DM) + 1e-5f);
    #pragma unroll
    for (int c = 0; c < 4; c++) {
        int idx = c*128 + lane*4;
        float4 gg = *(const float4*)&g[idx];
        float4 bb = *(const float4*)&be[idx];
        float4 r = make_float4(x[c].x*rs*gg.x + bb.x, x[c].y*rs*gg.y + bb.y,
                               x[c].z*rs*gg.z + bb.z, x[c].w*rs*gg.w + bb.w);
        *(float4*)&out[(size_t)row*DM + idx] = r;
    }
}

// ---------------- launcher ---------------------------------------------------
extern "C" void kernel_launch(void* const* d_in, const int* in_sizes, int n_in,
                              void* d_out, int out_size)
{
    (void)in_sizes; (void)n_in; (void)out_size;
    const float* w    = (const float*)d_in[0];
    const float* r    = (const float*)d_in[1];
    const float* mems = (const float*)d_in[2];
    const float* rwb  = (const float*)d_in[3];
    const float* rrb  = (const float*)d_in[4];
    const float* qkvW = (const float*)d_in[5];
    const float* rW   = (const float*)d_in[6];
    const float* cqw  = (const float*)d_in[7];
    const float* cqb  = (const float*)d_in[8];
    const float* ckw  = (const float*)d_in[9];
    const float* ckb  = (const float*)d_in[10];
    const float* cvw  = (const float*)d_in[11];
    const float* cvb  = (const float*)d_in[12];
    const float* oW   = (const float*)d_in[13];
    const float* lng  = (const float*)d_in[14];
    const float* lnb  = (const float*)d_in[15];
    float* out = (float*)d_out;

    uint32_t *p_qkvh, *p_rkh, *p_xh, *p_wh, *p_rh, *p_rWh, *p_oWh, *p_avh;
    float *p_ao;
    cudaGetSymbolAddress((void**)&p_qkvh, g_qkvh);
    cudaGetSymbolAddress((void**)&p_rkh,  g_rkh);
    cudaGetSymbolAddress((void**)&p_xh,   g_xh);
    cudaGetSymbolAddress((void**)&p_wh,   g_wh);
    cudaGetSymbolAddress((void**)&p_rh,   g_rh);
    cudaGetSymbolAddress((void**)&p_rWh,  g_rWh);
    cudaGetSymbolAddress((void**)&p_oWh,  g_oWh);
    cudaGetSymbolAddress((void**)&p_avh,  g_avh);
    cudaGetSymbolAddress((void**)&p_ao,   g_ao);

    dim3 b256(256);

    // fused fp32 -> bf16 conversions + conv weight prep
    k_cvt6<<<2048, b256>>>(mems, w, qkvW, r, rW, oW);
    k_prepw<<<21, b256>>>(cqw, ckw, cvw);

    // QKV projection over [mems; w] (bf16 in, bf16 out)
    mm_h<<<dim3(QKV/128, (KLEN*BSZ)/128), b256>>>(p_xh, p_xh, 1<<30,
                                                  p_wh, p_qkvh, QKV, DM, 1);
    // r @ r_W^T
    mm_h<<<dim3(DM/128, KLEN/128), b256>>>(p_rh, p_rh, 1<<30, p_rWh, p_rkh, DM, DM, 1);

    // fused convs
    int csm = (134*CSW + 7*64*CSW) * 4;
    cudaFuncSetAttribute(k_conv5, cudaFuncAttributeMaxDynamicSharedMemorySize, csm);
    k_conv5<<<dim3(40, NH*BSZ), b256, csm>>>(cqb, ckb, cvb);

    // attention (2 CTAs/SM)
    int asm_ = (W_BDR + 64*132) * 4;
    cudaFuncSetAttribute(k_attn8, cudaFuncAttributeMaxDynamicSharedMemorySize, asm_);
    k_attn8<<<dim3(QLEN/64, BSZ*NH), b256, asm_>>>(rwb, rrb);

    // output projection (bf16 A, fp32 out) + residual layernorm
    mm_h<<<dim3(DM/128, (QLEN*BSZ)/128), b256>>>(p_avh, p_avh, 1<<30,
                                                 p_oWh, p_ao, DM, DM, 0);
    k_ln2<<<(QLEN*BSZ)/8, b256>>>(w, lng, lnb, out);
}

// round 12
// speedup vs baseline: 10.6413x; 1.0274x over previous
#include <cuda_runtime.h>
#include <cuda_bf16.h>
#include <math.h>
#include <stdint.h>

#define QLEN 1024
#define KLEN 2048
#define MEMLEN 1024
#define BSZ 4
#define NH 8
#define DH 64
#define DM 512
#define QKV (3*DM)

__device__ uint32_t g_qkvh[(size_t)KLEN*BSZ*QKV/2]; // bf16 pairs (jk, b, 1536)
__device__ uint32_t g_rkh [(size_t)KLEN*DM/2];      // bf16 pairs (jj, n*64+d)
__device__ uint32_t g_q  [(size_t)QLEN*BSZ*DM/2];
__device__ uint32_t g_k  [(size_t)KLEN*BSZ*DM/2];
__device__ uint32_t g_v  [(size_t)KLEN*BSZ*DM/2];
__device__ uint32_t g_avh[(size_t)QLEN*BSZ*DM/2];   // attention out, bf16
__device__ float    g_ao [(size_t)QLEN*BSZ*DM];
__device__ uint32_t g_wt[3*7*64*32];
// bf16 copies of GEMM operands
__device__ uint32_t g_xh [(size_t)KLEN*BSZ*DM/2];   // [mems; w]
__device__ uint32_t g_wh [(size_t)QKV*DM/2];        // qkvW
__device__ uint32_t g_rh [(size_t)KLEN*DM/2];       // r
__device__ uint32_t g_rWh[(size_t)DM*DM/2];         // rW
__device__ uint32_t g_oWh[(size_t)DM*DM/2];         // oW

__device__ __forceinline__ uint32_t pk(float x, float y) {
    __nv_bfloat162 t = __floats2bfloat162_rn(x, y);
    return *(uint32_t*)&t;
}
__device__ __forceinline__ float bl(uint32_t w) {
    __nv_bfloat16 h = *(__nv_bfloat16*)&w;
    return __bfloat162float(h);
}
__device__ __forceinline__ float bh(uint32_t w) {
    uint16_t u = (uint16_t)(w >> 16);
    __nv_bfloat16 h = *(__nv_bfloat16*)&u;
    return __bfloat162float(h);
}

__device__ __forceinline__ void mma_bf16(float& c0, float& c1, float& c2, float& c3,
                                         uint32_t a0, uint32_t a1, uint32_t a2, uint32_t a3,
                                         uint32_t b0, uint32_t b1)
{
    asm volatile("mma.sync.aligned.m16n8k16.row.col.f32.bf16.bf16.f32 "
                 "{%0,%1,%2,%3},{%4,%5,%6,%7},{%8,%9},{%0,%1,%2,%3};\n"
                 : "+f"(c0), "+f"(c1), "+f"(c2), "+f"(c3)
                 : "r"(a0), "r"(a1), "r"(a2), "r"(a3), "r"(b0), "r"(b1));
}

__device__ __forceinline__ void ldsm4(uint32_t& r0, uint32_t& r1, uint32_t& r2, uint32_t& r3,
                                      uint32_t addr)
{
    asm volatile("ldmatrix.sync.aligned.m8n8.x4.shared.b16 {%0,%1,%2,%3}, [%4];"
                 : "=r"(r0), "=r"(r1), "=r"(r2), "=r"(r3) : "r"(addr));
}
__device__ __forceinline__ void ldsm4t(uint32_t& r0, uint32_t& r1, uint32_t& r2, uint32_t& r3,
                                       uint32_t addr)
{
    asm volatile("ldmatrix.sync.aligned.m8n8.x4.trans.shared.b16 {%0,%1,%2,%3}, [%4];"
                 : "=r"(r0), "=r"(r1), "=r"(r2), "=r"(r3) : "r"(addr));
}

__device__ __forceinline__ void cpa16(uint32_t saddr, const void* gaddr) {
    asm volatile("cp.async.cg.shared.global [%0], [%1], 16;" :: "r"(saddr), "l"(gaddr));
}
__device__ __forceinline__ void cpa16z(uint32_t saddr, const void* gaddr, int ok) {
    int sz = ok ? 16 : 0;
    asm volatile("cp.async.cg.shared.global [%0], [%1], 16, %2;"
                 :: "r"(saddr), "l"(gaddr), "r"(sz));
}
#define CP_COMMIT() asm volatile("cp.async.commit_group;")
#define CP_WAIT0()  asm volatile("cp.async.wait_group 0;")
#define CP_WAIT1()  asm volatile("cp.async.wait_group 1;")

__device__ __forceinline__ float exp2_fast(float y) {
    y = fmaxf(y, -100.f);
    float z = __fadd_rn(y, 12582912.f);
    float n = __fsub_rn(z, 12582912.f);
    float f = __fsub_rn(y, n);
    float r = 0.0096181291f;
    r = fmaf(r, f, 0.055504109f);
    r = fmaf(r, f, 0.24022651f);
    r = fmaf(r, f, 0.69314718f);
    r = fmaf(r, f, 1.0f);
    int e = __float_as_int(z);
    float s = __int_as_float((e - 1262485377) << 23);
    return r * s;
}

// ---------------- fused fp32 -> bf16-pair convert (6 segments) ---------------
#define CVT_N0 (MEMLEN*BSZ*DM/2)
#define CVT_N1 (QLEN*BSZ*DM/2)
#define CVT_N2 (QKV*DM/2)
#define CVT_N3 (KLEN*DM/2)
#define CVT_N4 (DM*DM/2)
#define CVT_C0 (CVT_N0)
#define CVT_C1 (CVT_C0 + CVT_N1)
#define CVT_C2 (CVT_C1 + CVT_N2)
#define CVT_C3 (CVT_C2 + CVT_N3)
#define CVT_C4 (CVT_C3 + CVT_N4)
#define CVT_TOT (CVT_C4 + CVT_N4)
__global__ void k_cvt6(const float* __restrict__ mems, const float* __restrict__ w,
                       const float* __restrict__ qkvW, const float* __restrict__ r,
                       const float* __restrict__ rW,   const float* __restrict__ oW)
{
    int idx = blockIdx.x * blockDim.x + threadIdx.x;
    int stride = gridDim.x * blockDim.x;
    for (int i = idx; i < CVT_TOT; i += stride) {
        const float* s;
        uint32_t* d;
        int off;
        if (i < CVT_C0)      { s = mems; d = g_xh;            off = i; }
        else if (i < CVT_C1) { s = w;    d = g_xh + CVT_C0;   off = i - CVT_C0; }
        else if (i < CVT_C2) { s = qkvW; d = g_wh;            off = i - CVT_C1; }
        else if (i < CVT_C3) { s = r;    d = g_rh;            off = i - CVT_C2; }
        else if (i < CVT_C4) { s = rW;   d = g_rWh;           off = i - CVT_C3; }
        else                 { s = oW;   d = g_oWh;           off = i - CVT_C4; }
        float2 v = *(const float2*)&s[2*off];
        d[off] = pk(v.x, v.y);
    }
}

// ---------------- BF16 GEMM: 3-stage cp.async pipeline + ldmatrix ------------
// C[M,N] = A[M,K] @ B[N,K]^T. A/B bf16-pair word pointers, Kw = K/2.
#define GSW 12
#define NSTG 3
__global__ __launch_bounds__(256, 2) void mm_h(const uint32_t* __restrict__ A,
                                               const uint32_t* __restrict__ B,
                                               void* __restrict__ Cout,
                                               int N, int K, int pack)
{
    __shared__ uint32_t As[NSTG][128*GSW];
    __shared__ uint32_t Bs[NSTG][128*GSW];
    const int tid = threadIdx.x;
    const int warp = tid >> 5, lane = tid & 31;
    const int wm = warp & 3, wn = warp >> 2;
    const int g = lane >> 2, tg = lane & 3;
    const int quad = lane >> 3;
    const int m0 = blockIdx.y * 128, n0 = blockIdx.x * 128;
    const int Kw = K / 2;
    const int iters = Kw / 8;       // BK = 16 elements = 8 words

    const uint32_t smA = (uint32_t)__cvta_generic_to_shared(As);
    const uint32_t smB = (uint32_t)__cvta_generic_to_shared(Bs);
    const uint32_t apat = (uint32_t)((lane & 15)*GSW + (lane >> 4)*4)*4;
    const uint32_t bpat = (uint32_t)((((quad & 2)*4) + (lane & 7))*GSW + (quad & 1)*4)*4;

    float c[2][8][4];
    #pragma unroll
    for (int mt = 0; mt < 2; mt++)
        #pragma unroll
        for (int nt = 0; nt < 8; nt++)
            #pragma unroll
            for (int q = 0; q < 4; q++) c[mt][nt][q] = 0.f;

    const int lr = tid >> 1;        // row 0..127
    const int lh = tid & 1;         // 4-word half of the BK chunk
    const uint32_t* Ap = A + (size_t)(m0 + lr) * Kw + lh * 4;
    const uint32_t* Bp = B + (size_t)(n0 + lr) * Kw + lh * 4;

    auto stage = [&](int s, int kw) {
        uint32_t so = (uint32_t)(s*128*GSW + lr*GSW + lh*4)*4;
        cpa16(smA + so, Ap + kw);
        cpa16(smB + so, Bp + kw);
    };

    // preamble: stages 0 and 1 in flight
    stage(0, 0);
    CP_COMMIT();
    if (iters > 1) stage(1, 8);
    CP_COMMIT();

    for (int i = 0; i < iters; i++) {
        CP_WAIT1();                  // stage i landed
        __syncthreads();             // visible to all; stage i-1 fully consumed
        int pf = i + NSTG - 1;
        if (pf < iters) stage(pf % NSTG, pf * 8);
        CP_COMMIT();

        const int buf = i % NSTG;
        const uint32_t abase = smA + (uint32_t)(buf*128*GSW)*4;
        const uint32_t bbase = smB + (uint32_t)(buf*128*GSW)*4;
        uint32_t af[2][4], bf[8][2];
        #pragma unroll
        for (int mt = 0; mt < 2; mt++)
            ldsm4(af[mt][0], af[mt][1], af[mt][2], af[mt][3],
                  abase + (uint32_t)((wm*32 + mt*16)*GSW)*4 + apat);
        #pragma unroll
        for (int nt2 = 0; nt2 < 4; nt2++) {
            uint32_t b0, b1, b2, b3;
            ldsm4(b0, b1, b2, b3,
                  bbase + (uint32_t)((wn*64 + nt2*16)*GSW)*4 + bpat);
            bf[nt2*2][0] = b0;   bf[nt2*2][1] = b1;
            bf[nt2*2+1][0] = b2; bf[nt2*2+1][1] = b3;
        }
        #pragma unroll
        for (int mt = 0; mt < 2; mt++)
            #pragma unroll
            for (int nt = 0; nt < 8; nt++)
                mma_bf16(c[mt][nt][0], c[mt][nt][1], c[mt][nt][2], c[mt][nt][3],
                         af[mt][0], af[mt][1], af[mt][2], af[mt][3],
                         bf[nt][0], bf[nt][1]);
    }

    #pragma unroll
    for (int mt = 0; mt < 2; mt++) {
        int row0 = m0 + wm * 32 + mt * 16 + g;
        #pragma unroll
        for (int nt = 0; nt < 8; nt++) {
            int col = n0 + wn * 64 + nt * 8 + tg * 2;
            if (pack) {
                uint32_t* Cp = (uint32_t*)Cout;
                Cp[((size_t)row0 * N + col)/2]       = pk(c[mt][nt][0], c[mt][nt][1]);
                Cp[((size_t)(row0 + 8) * N + col)/2] = pk(c[mt][nt][2], c[mt][nt][3]);
            } else {
                float* C = (float*)Cout;
                *(float2*)&C[(size_t)row0 * N + col]       = make_float2(c[mt][nt][0], c[mt][nt][1]);
                *(float2*)&C[(size_t)(row0 + 8) * N + col] = make_float2(c[mt][nt][2], c[mt][nt][3]);
            }
        }
    }
}

// ---------------- weight prep ------------------------------------------------
__global__ void k_prepw(const float* __restrict__ cq,
                        const float* __restrict__ ck,
                        const float* __restrict__ cv)
{
    int idx = blockIdx.x;
    int c = idx / 7, tap = idx % 7;
    const float* src = (c == 0) ? cq : (c == 1) ? ck : cv;
    for (int e = threadIdx.x; e < 2048; e += 256) {
        int oc = e >> 5, icw = e & 31;
        float w0 = src[(oc*64 + 2*icw    )*7 + tap];
        float w1 = src[(oc*64 + 2*icw + 1)*7 + tap];
        g_wt[((c*7 + tap)*64 + oc)*32 + icw] = pk(w0, w1);
    }
}

// ---------------- fused conv via bf16 MMA + ldmatrix + cp.async --------------
#define CSW 36
#define OFF_WS (134*CSW*4)
__global__ __launch_bounds__(256, 2) void k_conv5(const float* __restrict__ cqb,
                                                  const float* __restrict__ ckb,
                                                  const float* __restrict__ cvb)
{
    extern __shared__ uint32_t cs[];
    const int bx = blockIdx.x;
    int c, t0, len, posoff, chanoff;
    const float* cb;
    uint32_t* outp;
    if (bx < 8)       { c = 0; t0 = bx*128;      len = QLEN; posoff = MEMLEN; chanoff = 0;    cb = cqb; outp = g_q; }
    else if (bx < 24) { c = 1; t0 = (bx-8)*128;  len = KLEN; posoff = 0;      chanoff = DM;   cb = ckb; outp = g_k; }
    else              { c = 2; t0 = (bx-24)*128; len = KLEN; posoff = 0;      chanoff = 2*DM; cb = cvb; outp = g_v; }
    const int nb = blockIdx.y;
    const int n = nb >> 2, b = nb & 3;
    const int tid = threadIdx.x;
    const int warp = tid >> 5, lane = tid & 31;
    const int wm = warp;
    const int g = lane >> 2, tg = lane & 3;
    const int quad = lane >> 3;
    const uint32_t smbC = (uint32_t)__cvta_generic_to_shared(cs);

    for (int e = tid; e < 134*8; e += 256) {
        int u = e >> 3, w4 = (e & 7) * 4;
        int pos = t0 + u - 3;
        int ok = (pos >= 0 && pos < len);
        int pc = ok ? pos : 0;
        cpa16z(smbC + (uint32_t)(u*CSW + w4)*4,
               &g_qkvh[((size_t)(pc + posoff)*(BSZ*QKV) + b*QKV + chanoff + n*DH)/2 + w4], ok);
    }
    {
        const uint32_t* src = g_wt + c*7*64*32;
        for (int e = tid; e < 3584; e += 256) {
            int s4 = e * 4;
            int to = s4 >> 5, icw = s4 & 31;
            cpa16(smbC + OFF_WS + (uint32_t)(to*CSW + icw)*4, &src[s4]);
        }
    }
    CP_COMMIT();
    CP_WAIT0();
    __syncthreads();

    float acc[8][4];
    #pragma unroll
    for (int nf = 0; nf < 8; nf++)
        #pragma unroll
        for (int q = 0; q < 4; q++) acc[nf][q] = 0.f;

    const uint32_t bpat = (uint32_t)((((quad & 2)*4) + (lane & 7))*CSW + (quad & 1)*4)*4;

    #pragma unroll
    for (int tap = 0; tap < 7; tap++) {
        const uint32_t apat = (uint32_t)((wm*16 + (lane & 15) + tap)*CSW + (lane >> 4)*4)*4;
        #pragma unroll
        for (int k0 = 0; k0 < 4; k0++) {
            uint32_t a0, a1, a2, a3;
            ldsm4(a0, a1, a2, a3, smbC + apat + k0*32);
            #pragma unroll
            for (int nf2 = 0; nf2 < 4; nf2++) {
                uint32_t b0, b1, b2, b3;
                ldsm4(b0, b1, b2, b3,
                      smbC + OFF_WS + bpat + (uint32_t)((tap*64 + nf2*16)*CSW)*4 + k0*32);
                mma_bf16(acc[nf2*2][0], acc[nf2*2][1], acc[nf2*2][2], acc[nf2*2][3],
                         a0, a1, a2, a3, b0, b1);
                mma_bf16(acc[nf2*2+1][0], acc[nf2*2+1][1], acc[nf2*2+1][2], acc[nf2*2+1][3],
                         a0, a1, a2, a3, b2, b3);
            }
        }
    }

    #pragma unroll
    for (int nf = 0; nf < 8; nf++) {
        int oc = nf*8 + 2*tg;
        float2 bb = *(const float2*)&cb[oc];
        int row = t0 + wm*16 + g;
        size_t w0 = ((size_t)row*(BSZ*DM) + b*DM)/2 + n*32 + nf*4 + tg;
        size_t w1 = ((size_t)(row+8)*(BSZ*DM) + b*DM)/2 + n*32 + nf*4 + tg;
        outp[w0] = pk(acc[nf][0] + bb.x, acc[nf][1] + bb.y);
        outp[w1] = pk(acc[nf][2] + bb.x, acc[nf][3] + bb.y);
    }
}

// ---------------- attention v8: cp.async pipelined, ldmatrix.trans PV --------
#define ASW 36
#define W_QW 0
#define W_QR 2304
#define W_K0 4608
#define W_K1 6912
#define W_V0 9216
#define W_V1 11520
#define W_R0 13824
#define W_R1 16128
#define W_BDR 18432
__global__ __launch_bounds__(256, 2) void k_attn8(const float* __restrict__ rwb,
                                                  const float* __restrict__ rrb)
{
    extern __shared__ uint32_t smu[];
    float* BDR = (float*)(smu + W_BDR);

    const int i0 = (gridDim.x - 1 - blockIdx.x) * 64;
    const int bn = blockIdx.y;
    const int b = bn >> 3, n = bn & 7;
    const int tid = threadIdx.x;
    const int warp = tid >> 5, lane = tid & 31;
    const int wm = warp & 3, wn = warp >> 2;
    const int g = lane >> 2, tg = lane & 3;
    const int quad = lane >> 3;

    const uint32_t smb = (uint32_t)__cvta_generic_to_shared(smu);
    const uint32_t aoff  = (uint32_t)((wm*16 + (lane & 15))*ASW + (lane >> 4)*4)*4;
    const uint32_t bpat  = (uint32_t)((((quad & 2)*4) + (lane & 7))*ASW + (quad & 1)*4)*4;
    const uint32_t boff  = bpat + (uint32_t)(wn*32)*ASW*4;
    const uint32_t tvpat = (uint32_t)(((quad & 1)*8 + (lane & 7))*ASW + (quad >> 1)*4)*4;

    const int il0 = wm*16 + g;
    const int il1 = il0 + 8;
    const int jjb0 = 960 - i0;
    const int ntiles = i0/64 + 17;

    auto stage_kv = [&](int buf, int j0c) {
        const uint32_t kb = smb + (uint32_t)(buf ? W_K1 : W_K0)*4;
        const uint32_t vb = smb + (uint32_t)(buf ? W_V1 : W_V0)*4;
        #pragma unroll
        for (int e0 = 0; e0 < 2; e0++) {
            int e = tid + e0*256;
            int jl = e >> 3, w4 = (e & 7) * 4;
            size_t wi = ((size_t)(j0c + jl)*(BSZ*DM) + b*DM + n*DH)/2 + w4;
            uint32_t so = (uint32_t)(jl*ASW + w4)*4;
            cpa16(kb + so, &g_k[wi]);
            cpa16(vb + so, &g_v[wi]);
        }
    };
    auto stage_rw = [&](int buf, int cb2) {
        const uint32_t rb = smb + (uint32_t)(buf ? W_R1 : W_R0)*4;
        #pragma unroll
        for (int e0 = 0; e0 < 2; e0++) {
            int e = tid + e0*256;
            int l = e >> 3, w4 = (e & 7) * 4;
            int jj = cb2 + l;
            int ok = (jj < KLEN);
            int jc = ok ? jj : (KLEN - 1);
            cpa16z(rb + (uint32_t)(l*ASW + w4)*4,
                   &g_rkh[((size_t)jc*DM + n*DH)/2 + w4], ok);
        }
    };
    auto bd_pass = [&](int rbuf, int cb2) {
        const uint32_t rwo = smb + (uint32_t)(rbuf ? W_R1 : W_R0)*4;
        const int s0 = cb2 & 127;
        float pc[4][4];
        #pragma unroll
        for (int nf = 0; nf < 4; nf++)
            #pragma unroll
            for (int q = 0; q < 4; q++) pc[nf][q] = 0.f;
        #pragma unroll
        for (int k0 = 0; k0 < 4; k0++) {
            uint32_t a0, a1, a2, a3, p0, p1, p2, p3, q0, q1, q2, q3;
            ldsm4(a0, a1, a2, a3, smb + W_QR*4 + aoff + k0*32);
            ldsm4(p0, p1, p2, p3, rwo + boff + k0*32);
            ldsm4(q0, q1, q2, q3, rwo + boff + 16*ASW*4 + k0*32);
            mma_bf16(pc[0][0], pc[0][1], pc[0][2], pc[0][3], a0, a1, a2, a3, p0, p1);
            mma_bf16(pc[1][0], pc[1][1], pc[1][2], pc[1][3], a0, a1, a2, a3, p2, p3);
            mma_bf16(pc[2][0], pc[2][1], pc[2][2], pc[2][3], a0, a1, a2, a3, q0, q1);
            mma_bf16(pc[3][0], pc[3][1], pc[3][2], pc[3][3], a0, a1, a2, a3, q2, q3);
        }
        #pragma unroll
        for (int nf = 0; nf < 4; nf++) {
            int cc = s0 + wn*32 + nf*8 + 2*tg;
            *(float2*)&BDR[il0*132 + cc] = make_float2(pc[nf][0], pc[nf][1]);
            *(float2*)&BDR[il1*132 + cc] = make_float2(pc[nf][2], pc[nf][3]);
        }
    };

    stage_kv(0, 0);
    stage_rw(0, jjb0);
    stage_rw(1, jjb0 + 64);
    CP_COMMIT();

    for (int e = tid; e < 64*16; e += 256) {
        int ii = e >> 4, d4 = (e & 15) * 4;
        size_t wi = ((size_t)(i0+ii)*(BSZ*DM) + b*DM + n*DH + d4) / 2;
        uint2 qv = *(const uint2*)&g_q[wi];
        float q0 = bl(qv.x), q1 = bh(qv.x), q2 = bl(qv.y), q3 = bh(qv.y);
        float4 wv = *(const float4*)&rwb[n*DH + d4];
        float4 rv = *(const float4*)&rrb[n*DH + d4];
        smu[W_QW + ii*ASW + d4/2]     = pk(q0 + wv.x, q1 + wv.y);
        smu[W_QW + ii*ASW + d4/2 + 1] = pk(q2 + wv.z, q3 + wv.w);
        smu[W_QR + ii*ASW + d4/2]     = pk(q0 + rv.x, q1 + rv.y);
        smu[W_QR + ii*ASW + d4/2 + 1] = pk(q2 + rv.z, q3 + rv.w);
    }
    CP_WAIT0();
    __syncthreads();

    bd_pass(0, jjb0);

    float oacc[8][4];
    #pragma unroll
    for (int nf = 0; nf < 8; nf++)
        #pragma unroll
        for (int q = 0; q < 4; q++) oacc[nf][q] = 0.f;
    float l0 = 0.f, l1 = 0.f;

    for (int t = 0; t < ntiles; t++) {
        const int kvb = t & 1;
        const int j0 = t * 64;
        const int jjb = j0 - i0 + 960;

        if (t + 1 < ntiles) stage_kv(kvb ^ 1, j0 + 64);
        stage_rw(kvb, jjb0 + 64*(t + 2));
        CP_COMMIT();

        const uint32_t kso = smb + (uint32_t)(kvb ? W_K1 : W_K0)*4;
        float sc[4][4];
        #pragma unroll
        for (int nf = 0; nf < 4; nf++)
            #pragma unroll
            for (int q = 0; q < 4; q++) sc[nf][q] = 0.f;
        #pragma unroll
        for (int k0 = 0; k0 < 4; k0++) {
            uint32_t a0, a1, a2, a3, p0, p1, p2, p3, q0, q1, q2, q3;
            ldsm4(a0, a1, a2, a3, smb + W_QW*4 + aoff + k0*32);
            ldsm4(p0, p1, p2, p3, kso + boff + k0*32);
            ldsm4(q0, q1, q2, q3, kso + boff + 16*ASW*4 + k0*32);
            mma_bf16(sc[0][0], sc[0][1], sc[0][2], sc[0][3], a0, a1, a2, a3, p0, p1);
            mma_bf16(sc[1][0], sc[1][1], sc[1][2], sc[1][3], a0, a1, a2, a3, p2, p3);
            mma_bf16(sc[2][0], sc[2][1], sc[2][2], sc[2][3], a0, a1, a2, a3, q0, q1);
            mma_bf16(sc[3][0], sc[3][1], sc[3][2], sc[3][3], a0, a1, a2, a3, q2, q3);
        }

        bd_pass(kvb ^ 1, jjb0 + 64*(t + 1));
        __syncthreads();

        const int jjb2 = jjb + 63;
        uint32_t a_lo[4], a_hi[4];
        #pragma unroll
        for (int nf = 0; nf < 4; nf++) {
            int jl = wn*32 + nf*8 + 2*tg;
            int jg = j0 + jl;
            int s00 = (jjb2 + jl - il0) & 127;
            int s01 = (jjb2 + jl + 1 - il0) & 127;
            int s10 = (jjb2 + jl - il1) & 127;
            int s11 = (jjb2 + jl + 1 - il1) & 127;
            float p00 = 0.f, p01 = 0.f, p10 = 0.f, p11 = 0.f;
            if (jg <= i0 + il0 + MEMLEN)
                p00 = exp2_fast((sc[nf][0] + BDR[il0*132 + s00]) * 0.18033688f);
            if (jg + 1 <= i0 + il0 + MEMLEN)
                p01 = exp2_fast((sc[nf][1] + BDR[il0*132 + s01]) * 0.18033688f);
            if (jg <= i0 + il1 + MEMLEN)
                p10 = exp2_fast((sc[nf][2] + BDR[il1*132 + s10]) * 0.18033688f);
            if (jg + 1 <= i0 + il1 + MEMLEN)
                p11 = exp2_fast((sc[nf][3] + BDR[il1*132 + s11]) * 0.18033688f);
            l0 += p00 + p01;
            l1 += p10 + p11;
            a_lo[nf] = pk(p00, p01);
            a_hi[nf] = pk(p10, p11);
        }

        const uint32_t vso = smb + (uint32_t)(kvb ? W_V1 : W_V0)*4;
        #pragma unroll
        for (int k0 = 0; k0 < 2; k0++) {
            uint32_t a0 = a_lo[2*k0], a1 = a_hi[2*k0];
            uint32_t a2 = a_lo[2*k0+1], a3 = a_hi[2*k0+1];
            uint32_t jbase = (uint32_t)((wn*32 + k0*16)*ASW)*4;
            #pragma unroll
            for (int dd = 0; dd < 4; dd++) {
                uint32_t b0, b1, b2, b3;
                ldsm4t(b0, b1, b2, b3, vso + tvpat + jbase + (uint32_t)(dd*8)*4);
                mma_bf16(oacc[dd*2][0], oacc[dd*2][1], oacc[dd*2][2], oacc[dd*2][3],
                         a0, a1, a2, a3, b0, b1);
                mma_bf16(oacc[dd*2+1][0], oacc[dd*2+1][1], oacc[dd*2+1][2], oacc[dd*2+1][3],
                         a0, a1, a2, a3, b2, b3);
            }
        }

        CP_WAIT0();
        __syncthreads();
    }

    l0 += __shfl_xor_sync(0xffffffffu, l0, 1);
    l0 += __shfl_xor_sync(0xffffffffu, l0, 2);
    l1 += __shfl_xor_sync(0xffffffffu, l1, 1);
    l1 += __shfl_xor_sync(0xffffffffu, l1, 2);
    float* obuf = BDR;
    float* lbuf = BDR + 4*16*68;
    if (wn == 1) {
        #pragma unroll
        for (int nf = 0; nf < 8; nf++) {
            int d = nf*8 + 2*tg;
            *(float2*)&obuf[il0*68 + d] = make_float2(oacc[nf][0], oacc[nf][1]);
            *(float2*)&obuf[il1*68 + d] = make_float2(oacc[nf][2], oacc[nf][3]);
        }
        if (tg == 0) { lbuf[il0] = l0; lbuf[il1] = l1; }
    }
    __syncthreads();
    if (wn == 0) {
        float inv0 = 1.f / (l0 + lbuf[il0]);
        float inv1 = 1.f / (l1 + lbuf[il1]);
        #pragma unroll
        for (int nf = 0; nf < 8; nf++) {
            int d = nf*8 + 2*tg;
            float2 o0 = *(float2*)&obuf[il0*68 + d];
            float2 o1 = *(float2*)&obuf[il1*68 + d];
            g_avh[((size_t)(i0+il0)*(BSZ*DM) + b*DM + n*DH + d)/2] =
                pk((oacc[nf][0]+o0.x)*inv0, (oacc[nf][1]+o0.y)*inv0);
            g_avh[((size_t)(i0+il1)*(BSZ*DM) + b*DM + n*DH + d)/2] =
                pk((oacc[nf][2]+o1.x)*inv1, (oacc[nf][3]+o1.y)*inv1);
        }
    }
}

// ---------------- residual + layernorm: warp per row -------------------------
__global__ __launch_bounds__(256) void k_ln2(const float* __restrict__ w,
                                             const float* __restrict__ g,
                                             const float* __restrict__ be,
                                             float* __restrict__ out)
{
    int row = blockIdx.x * 8 + (threadIdx.x >> 5);
    int lane = threadIdx.x & 31;
    const float* wr = w    + (size_t)row * DM;
    const float* ar = g_ao + (size_t)row * DM;

    float4 x[4];
    float s = 0.f;
    #pragma unroll
    for (int c = 0; c < 4; c++) {
        int idx = c*128 + lane*4;
        float4 a = *(const float4*)&wr[idx];
        float4 o = *(const float4*)&ar[idx];
        x[c] = make_float4(a.x+o.x, a.y+o.y, a.z+o.z, a.w+o.w);
        s += x[c].x + x[c].y + x[c].z + x[c].w;
    }
    #pragma unroll
    for (int m = 16; m > 0; m >>= 1) s += __shfl_xor_sync(0xffffffffu, s, m);
    float mu = s * (1.f / DM);
    float v = 0.f;
    #pragma unroll
    for (int c = 0; c < 4; c++) {
        float dx = x[c].x - mu, dy = x[c].y - mu, dz = x[c].z - mu, dw = x[c].w - mu;
        x[c] = make_float4(dx, dy, dz, dw);
        v += dx*dx + dy*dy + dz*dz + dw*dw;
    }
    #pragma unroll
    for (int m = 16; m > 0; m >>= 1) v += __shfl_xor_sync(0xffffffffu, v, m);
    float rs = rsqrtf(v * (1.f / DM) + 1e-5f);
    #pragma unroll
    for (int c = 0; c < 4; c++) {
        int idx = c*128 + lane*4;
        float4 gg = *(const float4*)&g[idx];
        float4 bb = *(const float4*)&be[idx];
        float4 r = make_float4(x[c].x*rs*gg.x + bb.x, x[c].y*rs*gg.y + bb.y,
                               x[c].z*rs*gg.z + bb.z, x[c].w*rs*gg.w + bb.w);
        *(float4*)&out[(size_t)row*DM + idx] = r;
    }
}

// ---------------- launcher ---------------------------------------------------
extern "C" void kernel_launch(void* const* d_in, const int* in_sizes, int n_in,
                              void* d_out, int out_size)
{
    (void)in_sizes; (void)n_in; (void)out_size;
    const float* w    = (const float*)d_in[0];
    const float* r    = (const float*)d_in[1];
    const float* mems = (const float*)d_in[2];
    const float* rwb  = (const float*)d_in[3];
    const float* rrb  = (const float*)d_in[4];
    const float* qkvW = (const float*)d_in[5];
    const float* rW   = (const float*)d_in[6];
    const float* cqw  = (const float*)d_in[7];
    const float* cqb  = (const float*)d_in[8];
    const float* ckw  = (const float*)d_in[9];
    const float* ckb  = (const float*)d_in[10];
    const float* cvw  = (const float*)d_in[11];
    const float* cvb  = (const float*)d_in[12];
    const float* oW   = (const float*)d_in[13];
    const float* lng  = (const float*)d_in[14];
    const float* lnb  = (const float*)d_in[15];
    float* out = (float*)d_out;

    uint32_t *p_qkvh, *p_rkh, *p_xh, *p_wh, *p_rh, *p_rWh, *p_oWh, *p_avh;
    float *p_ao;
    cudaGetSymbolAddress((void**)&p_qkvh, g_qkvh);
    cudaGetSymbolAddress((void**)&p_rkh,  g_rkh);
    cudaGetSymbolAddress((void**)&p_xh,   g_xh);
    cudaGetSymbolAddress((void**)&p_wh,   g_wh);
    cudaGetSymbolAddress((void**)&p_rh,   g_rh);
    cudaGetSymbolAddress((void**)&p_rWh,  g_rWh);
    cudaGetSymbolAddress((void**)&p_oWh,  g_oWh);
    cudaGetSymbolAddress((void**)&p_avh,  g_avh);
    cudaGetSymbolAddress((void**)&p_ao,   g_ao);

    dim3 b256(256);

    // fused fp32 -> bf16 conversions + conv weight prep
    k_cvt6<<<2048, b256>>>(mems, w, qkvW, r, rW, oW);
    k_prepw<<<21, b256>>>(cqw, ckw, cvw);

    // QKV projection over [mems; w] (bf16 in, bf16 out)
    mm_h<<<dim3(QKV/128, (KLEN*BSZ)/128), b256>>>(p_xh, p_wh, p_qkvh, QKV, DM, 1);
    // r @ r_W^T
    mm_h<<<dim3(DM/128, KLEN/128), b256>>>(p_rh, p_rWh, p_rkh, DM, DM, 1);

    // fused convs
    int csm = (134*CSW + 7*64*CSW) * 4;
    cudaFuncSetAttribute(k_conv5, cudaFuncAttributeMaxDynamicSharedMemorySize, csm);
    k_conv5<<<dim3(40, NH*BSZ), b256, csm>>>(cqb, ckb, cvb);

    // attention (2 CTAs/SM)
    int asm_ = (W_BDR + 64*132) * 4;
    cudaFuncSetAttribute(k_attn8, cudaFuncAttributeMaxDynamicSharedMemorySize, asm_);
    k_attn8<<<dim3(QLEN/64, BSZ*NH), b256, asm_>>>(rwb, rrb);

    // output projection (bf16 A, fp32 out) + residual layernorm
    mm_h<<<dim3(DM/128, (QLEN*BSZ)/128), b256>>>(p_avh, p_oWh, p_ao, DM, DM, 0);
    k_ln2<<<(QLEN*BSZ)/8, b256>>>(w, lng, lnb, out);
}

// round 13
// speedup vs baseline: 12.3690x; 1.1623x over previous
#include <cuda_runtime.h>
#include <cuda_bf16.h>
#include <math.h>
#include <stdint.h>

#define QLEN 1024
#define KLEN 2048
#define MEMLEN 1024
#define BSZ 4
#define NH 8
#define DH 64
#define DM 512
#define QKV (3*DM)

__device__ uint32_t g_qkvh[(size_t)KLEN*BSZ*QKV/2]; // bf16 pairs (jk, b, 1536)
__device__ uint32_t g_rkh [(size_t)KLEN*DM/2];      // bf16 pairs (jj, n*64+d)
__device__ uint32_t g_q  [(size_t)QLEN*BSZ*DM/2];
__device__ uint32_t g_k  [(size_t)KLEN*BSZ*DM/2];
__device__ uint32_t g_v  [(size_t)KLEN*BSZ*DM/2];
__device__ uint32_t g_avh[(size_t)QLEN*BSZ*DM/2];   // attention out, bf16
__device__ float    g_ao [(size_t)QLEN*BSZ*DM];
__device__ uint32_t g_wt[3*7*64*32];
__device__ uint32_t g_xh [(size_t)KLEN*BSZ*DM/2];   // [mems; w]
__device__ uint32_t g_wh [(size_t)QKV*DM/2];        // qkvW
__device__ uint32_t g_rh [(size_t)KLEN*DM/2];       // r
__device__ uint32_t g_rWh[(size_t)DM*DM/2];         // rW
__device__ uint32_t g_oWh[(size_t)DM*DM/2];         // oW

__device__ __forceinline__ uint32_t pk(float x, float y) {
    __nv_bfloat162 t = __floats2bfloat162_rn(x, y);
    return *(uint32_t*)&t;
}
__device__ __forceinline__ float bl(uint32_t w) {
    __nv_bfloat16 h = *(__nv_bfloat16*)&w;
    return __bfloat162float(h);
}
__device__ __forceinline__ float bh(uint32_t w) {
    uint16_t u = (uint16_t)(w >> 16);
    __nv_bfloat16 h = *(__nv_bfloat16*)&u;
    return __bfloat162float(h);
}

__device__ __forceinline__ void mma_bf16(float& c0, float& c1, float& c2, float& c3,
                                         uint32_t a0, uint32_t a1, uint32_t a2, uint32_t a3,
                                         uint32_t b0, uint32_t b1)
{
    asm volatile("mma.sync.aligned.m16n8k16.row.col.f32.bf16.bf16.f32 "
                 "{%0,%1,%2,%3},{%4,%5,%6,%7},{%8,%9},{%0,%1,%2,%3};\n"
                 : "+f"(c0), "+f"(c1), "+f"(c2), "+f"(c3)
                 : "r"(a0), "r"(a1), "r"(a2), "r"(a3), "r"(b0), "r"(b1));
}

__device__ __forceinline__ void ldsm4(uint32_t& r0, uint32_t& r1, uint32_t& r2, uint32_t& r3,
                                      uint32_t addr)
{
    asm volatile("ldmatrix.sync.aligned.m8n8.x4.shared.b16 {%0,%1,%2,%3}, [%4];"
                 : "=r"(r0), "=r"(r1), "=r"(r2), "=r"(r3) : "r"(addr));
}
__device__ __forceinline__ void ldsm4t(uint32_t& r0, uint32_t& r1, uint32_t& r2, uint32_t& r3,
                                       uint32_t addr)
{
    asm volatile("ldmatrix.sync.aligned.m8n8.x4.trans.shared.b16 {%0,%1,%2,%3}, [%4];"
                 : "=r"(r0), "=r"(r1), "=r"(r2), "=r"(r3) : "r"(addr));
}

__device__ __forceinline__ void cpa16(uint32_t saddr, const void* gaddr) {
    asm volatile("cp.async.cg.shared.global [%0], [%1], 16;" :: "r"(saddr), "l"(gaddr));
}
__device__ __forceinline__ void cpa16z(uint32_t saddr, const void* gaddr, int ok) {
    int sz = ok ? 16 : 0;
    asm volatile("cp.async.cg.shared.global [%0], [%1], 16, %2;"
                 :: "r"(saddr), "l"(gaddr), "r"(sz));
}
#define CP_COMMIT() asm volatile("cp.async.commit_group;")
#define CP_WAIT0()  asm volatile("cp.async.wait_group 0;")
#define CP_WAIT1()  asm volatile("cp.async.wait_group 1;")

__device__ __forceinline__ float exp2_fast(float y) {
    y = fmaxf(y, -100.f);
    float z = __fadd_rn(y, 12582912.f);
    float n = __fsub_rn(z, 12582912.f);
    float f = __fsub_rn(y, n);
    float r = 0.0096181291f;
    r = fmaf(r, f, 0.055504109f);
    r = fmaf(r, f, 0.24022651f);
    r = fmaf(r, f, 0.69314718f);
    r = fmaf(r, f, 1.0f);
    int e = __float_as_int(z);
    float s = __int_as_float((e - 1262485377) << 23);
    return r * s;
}

// ---------------- fused fp32 -> bf16-pair convert (6 segments) ---------------
#define CVT_N0 (MEMLEN*BSZ*DM/2)
#define CVT_N1 (QLEN*BSZ*DM/2)
#define CVT_N2 (QKV*DM/2)
#define CVT_N3 (KLEN*DM/2)
#define CVT_N4 (DM*DM/2)
#define CVT_C0 (CVT_N0)
#define CVT_C1 (CVT_C0 + CVT_N1)
#define CVT_C2 (CVT_C1 + CVT_N2)
#define CVT_C3 (CVT_C2 + CVT_N3)
#define CVT_C4 (CVT_C3 + CVT_N4)
#define CVT_TOT (CVT_C4 + CVT_N4)
__global__ void k_cvt6(const float* __restrict__ mems, const float* __restrict__ w,
                       const float* __restrict__ qkvW, const float* __restrict__ r,
                       const float* __restrict__ rW,   const float* __restrict__ oW)
{
    int idx = blockIdx.x * blockDim.x + threadIdx.x;
    int stride = gridDim.x * blockDim.x;
    for (int i = idx; i < CVT_TOT; i += stride) {
        const float* s;
        uint32_t* d;
        int off;
        if (i < CVT_C0)      { s = mems; d = g_xh;            off = i; }
        else if (i < CVT_C1) { s = w;    d = g_xh + CVT_C0;   off = i - CVT_C0; }
        else if (i < CVT_C2) { s = qkvW; d = g_wh;            off = i - CVT_C1; }
        else if (i < CVT_C3) { s = r;    d = g_rh;            off = i - CVT_C2; }
        else if (i < CVT_C4) { s = rW;   d = g_rWh;           off = i - CVT_C3; }
        else                 { s = oW;   d = g_oWh;           off = i - CVT_C4; }
        float2 v = *(const float2*)&s[2*off];
        d[off] = pk(v.x, v.y);
    }
}

// ---------------- BF16 GEMM body: 3-stage cp.async + ldmatrix ----------------
#define GSW 12
#define NSTG 3
__device__ __forceinline__ void mm_body(const uint32_t* __restrict__ A,
                                        const uint32_t* __restrict__ B,
                                        void* __restrict__ Cout,
                                        int N, int K, int pack, int m0, int n0)
{
    __shared__ uint32_t As[NSTG][128*GSW];
    __shared__ uint32_t Bs[NSTG][128*GSW];
    const int tid = threadIdx.x;
    const int warp = tid >> 5, lane = tid & 31;
    const int wm = warp & 3, wn = warp >> 2;
    const int g = lane >> 2, tg = lane & 3;
    const int quad = lane >> 3;
    const int Kw = K / 2;
    const int iters = Kw / 8;

    const uint32_t smA = (uint32_t)__cvta_generic_to_shared(As);
    const uint32_t smB = (uint32_t)__cvta_generic_to_shared(Bs);
    const uint32_t apat = (uint32_t)((lane & 15)*GSW + (lane >> 4)*4)*4;
    const uint32_t bpat = (uint32_t)((((quad & 2)*4) + (lane & 7))*GSW + (quad & 1)*4)*4;

    float c[2][8][4];
    #pragma unroll
    for (int mt = 0; mt < 2; mt++)
        #pragma unroll
        for (int nt = 0; nt < 8; nt++)
            #pragma unroll
            for (int q = 0; q < 4; q++) c[mt][nt][q] = 0.f;

    const int lr = tid >> 1;
    const int lh = tid & 1;
    const uint32_t* Ap = A + (size_t)(m0 + lr) * Kw + lh * 4;
    const uint32_t* Bp = B + (size_t)(n0 + lr) * Kw + lh * 4;

    auto stage = [&](int s, int kw) {
        uint32_t so = (uint32_t)(s*128*GSW + lr*GSW + lh*4)*4;
        cpa16(smA + so, Ap + kw);
        cpa16(smB + so, Bp + kw);
    };

    stage(0, 0);
    CP_COMMIT();
    if (iters > 1) stage(1, 8);
    CP_COMMIT();

    for (int i = 0; i < iters; i++) {
        CP_WAIT1();
        __syncthreads();
        int pf = i + NSTG - 1;
        if (pf < iters) stage(pf % NSTG, pf * 8);
        CP_COMMIT();

        const int buf = i % NSTG;
        const uint32_t abase = smA + (uint32_t)(buf*128*GSW)*4;
        const uint32_t bbase = smB + (uint32_t)(buf*128*GSW)*4;
        uint32_t af[2][4], bf[8][2];
        #pragma unroll
        for (int mt = 0; mt < 2; mt++)
            ldsm4(af[mt][0], af[mt][1], af[mt][2], af[mt][3],
                  abase + (uint32_t)((wm*32 + mt*16)*GSW)*4 + apat);
        #pragma unroll
        for (int nt2 = 0; nt2 < 4; nt2++) {
            uint32_t b0, b1, b2, b3;
            ldsm4(b0, b1, b2, b3,
                  bbase + (uint32_t)((wn*64 + nt2*16)*GSW)*4 + bpat);
            bf[nt2*2][0] = b0;   bf[nt2*2][1] = b1;
            bf[nt2*2+1][0] = b2; bf[nt2*2+1][1] = b3;
        }
        #pragma unroll
        for (int mt = 0; mt < 2; mt++)
            #pragma unroll
            for (int nt = 0; nt < 8; nt++)
                mma_bf16(c[mt][nt][0], c[mt][nt][1], c[mt][nt][2], c[mt][nt][3],
                         af[mt][0], af[mt][1], af[mt][2], af[mt][3],
                         bf[nt][0], bf[nt][1]);
    }

    #pragma unroll
    for (int mt = 0; mt < 2; mt++) {
        int row0 = m0 + wm * 32 + mt * 16 + g;
        #pragma unroll
        for (int nt = 0; nt < 8; nt++) {
            int col = n0 + wn * 64 + nt * 8 + tg * 2;
            if (pack) {
                uint32_t* Cp = (uint32_t*)Cout;
                Cp[((size_t)row0 * N + col)/2]       = pk(c[mt][nt][0], c[mt][nt][1]);
                Cp[((size_t)(row0 + 8) * N + col)/2] = pk(c[mt][nt][2], c[mt][nt][3]);
            } else {
                float* C = (float*)Cout;
                *(float2*)&C[(size_t)row0 * N + col]       = make_float2(c[mt][nt][0], c[mt][nt][1]);
                *(float2*)&C[(size_t)(row0 + 8) * N + col] = make_float2(c[mt][nt][2], c[mt][nt][3]);
            }
        }
    }
}

// o-proj wrapper
__global__ __launch_bounds__(256, 2) void mm_h(const uint32_t* __restrict__ A,
                                               const uint32_t* __restrict__ B,
                                               void* __restrict__ Cout,
                                               int N, int K, int pack)
{
    mm_body(A, B, Cout, N, K, pack, blockIdx.y * 128, blockIdx.x * 128);
}

// fused QKV-proj + r-proj: y in [0,64) -> QKV rows, y in [64,80) -> r rows
__global__ __launch_bounds__(256, 2) void mm_qkr()
{
    int y = blockIdx.y;
    if (y < 64) {
        mm_body(g_xh, g_wh, g_qkvh, QKV, DM, 1, y * 128, blockIdx.x * 128);
    } else {
        if (blockIdx.x >= 4) return;
        mm_body(g_rh, g_rWh, g_rkh, DM, DM, 1, (y - 64) * 128, blockIdx.x * 128);
    }
}

// ---------------- weight prep ------------------------------------------------
__global__ void k_prepw(const float* __restrict__ cq,
                        const float* __restrict__ ck,
                        const float* __restrict__ cv)
{
    int idx = blockIdx.x;
    int c = idx / 7, tap = idx % 7;
    const float* src = (c == 0) ? cq : (c == 1) ? ck : cv;
    for (int e = threadIdx.x; e < 2048; e += 256) {
        int oc = e >> 5, icw = e & 31;
        float w0 = src[(oc*64 + 2*icw    )*7 + tap];
        float w1 = src[(oc*64 + 2*icw + 1)*7 + tap];
        g_wt[((c*7 + tap)*64 + oc)*32 + icw] = pk(w0, w1);
    }
}

// ---------------- fused conv via bf16 MMA + ldmatrix + cp.async --------------
#define CSW 36
#define OFF_WS (134*CSW*4)
__global__ __launch_bounds__(256, 2) void k_conv5(const float* __restrict__ cqb,
                                                  const float* __restrict__ ckb,
                                                  const float* __restrict__ cvb)
{
    extern __shared__ uint32_t cs[];
    const int bx = blockIdx.x;
    int c, t0, len, posoff, chanoff;
    const float* cb;
    uint32_t* outp;
    if (bx < 8)       { c = 0; t0 = bx*128;      len = QLEN; posoff = MEMLEN; chanoff = 0;    cb = cqb; outp = g_q; }
    else if (bx < 24) { c = 1; t0 = (bx-8)*128;  len = KLEN; posoff = 0;      chanoff = DM;   cb = ckb; outp = g_k; }
    else              { c = 2; t0 = (bx-24)*128; len = KLEN; posoff = 0;      chanoff = 2*DM; cb = cvb; outp = g_v; }
    const int nb = blockIdx.y;
    const int n = nb >> 2, b = nb & 3;
    const int tid = threadIdx.x;
    const int warp = tid >> 5, lane = tid & 31;
    const int wm = warp;
    const int g = lane >> 2, tg = lane & 3;
    const int quad = lane >> 3;
    const uint32_t smbC = (uint32_t)__cvta_generic_to_shared(cs);

    for (int e = tid; e < 134*8; e += 256) {
        int u = e >> 3, w4 = (e & 7) * 4;
        int pos = t0 + u - 3;
        int ok = (pos >= 0 && pos < len);
        int pc = ok ? pos : 0;
        cpa16z(smbC + (uint32_t)(u*CSW + w4)*4,
               &g_qkvh[((size_t)(pc + posoff)*(BSZ*QKV) + b*QKV + chanoff + n*DH)/2 + w4], ok);
    }
    {
        const uint32_t* src = g_wt + c*7*64*32;
        for (int e = tid; e < 3584; e += 256) {
            int s4 = e * 4;
            int to = s4 >> 5, icw = s4 & 31;
            cpa16(smbC + OFF_WS + (uint32_t)(to*CSW + icw)*4, &src[s4]);
        }
    }
    CP_COMMIT();
    CP_WAIT0();
    __syncthreads();

    float acc[8][4];
    #pragma unroll
    for (int nf = 0; nf < 8; nf++)
        #pragma unroll
        for (int q = 0; q < 4; q++) acc[nf][q] = 0.f;

    const uint32_t bpat = (uint32_t)((((quad & 2)*4) + (lane & 7))*CSW + (quad & 1)*4)*4;

    #pragma unroll
    for (int tap = 0; tap < 7; tap++) {
        const uint32_t apat = (uint32_t)((wm*16 + (lane & 15) + tap)*CSW + (lane >> 4)*4)*4;
        #pragma unroll
        for (int k0 = 0; k0 < 4; k0++) {
            uint32_t a0, a1, a2, a3;
            ldsm4(a0, a1, a2, a3, smbC + apat + k0*32);
            #pragma unroll
            for (int nf2 = 0; nf2 < 4; nf2++) {
                uint32_t b0, b1, b2, b3;
                ldsm4(b0, b1, b2, b3,
                      smbC + OFF_WS + bpat + (uint32_t)((tap*64 + nf2*16)*CSW)*4 + k0*32);
                mma_bf16(acc[nf2*2][0], acc[nf2*2][1], acc[nf2*2][2], acc[nf2*2][3],
                         a0, a1, a2, a3, b0, b1);
                mma_bf16(acc[nf2*2+1][0], acc[nf2*2+1][1], acc[nf2*2+1][2], acc[nf2*2+1][3],
                         a0, a1, a2, a3, b2, b3);
            }
        }
    }

    #pragma unroll
    for (int nf = 0; nf < 8; nf++) {
        int oc = nf*8 + 2*tg;
        float2 bb = *(const float2*)&cb[oc];
        int row = t0 + wm*16 + g;
        size_t w0 = ((size_t)row*(BSZ*DM) + b*DM)/2 + n*32 + nf*4 + tg;
        size_t w1 = ((size_t)(row+8)*(BSZ*DM) + b*DM)/2 + n*32 + nf*4 + tg;
        outp[w0] = pk(acc[nf][0] + bb.x, acc[nf][1] + bb.y);
        outp[w1] = pk(acc[nf][2] + bb.x, acc[nf][3] + bb.y);
    }
}

// ---------------- attention v9: tile-level mask hoisting ---------------------
#define ASW 36
#define W_QW 0
#define W_QR 2304
#define W_K0 4608
#define W_K1 6912
#define W_V0 9216
#define W_V1 11520
#define W_R0 13824
#define W_R1 16128
#define W_BDR 18432
__global__ __launch_bounds__(256, 2) void k_attn9(const float* __restrict__ rwb,
                                                  const float* __restrict__ rrb)
{
    extern __shared__ uint32_t smu[];
    float* BDR = (float*)(smu + W_BDR);

    const int i0 = (gridDim.x - 1 - blockIdx.x) * 64;
    const int bn = blockIdx.y;
    const int b = bn >> 3, n = bn & 7;
    const int tid = threadIdx.x;
    const int warp = tid >> 5, lane = tid & 31;
    const int wm = warp & 3, wn = warp >> 2;
    const int g = lane >> 2, tg = lane & 3;
    const int quad = lane >> 3;

    const uint32_t smb = (uint32_t)__cvta_generic_to_shared(smu);
    const uint32_t aoff  = (uint32_t)((wm*16 + (lane & 15))*ASW + (lane >> 4)*4)*4;
    const uint32_t bpat  = (uint32_t)((((quad & 2)*4) + (lane & 7))*ASW + (quad & 1)*4)*4;
    const uint32_t boff  = bpat + (uint32_t)(wn*32)*ASW*4;
    const uint32_t tvpat = (uint32_t)(((quad & 1)*8 + (lane & 7))*ASW + (quad >> 1)*4)*4;

    const int il0 = wm*16 + g;
    const int il1 = il0 + 8;
    const int jjb0 = 960 - i0;
    const int ntiles = i0/64 + 17;

    auto stage_kv = [&](int buf, int j0c) {
        const uint32_t kb = smb + (uint32_t)(buf ? W_K1 : W_K0)*4;
        const uint32_t vb = smb + (uint32_t)(buf ? W_V1 : W_V0)*4;
        #pragma unroll
        for (int e0 = 0; e0 < 2; e0++) {
            int e = tid + e0*256;
            int jl = e >> 3, w4 = (e & 7) * 4;
            size_t wi = ((size_t)(j0c + jl)*(BSZ*DM) + b*DM + n*DH)/2 + w4;
            uint32_t so = (uint32_t)(jl*ASW + w4)*4;
            cpa16(kb + so, &g_k[wi]);
            cpa16(vb + so, &g_v[wi]);
        }
    };
    auto stage_rw = [&](int buf, int cb2) {
        const uint32_t rb = smb + (uint32_t)(buf ? W_R1 : W_R0)*4;
        #pragma unroll
        for (int e0 = 0; e0 < 2; e0++) {
            int e = tid + e0*256;
            int l = e >> 3, w4 = (e & 7) * 4;
            int jj = cb2 + l;
            int ok = (jj < KLEN);
            int jc = ok ? jj : (KLEN - 1);
            cpa16z(rb + (uint32_t)(l*ASW + w4)*4,
                   &g_rkh[((size_t)jc*DM + n*DH)/2 + w4], ok);
        }
    };
    auto bd_pass = [&](int rbuf, int cb2) {
        const uint32_t rwo = smb + (uint32_t)(rbuf ? W_R1 : W_R0)*4;
        const int s0 = cb2 & 127;
        float pc[4][4];
        #pragma unroll
        for (int nf = 0; nf < 4; nf++)
            #pragma unroll
            for (int q = 0; q < 4; q++) pc[nf][q] = 0.f;
        #pragma unroll
        for (int k0 = 0; k0 < 4; k0++) {
            uint32_t a0, a1, a2, a3, p0, p1, p2, p3, q0, q1, q2, q3;
            ldsm4(a0, a1, a2, a3, smb + W_QR*4 + aoff + k0*32);
            ldsm4(p0, p1, p2, p3, rwo + boff + k0*32);
            ldsm4(q0, q1, q2, q3, rwo + boff + 16*ASW*4 + k0*32);
            mma_bf16(pc[0][0], pc[0][1], pc[0][2], pc[0][3], a0, a1, a2, a3, p0, p1);
            mma_bf16(pc[1][0], pc[1][1], pc[1][2], pc[1][3], a0, a1, a2, a3, p2, p3);
            mma_bf16(pc[2][0], pc[2][1], pc[2][2], pc[2][3], a0, a1, a2, a3, q0, q1);
            mma_bf16(pc[3][0], pc[3][1], pc[3][2], pc[3][3], a0, a1, a2, a3, q2, q3);
        }
        #pragma unroll
        for (int nf = 0; nf < 4; nf++) {
            int cc = s0 + wn*32 + nf*8 + 2*tg;
            *(float2*)&BDR[il0*132 + cc] = make_float2(pc[nf][0], pc[nf][1]);
            *(float2*)&BDR[il1*132 + cc] = make_float2(pc[nf][2], pc[nf][3]);
        }
    };

    stage_kv(0, 0);
    stage_rw(0, jjb0);
    stage_rw(1, jjb0 + 64);
    CP_COMMIT();

    for (int e = tid; e < 64*16; e += 256) {
        int ii = e >> 4, d4 = (e & 15) * 4;
        size_t wi = ((size_t)(i0+ii)*(BSZ*DM) + b*DM + n*DH + d4) / 2;
        uint2 qv = *(const uint2*)&g_q[wi];
        float q0 = bl(qv.x), q1 = bh(qv.x), q2 = bl(qv.y), q3 = bh(qv.y);
        float4 wv = *(const float4*)&rwb[n*DH + d4];
        float4 rv = *(const float4*)&rrb[n*DH + d4];
        smu[W_QW + ii*ASW + d4/2]     = pk(q0 + wv.x, q1 + wv.y);
        smu[W_QW + ii*ASW + d4/2 + 1] = pk(q2 + wv.z, q3 + wv.w);
        smu[W_QR + ii*ASW + d4/2]     = pk(q0 + rv.x, q1 + rv.y);
        smu[W_QR + ii*ASW + d4/2 + 1] = pk(q2 + rv.z, q3 + rv.w);
    }
    CP_WAIT0();
    __syncthreads();

    bd_pass(0, jjb0);

    float oacc[8][4];
    #pragma unroll
    for (int nf = 0; nf < 8; nf++)
        #pragma unroll
        for (int q = 0; q < 4; q++) oacc[nf][q] = 0.f;
    float l0 = 0.f, l1 = 0.f;

    for (int t = 0; t < ntiles; t++) {
        const int kvb = t & 1;
        const int j0 = t * 64;
        const int jjb = j0 - i0 + 960;

        if (t + 1 < ntiles) stage_kv(kvb ^ 1, j0 + 64);
        stage_rw(kvb, jjb0 + 64*(t + 2));
        CP_COMMIT();

        const uint32_t kso = smb + (uint32_t)(kvb ? W_K1 : W_K0)*4;
        float sc[4][4];
        #pragma unroll
        for (int nf = 0; nf < 4; nf++)
            #pragma unroll
            for (int q = 0; q < 4; q++) sc[nf][q] = 0.f;
        #pragma unroll
        for (int k0 = 0; k0 < 4; k0++) {
            uint32_t a0, a1, a2, a3, p0, p1, p2, p3, q0, q1, q2, q3;
            ldsm4(a0, a1, a2, a3, smb + W_QW*4 + aoff + k0*32);
            ldsm4(p0, p1, p2, p3, kso + boff + k0*32);
            ldsm4(q0, q1, q2, q3, kso + boff + 16*ASW*4 + k0*32);
            mma_bf16(sc[0][0], sc[0][1], sc[0][2], sc[0][3], a0, a1, a2, a3, p0, p1);
            mma_bf16(sc[1][0], sc[1][1], sc[1][2], sc[1][3], a0, a1, a2, a3, p2, p3);
            mma_bf16(sc[2][0], sc[2][1], sc[2][2], sc[2][3], a0, a1, a2, a3, q0, q1);
            mma_bf16(sc[3][0], sc[3][1], sc[3][2], sc[3][3], a0, a1, a2, a3, q2, q3);
        }

        bd_pass(kvb ^ 1, jjb0 + 64*(t + 1));
        __syncthreads();

        const int jjb2 = jjb + 63;
        uint32_t a_lo[4], a_hi[4];
        if (t + 1 < ntiles) {
            // fast path: no element can be masked (j0+63 <= i0+MEMLEN)
            #pragma unroll
            for (int nf = 0; nf < 4; nf++) {
                int jl = wn*32 + nf*8 + 2*tg;
                int s00 = (jjb2 + jl - il0) & 127;
                int s01 = (jjb2 + jl + 1 - il0) & 127;
                int s10 = (jjb2 + jl - il1) & 127;
                int s11 = (jjb2 + jl + 1 - il1) & 127;
                float p00 = exp2_fast((sc[nf][0] + BDR[il0*132 + s00]) * 0.18033688f);
                float p01 = exp2_fast((sc[nf][1] + BDR[il0*132 + s01]) * 0.18033688f);
                float p10 = exp2_fast((sc[nf][2] + BDR[il1*132 + s10]) * 0.18033688f);
                float p11 = exp2_fast((sc[nf][3] + BDR[il1*132 + s11]) * 0.18033688f);
                l0 += p00 + p01;
                l1 += p10 + p11;
                a_lo[nf] = pk(p00, p01);
                a_hi[nf] = pk(p10, p11);
            }
        } else {
            #pragma unroll
            for (int nf = 0; nf < 4; nf++) {
                int jl = wn*32 + nf*8 + 2*tg;
                int jg = j0 + jl;
                int s00 = (jjb2 + jl - il0) & 127;
                int s01 = (jjb2 + jl + 1 - il0) & 127;
                int s10 = (jjb2 + jl - il1) & 127;
                int s11 = (jjb2 + jl + 1 - il1) & 127;
                float p00 = 0.f, p01 = 0.f, p10 = 0.f, p11 = 0.f;
                if (jg <= i0 + il0 + MEMLEN)
                    p00 = exp2_fast((sc[nf][0] + BDR[il0*132 + s00]) * 0.18033688f);
                if (jg + 1 <= i0 + il0 + MEMLEN)
                    p01 = exp2_fast((sc[nf][1] + BDR[il0*132 + s01]) * 0.18033688f);
                if (jg <= i0 + il1 + MEMLEN)
                    p10 = exp2_fast((sc[nf][2] + BDR[il1*132 + s10]) * 0.18033688f);
                if (jg + 1 <= i0 + il1 + MEMLEN)
                    p11 = exp2_fast((sc[nf][3] + BDR[il1*132 + s11]) * 0.18033688f);
                l0 += p00 + p01;
                l1 += p10 + p11;
                a_lo[nf] = pk(p00, p01);
                a_hi[nf] = pk(p10, p11);
            }
        }

        const uint32_t vso = smb + (uint32_t)(kvb ? W_V1 : W_V0)*4;
        #pragma unroll
        for (int k0 = 0; k0 < 2; k0++) {
            uint32_t a0 = a_lo[2*k0], a1 = a_hi[2*k0];
            uint32_t a2 = a_lo[2*k0+1], a3 = a_hi[2*k0+1];
            uint32_t jbase = (uint32_t)((wn*32 + k0*16)*ASW)*4;
            #pragma unroll
            for (int dd = 0; dd < 4; dd++) {
                uint32_t b0, b1, b2, b3;
                ldsm4t(b0, b1, b2, b3, vso + tvpat + jbase + (uint32_t)(dd*8)*4);
                mma_bf16(oacc[dd*2][0], oacc[dd*2][1], oacc[dd*2][2], oacc[dd*2][3],
                         a0, a1, a2, a3, b0, b1);
                mma_bf16(oacc[dd*2+1][0], oacc[dd*2+1][1], oacc[dd*2+1][2], oacc[dd*2+1][3],
                         a0, a1, a2, a3, b2, b3);
            }
        }

        CP_WAIT0();
        __syncthreads();
    }

    l0 += __shfl_xor_sync(0xffffffffu, l0, 1);
    l0 += __shfl_xor_sync(0xffffffffu, l0, 2);
    l1 += __shfl_xor_sync(0xffffffffu, l1, 1);
    l1 += __shfl_xor_sync(0xffffffffu, l1, 2);
    float* obuf = BDR;
    float* lbuf = BDR + 4*16*68;
    if (wn == 1) {
        #pragma unroll
        for (int nf = 0; nf < 8; nf++) {
            int d = nf*8 + 2*tg;
            *(float2*)&obuf[il0*68 + d] = make_float2(oacc[nf][0], oacc[nf][1]);
            *(float2*)&obuf[il1*68 + d] = make_float2(oacc[nf][2], oacc[nf][3]);
        }
        if (tg == 0) { lbuf[il0] = l0; lbuf[il1] = l1; }
    }
    __syncthreads();
    if (wn == 0) {
        float inv0 = 1.f / (l0 + lbuf[il0]);
        float inv1 = 1.f / (l1 + lbuf[il1]);
        #pragma unroll
        for (int nf = 0; nf < 8; nf++) {
            int d = nf*8 + 2*tg;
            float2 o0 = *(float2*)&obuf[il0*68 + d];
            float2 o1 = *(float2*)&obuf[il1*68 + d];
            g_avh[((size_t)(i0+il0)*(BSZ*DM) + b*DM + n*DH + d)/2] =
                pk((oacc[nf][0]+o0.x)*inv0, (oacc[nf][1]+o0.y)*inv0);
            g_avh[((size_t)(i0+il1)*(BSZ*DM) + b*DM + n*DH + d)/2] =
                pk((oacc[nf][2]+o1.x)*inv1, (oacc[nf][3]+o1.y)*inv1);
        }
    }
}

// ---------------- residual + layernorm: warp per row -------------------------
__global__ __launch_bounds__(256) void k_ln2(const float* __restrict__ w,
                                             const float* __restrict__ g,
                                             const float* __restrict__ be,
                                             float* __restrict__ out)
{
    int row = blockIdx.x * 8 + (threadIdx.x >> 5);
    int lane = threadIdx.x & 31;
    const float* wr = w    + (size_t)row * DM;
    const float* ar = g_ao + (size_t)row * DM;

    float4 x[4];
    float s = 0.f;
    #pragma unroll
    for (int c = 0; c < 4; c++) {
        int idx = c*128 + lane*4;
        float4 a = *(const float4*)&wr[idx];
        float4 o = *(const float4*)&ar[idx];
        x[c] = make_float4(a.x+o.x, a.y+o.y, a.z+o.z, a.w+o.w);
        s += x[c].x + x[c].y + x[c].z + x[c].w;
    }
    #pragma unroll
    for (int m = 16; m > 0; m >>= 1) s += __shfl_xor_sync(0xffffffffu, s, m);
    float mu = s * (1.f / DM);
    float v = 0.f;
    #pragma unroll
    for (int c = 0; c < 4; c++) {
        float dx = x[c].x - mu, dy = x[c].y - mu, dz = x[c].z - mu, dw = x[c].w - mu;
        x[c] = make_float4(dx, dy, dz, dw);
        v += dx*dx + dy*dy + dz*dz + dw*dw;
    }
    #pragma unroll
    for (int m = 16; m > 0; m >>= 1) v += __shfl_xor_sync(0xffffffffu, v, m);
    float rs = rsqrtf(v * (1.f / DM) + 1e-5f);
    #pragma unroll
    for (int c = 0; c < 4; c++) {
        int idx = c*128 + lane*4;
        float4 gg = *(const float4*)&g[idx];
        float4 bb = *(const float4*)&be[idx];
        float4 r = make_float4(x[c].x*rs*gg.x + bb.x, x[c].y*rs*gg.y + bb.y,
                               x[c].z*rs*gg.z + bb.z, x[c].w*rs*gg.w + bb.w);
        *(float4*)&out[(size_t)row*DM + idx] = r;
    }
}

// ---------------- launcher ---------------------------------------------------
extern "C" void kernel_launch(void* const* d_in, const int* in_sizes, int n_in,
                              void* d_out, int out_size)
{
    (void)in_sizes; (void)n_in; (void)out_size;
    const float* w    = (const float*)d_in[0];
    const float* r    = (const float*)d_in[1];
    const float* mems = (const float*)d_in[2];
    const float* rwb  = (const float*)d_in[3];
    const float* rrb  = (const float*)d_in[4];
    const float* qkvW = (const float*)d_in[5];
    const float* rW   = (const float*)d_in[6];
    const float* cqw  = (const float*)d_in[7];
    const float* cqb  = (const float*)d_in[8];
    const float* ckw  = (const float*)d_in[9];
    const float* ckb  = (const float*)d_in[10];
    const float* cvw  = (const float*)d_in[11];
    const float* cvb  = (const float*)d_in[12];
    const float* oW   = (const float*)d_in[13];
    const float* lng  = (const float*)d_in[14];
    const float* lnb  = (const float*)d_in[15];
    float* out = (float*)d_out;

    uint32_t *p_avh, *p_oWh;
    float *p_ao;
    cudaGetSymbolAddress((void**)&p_avh, g_avh);
    cudaGetSymbolAddress((void**)&p_oWh, g_oWh);
    cudaGetSymbolAddress((void**)&p_ao,  g_ao);

    dim3 b256(256);

    // fused fp32 -> bf16 conversions + conv weight prep
    k_cvt6<<<2048, b256>>>(mems, w, qkvW, r, rW, oW);
    k_prepw<<<21, b256>>>(cqw, ckw, cvw);

    // fused QKV projection + r-projection (one launch)
    mm_qkr<<<dim3(QKV/128, 80), b256>>>();

    // fused convs
    int csm = (134*CSW + 7*64*CSW) * 4;
    cudaFuncSetAttribute(k_conv5, cudaFuncAttributeMaxDynamicSharedMemorySize, csm);
    k_conv5<<<dim3(40, NH*BSZ), b256, csm>>>(cqb, ckb, cvb);

    // attention (2 CTAs/SM)
    int asm_ = (W_BDR + 64*132) * 4;
    cudaFuncSetAttribute(k_attn9, cudaFuncAttributeMaxDynamicSharedMemorySize, asm_);
    k_attn9<<<dim3(QLEN/64, BSZ*NH), b256, asm_>>>(rwb, rrb);

    // output projection (bf16 A, fp32 out) + residual layernorm
    mm_h<<<dim3(DM/128, (QLEN*BSZ)/128), b256>>>(p_avh, p_oWh, p_ao, DM, DM, 0);
    k_ln2<<<(QLEN*BSZ)/8, b256>>>(w, lng, lnb, out);
}

// round 14
// speedup vs baseline: 12.9113x; 1.0438x over previous
#include <cuda_runtime.h>
#include <cuda_bf16.h>
#include <math.h>
#include <stdint.h>

#define QLEN 1024
#define KLEN 2048
#define MEMLEN 1024
#define BSZ 4
#define NH 8
#define DH 64
#define DM 512
#define QKV (3*DM)

__device__ uint32_t g_qkvh[(size_t)KLEN*BSZ*QKV/2]; // bf16 pairs (jk, b, 1536)
__device__ uint32_t g_rkh [(size_t)KLEN*DM/2];      // bf16 pairs (jj, n*64+d)
__device__ uint32_t g_q  [(size_t)QLEN*BSZ*DM/2];
__device__ uint32_t g_k  [(size_t)KLEN*BSZ*DM/2];
__device__ uint32_t g_v  [(size_t)KLEN*BSZ*DM/2];
__device__ uint32_t g_avh[(size_t)QLEN*BSZ*DM/2];   // attention out, bf16
__device__ float    g_ao [(size_t)QLEN*BSZ*DM];
__device__ uint32_t g_wt[3*7*64*32];
__device__ uint32_t g_xh [(size_t)KLEN*BSZ*DM/2];   // [mems; w]
__device__ uint32_t g_wh [(size_t)QKV*DM/2];        // qkvW
__device__ uint32_t g_rh [(size_t)KLEN*DM/2];       // r
__device__ uint32_t g_rWh[(size_t)DM*DM/2];         // rW
__device__ uint32_t g_oWh[(size_t)DM*DM/2];         // oW

__device__ __forceinline__ uint32_t pk(float x, float y) {
    __nv_bfloat162 t = __floats2bfloat162_rn(x, y);
    return *(uint32_t*)&t;
}
__device__ __forceinline__ float bl(uint32_t w) {
    __nv_bfloat16 h = *(__nv_bfloat16*)&w;
    return __bfloat162float(h);
}
__device__ __forceinline__ float bh(uint32_t w) {
    uint16_t u = (uint16_t)(w >> 16);
    __nv_bfloat16 h = *(__nv_bfloat16*)&u;
    return __bfloat162float(h);
}

__device__ __forceinline__ void mma_bf16(float& c0, float& c1, float& c2, float& c3,
                                         uint32_t a0, uint32_t a1, uint32_t a2, uint32_t a3,
                                         uint32_t b0, uint32_t b1)
{
    asm volatile("mma.sync.aligned.m16n8k16.row.col.f32.bf16.bf16.f32 "
                 "{%0,%1,%2,%3},{%4,%5,%6,%7},{%8,%9},{%0,%1,%2,%3};\n"
                 : "+f"(c0), "+f"(c1), "+f"(c2), "+f"(c3)
                 : "r"(a0), "r"(a1), "r"(a2), "r"(a3), "r"(b0), "r"(b1));
}

__device__ __forceinline__ void ldsm4(uint32_t& r0, uint32_t& r1, uint32_t& r2, uint32_t& r3,
                                      uint32_t addr)
{
    asm volatile("ldmatrix.sync.aligned.m8n8.x4.shared.b16 {%0,%1,%2,%3}, [%4];"
                 : "=r"(r0), "=r"(r1), "=r"(r2), "=r"(r3) : "r"(addr));
}
__device__ __forceinline__ void ldsm4t(uint32_t& r0, uint32_t& r1, uint32_t& r2, uint32_t& r3,
                                       uint32_t addr)
{
    asm volatile("ldmatrix.sync.aligned.m8n8.x4.trans.shared.b16 {%0,%1,%2,%3}, [%4];"
                 : "=r"(r0), "=r"(r1), "=r"(r2), "=r"(r3) : "r"(addr));
}

__device__ __forceinline__ void cpa16(uint32_t saddr, const void* gaddr) {
    asm volatile("cp.async.cg.shared.global [%0], [%1], 16;" :: "r"(saddr), "l"(gaddr));
}
__device__ __forceinline__ void cpa16z(uint32_t saddr, const void* gaddr, int ok) {
    int sz = ok ? 16 : 0;
    asm volatile("cp.async.cg.shared.global [%0], [%1], 16, %2;"
                 :: "r"(saddr), "l"(gaddr), "r"(sz));
}
#define CP_COMMIT() asm volatile("cp.async.commit_group;")
#define CP_WAIT0()  asm volatile("cp.async.wait_group 0;")
#define CP_WAIT1()  asm volatile("cp.async.wait_group 1;")

__device__ __forceinline__ float exp2_fast(float y) {
    y = fmaxf(y, -100.f);
    float z = __fadd_rn(y, 12582912.f);
    float n = __fsub_rn(z, 12582912.f);
    float f = __fsub_rn(y, n);
    float r = 0.0096181291f;
    r = fmaf(r, f, 0.055504109f);
    r = fmaf(r, f, 0.24022651f);
    r = fmaf(r, f, 0.69314718f);
    r = fmaf(r, f, 1.0f);
    int e = __float_as_int(z);
    float s = __int_as_float((e - 1262485377) << 23);
    return r * s;
}

// ---------------- fused fp32 -> bf16 convert + conv weight prep (7 segs) -----
#define CVT_N0 (MEMLEN*BSZ*DM/2)
#define CVT_N1 (QLEN*BSZ*DM/2)
#define CVT_N2 (QKV*DM/2)
#define CVT_N3 (KLEN*DM/2)
#define CVT_N4 (DM*DM/2)
#define CVT_N6 (3*7*64*32)
#define CVT_C0 (CVT_N0)
#define CVT_C1 (CVT_C0 + CVT_N1)
#define CVT_C2 (CVT_C1 + CVT_N2)
#define CVT_C3 (CVT_C2 + CVT_N3)
#define CVT_C4 (CVT_C3 + CVT_N4)
#define CVT_C5 (CVT_C4 + CVT_N4)
#define CVT_TOT (CVT_C5 + CVT_N6)
__global__ void k_cvt7(const float* __restrict__ mems, const float* __restrict__ w,
                       const float* __restrict__ qkvW, const float* __restrict__ r,
                       const float* __restrict__ rW,   const float* __restrict__ oW,
                       const float* __restrict__ cq,   const float* __restrict__ ck,
                       const float* __restrict__ cv)
{
    int idx = blockIdx.x * blockDim.x + threadIdx.x;
    int stride = gridDim.x * blockDim.x;
    for (int i = idx; i < CVT_TOT; i += stride) {
        if (i < CVT_C5) {
            const float* s;
            uint32_t* d;
            int off;
            if (i < CVT_C0)      { s = mems; d = g_xh;            off = i; }
            else if (i < CVT_C1) { s = w;    d = g_xh + CVT_C0;   off = i - CVT_C0; }
            else if (i < CVT_C2) { s = qkvW; d = g_wh;            off = i - CVT_C1; }
            else if (i < CVT_C3) { s = r;    d = g_rh;            off = i - CVT_C2; }
            else if (i < CVT_C4) { s = rW;   d = g_rWh;           off = i - CVT_C3; }
            else                 { s = oW;   d = g_oWh;           off = i - CVT_C4; }
            float2 v = *(const float2*)&s[2*off];
            d[off] = pk(v.x, v.y);
        } else {
            int off = i - CVT_C5;
            int ct = off >> 11;          // c*7 + tap
            int c = ct / 7, tap = ct % 7;
            int e = off & 2047;
            int oc = e >> 5, icw = e & 31;
            const float* src = (c == 0) ? cq : (c == 1) ? ck : cv;
            float w0 = src[(oc*64 + 2*icw    )*7 + tap];
            float w1 = src[(oc*64 + 2*icw + 1)*7 + tap];
            g_wt[(ct*64 + oc)*32 + icw] = pk(w0, w1);
        }
    }
}

// ---------------- BF16 GEMM body: 3-stage cp.async + ldmatrix ----------------
#define GSW 12
#define NSTG 3
__device__ __forceinline__ void mm_body(const uint32_t* __restrict__ A,
                                        const uint32_t* __restrict__ B,
                                        void* __restrict__ Cout,
                                        int N, int K, int pack, int m0, int n0)
{
    __shared__ uint32_t As[NSTG][128*GSW];
    __shared__ uint32_t Bs[NSTG][128*GSW];
    const int tid = threadIdx.x;
    const int warp = tid >> 5, lane = tid & 31;
    const int wm = warp & 3, wn = warp >> 2;
    const int g = lane >> 2, tg = lane & 3;
    const int quad = lane >> 3;
    const int Kw = K / 2;
    const int iters = Kw / 8;

    const uint32_t smA = (uint32_t)__cvta_generic_to_shared(As);
    const uint32_t smB = (uint32_t)__cvta_generic_to_shared(Bs);
    const uint32_t apat = (uint32_t)((lane & 15)*GSW + (lane >> 4)*4)*4;
    const uint32_t bpat = (uint32_t)((((quad & 2)*4) + (lane & 7))*GSW + (quad & 1)*4)*4;

    float c[2][8][4];
    #pragma unroll
    for (int mt = 0; mt < 2; mt++)
        #pragma unroll
        for (int nt = 0; nt < 8; nt++)
            #pragma unroll
            for (int q = 0; q < 4; q++) c[mt][nt][q] = 0.f;

    const int lr = tid >> 1;
    const int lh = tid & 1;
    const uint32_t* Ap = A + (size_t)(m0 + lr) * Kw + lh * 4;
    const uint32_t* Bp = B + (size_t)(n0 + lr) * Kw + lh * 4;

    auto stage = [&](int s, int kw) {
        uint32_t so = (uint32_t)(s*128*GSW + lr*GSW + lh*4)*4;
        cpa16(smA + so, Ap + kw);
        cpa16(smB + so, Bp + kw);
    };

    stage(0, 0);
    CP_COMMIT();
    if (iters > 1) stage(1, 8);
    CP_COMMIT();

    for (int i = 0; i < iters; i++) {
        CP_WAIT1();
        __syncthreads();
        int pf = i + NSTG - 1;
        if (pf < iters) stage(pf % NSTG, pf * 8);
        CP_COMMIT();

        const int buf = i % NSTG;
        const uint32_t abase = smA + (uint32_t)(buf*128*GSW)*4;
        const uint32_t bbase = smB + (uint32_t)(buf*128*GSW)*4;
        uint32_t af[2][4], bf[8][2];
        #pragma unroll
        for (int mt = 0; mt < 2; mt++)
            ldsm4(af[mt][0], af[mt][1], af[mt][2], af[mt][3],
                  abase + (uint32_t)((wm*32 + mt*16)*GSW)*4 + apat);
        #pragma unroll
        for (int nt2 = 0; nt2 < 4; nt2++) {
            uint32_t b0, b1, b2, b3;
            ldsm4(b0, b1, b2, b3,
                  bbase + (uint32_t)((wn*64 + nt2*16)*GSW)*4 + bpat);
            bf[nt2*2][0] = b0;   bf[nt2*2][1] = b1;
            bf[nt2*2+1][0] = b2; bf[nt2*2+1][1] = b3;
        }
        #pragma unroll
        for (int mt = 0; mt < 2; mt++)
            #pragma unroll
            for (int nt = 0; nt < 8; nt++)
                mma_bf16(c[mt][nt][0], c[mt][nt][1], c[mt][nt][2], c[mt][nt][3],
                         af[mt][0], af[mt][1], af[mt][2], af[mt][3],
                         bf[nt][0], bf[nt][1]);
    }

    #pragma unroll
    for (int mt = 0; mt < 2; mt++) {
        int row0 = m0 + wm * 32 + mt * 16 + g;
        #pragma unroll
        for (int nt = 0; nt < 8; nt++) {
            int col = n0 + wn * 64 + nt * 8 + tg * 2;
            if (pack) {
                uint32_t* Cp = (uint32_t*)Cout;
                Cp[((size_t)row0 * N + col)/2]       = pk(c[mt][nt][0], c[mt][nt][1]);
                Cp[((size_t)(row0 + 8) * N + col)/2] = pk(c[mt][nt][2], c[mt][nt][3]);
            } else {
                float* C = (float*)Cout;
                *(float2*)&C[(size_t)row0 * N + col]       = make_float2(c[mt][nt][0], c[mt][nt][1]);
                *(float2*)&C[(size_t)(row0 + 8) * N + col] = make_float2(c[mt][nt][2], c[mt][nt][3]);
            }
        }
    }
}

__global__ __launch_bounds__(256, 2) void mm_h(const uint32_t* __restrict__ A,
                                               const uint32_t* __restrict__ B,
                                               void* __restrict__ Cout,
                                               int N, int K, int pack)
{
    mm_body(A, B, Cout, N, K, pack, blockIdx.y * 128, blockIdx.x * 128);
}

__global__ __launch_bounds__(256, 2) void mm_qkr()
{
    int y = blockIdx.y;
    if (y < 64) {
        mm_body(g_xh, g_wh, g_qkvh, QKV, DM, 1, y * 128, blockIdx.x * 128);
    } else {
        if (blockIdx.x >= 4) return;
        mm_body(g_rh, g_rWh, g_rkh, DM, DM, 1, (y - 64) * 128, blockIdx.x * 128);
    }
}

// ---------------- fused conv v6: 4m x 2n warp tiling -------------------------
#define CSW 36
#define OFF_WS (134*CSW*4)
__global__ __launch_bounds__(256, 2) void k_conv6(const float* __restrict__ cqb,
                                                  const float* __restrict__ ckb,
                                                  const float* __restrict__ cvb)
{
    extern __shared__ uint32_t cs[];
    const int bx = blockIdx.x;
    int c, t0, len, posoff, chanoff;
    const float* cb;
    uint32_t* outp;
    if (bx < 8)       { c = 0; t0 = bx*128;      len = QLEN; posoff = MEMLEN; chanoff = 0;    cb = cqb; outp = g_q; }
    else if (bx < 24) { c = 1; t0 = (bx-8)*128;  len = KLEN; posoff = 0;      chanoff = DM;   cb = ckb; outp = g_k; }
    else              { c = 2; t0 = (bx-24)*128; len = KLEN; posoff = 0;      chanoff = 2*DM; cb = cvb; outp = g_v; }
    const int nb = blockIdx.y;
    const int n = nb >> 2, b = nb & 3;
    const int tid = threadIdx.x;
    const int warp = tid >> 5, lane = tid & 31;
    const int wm = warp & 3, wn = warp >> 2;       // 4 m-warps x 2 n-warps
    const int g = lane >> 2, tg = lane & 3;
    const int quad = lane >> 3;
    const uint32_t smbC = (uint32_t)__cvta_generic_to_shared(cs);

    for (int e = tid; e < 134*8; e += 256) {
        int u = e >> 3, w4 = (e & 7) * 4;
        int pos = t0 + u - 3;
        int ok = (pos >= 0 && pos < len);
        int pc = ok ? pos : 0;
        cpa16z(smbC + (uint32_t)(u*CSW + w4)*4,
               &g_qkvh[((size_t)(pc + posoff)*(BSZ*QKV) + b*QKV + chanoff + n*DH)/2 + w4], ok);
    }
    {
        const uint32_t* src = g_wt + c*7*64*32;
        for (int e = tid; e < 3584; e += 256) {
            int s4 = e * 4;
            int to = s4 >> 5, icw = s4 & 31;
            cpa16(smbC + OFF_WS + (uint32_t)(to*CSW + icw)*4, &src[s4]);
        }
    }
    CP_COMMIT();
    CP_WAIT0();
    __syncthreads();

    float acc[2][4][4];
    #pragma unroll
    for (int am = 0; am < 2; am++)
        #pragma unroll
        for (int nf = 0; nf < 4; nf++)
            #pragma unroll
            for (int q = 0; q < 4; q++) acc[am][nf][q] = 0.f;

    const uint32_t bpat = (uint32_t)((((quad & 2)*4) + (lane & 7))*CSW + (quad & 1)*4)*4;

    #pragma unroll
    for (int tap = 0; tap < 7; tap++) {
        const uint32_t apat0 = (uint32_t)((wm*16 + (lane & 15) + tap)*CSW + (lane >> 4)*4)*4;
        #pragma unroll
        for (int k0 = 0; k0 < 4; k0++) {
            uint32_t a0[2], a1[2], a2[2], a3[2];
            ldsm4(a0[0], a1[0], a2[0], a3[0], smbC + apat0 + k0*32);
            ldsm4(a0[1], a1[1], a2[1], a3[1], smbC + apat0 + (uint32_t)(64*CSW)*4 + k0*32);
            #pragma unroll
            for (int nf2 = 0; nf2 < 2; nf2++) {
                uint32_t b0, b1, b2, b3;
                ldsm4(b0, b1, b2, b3,
                      smbC + OFF_WS + bpat
                      + (uint32_t)((tap*64 + wn*32 + nf2*16)*CSW)*4 + k0*32);
                #pragma unroll
                for (int am = 0; am < 2; am++) {
                    mma_bf16(acc[am][nf2*2][0], acc[am][nf2*2][1],
                             acc[am][nf2*2][2], acc[am][nf2*2][3],
                             a0[am], a1[am], a2[am], a3[am], b0, b1);
                    mma_bf16(acc[am][nf2*2+1][0], acc[am][nf2*2+1][1],
                             acc[am][nf2*2+1][2], acc[am][nf2*2+1][3],
                             a0[am], a1[am], a2[am], a3[am], b2, b3);
                }
            }
        }
    }

    #pragma unroll
    for (int am = 0; am < 2; am++) {
        #pragma unroll
        for (int nf = 0; nf < 4; nf++) {
            int oc = wn*32 + nf*8 + 2*tg;
            float2 bb = *(const float2*)&cb[oc];
            int row = t0 + wm*16 + am*64 + g;
            size_t w0 = ((size_t)row*(BSZ*DM) + b*DM)/2 + n*32 + oc/2;
            size_t w1 = ((size_t)(row+8)*(BSZ*DM) + b*DM)/2 + n*32 + oc/2;
            outp[w0] = pk(acc[am][nf][0] + bb.x, acc[am][nf][1] + bb.y);
            outp[w1] = pk(acc[am][nf][2] + bb.x, acc[am][nf][3] + bb.y);
        }
    }
}

// ---------------- attention v10: prescaled Q, tile-level mask hoisting -------
#define ASW 36
#define W_QW 0
#define W_QR 2304
#define W_K0 4608
#define W_K1 6912
#define W_V0 9216
#define W_V1 11520
#define W_R0 13824
#define W_R1 16128
#define W_BDR 18432
__global__ __launch_bounds__(256, 2) void k_attn10(const float* __restrict__ rwb,
                                                   const float* __restrict__ rrb)
{
    extern __shared__ uint32_t smu[];
    float* BDR = (float*)(smu + W_BDR);

    const int i0 = (gridDim.x - 1 - blockIdx.x) * 64;
    const int bn = blockIdx.y;
    const int b = bn >> 3, n = bn & 7;
    const int tid = threadIdx.x;
    const int warp = tid >> 5, lane = tid & 31;
    const int wm = warp & 3, wn = warp >> 2;
    const int g = lane >> 2, tg = lane & 3;
    const int quad = lane >> 3;

    const uint32_t smb = (uint32_t)__cvta_generic_to_shared(smu);
    const uint32_t aoff  = (uint32_t)((wm*16 + (lane & 15))*ASW + (lane >> 4)*4)*4;
    const uint32_t bpat  = (uint32_t)((((quad & 2)*4) + (lane & 7))*ASW + (quad & 1)*4)*4;
    const uint32_t boff  = bpat + (uint32_t)(wn*32)*ASW*4;
    const uint32_t tvpat = (uint32_t)(((quad & 1)*8 + (lane & 7))*ASW + (quad >> 1)*4)*4;

    const int il0 = wm*16 + g;
    const int il1 = il0 + 8;
    const int jjb0 = 960 - i0;
    const int ntiles = i0/64 + 17;

    auto stage_kv = [&](int buf, int j0c) {
        const uint32_t kb = smb + (uint32_t)(buf ? W_K1 : W_K0)*4;
        const uint32_t vb = smb + (uint32_t)(buf ? W_V1 : W_V0)*4;
        #pragma unroll
        for (int e0 = 0; e0 < 2; e0++) {
            int e = tid + e0*256;
            int jl = e >> 3, w4 = (e & 7) * 4;
            size_t wi = ((size_t)(j0c + jl)*(BSZ*DM) + b*DM + n*DH)/2 + w4;
            uint32_t so = (uint32_t)(jl*ASW + w4)*4;
            cpa16(kb + so, &g_k[wi]);
            cpa16(vb + so, &g_v[wi]);
        }
    };
    auto stage_rw = [&](int buf, int cb2) {
        const uint32_t rb = smb + (uint32_t)(buf ? W_R1 : W_R0)*4;
        #pragma unroll
        for (int e0 = 0; e0 < 2; e0++) {
            int e = tid + e0*256;
            int l = e >> 3, w4 = (e & 7) * 4;
            int jj = cb2 + l;
            int ok = (jj < KLEN);
            int jc = ok ? jj : (KLEN - 1);
            cpa16z(rb + (uint32_t)(l*ASW + w4)*4,
                   &g_rkh[((size_t)jc*DM + n*DH)/2 + w4], ok);
        }
    };
    auto bd_pass = [&](int rbuf, int cb2) {
        const uint32_t rwo = smb + (uint32_t)(rbuf ? W_R1 : W_R0)*4;
        const int s0 = cb2 & 127;
        float pc[4][4];
        #pragma unroll
        for (int nf = 0; nf < 4; nf++)
            #pragma unroll
            for (int q = 0; q < 4; q++) pc[nf][q] = 0.f;
        #pragma unroll
        for (int k0 = 0; k0 < 4; k0++) {
            uint32_t a0, a1, a2, a3, p0, p1, p2, p3, q0, q1, q2, q3;
            ldsm4(a0, a1, a2, a3, smb + W_QR*4 + aoff + k0*32);
            ldsm4(p0, p1, p2, p3, rwo + boff + k0*32);
            ldsm4(q0, q1, q2, q3, rwo + boff + 16*ASW*4 + k0*32);
            mma_bf16(pc[0][0], pc[0][1], pc[0][2], pc[0][3], a0, a1, a2, a3, p0, p1);
            mma_bf16(pc[1][0], pc[1][1], pc[1][2], pc[1][3], a0, a1, a2, a3, p2, p3);
            mma_bf16(pc[2][0], pc[2][1], pc[2][2], pc[2][3], a0, a1, a2, a3, q0, q1);
            mma_bf16(pc[3][0], pc[3][1], pc[3][2], pc[3][3], a0, a1, a2, a3, q2, q3);
        }
        #pragma unroll
        for (int nf = 0; nf < 4; nf++) {
            int cc = s0 + wn*32 + nf*8 + 2*tg;
            *(float2*)&BDR[il0*132 + cc] = make_float2(pc[nf][0], pc[nf][1]);
            *(float2*)&BDR[il1*132 + cc] = make_float2(pc[nf][2], pc[nf][3]);
        }
    };

    stage_kv(0, 0);
    stage_rw(0, jjb0);
    stage_rw(1, jjb0 + 64);
    CP_COMMIT();

    // Q (+biases), pre-scaled by 0.125*log2(e)
    const float SCL = 0.18033688f;
    for (int e = tid; e < 64*16; e += 256) {
        int ii = e >> 4, d4 = (e & 15) * 4;
        size_t wi = ((size_t)(i0+ii)*(BSZ*DM) + b*DM + n*DH + d4) / 2;
        uint2 qv = *(const uint2*)&g_q[wi];
        float q0 = bl(qv.x), q1 = bh(qv.x), q2 = bl(qv.y), q3 = bh(qv.y);
        float4 wv = *(const float4*)&rwb[n*DH + d4];
        float4 rv = *(const float4*)&rrb[n*DH + d4];
        smu[W_QW + ii*ASW + d4/2]     = pk((q0 + wv.x)*SCL, (q1 + wv.y)*SCL);
        smu[W_QW + ii*ASW + d4/2 + 1] = pk((q2 + wv.z)*SCL, (q3 + wv.w)*SCL);
        smu[W_QR + ii*ASW + d4/2]     = pk((q0 + rv.x)*SCL, (q1 + rv.y)*SCL);
        smu[W_QR + ii*ASW + d4/2 + 1] = pk((q2 + rv.z)*SCL, (q3 + rv.w)*SCL);
    }
    CP_WAIT0();
    __syncthreads();

    bd_pass(0, jjb0);

    float oacc[8][4];
    #pragma unroll
    for (int nf = 0; nf < 8; nf++)
        #pragma unroll
        for (int q = 0; q < 4; q++) oacc[nf][q] = 0.f;
    float l0 = 0.f, l1 = 0.f;

    for (int t = 0; t < ntiles; t++) {
        const int kvb = t & 1;
        const int j0 = t * 64;
        const int jjb = j0 - i0 + 960;

        if (t + 1 < ntiles) stage_kv(kvb ^ 1, j0 + 64);
        stage_rw(kvb, jjb0 + 64*(t + 2));
        CP_COMMIT();

        const uint32_t kso = smb + (uint32_t)(kvb ? W_K1 : W_K0)*4;
        float sc[4][4];
        #pragma unroll
        for (int nf = 0; nf < 4; nf++)
            #pragma unroll
            for (int q = 0; q < 4; q++) sc[nf][q] = 0.f;
        #pragma unroll
        for (int k0 = 0; k0 < 4; k0++) {
            uint32_t a0, a1, a2, a3, p0, p1, p2, p3, q0, q1, q2, q3;
            ldsm4(a0, a1, a2, a3, smb + W_QW*4 + aoff + k0*32);
            ldsm4(p0, p1, p2, p3, kso + boff + k0*32);
            ldsm4(q0, q1, q2, q3, kso + boff + 16*ASW*4 + k0*32);
            mma_bf16(sc[0][0], sc[0][1], sc[0][2], sc[0][3], a0, a1, a2, a3, p0, p1);
            mma_bf16(sc[1][0], sc[1][1], sc[1][2], sc[1][3], a0, a1, a2, a3, p2, p3);
            mma_bf16(sc[2][0], sc[2][1], sc[2][2], sc[2][3], a0, a1, a2, a3, q0, q1);
            mma_bf16(sc[3][0], sc[3][1], sc[3][2], sc[3][3], a0, a1, a2, a3, q2, q3);
        }

        bd_pass(kvb ^ 1, jjb0 + 64*(t + 1));
        __syncthreads();

        const int jjb2 = jjb + 63;
        uint32_t a_lo[4], a_hi[4];
        if (t + 1 < ntiles) {
            #pragma unroll
            for (int nf = 0; nf < 4; nf++) {
                int jl = wn*32 + nf*8 + 2*tg;
                int s00 = (jjb2 + jl - il0) & 127;
                int s01 = (jjb2 + jl + 1 - il0) & 127;
                int s10 = (jjb2 + jl - il1) & 127;
                int s11 = (jjb2 + jl + 1 - il1) & 127;
                float p00 = exp2_fast(sc[nf][0] + BDR[il0*132 + s00]);
                float p01 = exp2_fast(sc[nf][1] + BDR[il0*132 + s01]);
                float p10 = exp2_fast(sc[nf][2] + BDR[il1*132 + s10]);
                float p11 = exp2_fast(sc[nf][3] + BDR[il1*132 + s11]);
                l0 += p00 + p01;
                l1 += p10 + p11;
                a_lo[nf] = pk(p00, p01);
                a_hi[nf] = pk(p10, p11);
            }
        } else {
            #pragma unroll
            for (int nf = 0; nf < 4; nf++) {
                int jl = wn*32 + nf*8 + 2*tg;
                int jg = j0 + jl;
                int s00 = (jjb2 + jl - il0) & 127;
                int s01 = (jjb2 + jl + 1 - il0) & 127;
                int s10 = (jjb2 + jl - il1) & 127;
                int s11 = (jjb2 + jl + 1 - il1) & 127;
                float p00 = 0.f, p01 = 0.f, p10 = 0.f, p11 = 0.f;
                if (jg <= i0 + il0 + MEMLEN)
                    p00 = exp2_fast(sc[nf][0] + BDR[il0*132 + s00]);
                if (jg + 1 <= i0 + il0 + MEMLEN)
                    p01 = exp2_fast(sc[nf][1] + BDR[il0*132 + s01]);
                if (jg <= i0 + il1 + MEMLEN)
                    p10 = exp2_fast(sc[nf][2] + BDR[il1*132 + s10]);
                if (jg + 1 <= i0 + il1 + MEMLEN)
                    p11 = exp2_fast(sc[nf][3] + BDR[il1*132 + s11]);
                l0 += p00 + p01;
                l1 += p10 + p11;
                a_lo[nf] = pk(p00, p01);
                a_hi[nf] = pk(p10, p11);
            }
        }

        const uint32_t vso = smb + (uint32_t)(kvb ? W_V1 : W_V0)*4;
        #pragma unroll
        for (int k0 = 0; k0 < 2; k0++) {
            uint32_t a0 = a_lo[2*k0], a1 = a_hi[2*k0];
            uint32_t a2 = a_lo[2*k0+1], a3 = a_hi[2*k0+1];
            uint32_t jbase = (uint32_t)((wn*32 + k0*16)*ASW)*4;
            #pragma unroll
            for (int dd = 0; dd < 4; dd++) {
                uint32_t b0, b1, b2, b3;
                ldsm4t(b0, b1, b2, b3, vso + tvpat + jbase + (uint32_t)(dd*8)*4);
                mma_bf16(oacc[dd*2][0], oacc[dd*2][1], oacc[dd*2][2], oacc[dd*2][3],
                         a0, a1, a2, a3, b0, b1);
                mma_bf16(oacc[dd*2+1][0], oacc[dd*2+1][1], oacc[dd*2+1][2], oacc[dd*2+1][3],
                         a0, a1, a2, a3, b2, b3);
            }
        }

        CP_WAIT0();
        __syncthreads();
    }

    l0 += __shfl_xor_sync(0xffffffffu, l0, 1);
    l0 += __shfl_xor_sync(0xffffffffu, l0, 2);
    l1 += __shfl_xor_sync(0xffffffffu, l1, 1);
    l1 += __shfl_xor_sync(0xffffffffu, l1, 2);
    float* obuf = BDR;
    float* lbuf = BDR + 4*16*68;
    if (wn == 1) {
        #pragma unroll
        for (int nf = 0; nf < 8; nf++) {
            int d = nf*8 + 2*tg;
            *(float2*)&obuf[il0*68 + d] = make_float2(oacc[nf][0], oacc[nf][1]);
            *(float2*)&obuf[il1*68 + d] = make_float2(oacc[nf][2], oacc[nf][3]);
        }
        if (tg == 0) { lbuf[il0] = l0; lbuf[il1] = l1; }
    }
    __syncthreads();
    if (wn == 0) {
        float inv0 = 1.f / (l0 + lbuf[il0]);
        float inv1 = 1.f / (l1 + lbuf[il1]);
        #pragma unroll
        for (int nf = 0; nf < 8; nf++) {
            int d = nf*8 + 2*tg;
            float2 o0 = *(float2*)&obuf[il0*68 + d];
            float2 o1 = *(float2*)&obuf[il1*68 + d];
            g_avh[((size_t)(i0+il0)*(BSZ*DM) + b*DM + n*DH + d)/2] =
                pk((oacc[nf][0]+o0.x)*inv0, (oacc[nf][1]+o0.y)*inv0);
            g_avh[((size_t)(i0+il1)*(BSZ*DM) + b*DM + n*DH + d)/2] =
                pk((oacc[nf][2]+o1.x)*inv1, (oacc[nf][3]+o1.y)*inv1);
        }
    }
}

// ---------------- residual + layernorm: warp per row -------------------------
__global__ __launch_bounds__(256) void k_ln2(const float* __restrict__ w,
                                             const float* __restrict__ g,
                                             const float* __restrict__ be,
                                             float* __restrict__ out)
{
    int row = blockIdx.x * 8 + (threadIdx.x >> 5);
    int lane = threadIdx.x & 31;
    const float* wr = w    + (size_t)row * DM;
    const float* ar = g_ao + (size_t)row * DM;

    float4 x[4];
    float s = 0.f;
    #pragma unroll
    for (int c = 0; c < 4; c++) {
        int idx = c*128 + lane*4;
        float4 a = *(const float4*)&wr[idx];
        float4 o = *(const float4*)&ar[idx];
        x[c] = make_float4(a.x+o.x, a.y+o.y, a.z+o.z, a.w+o.w);
        s += x[c].x + x[c].y + x[c].z + x[c].w;
    }
    #pragma unroll
    for (int m = 16; m > 0; m >>= 1) s += __shfl_xor_sync(0xffffffffu, s, m);
    float mu = s * (1.f / DM);
    float v = 0.f;
    #pragma unroll
    for (int c = 0; c < 4; c++) {
        float dx = x[c].x - mu, dy = x[c].y - mu, dz = x[c].z - mu, dw = x[c].w - mu;
        x[c] = make_float4(dx, dy, dz, dw);
        v += dx*dx + dy*dy + dz*dz + dw*dw;
    }
    #pragma unroll
    for (int m = 16; m > 0; m >>= 1) v += __shfl_xor_sync(0xffffffffu, v, m);
    float rs = rsqrtf(v * (1.f / DM) + 1e-5f);
    #pragma unroll
    for (int c = 0; c < 4; c++) {
        int idx = c*128 + lane*4;
        float4 gg = *(const float4*)&g[idx];
        float4 bb = *(const float4*)&be[idx];
        float4 r = make_float4(x[c].x*rs*gg.x + bb.x, x[c].y*rs*gg.y + bb.y,
                               x[c].z*rs*gg.z + bb.z, x[c].w*rs*gg.w + bb.w);
        *(float4*)&out[(size_t)row*DM + idx] = r;
    }
}

// ---------------- launcher ---------------------------------------------------
extern "C" void kernel_launch(void* const* d_in, const int* in_sizes, int n_in,
                              void* d_out, int out_size)
{
    (void)in_sizes; (void)n_in; (void)out_size;
    const float* w    = (const float*)d_in[0];
    const float* r    = (const float*)d_in[1];
    const float* mems = (const float*)d_in[2];
    const float* rwb  = (const float*)d_in[3];
    const float* rrb  = (const float*)d_in[4];
    const float* qkvW = (const float*)d_in[5];
    const float* rW   = (const float*)d_in[6];
    const float* cqw  = (const float*)d_in[7];
    const float* cqb  = (const float*)d_in[8];
    const float* ckw  = (const float*)d_in[9];
    const float* ckb  = (const float*)d_in[10];
    const float* cvw  = (const float*)d_in[11];
    const float* cvb  = (const float*)d_in[12];
    const float* oW   = (const float*)d_in[13];
    const float* lng  = (const float*)d_in[14];
    const float* lnb  = (const float*)d_in[15];
    float* out = (float*)d_out;

    uint32_t *p_avh, *p_oWh;
    float *p_ao;
    cudaGetSymbolAddress((void**)&p_avh, g_avh);
    cudaGetSymbolAddress((void**)&p_oWh, g_oWh);
    cudaGetSymbolAddress((void**)&p_ao,  g_ao);

    dim3 b256(256);

    // fused fp32 -> bf16 conversions + conv weight prep (one launch)
    k_cvt7<<<2048, b256>>>(mems, w, qkvW, r, rW, oW, cqw, ckw, cvw);

    // fused QKV projection + r-projection
    mm_qkr<<<dim3(QKV/128, 80), b256>>>();

    // fused convs (4m x 2n warp tiling)
    int csm = (134*CSW + 7*64*CSW) * 4;
    cudaFuncSetAttribute(k_conv6, cudaFuncAttributeMaxDynamicSharedMemorySize, csm);
    k_conv6<<<dim3(40, NH*BSZ), b256, csm>>>(cqb, ckb, cvb);

    // attention (2 CTAs/SM, prescaled Q)
    int asm_ = (W_BDR + 64*132) * 4;
    cudaFuncSetAttribute(k_attn10, cudaFuncAttributeMaxDynamicSharedMemorySize, asm_);
    k_attn10<<<dim3(QLEN/64, BSZ*NH), b256, asm_>>>(rwb, rrb);

    // output projection + residual layernorm
    mm_h<<<dim3(DM/128, (QLEN*BSZ)/128), b256>>>(p_avh, p_oWh, p_ao, DM, DM, 0);
    k_ln2<<<(QLEN*BSZ)/8, b256>>>(w, lng, lnb, out);
}

// round 15
// speedup vs baseline: 13.1319x; 1.0171x over previous
#include <cuda_runtime.h>
#include <cuda_bf16.h>
#include <math.h>
#include <stdint.h>

#define QLEN 1024
#define KLEN 2048
#define MEMLEN 1024
#define BSZ 4
#define NH 8
#define DH 64
#define DM 512
#define QKV (3*DM)

__device__ uint32_t g_qkvh[(size_t)KLEN*BSZ*QKV/2]; // bf16 pairs (jk, b, 1536)
__device__ uint32_t g_rkh [(size_t)KLEN*DM/2];      // bf16 pairs (jj, n*64+d)
__device__ uint32_t g_q  [(size_t)QLEN*BSZ*DM/2];
__device__ uint32_t g_k  [(size_t)KLEN*BSZ*DM/2];
__device__ uint32_t g_v  [(size_t)KLEN*BSZ*DM/2];
__device__ uint32_t g_avh[(size_t)QLEN*BSZ*DM/2];   // attention out, bf16
__device__ float    g_ao [(size_t)QLEN*BSZ*DM];
__device__ uint32_t g_wt[3*7*64*32];
__device__ uint32_t g_xh [(size_t)KLEN*BSZ*DM/2];   // [mems; w]
__device__ uint32_t g_wh [(size_t)QKV*DM/2];        // qkvW
__device__ uint32_t g_rh [(size_t)KLEN*DM/2];       // r
__device__ uint32_t g_rWh[(size_t)DM*DM/2];         // rW
__device__ uint32_t g_oWh[(size_t)DM*DM/2];         // oW

__device__ __forceinline__ uint32_t pk(float x, float y) {
    __nv_bfloat162 t = __floats2bfloat162_rn(x, y);
    return *(uint32_t*)&t;
}
__device__ __forceinline__ float bl(uint32_t w) {
    __nv_bfloat16 h = *(__nv_bfloat16*)&w;
    return __bfloat162float(h);
}
__device__ __forceinline__ float bh(uint32_t w) {
    uint16_t u = (uint16_t)(w >> 16);
    __nv_bfloat16 h = *(__nv_bfloat16*)&u;
    return __bfloat162float(h);
}

__device__ __forceinline__ void mma_bf16(float& c0, float& c1, float& c2, float& c3,
                                         uint32_t a0, uint32_t a1, uint32_t a2, uint32_t a3,
                                         uint32_t b0, uint32_t b1)
{
    asm volatile("mma.sync.aligned.m16n8k16.row.col.f32.bf16.bf16.f32 "
                 "{%0,%1,%2,%3},{%4,%5,%6,%7},{%8,%9},{%0,%1,%2,%3};\n"
                 : "+f"(c0), "+f"(c1), "+f"(c2), "+f"(c3)
                 : "r"(a0), "r"(a1), "r"(a2), "r"(a3), "r"(b0), "r"(b1));
}

__device__ __forceinline__ void ldsm4(uint32_t& r0, uint32_t& r1, uint32_t& r2, uint32_t& r3,
                                      uint32_t addr)
{
    asm volatile("ldmatrix.sync.aligned.m8n8.x4.shared.b16 {%0,%1,%2,%3}, [%4];"
                 : "=r"(r0), "=r"(r1), "=r"(r2), "=r"(r3) : "r"(addr));
}
__device__ __forceinline__ void ldsm4t(uint32_t& r0, uint32_t& r1, uint32_t& r2, uint32_t& r3,
                                       uint32_t addr)
{
    asm volatile("ldmatrix.sync.aligned.m8n8.x4.trans.shared.b16 {%0,%1,%2,%3}, [%4];"
                 : "=r"(r0), "=r"(r1), "=r"(r2), "=r"(r3) : "r"(addr));
}

__device__ __forceinline__ void cpa16(uint32_t saddr, const void* gaddr) {
    asm volatile("cp.async.cg.shared.global [%0], [%1], 16;" :: "r"(saddr), "l"(gaddr));
}
__device__ __forceinline__ void cpa16z(uint32_t saddr, const void* gaddr, int ok) {
    int sz = ok ? 16 : 0;
    asm volatile("cp.async.cg.shared.global [%0], [%1], 16, %2;"
                 :: "r"(saddr), "l"(gaddr), "r"(sz));
}
#define CP_COMMIT() asm volatile("cp.async.commit_group;")
#define CP_WAIT0()  asm volatile("cp.async.wait_group 0;")
#define CP_WAIT1()  asm volatile("cp.async.wait_group 1;")
#define BAR64(id)   asm volatile("bar.sync %0, 64;" :: "r"(id) : "memory")

// hot-path exp2: no clamp (|y| bounded by score magnitudes here)
__device__ __forceinline__ float exp2_nc(float y) {
    float z = __fadd_rn(y, 12582912.f);
    float n = __fsub_rn(z, 12582912.f);
    float f = __fsub_rn(y, n);
    float r = 0.0096181291f;
    r = fmaf(r, f, 0.055504109f);
    r = fmaf(r, f, 0.24022651f);
    r = fmaf(r, f, 0.69314718f);
    r = fmaf(r, f, 1.0f);
    int e = __float_as_int(z);
    float s = __int_as_float((e - 1262485377) << 23);
    return r * s;
}

// ---------------- fused fp32 -> bf16 convert + conv weight prep (7 segs) -----
#define CVT_N0 (MEMLEN*BSZ*DM/2)
#define CVT_N1 (QLEN*BSZ*DM/2)
#define CVT_N2 (QKV*DM/2)
#define CVT_N3 (KLEN*DM/2)
#define CVT_N4 (DM*DM/2)
#define CVT_N6 (3*7*64*32)
#define CVT_C0 (CVT_N0)
#define CVT_C1 (CVT_C0 + CVT_N1)
#define CVT_C2 (CVT_C1 + CVT_N2)
#define CVT_C3 (CVT_C2 + CVT_N3)
#define CVT_C4 (CVT_C3 + CVT_N4)
#define CVT_C5 (CVT_C4 + CVT_N4)
#define CVT_TOT (CVT_C5 + CVT_N6)
__global__ void k_cvt7(const float* __restrict__ mems, const float* __restrict__ w,
                       const float* __restrict__ qkvW, const float* __restrict__ r,
                       const float* __restrict__ rW,   const float* __restrict__ oW,
                       const float* __restrict__ cq,   const float* __restrict__ ck,
                       const float* __restrict__ cv)
{
    int idx = blockIdx.x * blockDim.x + threadIdx.x;
    int stride = gridDim.x * blockDim.x;
    for (int i = idx; i < CVT_TOT; i += stride) {
        if (i < CVT_C5) {
            const float* s;
            uint32_t* d;
            int off;
            if (i < CVT_C0)      { s = mems; d = g_xh;            off = i; }
            else if (i < CVT_C1) { s = w;    d = g_xh + CVT_C0;   off = i - CVT_C0; }
            else if (i < CVT_C2) { s = qkvW; d = g_wh;            off = i - CVT_C1; }
            else if (i < CVT_C3) { s = r;    d = g_rh;            off = i - CVT_C2; }
            else if (i < CVT_C4) { s = rW;   d = g_rWh;           off = i - CVT_C3; }
            else                 { s = oW;   d = g_oWh;           off = i - CVT_C4; }
            float2 v = *(const float2*)&s[2*off];
            d[off] = pk(v.x, v.y);
        } else {
            int off = i - CVT_C5;
            int ct = off >> 11;
            int c = ct / 7, tap = ct % 7;
            int e = off & 2047;
            int oc = e >> 5, icw = e & 31;
            const float* src = (c == 0) ? cq : (c == 1) ? ck : cv;
            float w0 = src[(oc*64 + 2*icw    )*7 + tap];
            float w1 = src[(oc*64 + 2*icw + 1)*7 + tap];
            g_wt[(ct*64 + oc)*32 + icw] = pk(w0, w1);
        }
    }
}

// ---------------- BF16 GEMM body: 3-stage cp.async + ldmatrix ----------------
#define GSW 12
#define NSTG 3
__device__ __forceinline__ void mm_body(const uint32_t* __restrict__ A,
                                        const uint32_t* __restrict__ B,
                                        void* __restrict__ Cout,
                                        int N, int K, int pack, int m0, int n0)
{
    __shared__ uint32_t As[NSTG][128*GSW];
    __shared__ uint32_t Bs[NSTG][128*GSW];
    const int tid = threadIdx.x;
    const int warp = tid >> 5, lane = tid & 31;
    const int wm = warp & 3, wn = warp >> 2;
    const int g = lane >> 2, tg = lane & 3;
    const int quad = lane >> 3;
    const int Kw = K / 2;
    const int iters = Kw / 8;

    const uint32_t smA = (uint32_t)__cvta_generic_to_shared(As);
    const uint32_t smB = (uint32_t)__cvta_generic_to_shared(Bs);
    const uint32_t apat = (uint32_t)((lane & 15)*GSW + (lane >> 4)*4)*4;
    const uint32_t bpat = (uint32_t)((((quad & 2)*4) + (lane & 7))*GSW + (quad & 1)*4)*4;

    float c[2][8][4];
    #pragma unroll
    for (int mt = 0; mt < 2; mt++)
        #pragma unroll
        for (int nt = 0; nt < 8; nt++)
            #pragma unroll
            for (int q = 0; q < 4; q++) c[mt][nt][q] = 0.f;

    const int lr = tid >> 1;
    const int lh = tid & 1;
    const uint32_t* Ap = A + (size_t)(m0 + lr) * Kw + lh * 4;
    const uint32_t* Bp = B + (size_t)(n0 + lr) * Kw + lh * 4;

    auto stage = [&](int s, int kw) {
        uint32_t so = (uint32_t)(s*128*GSW + lr*GSW + lh*4)*4;
        cpa16(smA + so, Ap + kw);
        cpa16(smB + so, Bp + kw);
    };

    stage(0, 0);
    CP_COMMIT();
    if (iters > 1) stage(1, 8);
    CP_COMMIT();

    for (int i = 0; i < iters; i++) {
        CP_WAIT1();
        __syncthreads();
        int pf = i + NSTG - 1;
        if (pf < iters) stage(pf % NSTG, pf * 8);
        CP_COMMIT();

        const int buf = i % NSTG;
        const uint32_t abase = smA + (uint32_t)(buf*128*GSW)*4;
        const uint32_t bbase = smB + (uint32_t)(buf*128*GSW)*4;
        uint32_t af[2][4], bf[8][2];
        #pragma unroll
        for (int mt = 0; mt < 2; mt++)
            ldsm4(af[mt][0], af[mt][1], af[mt][2], af[mt][3],
                  abase + (uint32_t)((wm*32 + mt*16)*GSW)*4 + apat);
        #pragma unroll
        for (int nt2 = 0; nt2 < 4; nt2++) {
            uint32_t b0, b1, b2, b3;
            ldsm4(b0, b1, b2, b3,
                  bbase + (uint32_t)((wn*64 + nt2*16)*GSW)*4 + bpat);
            bf[nt2*2][0] = b0;   bf[nt2*2][1] = b1;
            bf[nt2*2+1][0] = b2; bf[nt2*2+1][1] = b3;
        }
        #pragma unroll
        for (int mt = 0; mt < 2; mt++)
            #pragma unroll
            for (int nt = 0; nt < 8; nt++)
                mma_bf16(c[mt][nt][0], c[mt][nt][1], c[mt][nt][2], c[mt][nt][3],
                         af[mt][0], af[mt][1], af[mt][2], af[mt][3],
                         bf[nt][0], bf[nt][1]);
    }

    #pragma unroll
    for (int mt = 0; mt < 2; mt++) {
        int row0 = m0 + wm * 32 + mt * 16 + g;
        #pragma unroll
        for (int nt = 0; nt < 8; nt++) {
            int col = n0 + wn * 64 + nt * 8 + tg * 2;
            if (pack) {
                uint32_t* Cp = (uint32_t*)Cout;
                Cp[((size_t)row0 * N + col)/2]       = pk(c[mt][nt][0], c[mt][nt][1]);
                Cp[((size_t)(row0 + 8) * N + col)/2] = pk(c[mt][nt][2], c[mt][nt][3]);
            } else {
                float* C = (float*)Cout;
                *(float2*)&C[(size_t)row0 * N + col]       = make_float2(c[mt][nt][0], c[mt][nt][1]);
                *(float2*)&C[(size_t)(row0 + 8) * N + col] = make_float2(c[mt][nt][2], c[mt][nt][3]);
            }
        }
    }
}

__global__ __launch_bounds__(256, 2) void mm_h(const uint32_t* __restrict__ A,
                                               const uint32_t* __restrict__ B,
                                               void* __restrict__ Cout,
                                               int N, int K, int pack)
{
    mm_body(A, B, Cout, N, K, pack, blockIdx.y * 128, blockIdx.x * 128);
}

__global__ __launch_bounds__(256, 2) void mm_qkr()
{
    int y = blockIdx.y;
    if (y < 64) {
        mm_body(g_xh, g_wh, g_qkvh, QKV, DM, 1, y * 128, blockIdx.x * 128);
    } else {
        if (blockIdx.x >= 4) return;
        mm_body(g_rh, g_rWh, g_rkh, DM, DM, 1, (y - 64) * 128, blockIdx.x * 128);
    }
}

// ---------------- fused conv v6: 4m x 2n warp tiling -------------------------
#define CSW 36
#define OFF_WS (134*CSW*4)
__global__ __launch_bounds__(256, 2) void k_conv6(const float* __restrict__ cqb,
                                                  const float* __restrict__ ckb,
                                                  const float* __restrict__ cvb)
{
    extern __shared__ uint32_t cs[];
    const int bx = blockIdx.x;
    int c, t0, len, posoff, chanoff;
    const float* cb;
    uint32_t* outp;
    if (bx < 8)       { c = 0; t0 = bx*128;      len = QLEN; posoff = MEMLEN; chanoff = 0;    cb = cqb; outp = g_q; }
    else if (bx < 24) { c = 1; t0 = (bx-8)*128;  len = KLEN; posoff = 0;      chanoff = DM;   cb = ckb; outp = g_k; }
    else              { c = 2; t0 = (bx-24)*128; len = KLEN; posoff = 0;      chanoff = 2*DM; cb = cvb; outp = g_v; }
    const int nb = blockIdx.y;
    const int n = nb >> 2, b = nb & 3;
    const int tid = threadIdx.x;
    const int warp = tid >> 5, lane = tid & 31;
    const int wm = warp & 3, wn = warp >> 2;
    const int g = lane >> 2, tg = lane & 3;
    const int quad = lane >> 3;
    const uint32_t smbC = (uint32_t)__cvta_generic_to_shared(cs);

    for (int e = tid; e < 134*8; e += 256) {
        int u = e >> 3, w4 = (e & 7) * 4;
        int pos = t0 + u - 3;
        int ok = (pos >= 0 && pos < len);
        int pc = ok ? pos : 0;
        cpa16z(smbC + (uint32_t)(u*CSW + w4)*4,
               &g_qkvh[((size_t)(pc + posoff)*(BSZ*QKV) + b*QKV + chanoff + n*DH)/2 + w4], ok);
    }
    {
        const uint32_t* src = g_wt + c*7*64*32;
        for (int e = tid; e < 3584; e += 256) {
            int s4 = e * 4;
            int to = s4 >> 5, icw = s4 & 31;
            cpa16(smbC + OFF_WS + (uint32_t)(to*CSW + icw)*4, &src[s4]);
        }
    }
    CP_COMMIT();
    CP_WAIT0();
    __syncthreads();

    float acc[2][4][4];
    #pragma unroll
    for (int am = 0; am < 2; am++)
        #pragma unroll
        for (int nf = 0; nf < 4; nf++)
            #pragma unroll
            for (int q = 0; q < 4; q++) acc[am][nf][q] = 0.f;

    const uint32_t bpat = (uint32_t)((((quad & 2)*4) + (lane & 7))*CSW + (quad & 1)*4)*4;

    #pragma unroll
    for (int tap = 0; tap < 7; tap++) {
        const uint32_t apat0 = (uint32_t)((wm*16 + (lane & 15) + tap)*CSW + (lane >> 4)*4)*4;
        #pragma unroll
        for (int k0 = 0; k0 < 4; k0++) {
            uint32_t a0[2], a1[2], a2[2], a3[2];
            ldsm4(a0[0], a1[0], a2[0], a3[0], smbC + apat0 + k0*32);
            ldsm4(a0[1], a1[1], a2[1], a3[1], smbC + apat0 + (uint32_t)(64*CSW)*4 + k0*32);
            #pragma unroll
            for (int nf2 = 0; nf2 < 2; nf2++) {
                uint32_t b0, b1, b2, b3;
                ldsm4(b0, b1, b2, b3,
                      smbC + OFF_WS + bpat
                      + (uint32_t)((tap*64 + wn*32 + nf2*16)*CSW)*4 + k0*32);
                #pragma unroll
                for (int am = 0; am < 2; am++) {
                    mma_bf16(acc[am][nf2*2][0], acc[am][nf2*2][1],
                             acc[am][nf2*2][2], acc[am][nf2*2][3],
                             a0[am], a1[am], a2[am], a3[am], b0, b1);
                    mma_bf16(acc[am][nf2*2+1][0], acc[am][nf2*2+1][1],
                             acc[am][nf2*2+1][2], acc[am][nf2*2+1][3],
                             a0[am], a1[am], a2[am], a3[am], b2, b3);
                }
            }
        }
    }

    #pragma unroll
    for (int am = 0; am < 2; am++) {
        #pragma unroll
        for (int nf = 0; nf < 4; nf++) {
            int oc = wn*32 + nf*8 + 2*tg;
            float2 bb = *(const float2*)&cb[oc];
            int row = t0 + wm*16 + am*64 + g;
            size_t w0 = ((size_t)row*(BSZ*DM) + b*DM)/2 + n*32 + oc/2;
            size_t w1 = ((size_t)(row+8)*(BSZ*DM) + b*DM)/2 + n*32 + oc/2;
            outp[w0] = pk(acc[am][nf][0] + bb.x, acc[am][nf][1] + bb.y);
            outp[w1] = pk(acc[am][nf][2] + bb.x, acc[am][nf][3] + bb.y);
        }
    }
}

// ---------------- attention v11: named-barrier softmax handoff ---------------
#define ASW 36
#define W_QW 0
#define W_QR 2304
#define W_K0 4608
#define W_K1 6912
#define W_V0 9216
#define W_V1 11520
#define W_R0 13824
#define W_R1 16128
#define W_BDR 18432
__global__ __launch_bounds__(256, 2) void k_attn11(const float* __restrict__ rwb,
                                                   const float* __restrict__ rrb)
{
    extern __shared__ uint32_t smu[];
    float* BDR = (float*)(smu + W_BDR);

    const int i0 = (gridDim.x - 1 - blockIdx.x) * 64;
    const int bn = blockIdx.y;
    const int b = bn >> 3, n = bn & 7;
    const int tid = threadIdx.x;
    const int warp = tid >> 5, lane = tid & 31;
    const int wm = warp & 3, wn = warp >> 2;
    const int g = lane >> 2, tg = lane & 3;
    const int quad = lane >> 3;

    const uint32_t smb = (uint32_t)__cvta_generic_to_shared(smu);
    const uint32_t aoff  = (uint32_t)((wm*16 + (lane & 15))*ASW + (lane >> 4)*4)*4;
    const uint32_t bpat  = (uint32_t)((((quad & 2)*4) + (lane & 7))*ASW + (quad & 1)*4)*4;
    const uint32_t boff  = bpat + (uint32_t)(wn*32)*ASW*4;
    const uint32_t tvpat = (uint32_t)(((quad & 1)*8 + (lane & 7))*ASW + (quad >> 1)*4)*4;

    const int il0 = wm*16 + g;
    const int il1 = il0 + 8;
    float* const bdr0 = &BDR[il0*132];
    float* const bdr1 = &BDR[il1*132];
    const int jjb0 = 960 - i0;
    const int ntiles = i0/64 + 17;

    auto stage_kv = [&](int buf, int j0c) {
        const uint32_t kb = smb + (uint32_t)(buf ? W_K1 : W_K0)*4;
        const uint32_t vb = smb + (uint32_t)(buf ? W_V1 : W_V0)*4;
        #pragma unroll
        for (int e0 = 0; e0 < 2; e0++) {
            int e = tid + e0*256;
            int jl = e >> 3, w4 = (e & 7) * 4;
            size_t wi = ((size_t)(j0c + jl)*(BSZ*DM) + b*DM + n*DH)/2 + w4;
            uint32_t so = (uint32_t)(jl*ASW + w4)*4;
            cpa16(kb + so, &g_k[wi]);
            cpa16(vb + so, &g_v[wi]);
        }
    };
    auto stage_rw = [&](int buf, int cb2) {
        const uint32_t rb = smb + (uint32_t)(buf ? W_R1 : W_R0)*4;
        #pragma unroll
        for (int e0 = 0; e0 < 2; e0++) {
            int e = tid + e0*256;
            int l = e >> 3, w4 = (e & 7) * 4;
            int jj = cb2 + l;
            int ok = (jj < KLEN);
            int jc = ok ? jj : (KLEN - 1);
            cpa16z(rb + (uint32_t)(l*ASW + w4)*4,
                   &g_rkh[((size_t)jc*DM + n*DH)/2 + w4], ok);
        }
    };
    auto bd_pass = [&](int rbuf, int cb2) {
        const uint32_t rwo = smb + (uint32_t)(rbuf ? W_R1 : W_R0)*4;
        const int s0 = cb2 & 127;
        float pc[4][4];
        #pragma unroll
        for (int nf = 0; nf < 4; nf++)
            #pragma unroll
            for (int q = 0; q < 4; q++) pc[nf][q] = 0.f;
        #pragma unroll
        for (int k0 = 0; k0 < 4; k0++) {
            uint32_t a0, a1, a2, a3, p0, p1, p2, p3, q0, q1, q2, q3;
            ldsm4(a0, a1, a2, a3, smb + W_QR*4 + aoff + k0*32);
            ldsm4(p0, p1, p2, p3, rwo + boff + k0*32);
            ldsm4(q0, q1, q2, q3, rwo + boff + 16*ASW*4 + k0*32);
            mma_bf16(pc[0][0], pc[0][1], pc[0][2], pc[0][3], a0, a1, a2, a3, p0, p1);
            mma_bf16(pc[1][0], pc[1][1], pc[1][2], pc[1][3], a0, a1, a2, a3, p2, p3);
            mma_bf16(pc[2][0], pc[2][1], pc[2][2], pc[2][3], a0, a1, a2, a3, q0, q1);
            mma_bf16(pc[3][0], pc[3][1], pc[3][2], pc[3][3], a0, a1, a2, a3, q2, q3);
        }
        #pragma unroll
        for (int nf = 0; nf < 4; nf++) {
            int cc = s0 + wn*32 + nf*8 + 2*tg;
            *(float2*)&bdr0[cc] = make_float2(pc[nf][0], pc[nf][1]);
            *(float2*)&bdr1[cc] = make_float2(pc[nf][2], pc[nf][3]);
        }
    };

    stage_kv(0, 0);
    stage_rw(0, jjb0);
    stage_rw(1, jjb0 + 64);
    CP_COMMIT();

    // Q (+biases), pre-scaled by 0.125*log2(e)
    const float SCL = 0.18033688f;
    for (int e = tid; e < 64*16; e += 256) {
        int ii = e >> 4, d4 = (e & 15) * 4;
        size_t wi = ((size_t)(i0+ii)*(BSZ*DM) + b*DM + n*DH + d4) / 2;
        uint2 qv = *(const uint2*)&g_q[wi];
        float q0 = bl(qv.x), q1 = bh(qv.x), q2 = bl(qv.y), q3 = bh(qv.y);
        float4 wv = *(const float4*)&rwb[n*DH + d4];
        float4 rv = *(const float4*)&rrb[n*DH + d4];
        smu[W_QW + ii*ASW + d4/2]     = pk((q0 + wv.x)*SCL, (q1 + wv.y)*SCL);
        smu[W_QW + ii*ASW + d4/2 + 1] = pk((q2 + wv.z)*SCL, (q3 + wv.w)*SCL);
        smu[W_QR + ii*ASW + d4/2]     = pk((q0 + rv.x)*SCL, (q1 + rv.y)*SCL);
        smu[W_QR + ii*ASW + d4/2 + 1] = pk((q2 + rv.z)*SCL, (q3 + rv.w)*SCL);
    }
    CP_WAIT0();
    __syncthreads();

    bd_pass(0, jjb0);

    float oacc[8][4];
    #pragma unroll
    for (int nf = 0; nf < 8; nf++)
        #pragma unroll
        for (int q = 0; q < 4; q++) oacc[nf][q] = 0.f;
    float l0 = 0.f, l1 = 0.f;

    for (int t = 0; t < ntiles; t++) {
        const int kvb = t & 1;
        const int j0 = t * 64;
        const int jjb = j0 - i0 + 960;

        if (t + 1 < ntiles) stage_kv(kvb ^ 1, j0 + 64);
        stage_rw(kvb, jjb0 + 64*(t + 2));
        CP_COMMIT();

        const uint32_t kso = smb + (uint32_t)(kvb ? W_K1 : W_K0)*4;
        float sc[4][4];
        #pragma unroll
        for (int nf = 0; nf < 4; nf++)
            #pragma unroll
            for (int q = 0; q < 4; q++) sc[nf][q] = 0.f;
        #pragma unroll
        for (int k0 = 0; k0 < 4; k0++) {
            uint32_t a0, a1, a2, a3, p0, p1, p2, p3, q0, q1, q2, q3;
            ldsm4(a0, a1, a2, a3, smb + W_QW*4 + aoff + k0*32);
            ldsm4(p0, p1, p2, p3, kso + boff + k0*32);
            ldsm4(q0, q1, q2, q3, kso + boff + 16*ASW*4 + k0*32);
            mma_bf16(sc[0][0], sc[0][1], sc[0][2], sc[0][3], a0, a1, a2, a3, p0, p1);
            mma_bf16(sc[1][0], sc[1][1], sc[1][2], sc[1][3], a0, a1, a2, a3, p2, p3);
            mma_bf16(sc[2][0], sc[2][1], sc[2][2], sc[2][3], a0, a1, a2, a3, q0, q1);
            mma_bf16(sc[3][0], sc[3][1], sc[3][2], sc[3][3], a0, a1, a2, a3, q2, q3);
        }

        bd_pass(kvb ^ 1, jjb0 + 64*(t + 1));
        // BDR producer->consumer is confined to the wm-pair (2 warps, 64 thr)
        BAR64(wm + 1);

        const int jjb2 = jjb + 63;
        uint32_t a_lo[4], a_hi[4];
        if (t + 1 < ntiles) {
            #pragma unroll
            for (int nf = 0; nf < 4; nf++) {
                int jl = wn*32 + nf*8 + 2*tg;
                int s00 = (jjb2 + jl - il0) & 127;
                int s01 = (jjb2 + jl + 1 - il0) & 127;
                int s10 = (jjb2 + jl - il1) & 127;
                int s11 = (jjb2 + jl + 1 - il1) & 127;
                float p00 = exp2_nc(sc[nf][0] + bdr0[s00]);
                float p01 = exp2_nc(sc[nf][1] + bdr0[s01]);
                float p10 = exp2_nc(sc[nf][2] + bdr1[s10]);
                float p11 = exp2_nc(sc[nf][3] + bdr1[s11]);
                l0 += p00 + p01;
                l1 += p10 + p11;
                a_lo[nf] = pk(p00, p01);
                a_hi[nf] = pk(p10, p11);
            }
        } else {
            #pragma unroll
            for (int nf = 0; nf < 4; nf++) {
                int jl = wn*32 + nf*8 + 2*tg;
                int jg = j0 + jl;
                int s00 = (jjb2 + jl - il0) & 127;
                int s01 = (jjb2 + jl + 1 - il0) & 127;
                int s10 = (jjb2 + jl - il1) & 127;
                int s11 = (jjb2 + jl + 1 - il1) & 127;
                float p00 = 0.f, p01 = 0.f, p10 = 0.f, p11 = 0.f;
                if (jg <= i0 + il0 + MEMLEN)     p00 = exp2_nc(sc[nf][0] + bdr0[s00]);
                if (jg + 1 <= i0 + il0 + MEMLEN) p01 = exp2_nc(sc[nf][1] + bdr0[s01]);
                if (jg <= i0 + il1 + MEMLEN)     p10 = exp2_nc(sc[nf][2] + bdr1[s10]);
                if (jg + 1 <= i0 + il1 + MEMLEN) p11 = exp2_nc(sc[nf][3] + bdr1[s11]);
                l0 += p00 + p01;
                l1 += p10 + p11;
                a_lo[nf] = pk(p00, p01);
                a_hi[nf] = pk(p10, p11);
            }
        }

        const uint32_t vso = smb + (uint32_t)(kvb ? W_V1 : W_V0)*4;
        #pragma unroll
        for (int k0 = 0; k0 < 2; k0++) {
            uint32_t a0 = a_lo[2*k0], a1 = a_hi[2*k0];
            uint32_t a2 = a_lo[2*k0+1], a3 = a_hi[2*k0+1];
            uint32_t jbase = (uint32_t)((wn*32 + k0*16)*ASW)*4;
            #pragma unroll
            for (int dd = 0; dd < 4; dd++) {
                uint32_t b0, b1, b2, b3;
                ldsm4t(b0, b1, b2, b3, vso + tvpat + jbase + (uint32_t)(dd*8)*4);
                mma_bf16(oacc[dd*2][0], oacc[dd*2][1], oacc[dd*2][2], oacc[dd*2][3],
                         a0, a1, a2, a3, b0, b1);
                mma_bf16(oacc[dd*2+1][0], oacc[dd*2+1][1], oacc[dd*2+1][2], oacc[dd*2+1][3],
                         a0, a1, a2, a3, b2, b3);
            }
        }

        CP_WAIT0();
        __syncthreads();
    }

    l0 += __shfl_xor_sync(0xffffffffu, l0, 1);
    l0 += __shfl_xor_sync(0xffffffffu, l0, 2);
    l1 += __shfl_xor_sync(0xffffffffu, l1, 1);
    l1 += __shfl_xor_sync(0xffffffffu, l1, 2);
    float* obuf = BDR;
    float* lbuf = BDR + 4*16*68;
    if (wn == 1) {
        #pragma unroll
        for (int nf = 0; nf < 8; nf++) {
            int d = nf*8 + 2*tg;
            *(float2*)&obuf[il0*68 + d] = make_float2(oacc[nf][0], oacc[nf][1]);
            *(float2*)&obuf[il1*68 + d] = make_float2(oacc[nf][2], oacc[nf][3]);
        }
        if (tg == 0) { lbuf[il0] = l0; lbuf[il1] = l1; }
    }
    __syncthreads();
    if (wn == 0) {
        float inv0 = 1.f / (l0 + lbuf[il0]);
        float inv1 = 1.f / (l1 + lbuf[il1]);
        #pragma unroll
        for (int nf = 0; nf < 8; nf++) {
            int d = nf*8 + 2*tg;
            float2 o0 = *(float2*)&obuf[il0*68 + d];
            float2 o1 = *(float2*)&obuf[il1*68 + d];
            g_avh[((size_t)(i0+il0)*(BSZ*DM) + b*DM + n*DH + d)/2] =
                pk((oacc[nf][0]+o0.x)*inv0, (oacc[nf][1]+o0.y)*inv0);
            g_avh[((size_t)(i0+il1)*(BSZ*DM) + b*DM + n*DH + d)/2] =
                pk((oacc[nf][2]+o1.x)*inv1, (oacc[nf][3]+o1.y)*inv1);
        }
    }
}

// ---------------- residual + layernorm: warp per row -------------------------
__global__ __launch_bounds__(256) void k_ln2(const float* __restrict__ w,
                                             const float* __restrict__ g,
                                             const float* __restrict__ be,
                                             float* __restrict__ out)
{
    int row = blockIdx.x * 8 + (threadIdx.x >> 5);
    int lane = threadIdx.x & 31;
    const float* wr = w    + (size_t)row * DM;
    const float* ar = g_ao + (size_t)row * DM;

    float4 x[4];
    float s = 0.f;
    #pragma unroll
    for (int c = 0; c < 4; c++) {
        int idx = c*128 + lane*4;
        float4 a = *(const float4*)&wr[idx];
        float4 o = *(const float4*)&ar[idx];
        x[c] = make_float4(a.x+o.x, a.y+o.y, a.z+o.z, a.w+o.w);
        s += x[c].x + x[c].y + x[c].z + x[c].w;
    }
    #pragma unroll
    for (int m = 16; m > 0; m >>= 1) s += __shfl_xor_sync(0xffffffffu, s, m);
    float mu = s * (1.f / DM);
    float v = 0.f;
    #pragma unroll
    for (int c = 0; c < 4; c++) {
        float dx = x[c].x - mu, dy = x[c].y - mu, dz = x[c].z - mu, dw = x[c].w - mu;
        x[c] = make_float4(dx, dy, dz, dw);
        v += dx*dx + dy*dy + dz*dz + dw*dw;
    }
    #pragma unroll
    for (int m = 16; m > 0; m >>= 1) v += __shfl_xor_sync(0xffffffffu, v, m);
    float rs = rsqrtf(v * (1.f / DM) + 1e-5f);
    #pragma unroll
    for (int c = 0; c < 4; c++) {
        int idx = c*128 + lane*4;
        float4 gg = *(const float4*)&g[idx];
        float4 bb = *(const float4*)&be[idx];
        float4 r = make_float4(x[c].x*rs*gg.x + bb.x, x[c].y*rs*gg.y + bb.y,
                               x[c].z*rs*gg.z + bb.z, x[c].w*rs*gg.w + bb.w);
        *(float4*)&out[(size_t)row*DM + idx] = r;
    }
}

// ---------------- launcher ---------------------------------------------------
extern "C" void kernel_launch(void* const* d_in, const int* in_sizes, int n_in,
                              void* d_out, int out_size)
{
    (void)in_sizes; (void)n_in; (void)out_size;
    const float* w    = (const float*)d_in[0];
    const float* r    = (const float*)d_in[1];
    const float* mems = (const float*)d_in[2];
    const float* rwb  = (const float*)d_in[3];
    const float* rrb  = (const float*)d_in[4];
    const float* qkvW = (const float*)d_in[5];
    const float* rW   = (const float*)d_in[6];
    const float* cqw  = (const float*)d_in[7];
    const float* cqb  = (const float*)d_in[8];
    const float* ckw  = (const float*)d_in[9];
    const float* ckb  = (const float*)d_in[10];
    const float* cvw  = (const float*)d_in[11];
    const float* cvb  = (const float*)d_in[12];
    const float* oW   = (const float*)d_in[13];
    const float* lng  = (const float*)d_in[14];
    const float* lnb  = (const float*)d_in[15];
    float* out = (float*)d_out;

    uint32_t *p_avh, *p_oWh;
    float *p_ao;
    cudaGetSymbolAddress((void**)&p_avh, g_avh);
    cudaGetSymbolAddress((void**)&p_oWh, g_oWh);
    cudaGetSymbolAddress((void**)&p_ao,  g_ao);

    dim3 b256(256);

    k_cvt7<<<2048, b256>>>(mems, w, qkvW, r, rW, oW, cqw, ckw, cvw);

    mm_qkr<<<dim3(QKV/128, 80), b256>>>();

    int csm = (134*CSW + 7*64*CSW) * 4;
    cudaFuncSetAttribute(k_conv6, cudaFuncAttributeMaxDynamicSharedMemorySize, csm);
    k_conv6<<<dim3(40, NH*BSZ), b256, csm>>>(cqb, ckb, cvb);

    int asm_ = (W_BDR + 64*132) * 4;
    cudaFuncSetAttribute(k_attn11, cudaFuncAttributeMaxDynamicSharedMemorySize, asm_);
    k_attn11<<<dim3(QLEN/64, BSZ*NH), b256, asm_>>>(rwb, rrb);

    mm_h<<<dim3(DM/128, (QLEN*BSZ)/128), b256>>>(p_avh, p_oWh, p_ao, DM, DM, 0);
    k_ln2<<<(QLEN*BSZ)/8, b256>>>(w, lng, lnb, out);
}

// round 16
// speedup vs baseline: 13.4406x; 1.0235x over previous
#include <cuda_runtime.h>
#include <cuda_bf16.h>
#include <math.h>
#include <stdint.h>

#define QLEN 1024
#define KLEN 2048
#define MEMLEN 1024
#define BSZ 4
#define NH 8
#define DH 64
#define DM 512
#define QKV (3*DM)

__device__ uint32_t g_qkvh[(size_t)KLEN*BSZ*QKV/2]; // bf16 pairs (jk, b, 1536)
__device__ uint32_t g_rkh [(size_t)KLEN*DM/2];      // bf16 pairs (jj, n*64+d)
__device__ uint32_t g_q  [(size_t)QLEN*BSZ*DM/2];
__device__ uint32_t g_k  [(size_t)KLEN*BSZ*DM/2];
__device__ uint32_t g_v  [(size_t)KLEN*BSZ*DM/2];
__device__ uint32_t g_avh[(size_t)QLEN*BSZ*DM/2];   // attention out, bf16
__device__ float    g_ao [(size_t)QLEN*BSZ*DM];
__device__ uint32_t g_wt[3*7*64*32];
__device__ uint32_t g_xh [(size_t)KLEN*BSZ*DM/2];   // [mems; w]
__device__ uint32_t g_wh [(size_t)QKV*DM/2];        // qkvW
__device__ uint32_t g_rh [(size_t)KLEN*DM/2];       // r
__device__ uint32_t g_rWh[(size_t)DM*DM/2];         // rW
__device__ uint32_t g_oWh[(size_t)DM*DM/2];         // oW

__device__ __forceinline__ uint32_t pk(float x, float y) {
    __nv_bfloat162 t = __floats2bfloat162_rn(x, y);
    return *(uint32_t*)&t;
}
__device__ __forceinline__ float bl(uint32_t w) {
    __nv_bfloat16 h = *(__nv_bfloat16*)&w;
    return __bfloat162float(h);
}
__device__ __forceinline__ float bh(uint32_t w) {
    uint16_t u = (uint16_t)(w >> 16);
    __nv_bfloat16 h = *(__nv_bfloat16*)&u;
    return __bfloat162float(h);
}

__device__ __forceinline__ void mma_bf16(float& c0, float& c1, float& c2, float& c3,
                                         uint32_t a0, uint32_t a1, uint32_t a2, uint32_t a3,
                                         uint32_t b0, uint32_t b1)
{
    asm volatile("mma.sync.aligned.m16n8k16.row.col.f32.bf16.bf16.f32 "
                 "{%0,%1,%2,%3},{%4,%5,%6,%7},{%8,%9},{%0,%1,%2,%3};\n"
                 : "+f"(c0), "+f"(c1), "+f"(c2), "+f"(c3)
                 : "r"(a0), "r"(a1), "r"(a2), "r"(a3), "r"(b0), "r"(b1));
}

__device__ __forceinline__ void ldsm4(uint32_t& r0, uint32_t& r1, uint32_t& r2, uint32_t& r3,
                                      uint32_t addr)
{
    asm volatile("ldmatrix.sync.aligned.m8n8.x4.shared.b16 {%0,%1,%2,%3}, [%4];"
                 : "=r"(r0), "=r"(r1), "=r"(r2), "=r"(r3) : "r"(addr));
}
__device__ __forceinline__ void ldsm4t(uint32_t& r0, uint32_t& r1, uint32_t& r2, uint32_t& r3,
                                       uint32_t addr)
{
    asm volatile("ldmatrix.sync.aligned.m8n8.x4.trans.shared.b16 {%0,%1,%2,%3}, [%4];"
                 : "=r"(r0), "=r"(r1), "=r"(r2), "=r"(r3) : "r"(addr));
}

__device__ __forceinline__ void cpa16(uint32_t saddr, const void* gaddr) {
    asm volatile("cp.async.cg.shared.global [%0], [%1], 16;" :: "r"(saddr), "l"(gaddr));
}
__device__ __forceinline__ void cpa16z(uint32_t saddr, const void* gaddr, int ok) {
    int sz = ok ? 16 : 0;
    asm volatile("cp.async.cg.shared.global [%0], [%1], 16, %2;"
                 :: "r"(saddr), "l"(gaddr), "r"(sz));
}
#define CP_COMMIT() asm volatile("cp.async.commit_group;")
#define CP_WAIT0()  asm volatile("cp.async.wait_group 0;")
#define CP_WAIT1()  asm volatile("cp.async.wait_group 1;")
#define BAR64(id)   asm volatile("bar.sync %0, 64;" :: "r"(id) : "memory")

__device__ __forceinline__ float exp2_nc(float y) {
    float z = __fadd_rn(y, 12582912.f);
    float n = __fsub_rn(z, 12582912.f);
    float f = __fsub_rn(y, n);
    float r = 0.0096181291f;
    r = fmaf(r, f, 0.055504109f);
    r = fmaf(r, f, 0.24022651f);
    r = fmaf(r, f, 0.69314718f);
    r = fmaf(r, f, 1.0f);
    int e = __float_as_int(z);
    float s = __int_as_float((e - 1262485377) << 23);
    return r * s;
}

// ---------------- fused fp32 -> bf16 convert + conv weight prep (7 segs) -----
#define CVT_N0 (MEMLEN*BSZ*DM/2)
#define CVT_N1 (QLEN*BSZ*DM/2)
#define CVT_N2 (QKV*DM/2)
#define CVT_N3 (KLEN*DM/2)
#define CVT_N4 (DM*DM/2)
#define CVT_N6 (3*7*64*32)
#define CVT_C0 (CVT_N0)
#define CVT_C1 (CVT_C0 + CVT_N1)
#define CVT_C2 (CVT_C1 + CVT_N2)
#define CVT_C3 (CVT_C2 + CVT_N3)
#define CVT_C4 (CVT_C3 + CVT_N4)
#define CVT_C5 (CVT_C4 + CVT_N4)
#define CVT_TOT (CVT_C5 + CVT_N6)
__global__ void k_cvt7(const float* __restrict__ mems, const float* __restrict__ w,
                       const float* __restrict__ qkvW, const float* __restrict__ r,
                       const float* __restrict__ rW,   const float* __restrict__ oW,
                       const float* __restrict__ cq,   const float* __restrict__ ck,
                       const float* __restrict__ cv)
{
    int idx = blockIdx.x * blockDim.x + threadIdx.x;
    int stride = gridDim.x * blockDim.x;
    for (int i = idx; i < CVT_TOT; i += stride) {
        if (i < CVT_C5) {
            const float* s;
            uint32_t* d;
            int off;
            if (i < CVT_C0)      { s = mems; d = g_xh;            off = i; }
            else if (i < CVT_C1) { s = w;    d = g_xh + CVT_C0;   off = i - CVT_C0; }
            else if (i < CVT_C2) { s = qkvW; d = g_wh;            off = i - CVT_C1; }
            else if (i < CVT_C3) { s = r;    d = g_rh;            off = i - CVT_C2; }
            else if (i < CVT_C4) { s = rW;   d = g_rWh;           off = i - CVT_C3; }
            else                 { s = oW;   d = g_oWh;           off = i - CVT_C4; }
            float2 v = *(const float2*)&s[2*off];
            d[off] = pk(v.x, v.y);
        } else {
            int off = i - CVT_C5;
            int ct = off >> 11;
            int c = ct / 7, tap = ct % 7;
            int e = off & 2047;
            int oc = e >> 5, icw = e & 31;
            const float* src = (c == 0) ? cq : (c == 1) ? ck : cv;
            float w0 = src[(oc*64 + 2*icw    )*7 + tap];
            float w1 = src[(oc*64 + 2*icw + 1)*7 + tap];
            g_wt[(ct*64 + oc)*32 + icw] = pk(w0, w1);
        }
    }
}

// ---------------- BF16 GEMM body: 3-stage cp.async + ldmatrix ----------------
#define GSW 12
#define NSTG 3
__device__ __forceinline__ void mm_body(const uint32_t* __restrict__ A,
                                        const uint32_t* __restrict__ B,
                                        void* __restrict__ Cout,
                                        int N, int K, int pack, int m0, int n0)
{
    __shared__ uint32_t As[NSTG][128*GSW];
    __shared__ uint32_t Bs[NSTG][128*GSW];
    const int tid = threadIdx.x;
    const int warp = tid >> 5, lane = tid & 31;
    const int wm = warp & 3, wn = warp >> 2;
    const int g = lane >> 2, tg = lane & 3;
    const int quad = lane >> 3;
    const int Kw = K / 2;
    const int iters = Kw / 8;

    const uint32_t smA = (uint32_t)__cvta_generic_to_shared(As);
    const uint32_t smB = (uint32_t)__cvta_generic_to_shared(Bs);
    const uint32_t apat = (uint32_t)((lane & 15)*GSW + (lane >> 4)*4)*4;
    const uint32_t bpat = (uint32_t)((((quad & 2)*4) + (lane & 7))*GSW + (quad & 1)*4)*4;

    float c[2][8][4];
    #pragma unroll
    for (int mt = 0; mt < 2; mt++)
        #pragma unroll
        for (int nt = 0; nt < 8; nt++)
            #pragma unroll
            for (int q = 0; q < 4; q++) c[mt][nt][q] = 0.f;

    const int lr = tid >> 1;
    const int lh = tid & 1;
    const uint32_t* Ap = A + (size_t)(m0 + lr) * Kw + lh * 4;
    const uint32_t* Bp = B + (size_t)(n0 + lr) * Kw + lh * 4;

    auto stage = [&](int s, int kw) {
        uint32_t so = (uint32_t)(s*128*GSW + lr*GSW + lh*4)*4;
        cpa16(smA + so, Ap + kw);
        cpa16(smB + so, Bp + kw);
    };

    stage(0, 0);
    CP_COMMIT();
    if (iters > 1) stage(1, 8);
    CP_COMMIT();

    for (int i = 0; i < iters; i++) {
        CP_WAIT1();
        __syncthreads();
        int pf = i + NSTG - 1;
        if (pf < iters) stage(pf % NSTG, pf * 8);
        CP_COMMIT();

        const int buf = i % NSTG;
        const uint32_t abase = smA + (uint32_t)(buf*128*GSW)*4;
        const uint32_t bbase = smB + (uint32_t)(buf*128*GSW)*4;
        uint32_t af[2][4], bf[8][2];
        #pragma unroll
        for (int mt = 0; mt < 2; mt++)
            ldsm4(af[mt][0], af[mt][1], af[mt][2], af[mt][3],
                  abase + (uint32_t)((wm*32 + mt*16)*GSW)*4 + apat);
        #pragma unroll
        for (int nt2 = 0; nt2 < 4; nt2++) {
            uint32_t b0, b1, b2, b3;
            ldsm4(b0, b1, b2, b3,
                  bbase + (uint32_t)((wn*64 + nt2*16)*GSW)*4 + bpat);
            bf[nt2*2][0] = b0;   bf[nt2*2][1] = b1;
            bf[nt2*2+1][0] = b2; bf[nt2*2+1][1] = b3;
        }
        #pragma unroll
        for (int mt = 0; mt < 2; mt++)
            #pragma unroll
            for (int nt = 0; nt < 8; nt++)
                mma_bf16(c[mt][nt][0], c[mt][nt][1], c[mt][nt][2], c[mt][nt][3],
                         af[mt][0], af[mt][1], af[mt][2], af[mt][3],
                         bf[nt][0], bf[nt][1]);
    }

    #pragma unroll
    for (int mt = 0; mt < 2; mt++) {
        int row0 = m0 + wm * 32 + mt * 16 + g;
        #pragma unroll
        for (int nt = 0; nt < 8; nt++) {
            int col = n0 + wn * 64 + nt * 8 + tg * 2;
            if (pack) {
                uint32_t* Cp = (uint32_t*)Cout;
                Cp[((size_t)row0 * N + col)/2]       = pk(c[mt][nt][0], c[mt][nt][1]);
                Cp[((size_t)(row0 + 8) * N + col)/2] = pk(c[mt][nt][2], c[mt][nt][3]);
            } else {
                float* C = (float*)Cout;
                *(float2*)&C[(size_t)row0 * N + col]       = make_float2(c[mt][nt][0], c[mt][nt][1]);
                *(float2*)&C[(size_t)(row0 + 8) * N + col] = make_float2(c[mt][nt][2], c[mt][nt][3]);
            }
        }
    }
}

__global__ __launch_bounds__(256, 2) void mm_h(const uint32_t* __restrict__ A,
                                               const uint32_t* __restrict__ B,
                                               void* __restrict__ Cout,
                                               int N, int K, int pack)
{
    mm_body(A, B, Cout, N, K, pack, blockIdx.y * 128, blockIdx.x * 128);
}

__global__ __launch_bounds__(256, 2) void mm_qkr()
{
    int y = blockIdx.y;
    if (y < 64) {
        mm_body(g_xh, g_wh, g_qkvh, QKV, DM, 1, y * 128, blockIdx.x * 128);
    } else {
        if (blockIdx.x >= 4) return;
        mm_body(g_rh, g_rWh, g_rkh, DM, DM, 1, (y - 64) * 128, blockIdx.x * 128);
    }
}

// ---------------- fused conv v6: 4m x 2n warp tiling -------------------------
#define CSW 36
#define OFF_WS (134*CSW*4)
__global__ __launch_bounds__(256, 2) void k_conv6(const float* __restrict__ cqb,
                                                  const float* __restrict__ ckb,
                                                  const float* __restrict__ cvb)
{
    extern __shared__ uint32_t cs[];
    const int bx = blockIdx.x;
    int c, t0, len, posoff, chanoff;
    const float* cb;
    uint32_t* outp;
    if (bx < 8)       { c = 0; t0 = bx*128;      len = QLEN; posoff = MEMLEN; chanoff = 0;    cb = cqb; outp = g_q; }
    else if (bx < 24) { c = 1; t0 = (bx-8)*128;  len = KLEN; posoff = 0;      chanoff = DM;   cb = ckb; outp = g_k; }
    else              { c = 2; t0 = (bx-24)*128; len = KLEN; posoff = 0;      chanoff = 2*DM; cb = cvb; outp = g_v; }
    const int nb = blockIdx.y;
    const int n = nb >> 2, b = nb & 3;
    const int tid = threadIdx.x;
    const int warp = tid >> 5, lane = tid & 31;
    const int wm = warp & 3, wn = warp >> 2;
    const int g = lane >> 2, tg = lane & 3;
    const int quad = lane >> 3;
    const uint32_t smbC = (uint32_t)__cvta_generic_to_shared(cs);

    for (int e = tid; e < 134*8; e += 256) {
        int u = e >> 3, w4 = (e & 7) * 4;
        int pos = t0 + u - 3;
        int ok = (pos >= 0 && pos < len);
        int pc = ok ? pos : 0;
        cpa16z(smbC + (uint32_t)(u*CSW + w4)*4,
               &g_qkvh[((size_t)(pc + posoff)*(BSZ*QKV) + b*QKV + chanoff + n*DH)/2 + w4], ok);
    }
    {
        const uint32_t* src = g_wt + c*7*64*32;
        for (int e = tid; e < 3584; e += 256) {
            int s4 = e * 4;
            int to = s4 >> 5, icw = s4 & 31;
            cpa16(smbC + OFF_WS + (uint32_t)(to*CSW + icw)*4, &src[s4]);
        }
    }
    CP_COMMIT();
    CP_WAIT0();
    __syncthreads();

    float acc[2][4][4];
    #pragma unroll
    for (int am = 0; am < 2; am++)
        #pragma unroll
        for (int nf = 0; nf < 4; nf++)
            #pragma unroll
            for (int q = 0; q < 4; q++) acc[am][nf][q] = 0.f;

    const uint32_t bpat = (uint32_t)((((quad & 2)*4) + (lane & 7))*CSW + (quad & 1)*4)*4;

    #pragma unroll
    for (int tap = 0; tap < 7; tap++) {
        const uint32_t apat0 = (uint32_t)((wm*16 + (lane & 15) + tap)*CSW + (lane >> 4)*4)*4;
        #pragma unroll
        for (int k0 = 0; k0 < 4; k0++) {
            uint32_t a0[2], a1[2], a2[2], a3[2];
            ldsm4(a0[0], a1[0], a2[0], a3[0], smbC + apat0 + k0*32);
            ldsm4(a0[1], a1[1], a2[1], a3[1], smbC + apat0 + (uint32_t)(64*CSW)*4 + k0*32);
            #pragma unroll
            for (int nf2 = 0; nf2 < 2; nf2++) {
                uint32_t b0, b1, b2, b3;
                ldsm4(b0, b1, b2, b3,
                      smbC + OFF_WS + bpat
                      + (uint32_t)((tap*64 + wn*32 + nf2*16)*CSW)*4 + k0*32);
                #pragma unroll
                for (int am = 0; am < 2; am++) {
                    mma_bf16(acc[am][nf2*2][0], acc[am][nf2*2][1],
                             acc[am][nf2*2][2], acc[am][nf2*2][3],
                             a0[am], a1[am], a2[am], a3[am], b0, b1);
                    mma_bf16(acc[am][nf2*2+1][0], acc[am][nf2*2+1][1],
                             acc[am][nf2*2+1][2], acc[am][nf2*2+1][3],
                             a0[am], a1[am], a2[am], a3[am], b2, b3);
                }
            }
        }
    }

    #pragma unroll
    for (int am = 0; am < 2; am++) {
        #pragma unroll
        for (int nf = 0; nf < 4; nf++) {
            int oc = wn*32 + nf*8 + 2*tg;
            float2 bb = *(const float2*)&cb[oc];
            int row = t0 + wm*16 + am*64 + g;
            size_t w0 = ((size_t)row*(BSZ*DM) + b*DM)/2 + n*32 + oc/2;
            size_t w1 = ((size_t)(row+8)*(BSZ*DM) + b*DM)/2 + n*32 + oc/2;
            outp[w0] = pk(acc[am][nf][0] + bb.x, acc[am][nf][1] + bb.y);
            outp[w1] = pk(acc[am][nf][2] + bb.x, acc[am][nf][3] + bb.y);
        }
    }
}

// ---------------- attention v12: balanced dual-item persistent blocks --------
#define ASW 36
#define W_QW 0
#define W_QR 2304
#define W_K0 4608
#define W_K1 6912
#define W_V0 9216
#define W_V1 11520
#define W_R0 13824
#define W_R1 16128
#define W_BDR 18432
__global__ __launch_bounds__(256, 2) void k_attn12(const float* __restrict__ rwb,
                                                   const float* __restrict__ rrb)
{
    extern __shared__ uint32_t smu[];
    float* BDR = (float*)(smu + W_BDR);

    const int tid = threadIdx.x;
    const int warp = tid >> 5, lane = tid & 31;
    const int wm = warp & 3, wn = warp >> 2;
    const int g = lane >> 2, tg = lane & 3;
    const int quad = lane >> 3;

    const uint32_t smb = (uint32_t)__cvta_generic_to_shared(smu);
    const uint32_t aoff  = (uint32_t)((wm*16 + (lane & 15))*ASW + (lane >> 4)*4)*4;
    const uint32_t bpat  = (uint32_t)((((quad & 2)*4) + (lane & 7))*ASW + (quad & 1)*4)*4;
    const uint32_t boff  = bpat + (uint32_t)(wn*32)*ASW*4;
    const uint32_t tvpat = (uint32_t)(((quad & 1)*8 + (lane & 7))*ASW + (quad >> 1)*4)*4;

    const int il0 = wm*16 + g;
    const int il1 = il0 + 8;
    float* const bdr0 = &BDR[il0*132];
    float* const bdr1 = &BDR[il1*132];

    // two work items per block: q = bid (heavy, x in [0,8)) and 511-bid (light)
    #pragma unroll 1
    for (int s = 0; s < 2; s++) {
        const int q = s ? (511 - (int)blockIdx.x) : (int)blockIdx.x;
        const int x = q >> 5;
        const int bn = q & 31;
        const int b = bn >> 3, n = bn & 7;
        const int i0 = (15 - x) * 64;
        const int jjb0 = 960 - i0;
        const int ntiles = i0/64 + 17;

        auto stage_kv = [&](int buf, int j0c) {
            const uint32_t kb = smb + (uint32_t)(buf ? W_K1 : W_K0)*4;
            const uint32_t vb = smb + (uint32_t)(buf ? W_V1 : W_V0)*4;
            #pragma unroll
            for (int e0 = 0; e0 < 2; e0++) {
                int e = tid + e0*256;
                int jl = e >> 3, w4 = (e & 7) * 4;
                size_t wi = ((size_t)(j0c + jl)*(BSZ*DM) + b*DM + n*DH)/2 + w4;
                uint32_t so = (uint32_t)(jl*ASW + w4)*4;
                cpa16(kb + so, &g_k[wi]);
                cpa16(vb + so, &g_v[wi]);
            }
        };
        auto stage_rw = [&](int buf, int cb2) {
            const uint32_t rb = smb + (uint32_t)(buf ? W_R1 : W_R0)*4;
            #pragma unroll
            for (int e0 = 0; e0 < 2; e0++) {
                int e = tid + e0*256;
                int l = e >> 3, w4 = (e & 7) * 4;
                int jj = cb2 + l;
                int ok = (jj < KLEN);
                int jc = ok ? jj : (KLEN - 1);
                cpa16z(rb + (uint32_t)(l*ASW + w4)*4,
                       &g_rkh[((size_t)jc*DM + n*DH)/2 + w4], ok);
            }
        };
        auto bd_pass = [&](int rbuf, int cb2) {
            const uint32_t rwo = smb + (uint32_t)(rbuf ? W_R1 : W_R0)*4;
            const int s0 = cb2 & 127;
            float pc[4][4];
            #pragma unroll
            for (int nf = 0; nf < 4; nf++)
                #pragma unroll
                for (int qq = 0; qq < 4; qq++) pc[nf][qq] = 0.f;
            #pragma unroll
            for (int k0 = 0; k0 < 4; k0++) {
                uint32_t a0, a1, a2, a3, p0, p1, p2, p3, q0, q1, q2, q3;
                ldsm4(a0, a1, a2, a3, smb + W_QR*4 + aoff + k0*32);
                ldsm4(p0, p1, p2, p3, rwo + boff + k0*32);
                ldsm4(q0, q1, q2, q3, rwo + boff + 16*ASW*4 + k0*32);
                mma_bf16(pc[0][0], pc[0][1], pc[0][2], pc[0][3], a0, a1, a2, a3, p0, p1);
                mma_bf16(pc[1][0], pc[1][1], pc[1][2], pc[1][3], a0, a1, a2, a3, p2, p3);
                mma_bf16(pc[2][0], pc[2][1], pc[2][2], pc[2][3], a0, a1, a2, a3, q0, q1);
                mma_bf16(pc[3][0], pc[3][1], pc[3][2], pc[3][3], a0, a1, a2, a3, q2, q3);
            }
            #pragma unroll
            for (int nf = 0; nf < 4; nf++) {
                int cc = s0 + wn*32 + nf*8 + 2*tg;
                *(float2*)&bdr0[cc] = make_float2(pc[nf][0], pc[nf][1]);
                *(float2*)&bdr1[cc] = make_float2(pc[nf][2], pc[nf][3]);
            }
        };

        stage_kv(0, 0);
        stage_rw(0, jjb0);
        stage_rw(1, jjb0 + 64);
        CP_COMMIT();

        // Q (+biases), pre-scaled by 0.125*log2(e)
        const float SCL = 0.18033688f;
        for (int e = tid; e < 64*16; e += 256) {
            int ii = e >> 4, d4 = (e & 15) * 4;
            size_t wi = ((size_t)(i0+ii)*(BSZ*DM) + b*DM + n*DH + d4) / 2;
            uint2 qv = *(const uint2*)&g_q[wi];
            float q0 = bl(qv.x), q1 = bh(qv.x), q2 = bl(qv.y), q3 = bh(qv.y);
            float4 wv = *(const float4*)&rwb[n*DH + d4];
            float4 rv = *(const float4*)&rrb[n*DH + d4];
            smu[W_QW + ii*ASW + d4/2]     = pk((q0 + wv.x)*SCL, (q1 + wv.y)*SCL);
            smu[W_QW + ii*ASW + d4/2 + 1] = pk((q2 + wv.z)*SCL, (q3 + wv.w)*SCL);
            smu[W_QR + ii*ASW + d4/2]     = pk((q0 + rv.x)*SCL, (q1 + rv.y)*SCL);
            smu[W_QR + ii*ASW + d4/2 + 1] = pk((q2 + rv.z)*SCL, (q3 + rv.w)*SCL);
        }
        CP_WAIT0();
        __syncthreads();

        bd_pass(0, jjb0);

        float oacc[8][4];
        #pragma unroll
        for (int nf = 0; nf < 8; nf++)
            #pragma unroll
            for (int qq = 0; qq < 4; qq++) oacc[nf][qq] = 0.f;
        float l0 = 0.f, l1 = 0.f;

        for (int t = 0; t < ntiles; t++) {
            const int kvb = t & 1;
            const int j0 = t * 64;
            const int jjb = j0 - i0 + 960;

            if (t + 1 < ntiles) stage_kv(kvb ^ 1, j0 + 64);
            stage_rw(kvb, jjb0 + 64*(t + 2));
            CP_COMMIT();

            const uint32_t kso = smb + (uint32_t)(kvb ? W_K1 : W_K0)*4;
            float sc[4][4];
            #pragma unroll
            for (int nf = 0; nf < 4; nf++)
                #pragma unroll
                for (int qq = 0; qq < 4; qq++) sc[nf][qq] = 0.f;
            #pragma unroll
            for (int k0 = 0; k0 < 4; k0++) {
                uint32_t a0, a1, a2, a3, p0, p1, p2, p3, q0, q1, q2, q3;
                ldsm4(a0, a1, a2, a3, smb + W_QW*4 + aoff + k0*32);
                ldsm4(p0, p1, p2, p3, kso + boff + k0*32);
                ldsm4(q0, q1, q2, q3, kso + boff + 16*ASW*4 + k0*32);
                mma_bf16(sc[0][0], sc[0][1], sc[0][2], sc[0][3], a0, a1, a2, a3, p0, p1);
                mma_bf16(sc[1][0], sc[1][1], sc[1][2], sc[1][3], a0, a1, a2, a3, p2, p3);
                mma_bf16(sc[2][0], sc[2][1], sc[2][2], sc[2][3], a0, a1, a2, a3, q0, q1);
                mma_bf16(sc[3][0], sc[3][1], sc[3][2], sc[3][3], a0, a1, a2, a3, q2, q3);
            }

            bd_pass(kvb ^ 1, jjb0 + 64*(t + 1));
            BAR64(wm + 1);

            const int jjb2 = jjb + 63;
            uint32_t a_lo[4], a_hi[4];
            if (t + 1 < ntiles) {
                #pragma unroll
                for (int nf = 0; nf < 4; nf++) {
                    int jl = wn*32 + nf*8 + 2*tg;
                    int s00 = (jjb2 + jl - il0) & 127;
                    int s01 = (jjb2 + jl + 1 - il0) & 127;
                    int s10 = (jjb2 + jl - il1) & 127;
                    int s11 = (jjb2 + jl + 1 - il1) & 127;
                    float p00 = exp2_nc(sc[nf][0] + bdr0[s00]);
                    float p01 = exp2_nc(sc[nf][1] + bdr0[s01]);
                    float p10 = exp2_nc(sc[nf][2] + bdr1[s10]);
                    float p11 = exp2_nc(sc[nf][3] + bdr1[s11]);
                    l0 += p00 + p01;
                    l1 += p10 + p11;
                    a_lo[nf] = pk(p00, p01);
                    a_hi[nf] = pk(p10, p11);
                }
            } else {
                #pragma unroll
                for (int nf = 0; nf < 4; nf++) {
                    int jl = wn*32 + nf*8 + 2*tg;
                    int jg = j0 + jl;
                    int s00 = (jjb2 + jl - il0) & 127;
                    int s01 = (jjb2 + jl + 1 - il0) & 127;
                    int s10 = (jjb2 + jl - il1) & 127;
                    int s11 = (jjb2 + jl + 1 - il1) & 127;
                    float p00 = 0.f, p01 = 0.f, p10 = 0.f, p11 = 0.f;
                    if (jg <= i0 + il0 + MEMLEN)     p00 = exp2_nc(sc[nf][0] + bdr0[s00]);
                    if (jg + 1 <= i0 + il0 + MEMLEN) p01 = exp2_nc(sc[nf][1] + bdr0[s01]);
                    if (jg <= i0 + il1 + MEMLEN)     p10 = exp2_nc(sc[nf][2] + bdr1[s10]);
                    if (jg + 1 <= i0 + il1 + MEMLEN) p11 = exp2_nc(sc[nf][3] + bdr1[s11]);
                    l0 += p00 + p01;
                    l1 += p10 + p11;
                    a_lo[nf] = pk(p00, p01);
                    a_hi[nf] = pk(p10, p11);
                }
            }

            const uint32_t vso = smb + (uint32_t)(kvb ? W_V1 : W_V0)*4;
            #pragma unroll
            for (int k0 = 0; k0 < 2; k0++) {
                uint32_t a0 = a_lo[2*k0], a1 = a_hi[2*k0];
                uint32_t a2 = a_lo[2*k0+1], a3 = a_hi[2*k0+1];
                uint32_t jbase = (uint32_t)((wn*32 + k0*16)*ASW)*4;
                #pragma unroll
                for (int dd = 0; dd < 4; dd++) {
                    uint32_t b0, b1, b2, b3;
                    ldsm4t(b0, b1, b2, b3, vso + tvpat + jbase + (uint32_t)(dd*8)*4);
                    mma_bf16(oacc[dd*2][0], oacc[dd*2][1], oacc[dd*2][2], oacc[dd*2][3],
                             a0, a1, a2, a3, b0, b1);
                    mma_bf16(oacc[dd*2+1][0], oacc[dd*2+1][1], oacc[dd*2+1][2], oacc[dd*2+1][3],
                             a0, a1, a2, a3, b2, b3);
                }
            }

            CP_WAIT0();
            __syncthreads();
        }

        l0 += __shfl_xor_sync(0xffffffffu, l0, 1);
        l0 += __shfl_xor_sync(0xffffffffu, l0, 2);
        l1 += __shfl_xor_sync(0xffffffffu, l1, 1);
        l1 += __shfl_xor_sync(0xffffffffu, l1, 2);
        float* obuf = BDR;
        float* lbuf = BDR + 4*16*68;
        if (wn == 1) {
            #pragma unroll
            for (int nf = 0; nf < 8; nf++) {
                int d = nf*8 + 2*tg;
                *(float2*)&obuf[il0*68 + d] = make_float2(oacc[nf][0], oacc[nf][1]);
                *(float2*)&obuf[il1*68 + d] = make_float2(oacc[nf][2], oacc[nf][3]);
            }
            if (tg == 0) { lbuf[il0] = l0; lbuf[il1] = l1; }
        }
        __syncthreads();
        if (wn == 0) {
            float inv0 = 1.f / (l0 + lbuf[il0]);
            float inv1 = 1.f / (l1 + lbuf[il1]);
            #pragma unroll
            for (int nf = 0; nf < 8; nf++) {
                int d = nf*8 + 2*tg;
                float2 o0 = *(float2*)&obuf[il0*68 + d];
                float2 o1 = *(float2*)&obuf[il1*68 + d];
                g_avh[((size_t)(i0+il0)*(BSZ*DM) + b*DM + n*DH + d)/2] =
                    pk((oacc[nf][0]+o0.x)*inv0, (oacc[nf][1]+o0.y)*inv0);
                g_avh[((size_t)(i0+il1)*(BSZ*DM) + b*DM + n*DH + d)/2] =
                    pk((oacc[nf][2]+o1.x)*inv1, (oacc[nf][3]+o1.y)*inv1);
            }
        }
    }
}

// ---------------- residual + layernorm: warp per row -------------------------
__global__ __launch_bounds__(256) void k_ln2(const float* __restrict__ w,
                                             const float* __restrict__ g,
                                             const float* __restrict__ be,
                                             float* __restrict__ out)
{
    int row = blockIdx.x * 8 + (threadIdx.x >> 5);
    int lane = threadIdx.x & 31;
    const float* wr = w    + (size_t)row * DM;
    const float* ar = g_ao + (size_t)row * DM;

    float4 x[4];
    float s = 0.f;
    #pragma unroll
    for (int c = 0; c < 4; c++) {
        int idx = c*128 + lane*4;
        float4 a = *(const float4*)&wr[idx];
        float4 o = *(const float4*)&ar[idx];
        x[c] = make_float4(a.x+o.x, a.y+o.y, a.z+o.z, a.w+o.w);
        s += x[c].x + x[c].y + x[c].z + x[c].w;
    }
    #pragma unroll
    for (int m = 16; m > 0; m >>= 1) s += __shfl_xor_sync(0xffffffffu, s, m);
    float mu = s * (1.f / DM);
    float v = 0.f;
    #pragma unroll
    for (int c = 0; c < 4; c++) {
        float dx = x[c].x - mu, dy = x[c].y - mu, dz = x[c].z - mu, dw = x[c].w - mu;
        x[c] = make_float4(dx, dy, dz, dw);
        v += dx*dx + dy*dy + dz*dz + dw*dw;
    }
    #pragma unroll
    for (int m = 16; m > 0; m >>= 1) v += __shfl_xor_sync(0xffffffffu, v, m);
    float rs = rsqrtf(v * (1.f / DM) + 1e-5f);
    #pragma unroll
    for (int c = 0; c < 4; c++) {
        int idx = c*128 + lane*4;
        float4 gg = *(const float4*)&g[idx];
        float4 bb = *(const float4*)&be[idx];
        float4 r = make_float4(x[c].x*rs*gg.x + bb.x, x[c].y*rs*gg.y + bb.y,
                               x[c].z*rs*gg.z + bb.z, x[c].w*rs*gg.w + bb.w);
        *(float4*)&out[(size_t)row*DM + idx] = r;
    }
}

// ---------------- launcher ---------------------------------------------------
extern "C" void kernel_launch(void* const* d_in, const int* in_sizes, int n_in,
                              void* d_out, int out_size)
{
    (void)in_sizes; (void)n_in; (void)out_size;
    const float* w    = (const float*)d_in[0];
    const float* r    = (const float*)d_in[1];
    const float* mems = (const float*)d_in[2];
    const float* rwb  = (const float*)d_in[3];
    const float* rrb  = (const float*)d_in[4];
    const float* qkvW = (const float*)d_in[5];
    const float* rW   = (const float*)d_in[6];
    const float* cqw  = (const float*)d_in[7];
    const float* cqb  = (const float*)d_in[8];
    const float* ckw  = (const float*)d_in[9];
    const float* ckb  = (const float*)d_in[10];
    const float* cvw  = (const float*)d_in[11];
    const float* cvb  = (const float*)d_in[12];
    const float* oW   = (const float*)d_in[13];
    const float* lng  = (const float*)d_in[14];
    const float* lnb  = (const float*)d_in[15];
    float* out = (float*)d_out;

    uint32_t *p_avh, *p_oWh;
    float *p_ao;
    cudaGetSymbolAddress((void**)&p_avh, g_avh);
    cudaGetSymbolAddress((void**)&p_oWh, g_oWh);
    cudaGetSymbolAddress((void**)&p_ao,  g_ao);

    dim3 b256(256);

    k_cvt7<<<2048, b256>>>(mems, w, qkvW, r, rW, oW, cqw, ckw, cvw);

    mm_qkr<<<dim3(QKV/128, 80), b256>>>();

    int csm = (134*CSW + 7*64*CSW) * 4;
    cudaFuncSetAttribute(k_conv6, cudaFuncAttributeMaxDynamicSharedMemorySize, csm);
    k_conv6<<<dim3(40, NH*BSZ), b256, csm>>>(cqb, ckb, cvb);

    // attention: 256 balanced dual-item blocks, 2 CTAs/SM -> one wave
    int asm_ = (W_BDR + 64*132) * 4;
    cudaFuncSetAttribute(k_attn12, cudaFuncAttributeMaxDynamicSharedMemorySize, asm_);
    k_attn12<<<256, b256, asm_>>>(rwb, rrb);

    mm_h<<<dim3(DM/128, (QLEN*BSZ)/128), b256>>>(p_avh, p_oWh, p_ao, DM, DM, 0);
    k_ln2<<<(QLEN*BSZ)/8, b256>>>(w, lng, lnb, out);
}

// round 17
// speedup vs baseline: 13.7180x; 1.0206x over previous
#include <cuda_runtime.h>
#include <cuda_bf16.h>
#include <math.h>
#include <stdint.h>

#define QLEN 1024
#define KLEN 2048
#define MEMLEN 1024
#define BSZ 4
#define NH 8
#define DH 64
#define DM 512
#define QKV (3*DM)

__device__ uint32_t g_qkvh[(size_t)KLEN*BSZ*QKV/2]; // bf16 pairs (jk, b, 1536)
__device__ uint32_t g_rkh [(size_t)KLEN*DM/2];      // bf16 pairs (jj, n*64+d)
__device__ uint32_t g_q  [(size_t)QLEN*BSZ*DM/2];
__device__ uint32_t g_k  [(size_t)KLEN*BSZ*DM/2];
__device__ uint32_t g_v  [(size_t)KLEN*BSZ*DM/2];
__device__ uint32_t g_avh[(size_t)QLEN*BSZ*DM/2];   // attention out, bf16
__device__ float    g_ao [(size_t)QLEN*BSZ*DM];
__device__ uint32_t g_wt[3*7*64*32];
__device__ uint32_t g_xh [(size_t)KLEN*BSZ*DM/2];   // [mems; w]
__device__ uint32_t g_wh [(size_t)QKV*DM/2];        // qkvW
__device__ uint32_t g_rh [(size_t)KLEN*DM/2];       // r
__device__ uint32_t g_rWh[(size_t)DM*DM/2];         // rW
__device__ uint32_t g_oWh[(size_t)DM*DM/2];         // oW

__device__ __forceinline__ uint32_t pk(float x, float y) {
    __nv_bfloat162 t = __floats2bfloat162_rn(x, y);
    return *(uint32_t*)&t;
}
__device__ __forceinline__ float bl(uint32_t w) {
    __nv_bfloat16 h = *(__nv_bfloat16*)&w;
    return __bfloat162float(h);
}
__device__ __forceinline__ float bh(uint32_t w) {
    uint16_t u = (uint16_t)(w >> 16);
    __nv_bfloat16 h = *(__nv_bfloat16*)&u;
    return __bfloat162float(h);
}

__device__ __forceinline__ void mma_bf16(float& c0, float& c1, float& c2, float& c3,
                                         uint32_t a0, uint32_t a1, uint32_t a2, uint32_t a3,
                                         uint32_t b0, uint32_t b1)
{
    asm volatile("mma.sync.aligned.m16n8k16.row.col.f32.bf16.bf16.f32 "
                 "{%0,%1,%2,%3},{%4,%5,%6,%7},{%8,%9},{%0,%1,%2,%3};\n"
                 : "+f"(c0), "+f"(c1), "+f"(c2), "+f"(c3)
                 : "r"(a0), "r"(a1), "r"(a2), "r"(a3), "r"(b0), "r"(b1));
}

__device__ __forceinline__ void ldsm4(uint32_t& r0, uint32_t& r1, uint32_t& r2, uint32_t& r3,
                                      uint32_t addr)
{
    asm volatile("ldmatrix.sync.aligned.m8n8.x4.shared.b16 {%0,%1,%2,%3}, [%4];"
                 : "=r"(r0), "=r"(r1), "=r"(r2), "=r"(r3) : "r"(addr));
}
__device__ __forceinline__ void ldsm4t(uint32_t& r0, uint32_t& r1, uint32_t& r2, uint32_t& r3,
                                       uint32_t addr)
{
    asm volatile("ldmatrix.sync.aligned.m8n8.x4.trans.shared.b16 {%0,%1,%2,%3}, [%4];"
                 : "=r"(r0), "=r"(r1), "=r"(r2), "=r"(r3) : "r"(addr));
}

__device__ __forceinline__ void cpa16(uint32_t saddr, const void* gaddr) {
    asm volatile("cp.async.cg.shared.global [%0], [%1], 16;" :: "r"(saddr), "l"(gaddr));
}
__device__ __forceinline__ void cpa16z(uint32_t saddr, const void* gaddr, int ok) {
    int sz = ok ? 16 : 0;
    asm volatile("cp.async.cg.shared.global [%0], [%1], 16, %2;"
                 :: "r"(saddr), "l"(gaddr), "r"(sz));
}
#define CP_COMMIT() asm volatile("cp.async.commit_group;")
#define CP_WAIT0()  asm volatile("cp.async.wait_group 0;")
#define CP_WAIT1()  asm volatile("cp.async.wait_group 1;")
#define BAR64(id)   asm volatile("bar.sync %0, 64;" :: "r"(id) : "memory")

__device__ __forceinline__ float exp2_nc(float y) {
    float z = __fadd_rn(y, 12582912.f);
    float n = __fsub_rn(z, 12582912.f);
    float f = __fsub_rn(y, n);
    float r = 0.0096181291f;
    r = fmaf(r, f, 0.055504109f);
    r = fmaf(r, f, 0.24022651f);
    r = fmaf(r, f, 0.69314718f);
    r = fmaf(r, f, 1.0f);
    int e = __float_as_int(z);
    float s = __int_as_float((e - 1262485377) << 23);
    return r * s;
}

// ---------------- fused fp32 -> bf16 convert (paired) + conv weight prep -----
#define CVT_N0 (MEMLEN*BSZ*DM/2)
#define CVT_N1 (QLEN*BSZ*DM/2)
#define CVT_N2 (QKV*DM/2)
#define CVT_N3 (KLEN*DM/2)
#define CVT_N4 (DM*DM/2)
#define CVT_N6 (3*7*64*32)
#define CVT_C0 (CVT_N0)
#define CVT_C1 (CVT_C0 + CVT_N1)
#define CVT_C2 (CVT_C1 + CVT_N2)
#define CVT_C3 (CVT_C2 + CVT_N3)
#define CVT_C4 (CVT_C3 + CVT_N4)
#define CVT_C5 (CVT_C4 + CVT_N4)
#define CVT_NPAIR (CVT_C5/2)
__global__ void k_cvt8(const float* __restrict__ mems, const float* __restrict__ w,
                       const float* __restrict__ qkvW, const float* __restrict__ r,
                       const float* __restrict__ rW,   const float* __restrict__ oW,
                       const float* __restrict__ cq,   const float* __restrict__ ck,
                       const float* __restrict__ cv)
{
    int idx = blockIdx.x * blockDim.x + threadIdx.x;
    int stride = gridDim.x * blockDim.x;
    for (int i = idx; i < CVT_NPAIR + CVT_N6; i += stride) {
        if (i < CVT_NPAIR) {
            int ww = 2 * i;                  // word index (pairs never straddle segs)
            const float* s;
            uint32_t* d;
            int off;
            if (ww < CVT_C0)      { s = mems; d = g_xh;          off = ww; }
            else if (ww < CVT_C1) { s = w;    d = g_xh + CVT_C0; off = ww - CVT_C0; }
            else if (ww < CVT_C2) { s = qkvW; d = g_wh;          off = ww - CVT_C1; }
            else if (ww < CVT_C3) { s = r;    d = g_rh;          off = ww - CVT_C2; }
            else if (ww < CVT_C4) { s = rW;   d = g_rWh;         off = ww - CVT_C3; }
            else                  { s = oW;   d = g_oWh;         off = ww - CVT_C4; }
            float4 v = *(const float4*)&s[2*off];
            *(uint2*)&d[off] = make_uint2(pk(v.x, v.y), pk(v.z, v.w));
        } else {
            int off = i - CVT_NPAIR;
            int ct = off >> 11;
            int c = ct / 7, tap = ct % 7;
            int e = off & 2047;
            int oc = e >> 5, icw = e & 31;
            const float* src = (c == 0) ? cq : (c == 1) ? ck : cv;
            float w0 = src[(oc*64 + 2*icw    )*7 + tap];
            float w1 = src[(oc*64 + 2*icw + 1)*7 + tap];
            g_wt[(ct*64 + oc)*32 + icw] = pk(w0, w1);
        }
    }
}

// ---------------- BF16 GEMM body: 3-stage cp.async + ldmatrix ----------------
#define GSW 12
#define NSTG 3
__device__ __forceinline__ void mm_body(const uint32_t* __restrict__ A,
                                        const uint32_t* __restrict__ B,
                                        void* __restrict__ Cout,
                                        int N, int K, int pack, int m0, int n0)
{
    __shared__ uint32_t As[NSTG][128*GSW];
    __shared__ uint32_t Bs[NSTG][128*GSW];
    const int tid = threadIdx.x;
    const int warp = tid >> 5, lane = tid & 31;
    const int wm = warp & 3, wn = warp >> 2;
    const int g = lane >> 2, tg = lane & 3;
    const int quad = lane >> 3;
    const int Kw = K / 2;
    const int iters = Kw / 8;

    const uint32_t smA = (uint32_t)__cvta_generic_to_shared(As);
    const uint32_t smB = (uint32_t)__cvta_generic_to_shared(Bs);
    const uint32_t apat = (uint32_t)((lane & 15)*GSW + (lane >> 4)*4)*4;
    const uint32_t bpat = (uint32_t)((((quad & 2)*4) + (lane & 7))*GSW + (quad & 1)*4)*4;

    float c[2][8][4];
    #pragma unroll
    for (int mt = 0; mt < 2; mt++)
        #pragma unroll
        for (int nt = 0; nt < 8; nt++)
            #pragma unroll
            for (int q = 0; q < 4; q++) c[mt][nt][q] = 0.f;

    const int lr = tid >> 1;
    const int lh = tid & 1;
    const uint32_t* Ap = A + (size_t)(m0 + lr) * Kw + lh * 4;
    const uint32_t* Bp = B + (size_t)(n0 + lr) * Kw + lh * 4;

    auto stage = [&](int s, int kw) {
        uint32_t so = (uint32_t)(s*128*GSW + lr*GSW + lh*4)*4;
        cpa16(smA + so, Ap + kw);
        cpa16(smB + so, Bp + kw);
    };

    stage(0, 0);
    CP_COMMIT();
    if (iters > 1) stage(1, 8);
    CP_COMMIT();

    for (int i = 0; i < iters; i++) {
        CP_WAIT1();
        __syncthreads();
        int pf = i + NSTG - 1;
        if (pf < iters) stage(pf % NSTG, pf * 8);
        CP_COMMIT();

        const int buf = i % NSTG;
        const uint32_t abase = smA + (uint32_t)(buf*128*GSW)*4;
        const uint32_t bbase = smB + (uint32_t)(buf*128*GSW)*4;
        uint32_t af[2][4], bf[8][2];
        #pragma unroll
        for (int mt = 0; mt < 2; mt++)
            ldsm4(af[mt][0], af[mt][1], af[mt][2], af[mt][3],
                  abase + (uint32_t)((wm*32 + mt*16)*GSW)*4 + apat);
        #pragma unroll
        for (int nt2 = 0; nt2 < 4; nt2++) {
            uint32_t b0, b1, b2, b3;
            ldsm4(b0, b1, b2, b3,
                  bbase + (uint32_t)((wn*64 + nt2*16)*GSW)*4 + bpat);
            bf[nt2*2][0] = b0;   bf[nt2*2][1] = b1;
            bf[nt2*2+1][0] = b2; bf[nt2*2+1][1] = b3;
        }
        #pragma unroll
        for (int mt = 0; mt < 2; mt++)
            #pragma unroll
            for (int nt = 0; nt < 8; nt++)
                mma_bf16(c[mt][nt][0], c[mt][nt][1], c[mt][nt][2], c[mt][nt][3],
                         af[mt][0], af[mt][1], af[mt][2], af[mt][3],
                         bf[nt][0], bf[nt][1]);
    }

    #pragma unroll
    for (int mt = 0; mt < 2; mt++) {
        int row0 = m0 + wm * 32 + mt * 16 + g;
        #pragma unroll
        for (int nt = 0; nt < 8; nt++) {
            int col = n0 + wn * 64 + nt * 8 + tg * 2;
            if (pack) {
                uint32_t* Cp = (uint32_t*)Cout;
                Cp[((size_t)row0 * N + col)/2]       = pk(c[mt][nt][0], c[mt][nt][1]);
                Cp[((size_t)(row0 + 8) * N + col)/2] = pk(c[mt][nt][2], c[mt][nt][3]);
            } else {
                float* C = (float*)Cout;
                *(float2*)&C[(size_t)row0 * N + col]       = make_float2(c[mt][nt][0], c[mt][nt][1]);
                *(float2*)&C[(size_t)(row0 + 8) * N + col] = make_float2(c[mt][nt][2], c[mt][nt][3]);
            }
        }
    }
}

__global__ __launch_bounds__(256, 2) void mm_h(const uint32_t* __restrict__ A,
                                               const uint32_t* __restrict__ B,
                                               void* __restrict__ Cout,
                                               int N, int K, int pack)
{
    mm_body(A, B, Cout, N, K, pack, blockIdx.y * 128, blockIdx.x * 128);
}

__global__ __launch_bounds__(256, 2) void mm_qkr()
{
    int y = blockIdx.y;
    if (y < 64) {
        mm_body(g_xh, g_wh, g_qkvh, QKV, DM, 1, y * 128, blockIdx.x * 128);
    } else {
        if (blockIdx.x >= 4) return;
        mm_body(g_rh, g_rWh, g_rkh, DM, DM, 1, (y - 64) * 128, blockIdx.x * 128);
    }
}

// ---------------- fused conv v6: 4m x 2n warp tiling -------------------------
#define CSW 36
#define OFF_WS (134*CSW*4)
__global__ __launch_bounds__(256, 2) void k_conv6(const float* __restrict__ cqb,
                                                  const float* __restrict__ ckb,
                                                  const float* __restrict__ cvb)
{
    extern __shared__ uint32_t cs[];
    const int bx = blockIdx.x;
    int c, t0, len, posoff, chanoff;
    const float* cb;
    uint32_t* outp;
    if (bx < 8)       { c = 0; t0 = bx*128;      len = QLEN; posoff = MEMLEN; chanoff = 0;    cb = cqb; outp = g_q; }
    else if (bx < 24) { c = 1; t0 = (bx-8)*128;  len = KLEN; posoff = 0;      chanoff = DM;   cb = ckb; outp = g_k; }
    else              { c = 2; t0 = (bx-24)*128; len = KLEN; posoff = 0;      chanoff = 2*DM; cb = cvb; outp = g_v; }
    const int nb = blockIdx.y;
    const int n = nb >> 2, b = nb & 3;
    const int tid = threadIdx.x;
    const int warp = tid >> 5, lane = tid & 31;
    const int wm = warp & 3, wn = warp >> 2;
    const int g = lane >> 2, tg = lane & 3;
    const int quad = lane >> 3;
    const uint32_t smbC = (uint32_t)__cvta_generic_to_shared(cs);

    for (int e = tid; e < 134*8; e += 256) {
        int u = e >> 3, w4 = (e & 7) * 4;
        int pos = t0 + u - 3;
        int ok = (pos >= 0 && pos < len);
        int pc = ok ? pos : 0;
        cpa16z(smbC + (uint32_t)(u*CSW + w4)*4,
               &g_qkvh[((size_t)(pc + posoff)*(BSZ*QKV) + b*QKV + chanoff + n*DH)/2 + w4], ok);
    }
    {
        const uint32_t* src = g_wt + c*7*64*32;
        for (int e = tid; e < 3584; e += 256) {
            int s4 = e * 4;
            int to = s4 >> 5, icw = s4 & 31;
            cpa16(smbC + OFF_WS + (uint32_t)(to*CSW + icw)*4, &src[s4]);
        }
    }
    CP_COMMIT();
    CP_WAIT0();
    __syncthreads();

    float acc[2][4][4];
    #pragma unroll
    for (int am = 0; am < 2; am++)
        #pragma unroll
        for (int nf = 0; nf < 4; nf++)
            #pragma unroll
            for (int q = 0; q < 4; q++) acc[am][nf][q] = 0.f;

    const uint32_t bpat = (uint32_t)((((quad & 2)*4) + (lane & 7))*CSW + (quad & 1)*4)*4;

    #pragma unroll
    for (int tap = 0; tap < 7; tap++) {
        const uint32_t apat0 = (uint32_t)((wm*16 + (lane & 15) + tap)*CSW + (lane >> 4)*4)*4;
        #pragma unroll
        for (int k0 = 0; k0 < 4; k0++) {
            uint32_t a0[2], a1[2], a2[2], a3[2];
            ldsm4(a0[0], a1[0], a2[0], a3[0], smbC + apat0 + k0*32);
            ldsm4(a0[1], a1[1], a2[1], a3[1], smbC + apat0 + (uint32_t)(64*CSW)*4 + k0*32);
            #pragma unroll
            for (int nf2 = 0; nf2 < 2; nf2++) {
                uint32_t b0, b1, b2, b3;
                ldsm4(b0, b1, b2, b3,
                      smbC + OFF_WS + bpat
                      + (uint32_t)((tap*64 + wn*32 + nf2*16)*CSW)*4 + k0*32);
                #pragma unroll
                for (int am = 0; am < 2; am++) {
                    mma_bf16(acc[am][nf2*2][0], acc[am][nf2*2][1],
                             acc[am][nf2*2][2], acc[am][nf2*2][3],
                             a0[am], a1[am], a2[am], a3[am], b0, b1);
                    mma_bf16(acc[am][nf2*2+1][0], acc[am][nf2*2+1][1],
                             acc[am][nf2*2+1][2], acc[am][nf2*2+1][3],
                             a0[am], a1[am], a2[am], a3[am], b2, b3);
                }
            }
        }
    }

    #pragma unroll
    for (int am = 0; am < 2; am++) {
        #pragma unroll
        for (int nf = 0; nf < 4; nf++) {
            int oc = wn*32 + nf*8 + 2*tg;
            float2 bb = *(const float2*)&cb[oc];
            int row = t0 + wm*16 + am*64 + g;
            size_t w0 = ((size_t)row*(BSZ*DM) + b*DM)/2 + n*32 + oc/2;
            size_t w1 = ((size_t)(row+8)*(BSZ*DM) + b*DM)/2 + n*32 + oc/2;
            outp[w0] = pk(acc[am][nf][0] + bb.x, acc[am][nf][1] + bb.y);
            outp[w1] = pk(acc[am][nf][2] + bb.x, acc[am][nf][3] + bb.y);
        }
    }
}

// ---------------- attention v13: rotated BDR (vector softmax gather) ---------
#define ASW 36
#define W_QW 0
#define W_QR 2304
#define W_K0 4608
#define W_K1 6912
#define W_V0 9216
#define W_V1 11520
#define W_R0 13824
#define W_R1 16128
#define W_BDR 18432
__global__ __launch_bounds__(256, 2) void k_attn13(const float* __restrict__ rwb,
                                                   const float* __restrict__ rrb)
{
    extern __shared__ uint32_t smu[];
    float* BDR = (float*)(smu + W_BDR);

    const int tid = threadIdx.x;
    const int warp = tid >> 5, lane = tid & 31;
    const int wm = warp & 3, wn = warp >> 2;
    const int g = lane >> 2, tg = lane & 3;
    const int quad = lane >> 3;

    const uint32_t smb = (uint32_t)__cvta_generic_to_shared(smu);
    const uint32_t aoff  = (uint32_t)((wm*16 + (lane & 15))*ASW + (lane >> 4)*4)*4;
    const uint32_t bpat  = (uint32_t)((((quad & 2)*4) + (lane & 7))*ASW + (quad & 1)*4)*4;
    const uint32_t boff  = bpat + (uint32_t)(wn*32)*ASW*4;
    const uint32_t tvpat = (uint32_t)(((quad & 1)*8 + (lane & 7))*ASW + (quad >> 1)*4)*4;

    const int il0 = wm*16 + g;
    const int il1 = il0 + 8;
    float* const bdr0 = &BDR[il0*132];
    float* const bdr1 = &BDR[il1*132];

    #pragma unroll 1
    for (int s = 0; s < 2; s++) {
        const int q = s ? (511 - (int)blockIdx.x) : (int)blockIdx.x;
        const int x = q >> 5;
        const int bn = q & 31;
        const int b = bn >> 3, n = bn & 7;
        const int i0 = (15 - x) * 64;
        const int jjb0 = 960 - i0;
        const int ntiles = i0/64 + 17;

        auto stage_kv = [&](int buf, int j0c) {
            const uint32_t kb = smb + (uint32_t)(buf ? W_K1 : W_K0)*4;
            const uint32_t vb = smb + (uint32_t)(buf ? W_V1 : W_V0)*4;
            #pragma unroll
            for (int e0 = 0; e0 < 2; e0++) {
                int e = tid + e0*256;
                int jl = e >> 3, w4 = (e & 7) * 4;
                size_t wi = ((size_t)(j0c + jl)*(BSZ*DM) + b*DM + n*DH)/2 + w4;
                uint32_t so = (uint32_t)(jl*ASW + w4)*4;
                cpa16(kb + so, &g_k[wi]);
                cpa16(vb + so, &g_v[wi]);
            }
        };
        auto stage_rw = [&](int buf, int cb2) {
            const uint32_t rb = smb + (uint32_t)(buf ? W_R1 : W_R0)*4;
            #pragma unroll
            for (int e0 = 0; e0 < 2; e0++) {
                int e = tid + e0*256;
                int l = e >> 3, w4 = (e & 7) * 4;
                int jj = cb2 + l;
                int ok = (jj < KLEN);
                int jc = ok ? jj : (KLEN - 1);
                cpa16z(rb + (uint32_t)(l*ASW + w4)*4,
                       &g_rkh[((size_t)jc*DM + n*DH)/2 + w4], ok);
            }
        };
        // BD pass with rotated write: BDR[il][(slot + il + 1)&127] = BD[il][slot]
        auto bd_pass = [&](int rbuf, int cb2) {
            const uint32_t rwo = smb + (uint32_t)(rbuf ? W_R1 : W_R0)*4;
            const int s0 = cb2 & 127;
            float pc[4][4];
            #pragma unroll
            for (int nf = 0; nf < 4; nf++)
                #pragma unroll
                for (int qq = 0; qq < 4; qq++) pc[nf][qq] = 0.f;
            #pragma unroll
            for (int k0 = 0; k0 < 4; k0++) {
                uint32_t a0, a1, a2, a3, p0, p1, p2, p3, q0, q1, q2, q3;
                ldsm4(a0, a1, a2, a3, smb + W_QR*4 + aoff + k0*32);
                ldsm4(p0, p1, p2, p3, rwo + boff + k0*32);
                ldsm4(q0, q1, q2, q3, rwo + boff + 16*ASW*4 + k0*32);
                mma_bf16(pc[0][0], pc[0][1], pc[0][2], pc[0][3], a0, a1, a2, a3, p0, p1);
                mma_bf16(pc[1][0], pc[1][1], pc[1][2], pc[1][3], a0, a1, a2, a3, p2, p3);
                mma_bf16(pc[2][0], pc[2][1], pc[2][2], pc[2][3], a0, a1, a2, a3, q0, q1);
                mma_bf16(pc[3][0], pc[3][1], pc[3][2], pc[3][3], a0, a1, a2, a3, q2, q3);
            }
            #pragma unroll
            for (int nf = 0; nf < 4; nf++) {
                int cc = s0 + wn*32 + nf*8 + 2*tg;     // slot of pc[nf][0]
                int c0 = (cc + il0 + 1) & 127;
                bdr0[c0]            = pc[nf][0];
                bdr0[(c0 + 1) & 127] = pc[nf][1];
                int d0 = (c0 + 8) & 127;               // = (cc + il1 + 1)&127
                bdr1[d0]            = pc[nf][2];
                bdr1[(d0 + 1) & 127] = pc[nf][3];
            }
        };

        stage_kv(0, 0);
        stage_rw(0, jjb0);
        stage_rw(1, jjb0 + 64);
        CP_COMMIT();

        const float SCL = 0.18033688f;
        for (int e = tid; e < 64*16; e += 256) {
            int ii = e >> 4, d4 = (e & 15) * 4;
            size_t wi = ((size_t)(i0+ii)*(BSZ*DM) + b*DM + n*DH + d4) / 2;
            uint2 qv = *(const uint2*)&g_q[wi];
            float q0 = bl(qv.x), q1 = bh(qv.x), q2 = bl(qv.y), q3 = bh(qv.y);
            float4 wv = *(const float4*)&rwb[n*DH + d4];
            float4 rv = *(const float4*)&rrb[n*DH + d4];
            smu[W_QW + ii*ASW + d4/2]     = pk((q0 + wv.x)*SCL, (q1 + wv.y)*SCL);
            smu[W_QW + ii*ASW + d4/2 + 1] = pk((q2 + wv.z)*SCL, (q3 + wv.w)*SCL);
            smu[W_QR + ii*ASW + d4/2]     = pk((q0 + rv.x)*SCL, (q1 + rv.y)*SCL);
            smu[W_QR + ii*ASW + d4/2 + 1] = pk((q2 + rv.z)*SCL, (q3 + rv.w)*SCL);
        }
        CP_WAIT0();
        __syncthreads();

        bd_pass(0, jjb0);

        float oacc[8][4];
        #pragma unroll
        for (int nf = 0; nf < 8; nf++)
            #pragma unroll
            for (int qq = 0; qq < 4; qq++) oacc[nf][qq] = 0.f;
        float l0 = 0.f, l1 = 0.f;

        for (int t = 0; t < ntiles; t++) {
            const int kvb = t & 1;
            const int j0 = t * 64;
            const int jjb = j0 - i0 + 960;

            if (t + 1 < ntiles) stage_kv(kvb ^ 1, j0 + 64);
            stage_rw(kvb, jjb0 + 64*(t + 2));
            CP_COMMIT();

            const uint32_t kso = smb + (uint32_t)(kvb ? W_K1 : W_K0)*4;
            float sc[4][4];
            #pragma unroll
            for (int nf = 0; nf < 4; nf++)
                #pragma unroll
                for (int qq = 0; qq < 4; qq++) sc[nf][qq] = 0.f;
            #pragma unroll
            for (int k0 = 0; k0 < 4; k0++) {
                uint32_t a0, a1, a2, a3, p0, p1, p2, p3, q0, q1, q2, q3;
                ldsm4(a0, a1, a2, a3, smb + W_QW*4 + aoff + k0*32);
                ldsm4(p0, p1, p2, p3, kso + boff + k0*32);
                ldsm4(q0, q1, q2, q3, kso + boff + 16*ASW*4 + k0*32);
                mma_bf16(sc[0][0], sc[0][1], sc[0][2], sc[0][3], a0, a1, a2, a3, p0, p1);
                mma_bf16(sc[1][0], sc[1][1], sc[1][2], sc[1][3], a0, a1, a2, a3, p2, p3);
                mma_bf16(sc[2][0], sc[2][1], sc[2][2], sc[2][3], a0, a1, a2, a3, q0, q1);
                mma_bf16(sc[3][0], sc[3][1], sc[3][2], sc[3][3], a0, a1, a2, a3, q2, q3);
            }

            bd_pass(kvb ^ 1, jjb0 + 64*(t + 1));
            BAR64(wm + 1);

            const int jjb2 = jjb + 63;
            uint32_t a_lo[4], a_hi[4];
            if (t + 1 < ntiles) {
                #pragma unroll
                for (int nf = 0; nf < 4; nf++) {
                    int jl = wn*32 + nf*8 + 2*tg;
                    int c = (jjb2 + jl + 1) & 127;     // even; il-independent
                    float2 b0 = *(float2*)&bdr0[c];
                    float2 b1 = *(float2*)&bdr1[c];
                    float p00 = exp2_nc(sc[nf][0] + b0.x);
                    float p01 = exp2_nc(sc[nf][1] + b0.y);
                    float p10 = exp2_nc(sc[nf][2] + b1.x);
                    float p11 = exp2_nc(sc[nf][3] + b1.y);
                    l0 += p00 + p01;
                    l1 += p10 + p11;
                    a_lo[nf] = pk(p00, p01);
                    a_hi[nf] = pk(p10, p11);
                }
            } else {
                #pragma unroll
                for (int nf = 0; nf < 4; nf++) {
                    int jl = wn*32 + nf*8 + 2*tg;
                    int jg = j0 + jl;
                    int c = (jjb2 + jl + 1) & 127;
                    float2 b0 = *(float2*)&bdr0[c];
                    float2 b1 = *(float2*)&bdr1[c];
                    float p00 = 0.f, p01 = 0.f, p10 = 0.f, p11 = 0.f;
                    if (jg <= i0 + il0 + MEMLEN)     p00 = exp2_nc(sc[nf][0] + b0.x);
                    if (jg + 1 <= i0 + il0 + MEMLEN) p01 = exp2_nc(sc[nf][1] + b0.y);
                    if (jg <= i0 + il1 + MEMLEN)     p10 = exp2_nc(sc[nf][2] + b1.x);
                    if (jg + 1 <= i0 + il1 + MEMLEN) p11 = exp2_nc(sc[nf][3] + b1.y);
                    l0 += p00 + p01;
                    l1 += p10 + p11;
                    a_lo[nf] = pk(p00, p01);
                    a_hi[nf] = pk(p10, p11);
                }
            }

            const uint32_t vso = smb + (uint32_t)(kvb ? W_V1 : W_V0)*4;
            #pragma unroll
            for (int k0 = 0; k0 < 2; k0++) {
                uint32_t a0 = a_lo[2*k0], a1 = a_hi[2*k0];
                uint32_t a2 = a_lo[2*k0+1], a3 = a_hi[2*k0+1];
                uint32_t jbase = (uint32_t)((wn*32 + k0*16)*ASW)*4;
                #pragma unroll
                for (int dd = 0; dd < 4; dd++) {
                    uint32_t b0, b1, b2, b3;
                    ldsm4t(b0, b1, b2, b3, vso + tvpat + jbase + (uint32_t)(dd*8)*4);
                    mma_bf16(oacc[dd*2][0], oacc[dd*2][1], oacc[dd*2][2], oacc[dd*2][3],
                             a0, a1, a2, a3, b0, b1);
                    mma_bf16(oacc[dd*2+1][0], oacc[dd*2+1][1], oacc[dd*2+1][2], oacc[dd*2+1][3],
                             a0, a1, a2, a3, b2, b3);
                }
            }

            CP_WAIT0();
            __syncthreads();
        }

        l0 += __shfl_xor_sync(0xffffffffu, l0, 1);
        l0 += __shfl_xor_sync(0xffffffffu, l0, 2);
        l1 += __shfl_xor_sync(0xffffffffu, l1, 1);
        l1 += __shfl_xor_sync(0xffffffffu, l1, 2);
        float* obuf = BDR;
        float* lbuf = BDR + 4*16*68;
        if (wn == 1) {
            #pragma unroll
            for (int nf = 0; nf < 8; nf++) {
                int d = nf*8 + 2*tg;
                *(float2*)&obuf[il0*68 + d] = make_float2(oacc[nf][0], oacc[nf][1]);
                *(float2*)&obuf[il1*68 + d] = make_float2(oacc[nf][2], oacc[nf][3]);
            }
            if (tg == 0) { lbuf[il0] = l0; lbuf[il1] = l1; }
        }
        __syncthreads();
        if (wn == 0) {
            float inv0 = 1.f / (l0 + lbuf[il0]);
            float inv1 = 1.f / (l1 + lbuf[il1]);
            #pragma unroll
            for (int nf = 0; nf < 8; nf++) {
                int d = nf*8 + 2*tg;
                float2 o0 = *(float2*)&obuf[il0*68 + d];
                float2 o1 = *(float2*)&obuf[il1*68 + d];
                g_avh[((size_t)(i0+il0)*(BSZ*DM) + b*DM + n*DH + d)/2] =
                    pk((oacc[nf][0]+o0.x)*inv0, (oacc[nf][1]+o0.y)*inv0);
                g_avh[((size_t)(i0+il1)*(BSZ*DM) + b*DM + n*DH + d)/2] =
                    pk((oacc[nf][2]+o1.x)*inv1, (oacc[nf][3]+o1.y)*inv1);
            }
        }
    }
}

// ---------------- residual + layernorm: warp per row -------------------------
__global__ __launch_bounds__(256) void k_ln2(const float* __restrict__ w,
                                             const float* __restrict__ g,
                                             const float* __restrict__ be,
                                             float* __restrict__ out)
{
    int row = blockIdx.x * 8 + (threadIdx.x >> 5);
    int lane = threadIdx.x & 31;
    const float* wr = w    + (size_t)row * DM;
    const float* ar = g_ao + (size_t)row * DM;

    float4 x[4];
    float s = 0.f;
    #pragma unroll
    for (int c = 0; c < 4; c++) {
        int idx = c*128 + lane*4;
        float4 a = *(const float4*)&wr[idx];
        float4 o = *(const float4*)&ar[idx];
        x[c] = make_float4(a.x+o.x, a.y+o.y, a.z+o.z, a.w+o.w);
        s += x[c].x + x[c].y + x[c].z + x[c].w;
    }
    #pragma unroll
    for (int m = 16; m > 0; m >>= 1) s += __shfl_xor_sync(0xffffffffu, s, m);
    float mu = s * (1.f / DM);
    float v = 0.f;
    #pragma unroll
    for (int c = 0; c < 4; c++) {
        float dx = x[c].x - mu, dy = x[c].y - mu, dz = x[c].z - mu, dw = x[c].w - mu;
        x[c] = make_float4(dx, dy, dz, dw);
        v += dx*dx + dy*dy + dz*dz + dw*dw;
    }
    #pragma unroll
    for (int m = 16; m > 0; m >>= 1) v += __shfl_xor_sync(0xffffffffu, v, m);
    float rs = rsqrtf(v * (1.f / DM) + 1e-5f);
    #pragma unroll
    for (int c = 0; c < 4; c++) {
        int idx = c*128 + lane*4;
        float4 gg = *(const float4*)&g[idx];
        float4 bb = *(const float4*)&be[idx];
        float4 r = make_float4(x[c].x*rs*gg.x + bb.x, x[c].y*rs*gg.y + bb.y,
                               x[c].z*rs*gg.z + bb.z, x[c].w*rs*gg.w + bb.w);
        *(float4*)&out[(size_t)row*DM + idx] = r;
    }
}

// ---------------- launcher ---------------------------------------------------
extern "C" void kernel_launch(void* const* d_in, const int* in_sizes, int n_in,
                              void* d_out, int out_size)
{
    (void)in_sizes; (void)n_in; (void)out_size;
    const float* w    = (const float*)d_in[0];
    const float* r    = (const float*)d_in[1];
    const float* mems = (const float*)d_in[2];
    const float* rwb  = (const float*)d_in[3];
    const float* rrb  = (const float*)d_in[4];
    const float* qkvW = (const float*)d_in[5];
    const float* rW   = (const float*)d_in[6];
    const float* cqw  = (const float*)d_in[7];
    const float* cqb  = (const float*)d_in[8];
    const float* ckw  = (const float*)d_in[9];
    const float* ckb  = (const float*)d_in[10];
    const float* cvw  = (const float*)d_in[11];
    const float* cvb  = (const float*)d_in[12];
    const float* oW   = (const float*)d_in[13];
    const float* lng  = (const float*)d_in[14];
    const float* lnb  = (const float*)d_in[15];
    float* out = (float*)d_out;

    uint32_t *p_avh, *p_oWh;
    float *p_ao;
    cudaGetSymbolAddress((void**)&p_avh, g_avh);
    cudaGetSymbolAddress((void**)&p_oWh, g_oWh);
    cudaGetSymbolAddress((void**)&p_ao,  g_ao);

    dim3 b256(256);

    k_cvt8<<<1024, b256>>>(mems, w, qkvW, r, rW, oW, cqw, ckw, cvw);

    mm_qkr<<<dim3(QKV/128, 80), b256>>>();

    int csm = (134*CSW + 7*64*CSW) * 4;
    cudaFuncSetAttribute(k_conv6, cudaFuncAttributeMaxDynamicSharedMemorySize, csm);
    k_conv6<<<dim3(40, NH*BSZ), b256, csm>>>(cqb, ckb, cvb);

    int asm_ = (W_BDR + 64*132) * 4;
    cudaFuncSetAttribute(k_attn13, cudaFuncAttributeMaxDynamicSharedMemorySize, asm_);
    k_attn13<<<256, b256, asm_>>>(rwb, rrb);

    mm_h<<<dim3(DM/128, (QLEN*BSZ)/128), b256>>>(p_avh, p_oWh, p_ao, DM, DM, 0);
    k_ln2<<<(QLEN*BSZ)/8, b256>>>(w, lng, lnb, out);
}